// round 2
// baseline (speedup 1.0000x reference)
#include <cuda_runtime.h>
#include <math.h>

#define HH   512
#define ZZ   128
#define EE   512
#define DD   1152      // 2H + Z
#define VV   32000
#define BSZ  256
#define NN   128
#define G3D  3456      // 3*D

// ---------------- scratch (device globals; no allocation allowed) ----------------
__device__ float g_dt_e [BSZ * HH];
__device__ float g_dt_s [BSZ * HH];
__device__ float g_u_e  [BSZ * NN];
__device__ float g_u_s  [BSZ * NN];
__device__ float g_ctx_e[BSZ * HH];
__device__ float g_ctx_s[BSZ * HH];
__device__ float g_plan [BSZ * 2];
__device__ float g_yctx [BSZ * (EE + HH)];
__device__ float g_x    [BSZ * HH];
__device__ float g_gx   [BSZ * G3D];
__device__ float g_gh   [BSZ * G3D];
__device__ float g_h    [BSZ * DD];

// =================================================================================
// Generic fp32 GEMM:  C[M,N] = A[M,K] @ B[N,K]^T (+ bias[n])
// Tiles: BM=BN=128, BK=16, 256 threads, 8x8 micro-tile per thread.
// Requires M%128==0, N%128==0, K%16==0 (true for every call here).
// =================================================================================
__global__ void __launch_bounds__(256, 2) gemm_kernel(
    const float* __restrict__ A, const float* __restrict__ B,
    const float* __restrict__ bias, float* __restrict__ C,
    int M, int N, int K)
{
    __shared__ float As[16][132];
    __shared__ float Bs[16][132];

    const int m0 = blockIdx.y * 128;
    const int n0 = blockIdx.x * 128;
    const int t  = threadIdx.x;
    const int tr = t >> 4;          // 0..15
    const int tc = t & 15;          // 0..15
    const int r0 = t >> 2;          // 0..63
    const int c4 = (t & 3) * 4;     // 0,4,8,12

    const float* Ab = A + (size_t)m0 * K;
    const float* Bb = B + (size_t)n0 * K;

    float acc[8][8];
#pragma unroll
    for (int i = 0; i < 8; i++)
#pragma unroll
        for (int j = 0; j < 8; j++) acc[i][j] = 0.f;

    for (int k0 = 0; k0 < K; k0 += 16) {
        float4 av0 = *(const float4*)(Ab + (size_t)r0        * K + k0 + c4);
        float4 av1 = *(const float4*)(Ab + (size_t)(r0 + 64) * K + k0 + c4);
        float4 bv0 = *(const float4*)(Bb + (size_t)r0        * K + k0 + c4);
        float4 bv1 = *(const float4*)(Bb + (size_t)(r0 + 64) * K + k0 + c4);
        __syncthreads();
        As[c4 + 0][r0] = av0.x; As[c4 + 1][r0] = av0.y;
        As[c4 + 2][r0] = av0.z; As[c4 + 3][r0] = av0.w;
        As[c4 + 0][r0 + 64] = av1.x; As[c4 + 1][r0 + 64] = av1.y;
        As[c4 + 2][r0 + 64] = av1.z; As[c4 + 3][r0 + 64] = av1.w;
        Bs[c4 + 0][r0] = bv0.x; Bs[c4 + 1][r0] = bv0.y;
        Bs[c4 + 2][r0] = bv0.z; Bs[c4 + 3][r0] = bv0.w;
        Bs[c4 + 0][r0 + 64] = bv1.x; Bs[c4 + 1][r0 + 64] = bv1.y;
        Bs[c4 + 2][r0 + 64] = bv1.z; Bs[c4 + 3][r0 + 64] = bv1.w;
        __syncthreads();
#pragma unroll
        for (int k = 0; k < 16; k++) {
            float a[8], b[8];
            *(float4*)&a[0] = *(const float4*)&As[k][tr * 8];
            *(float4*)&a[4] = *(const float4*)&As[k][tr * 8 + 4];
            *(float4*)&b[0] = *(const float4*)&Bs[k][tc * 8];
            *(float4*)&b[4] = *(const float4*)&Bs[k][tc * 8 + 4];
#pragma unroll
            for (int i = 0; i < 8; i++)
#pragma unroll
                for (int j = 0; j < 8; j++)
                    acc[i][j] += a[i] * b[j];
        }
    }

#pragma unroll
    for (int i = 0; i < 8; i++) {
        const int m = m0 + tr * 8 + i;
#pragma unroll
        for (int j4 = 0; j4 < 8; j4 += 4) {
            const int n = n0 + tc * 8 + j4;
            float4 v;
            v.x = acc[i][j4 + 0]; v.y = acc[i][j4 + 1];
            v.z = acc[i][j4 + 2]; v.w = acc[i][j4 + 3];
            if (bias) {
                v.x += bias[n + 0]; v.y += bias[n + 1];
                v.z += bias[n + 2]; v.w += bias[n + 3];
            }
            *(float4*)(C + (size_t)m * N + n) = v;
        }
    }
}

// =================================================================================
// Fused attention score kernel:
//   u[m] = sum_k vt[k] * tanh( enc[m,:] @ W1[k,:] + dt[b,k] ),  masked to -inf.
// enc flattened to [BS*NN, 512]; one block computes a 128-row tile (one batch),
// looping over the 512 output columns in 4 chunks of 128 with fused epilogue.
// This never materializes et (saves ~256 MB of HBM round trip).
// =================================================================================
__global__ void __launch_bounds__(256, 2) attn_u_kernel(
    const float* __restrict__ enc,              // [BS*NN, 512]
    const float* __restrict__ W1,               // [512, 512]
    const float* __restrict__ dt,               // [BS, 512]
    const float* __restrict__ vt,               // [512]
    const int* __restrict__ mask,               // [BS*NN] (bool stored as int32)
    float* __restrict__ u)                      // [BS*NN]
{
    __shared__ float As[16][132];
    __shared__ float Bs[16][132];

    const int m0 = blockIdx.x * 128;
    const int b  = m0 >> 7;            // 128 rows per batch, tile-aligned
    const int t  = threadIdx.x;
    const int tr = t >> 4;
    const int tc = t & 15;
    const int r0 = t >> 2;
    const int c4 = (t & 3) * 4;

    const float* Ab = enc + (size_t)m0 * 512;
    float up[8];
#pragma unroll
    for (int i = 0; i < 8; i++) up[i] = 0.f;

    for (int nc = 0; nc < 4; nc++) {
        const int n0 = nc * 128;
        const float* Bb = W1 + (size_t)n0 * 512;

        float acc[8][8];
#pragma unroll
        for (int i = 0; i < 8; i++)
#pragma unroll
            for (int j = 0; j < 8; j++) acc[i][j] = 0.f;

        for (int k0 = 0; k0 < 512; k0 += 16) {
            float4 av0 = *(const float4*)(Ab + (size_t)r0        * 512 + k0 + c4);
            float4 av1 = *(const float4*)(Ab + (size_t)(r0 + 64) * 512 + k0 + c4);
            float4 bv0 = *(const float4*)(Bb + (size_t)r0        * 512 + k0 + c4);
            float4 bv1 = *(const float4*)(Bb + (size_t)(r0 + 64) * 512 + k0 + c4);
            __syncthreads();
            As[c4 + 0][r0] = av0.x; As[c4 + 1][r0] = av0.y;
            As[c4 + 2][r0] = av0.z; As[c4 + 3][r0] = av0.w;
            As[c4 + 0][r0 + 64] = av1.x; As[c4 + 1][r0 + 64] = av1.y;
            As[c4 + 2][r0 + 64] = av1.z; As[c4 + 3][r0 + 64] = av1.w;
            Bs[c4 + 0][r0] = bv0.x; Bs[c4 + 1][r0] = bv0.y;
            Bs[c4 + 2][r0] = bv0.z; Bs[c4 + 3][r0] = bv0.w;
            Bs[c4 + 0][r0 + 64] = bv1.x; Bs[c4 + 1][r0 + 64] = bv1.y;
            Bs[c4 + 2][r0 + 64] = bv1.z; Bs[c4 + 3][r0 + 64] = bv1.w;
            __syncthreads();
#pragma unroll
            for (int k = 0; k < 16; k++) {
                float a[8], bb[8];
                *(float4*)&a[0]  = *(const float4*)&As[k][tr * 8];
                *(float4*)&a[4]  = *(const float4*)&As[k][tr * 8 + 4];
                *(float4*)&bb[0] = *(const float4*)&Bs[k][tc * 8];
                *(float4*)&bb[4] = *(const float4*)&Bs[k][tc * 8 + 4];
#pragma unroll
                for (int i = 0; i < 8; i++)
#pragma unroll
                    for (int j = 0; j < 8; j++)
                        acc[i][j] += a[i] * bb[j];
            }
        }

        // fused epilogue: tanh(et + dt) . vt  -> per-row partials
#pragma unroll
        for (int j = 0; j < 8; j++) {
            const int n = n0 + tc * 8 + j;
            const float dtv = dt[(size_t)b * 512 + n];
            const float vtv = vt[n];
#pragma unroll
            for (int i = 0; i < 8; i++)
                up[i] += vtv * tanhf(acc[i][j] + dtv);
        }
    }

    // reduce partials across the 16 column-threads (16-lane shuffle groups)
#pragma unroll
    for (int i = 0; i < 8; i++) {
        float v = up[i];
#pragma unroll
        for (int off = 8; off > 0; off >>= 1)
            v += __shfl_down_sync(0xffffffffu, v, off, 16);
        if (tc == 0) {
            const int m = m0 + tr * 8 + i;
            const int nidx = m & 127;
            u[m] = (mask[(size_t)b * NN + nidx] != 0) ? -INFINITY : v;
        }
    }
}

// =================================================================================
// plan = softmax(prev_h @ plan_W^T + plan_b)   (one block per batch row)
// =================================================================================
__global__ void plan_kernel(const float* __restrict__ prev_h,
                            const float* __restrict__ plan_W,
                            const float* __restrict__ plan_b,
                            float* __restrict__ plan,
                            float* __restrict__ out_plan)
{
    const int b = blockIdx.x;
    const int t = threadIdx.x;          // 128 threads
    __shared__ float s0[128], s1[128];
    float a0 = 0.f, a1 = 0.f;
    const float* hb = prev_h + (size_t)b * DD;
    for (int k = t; k < DD; k += 128) {
        const float h = hb[k];
        a0 += h * plan_W[k];
        a1 += h * plan_W[DD + k];
    }
    s0[t] = a0; s1[t] = a1;
    __syncthreads();
    for (int s = 64; s > 0; s >>= 1) {
        if (t < s) { s0[t] += s0[t + s]; s1[t] += s1[t + s]; }
        __syncthreads();
    }
    if (t == 0) {
        const float l0 = s0[0] + plan_b[0];
        const float l1 = s1[0] + plan_b[1];
        const float mx = fmaxf(l0, l1);
        const float e0 = expf(l0 - mx), e1 = expf(l1 - mx);
        const float inv = 1.f / (e0 + e1);
        plan[2 * b] = e0 * inv;       plan[2 * b + 1] = e1 * inv;
        out_plan[2 * b] = e0 * inv;   out_plan[2 * b + 1] = e1 * inv;
    }
}

// =================================================================================
// softmax over u[b,:] then ctx[b,h] = sum_n aw[n] * enc[b,n,h]
// =================================================================================
__global__ void softmax_ctx_kernel(const float* __restrict__ u,
                                   const float* __restrict__ enc,
                                   float* __restrict__ ctx)
{
    const int b = blockIdx.x;
    const int t = threadIdx.x;          // 256 threads
    __shared__ float red[256];
    __shared__ float aw[NN];

    const float uv = (t < NN) ? u[(size_t)b * NN + t] : -INFINITY;
    red[t] = uv;
    __syncthreads();
    for (int s = 128; s > 0; s >>= 1) {
        if (t < s) red[t] = fmaxf(red[t], red[t + s]);
        __syncthreads();
    }
    const float mx = red[0];
    __syncthreads();
    const float e = (t < NN) ? expf(uv - mx) : 0.f;
    red[t] = e;
    __syncthreads();
    for (int s = 128; s > 0; s >>= 1) {
        if (t < s) red[t] += red[t + s];
        __syncthreads();
    }
    const float inv = 1.f / red[0];
    if (t < NN) aw[t] = e * inv;
    __syncthreads();

    const float* eb = enc + (size_t)b * NN * HH;
    for (int h = t; h < HH; h += 256) {
        float s = 0.f;
#pragma unroll 4
        for (int n = 0; n < NN; n++)
            s += aw[n] * eb[(size_t)n * HH + h];
        ctx[(size_t)b * HH + h] = s;
    }
}

// =================================================================================
// context mix + y_ctx = [prev_y | plan0*ctx_e + plan1*ctx_s]
// =================================================================================
__global__ void combine_kernel(const float* __restrict__ prev_y,
                               const float* __restrict__ plan,
                               const float* __restrict__ ctx_e,
                               const float* __restrict__ ctx_s,
                               float* __restrict__ yctx)
{
    const int idx = blockIdx.x * blockDim.x + threadIdx.x;
    if (idx >= BSZ * (EE + HH)) return;
    const int b = idx >> 10;            // E+H = 1024
    const int c = idx & 1023;
    float v;
    if (c < EE) {
        v = prev_y[(size_t)b * EE + c];
    } else {
        const float p0 = plan[2 * b], p1 = plan[2 * b + 1];
        const int h = c - EE;
        v = p0 * ctx_e[(size_t)b * HH + h] + p1 * ctx_s[(size_t)b * HH + h];
    }
    yctx[idx] = v;
}

// =================================================================================
// GRU cell elementwise
// =================================================================================
__global__ void gru_kernel(const float* __restrict__ gx,
                           const float* __restrict__ gh,
                           const float* __restrict__ prev_h,
                           float* __restrict__ h_new,
                           float* __restrict__ out_hid)
{
    const int idx = blockIdx.x * blockDim.x + threadIdx.x;
    if (idx >= BSZ * DD) return;
    const int b = idx / DD;
    const int d = idx - b * DD;
    const float* gxb = gx + (size_t)b * G3D;
    const float* ghb = gh + (size_t)b * G3D;
    const float r = 1.f / (1.f + expf(-(gxb[d] + ghb[d])));
    const float z = 1.f / (1.f + expf(-(gxb[DD + d] + ghb[DD + d])));
    const float n = tanhf(gxb[2 * DD + d] + r * ghb[2 * DD + d]);
    const float h = (1.f - z) * n + z * prev_h[idx];
    h_new[idx] = h;
    out_hid[idx] = h;
}

// =================================================================================
// host launcher — graph-capturable (kernel launches only, default stream)
// =================================================================================
extern "C" void kernel_launch(void* const* d_in, const int* in_sizes, int n_in,
                              void* d_out, int out_size)
{
    const float* prev_y  = (const float*)d_in[0];
    const float* prev_h  = (const float*)d_in[1];
    const float* equ_enc = (const float*)d_in[2];
    const float* sns_enc = (const float*)d_in[3];
    /* d_in[4] z_sample unused by the reference */
    const int* equ_mask = (const int*)d_in[5];
    const int* sns_mask = (const int*)d_in[6];
    const float* W1e    = (const float*)d_in[7];
    const float* W2e    = (const float*)d_in[8];
    const float* vte    = (const float*)d_in[9];
    const float* W1s    = (const float*)d_in[10];
    const float* W2s    = (const float*)d_in[11];
    const float* vts    = (const float*)d_in[12];
    const float* plan_W = (const float*)d_in[13];
    const float* plan_b = (const float*)d_in[14];
    const float* Wc     = (const float*)d_in[15];
    const float* bc     = (const float*)d_in[16];
    const float* w_ih   = (const float*)d_in[17];
    const float* w_hh   = (const float*)d_in[18];
    const float* b_ih   = (const float*)d_in[19];
    const float* b_hh   = (const float*)d_in[20];
    const float* Wout   = (const float*)d_in[21];
    const float* bout   = (const float*)d_in[22];

    float* out      = (float*)d_out;
    float* out_dec  = out;                                        // [256, 32000]
    float* out_hid  = out + (size_t)BSZ * VV;                     // [256, 1152]
    float* out_plan = out + (size_t)BSZ * VV + (size_t)BSZ * DD;  // [256, 2]

    float *dt_e, *dt_s, *u_e, *u_s, *ctx_e, *ctx_s, *plan, *yctx, *x, *gx, *gh, *hn;
    cudaGetSymbolAddress((void**)&dt_e,  g_dt_e);
    cudaGetSymbolAddress((void**)&dt_s,  g_dt_s);
    cudaGetSymbolAddress((void**)&u_e,   g_u_e);
    cudaGetSymbolAddress((void**)&u_s,   g_u_s);
    cudaGetSymbolAddress((void**)&ctx_e, g_ctx_e);
    cudaGetSymbolAddress((void**)&ctx_s, g_ctx_s);
    cudaGetSymbolAddress((void**)&plan,  g_plan);
    cudaGetSymbolAddress((void**)&yctx,  g_yctx);
    cudaGetSymbolAddress((void**)&x,     g_x);
    cudaGetSymbolAddress((void**)&gx,    g_gx);
    cudaGetSymbolAddress((void**)&gh,    g_gh);
    cudaGetSymbolAddress((void**)&hn,    g_h);

    const dim3 blk(256);

    // dt_e = prev_h @ W2e^T ;  dt_s = prev_h @ W2s^T
    gemm_kernel<<<dim3(HH / 128, BSZ / 128), blk>>>(prev_h, W2e, nullptr, dt_e, BSZ, HH, DD);
    gemm_kernel<<<dim3(HH / 128, BSZ / 128), blk>>>(prev_h, W2s, nullptr, dt_s, BSZ, HH, DD);
    // gh = prev_h @ w_hh^T + b_hh
    gemm_kernel<<<dim3(G3D / 128, BSZ / 128), blk>>>(prev_h, w_hh, b_hh, gh, BSZ, G3D, DD);
    // plan softmax (also writes output region)
    plan_kernel<<<BSZ, 128>>>(prev_h, plan_W, plan_b, plan, out_plan);

    // fused attention scores
    attn_u_kernel<<<BSZ * NN / 128, blk>>>(equ_enc, W1e, dt_e, vte, equ_mask, u_e);
    attn_u_kernel<<<BSZ * NN / 128, blk>>>(sns_enc, W1s, dt_s, vts, sns_mask, u_s);

    // softmax + context
    softmax_ctx_kernel<<<BSZ, blk>>>(u_e, equ_enc, ctx_e);
    softmax_ctx_kernel<<<BSZ, blk>>>(u_s, sns_enc, ctx_s);

    // y_ctx assembly
    combine_kernel<<<(BSZ * (EE + HH)) / 256, blk>>>(prev_y, plan, ctx_e, ctx_s, yctx);

    // x = y_ctx @ Wc^T + bc ;  gx = x @ w_ih^T + b_ih
    gemm_kernel<<<dim3(HH / 128, BSZ / 128), blk>>>(yctx, Wc, bc, x, BSZ, HH, EE + HH);
    gemm_kernel<<<dim3(G3D / 128, BSZ / 128), blk>>>(x, w_ih, b_ih, gx, BSZ, G3D, HH);

    // GRU elementwise (writes h_new + output hidden region)
    gru_kernel<<<(BSZ * DD) / 256, blk>>>(gx, gh, prev_h, hn, out_hid);

    // dec_output = h_new @ Wout^T + bout  (written directly into output region)
    gemm_kernel<<<dim3(VV / 128, BSZ / 128), blk>>>(hn, Wout, bout, out_dec, BSZ, VV, DD);
}

// round 3
// speedup vs baseline: 1.7284x; 1.7284x over previous
#include <cuda_runtime.h>
#include <cuda_bf16.h>
#include <math.h>
#include <stdint.h>

#define HH   512
#define ZZ   128
#define EE   512
#define DD   1152      // 2H + Z
#define VV   32000
#define BSZ  256
#define NN   128
#define G3D  3456      // 3*D

// ---------------- scratch (device globals; no allocation allowed) ----------------
__device__ float g_dt_e [BSZ * HH];
__device__ float g_dt_s [BSZ * HH];
__device__ float g_u_e  [BSZ * NN];
__device__ float g_u_s  [BSZ * NN];
__device__ float g_ctx_e[BSZ * HH];
__device__ float g_ctx_s[BSZ * HH];
__device__ float g_plan [BSZ * 2];
__device__ float g_yctx [BSZ * (EE + HH)];
__device__ float g_x    [BSZ * HH];
__device__ float g_gx   [BSZ * G3D];
__device__ float g_gh   [BSZ * G3D];
__device__ float g_h    [BSZ * DD];

// ---------------- helpers ----------------
__device__ __forceinline__ uint32_t pack_bf2(float a, float b) {
    __nv_bfloat162 t = __floats2bfloat162_rn(a, b);
    return *reinterpret_cast<uint32_t*>(&t);
}

__device__ __forceinline__ void mma16816(float c[4],
                                         uint32_t a0, uint32_t a1, uint32_t a2, uint32_t a3,
                                         uint32_t b0, uint32_t b1) {
    asm volatile(
        "mma.sync.aligned.m16n8k16.row.col.f32.bf16.bf16.f32 "
        "{%0,%1,%2,%3}, {%4,%5,%6,%7}, {%8,%9}, {%0,%1,%2,%3};\n"
        : "+f"(c[0]), "+f"(c[1]), "+f"(c[2]), "+f"(c[3])
        : "r"(a0), "r"(a1), "r"(a2), "r"(a3), "r"(b0), "r"(b1));
}

#define SMS 40   // smem row stride in bf16 elements (conflict-free, 8B-aligned)

// =================================================================================
// bf16x3 GEMM: C[M,N] = A[M,K] @ B[N,K]^T (+ bias[n]), fp32-equivalent precision.
// 128x128 block tile, 8 warps (2x4), 64x32 warp tiles, K chunks of 32,
// register-staged global prefetch, in-kernel fp32 -> (hi,lo) bf16 split.
// Requires M%128==0, N%128==0, K%32==0.
// =================================================================================
__global__ void __launch_bounds__(256) gemm_bf16x3(
    const float* __restrict__ A, const float* __restrict__ B,
    const float* __restrict__ bias, float* __restrict__ C,
    int M, int N, int K)
{
    __shared__ __nv_bfloat16 sAhi[128][SMS];
    __shared__ __nv_bfloat16 sAlo[128][SMS];
    __shared__ __nv_bfloat16 sBhi[128][SMS];
    __shared__ __nv_bfloat16 sBlo[128][SMS];

    const int t    = threadIdx.x;
    const int m0   = blockIdx.y * 128;
    const int n0   = blockIdx.x * 128;
    const int lane = t & 31;
    const int wid  = t >> 5;
    const int g    = lane >> 2;
    const int tg   = lane & 3;
    const int wr   = wid & 1;    // warp row (0..1) -> 64 rows each
    const int wc   = wid >> 1;   // warp col (0..3) -> 32 cols each

    // staging: thread loads row r, 16 contiguous K elements starting at hh
    const int r  = t >> 1;
    const int hh = (t & 1) * 16;
    const float* Ap = A + (size_t)(m0 + r) * K + hh;
    const float* Bp = B + (size_t)(n0 + r) * K + hh;

    float acc[4][4][4];
#pragma unroll
    for (int mi = 0; mi < 4; mi++)
#pragma unroll
        for (int ni = 0; ni < 4; ni++)
#pragma unroll
            for (int q = 0; q < 4; q++) acc[mi][ni][q] = 0.f;

    float4 ra[4], rb[4];
#pragma unroll
    for (int i = 0; i < 4; i++) {
        ra[i] = *(const float4*)(Ap + i * 4);
        rb[i] = *(const float4*)(Bp + i * 4);
    }

    for (int k0 = 0; k0 < K; k0 += 32) {
        __syncthreads();   // protect smem from previous iteration's readers
#pragma unroll
        for (int i = 0; i < 4; i++) {
            // split A
            float ax = ra[i].x, ay = ra[i].y, az = ra[i].z, aw = ra[i].w;
            __nv_bfloat16 hx = __float2bfloat16(ax), hy = __float2bfloat16(ay);
            __nv_bfloat16 hz = __float2bfloat16(az), hw = __float2bfloat16(aw);
            uint2 vhi, vlo;
            vhi.x = pack_bf2(ax, ay); vhi.y = pack_bf2(az, aw);
            vlo.x = pack_bf2(ax - __bfloat162float(hx), ay - __bfloat162float(hy));
            vlo.y = pack_bf2(az - __bfloat162float(hz), aw - __bfloat162float(hw));
            *(uint2*)&sAhi[r][hh + i * 4] = vhi;
            *(uint2*)&sAlo[r][hh + i * 4] = vlo;
            // split B
            float bx = rb[i].x, by = rb[i].y, bz = rb[i].z, bw = rb[i].w;
            __nv_bfloat16 gx_ = __float2bfloat16(bx), gy = __float2bfloat16(by);
            __nv_bfloat16 gz = __float2bfloat16(bz), gw = __float2bfloat16(bw);
            vhi.x = pack_bf2(bx, by); vhi.y = pack_bf2(bz, bw);
            vlo.x = pack_bf2(bx - __bfloat162float(gx_), by - __bfloat162float(gy));
            vlo.y = pack_bf2(bz - __bfloat162float(gz), bw - __bfloat162float(gw));
            *(uint2*)&sBhi[r][hh + i * 4] = vhi;
            *(uint2*)&sBlo[r][hh + i * 4] = vlo;
        }
        __syncthreads();

        // prefetch next chunk
        if (k0 + 32 < K) {
#pragma unroll
            for (int i = 0; i < 4; i++) {
                ra[i] = *(const float4*)(Ap + k0 + 32 + i * 4);
                rb[i] = *(const float4*)(Bp + k0 + 32 + i * 4);
            }
        }

#pragma unroll
        for (int ks = 0; ks < 2; ks++) {
            const int kb = ks * 16;
            uint32_t ahi[4][4], alo[4][4];
#pragma unroll
            for (int mi = 0; mi < 4; mi++) {
                const int row = wr * 64 + mi * 16;
                ahi[mi][0] = *(const uint32_t*)&sAhi[row + g    ][kb + tg * 2];
                ahi[mi][1] = *(const uint32_t*)&sAhi[row + g + 8][kb + tg * 2];
                ahi[mi][2] = *(const uint32_t*)&sAhi[row + g    ][kb + tg * 2 + 8];
                ahi[mi][3] = *(const uint32_t*)&sAhi[row + g + 8][kb + tg * 2 + 8];
                alo[mi][0] = *(const uint32_t*)&sAlo[row + g    ][kb + tg * 2];
                alo[mi][1] = *(const uint32_t*)&sAlo[row + g + 8][kb + tg * 2];
                alo[mi][2] = *(const uint32_t*)&sAlo[row + g    ][kb + tg * 2 + 8];
                alo[mi][3] = *(const uint32_t*)&sAlo[row + g + 8][kb + tg * 2 + 8];
            }
            uint32_t bhi[4][2], blo[4][2];
#pragma unroll
            for (int ni = 0; ni < 4; ni++) {
                const int row = wc * 32 + ni * 8 + g;
                bhi[ni][0] = *(const uint32_t*)&sBhi[row][kb + tg * 2];
                bhi[ni][1] = *(const uint32_t*)&sBhi[row][kb + tg * 2 + 8];
                blo[ni][0] = *(const uint32_t*)&sBlo[row][kb + tg * 2];
                blo[ni][1] = *(const uint32_t*)&sBlo[row][kb + tg * 2 + 8];
            }
#pragma unroll
            for (int mi = 0; mi < 4; mi++)
#pragma unroll
                for (int ni = 0; ni < 4; ni++) {
                    mma16816(acc[mi][ni], ahi[mi][0], ahi[mi][1], ahi[mi][2], ahi[mi][3],
                             bhi[ni][0], bhi[ni][1]);
                    mma16816(acc[mi][ni], ahi[mi][0], ahi[mi][1], ahi[mi][2], ahi[mi][3],
                             blo[ni][0], blo[ni][1]);
                    mma16816(acc[mi][ni], alo[mi][0], alo[mi][1], alo[mi][2], alo[mi][3],
                             bhi[ni][0], bhi[ni][1]);
                }
        }
    }

    // epilogue
#pragma unroll
    for (int mi = 0; mi < 4; mi++) {
        const int row = m0 + wr * 64 + mi * 16 + g;
#pragma unroll
        for (int ni = 0; ni < 4; ni++) {
            const int col = n0 + wc * 32 + ni * 8 + tg * 2;
            float b0 = bias ? bias[col] : 0.f;
            float b1 = bias ? bias[col + 1] : 0.f;
            float2 v0 = make_float2(acc[mi][ni][0] + b0, acc[mi][ni][1] + b1);
            float2 v1 = make_float2(acc[mi][ni][2] + b0, acc[mi][ni][3] + b1);
            *(float2*)&C[(size_t)row * N + col]       = v0;
            *(float2*)&C[(size_t)(row + 8) * N + col] = v1;
        }
    }
}

// =================================================================================
// Fused attention scores, bf16x3 tensor-core version:
//   u[b,n] = sum_k vt[k] * tanh( (enc[b] @ W1^T)[n,k] + dt[b,k] ), mask -> -inf
// One block per batch (128 enc rows). N loop: 4 chunks of 128 cols; per chunk a
// full K=512 mma pass with fused tanh-dot epilogue into per-row partials.
// =================================================================================
__global__ void __launch_bounds__(256) attn_bf16x3(
    const float* __restrict__ enc,              // [BS*NN, 512]
    const float* __restrict__ W1,               // [512, 512]
    const float* __restrict__ dt,               // [BS, 512]
    const float* __restrict__ vt,               // [512]
    const int* __restrict__ mask,               // [BS*NN] int32 bool
    float* __restrict__ u)                      // [BS*NN]
{
    __shared__ __nv_bfloat16 sAhi[128][SMS];
    __shared__ __nv_bfloat16 sAlo[128][SMS];
    __shared__ __nv_bfloat16 sBhi[128][SMS];
    __shared__ __nv_bfloat16 sBlo[128][SMS];
    __shared__ float s_dt[512];
    __shared__ float s_vt[512];
    __shared__ float s_u[128];

    const int t    = threadIdx.x;
    const int b    = blockIdx.x;
    const int lane = t & 31;
    const int wid  = t >> 5;
    const int g    = lane >> 2;
    const int tg   = lane & 3;
    const int wr   = wid & 1;
    const int wc   = wid >> 1;

    // preload dt row and vt
    for (int i = t; i < 512; i += 256) {
        s_dt[i] = dt[(size_t)b * 512 + i];
        s_vt[i] = vt[i];
    }
    if (t < 128) s_u[t] = 0.f;

    const int r  = t >> 1;
    const int hh = (t & 1) * 16;
    const float* Ap = enc + (size_t)(b * 128 + r) * 512 + hh;

    float up[8];
#pragma unroll
    for (int i = 0; i < 8; i++) up[i] = 0.f;

    for (int nc = 0; nc < 4; nc++) {
        const float* Bp = W1 + (size_t)(nc * 128 + r) * 512 + hh;

        float acc[4][4][4];
#pragma unroll
        for (int mi = 0; mi < 4; mi++)
#pragma unroll
            for (int ni = 0; ni < 4; ni++)
#pragma unroll
                for (int q = 0; q < 4; q++) acc[mi][ni][q] = 0.f;

        float4 ra[4], rb[4];
#pragma unroll
        for (int i = 0; i < 4; i++) {
            ra[i] = *(const float4*)(Ap + i * 4);
            rb[i] = *(const float4*)(Bp + i * 4);
        }

        for (int k0 = 0; k0 < 512; k0 += 32) {
            __syncthreads();
#pragma unroll
            for (int i = 0; i < 4; i++) {
                float ax = ra[i].x, ay = ra[i].y, az = ra[i].z, aw = ra[i].w;
                __nv_bfloat16 hx = __float2bfloat16(ax), hy = __float2bfloat16(ay);
                __nv_bfloat16 hz = __float2bfloat16(az), hw = __float2bfloat16(aw);
                uint2 vhi, vlo;
                vhi.x = pack_bf2(ax, ay); vhi.y = pack_bf2(az, aw);
                vlo.x = pack_bf2(ax - __bfloat162float(hx), ay - __bfloat162float(hy));
                vlo.y = pack_bf2(az - __bfloat162float(hz), aw - __bfloat162float(hw));
                *(uint2*)&sAhi[r][hh + i * 4] = vhi;
                *(uint2*)&sAlo[r][hh + i * 4] = vlo;
                float bx = rb[i].x, by = rb[i].y, bz = rb[i].z, bw = rb[i].w;
                __nv_bfloat16 qx = __float2bfloat16(bx), qy = __float2bfloat16(by);
                __nv_bfloat16 qz = __float2bfloat16(bz), qw = __float2bfloat16(bw);
                vhi.x = pack_bf2(bx, by); vhi.y = pack_bf2(bz, bw);
                vlo.x = pack_bf2(bx - __bfloat162float(qx), by - __bfloat162float(qy));
                vlo.y = pack_bf2(bz - __bfloat162float(qz), bw - __bfloat162float(qw));
                *(uint2*)&sBhi[r][hh + i * 4] = vhi;
                *(uint2*)&sBlo[r][hh + i * 4] = vlo;
            }
            __syncthreads();

            if (k0 + 32 < 512) {
#pragma unroll
                for (int i = 0; i < 4; i++) {
                    ra[i] = *(const float4*)(Ap + k0 + 32 + i * 4);
                    rb[i] = *(const float4*)(Bp + k0 + 32 + i * 4);
                }
            }

#pragma unroll
            for (int ks = 0; ks < 2; ks++) {
                const int kb = ks * 16;
                uint32_t ahi[4][4], alo[4][4];
#pragma unroll
                for (int mi = 0; mi < 4; mi++) {
                    const int row = wr * 64 + mi * 16;
                    ahi[mi][0] = *(const uint32_t*)&sAhi[row + g    ][kb + tg * 2];
                    ahi[mi][1] = *(const uint32_t*)&sAhi[row + g + 8][kb + tg * 2];
                    ahi[mi][2] = *(const uint32_t*)&sAhi[row + g    ][kb + tg * 2 + 8];
                    ahi[mi][3] = *(const uint32_t*)&sAhi[row + g + 8][kb + tg * 2 + 8];
                    alo[mi][0] = *(const uint32_t*)&sAlo[row + g    ][kb + tg * 2];
                    alo[mi][1] = *(const uint32_t*)&sAlo[row + g + 8][kb + tg * 2];
                    alo[mi][2] = *(const uint32_t*)&sAlo[row + g    ][kb + tg * 2 + 8];
                    alo[mi][3] = *(const uint32_t*)&sAlo[row + g + 8][kb + tg * 2 + 8];
                }
                uint32_t bhi[4][2], blo[4][2];
#pragma unroll
                for (int ni = 0; ni < 4; ni++) {
                    const int row = wc * 32 + ni * 8 + g;
                    bhi[ni][0] = *(const uint32_t*)&sBhi[row][kb + tg * 2];
                    bhi[ni][1] = *(const uint32_t*)&sBhi[row][kb + tg * 2 + 8];
                    blo[ni][0] = *(const uint32_t*)&sBlo[row][kb + tg * 2];
                    blo[ni][1] = *(const uint32_t*)&sBlo[row][kb + tg * 2 + 8];
                }
#pragma unroll
                for (int mi = 0; mi < 4; mi++)
#pragma unroll
                    for (int ni = 0; ni < 4; ni++) {
                        mma16816(acc[mi][ni], ahi[mi][0], ahi[mi][1], ahi[mi][2], ahi[mi][3],
                                 bhi[ni][0], bhi[ni][1]);
                        mma16816(acc[mi][ni], ahi[mi][0], ahi[mi][1], ahi[mi][2], ahi[mi][3],
                                 blo[ni][0], blo[ni][1]);
                        mma16816(acc[mi][ni], alo[mi][0], alo[mi][1], alo[mi][2], alo[mi][3],
                                 bhi[ni][0], bhi[ni][1]);
                    }
            }
        }

        // fused epilogue for this n-chunk
#pragma unroll
        for (int mi = 0; mi < 4; mi++)
#pragma unroll
            for (int ni = 0; ni < 4; ni++) {
                const int col = nc * 128 + wc * 32 + ni * 8 + tg * 2;
                const float d0 = s_dt[col], d1 = s_dt[col + 1];
                const float v0 = s_vt[col], v1 = s_vt[col + 1];
                up[mi * 2 + 0] += v0 * tanhf(acc[mi][ni][0] + d0)
                                + v1 * tanhf(acc[mi][ni][1] + d1);
                up[mi * 2 + 1] += v0 * tanhf(acc[mi][ni][2] + d0)
                                + v1 * tanhf(acc[mi][ni][3] + d1);
            }
    }

    // reduce across the 4 lanes sharing g (tg = 0..3 are consecutive lanes)
#pragma unroll
    for (int mi = 0; mi < 4; mi++)
#pragma unroll
        for (int rr = 0; rr < 2; rr++) {
            float v = up[mi * 2 + rr];
            v += __shfl_down_sync(0xffffffffu, v, 1);
            v += __shfl_down_sync(0xffffffffu, v, 2);
            if (tg == 0)
                atomicAdd(&s_u[wr * 64 + mi * 16 + g + rr * 8], v);
        }
    __syncthreads();

    if (t < 128) {
        const int m = b * 128 + t;
        u[m] = (mask[(size_t)b * NN + t] != 0) ? -INFINITY : s_u[t];
    }
}

// =================================================================================
// plan = softmax(prev_h @ plan_W^T + plan_b)
// =================================================================================
__global__ void plan_kernel(const float* __restrict__ prev_h,
                            const float* __restrict__ plan_W,
                            const float* __restrict__ plan_b,
                            float* __restrict__ plan,
                            float* __restrict__ out_plan)
{
    const int b = blockIdx.x;
    const int t = threadIdx.x;          // 128 threads
    __shared__ float s0[128], s1[128];
    float a0 = 0.f, a1 = 0.f;
    const float* hb = prev_h + (size_t)b * DD;
    for (int k = t; k < DD; k += 128) {
        const float h = hb[k];
        a0 += h * plan_W[k];
        a1 += h * plan_W[DD + k];
    }
    s0[t] = a0; s1[t] = a1;
    __syncthreads();
    for (int s = 64; s > 0; s >>= 1) {
        if (t < s) { s0[t] += s0[t + s]; s1[t] += s1[t + s]; }
        __syncthreads();
    }
    if (t == 0) {
        const float l0 = s0[0] + plan_b[0];
        const float l1 = s1[0] + plan_b[1];
        const float mx = fmaxf(l0, l1);
        const float e0 = expf(l0 - mx), e1 = expf(l1 - mx);
        const float inv = 1.f / (e0 + e1);
        plan[2 * b] = e0 * inv;       plan[2 * b + 1] = e1 * inv;
        out_plan[2 * b] = e0 * inv;   out_plan[2 * b + 1] = e1 * inv;
    }
}

// =================================================================================
// softmax over u[b,:] then ctx[b,h] = sum_n aw[n] * enc[b,n,h]
// =================================================================================
__global__ void softmax_ctx_kernel(const float* __restrict__ u,
                                   const float* __restrict__ enc,
                                   float* __restrict__ ctx)
{
    const int b = blockIdx.x;
    const int t = threadIdx.x;          // 256 threads
    __shared__ float red[256];
    __shared__ float aw[NN];

    const float uv = (t < NN) ? u[(size_t)b * NN + t] : -INFINITY;
    red[t] = uv;
    __syncthreads();
    for (int s = 128; s > 0; s >>= 1) {
        if (t < s) red[t] = fmaxf(red[t], red[t + s]);
        __syncthreads();
    }
    const float mx = red[0];
    __syncthreads();
    const float e = (t < NN) ? expf(uv - mx) : 0.f;
    red[t] = e;
    __syncthreads();
    for (int s = 128; s > 0; s >>= 1) {
        if (t < s) red[t] += red[t + s];
        __syncthreads();
    }
    const float inv = 1.f / red[0];
    if (t < NN) aw[t] = e * inv;
    __syncthreads();

    const float* eb = enc + (size_t)b * NN * HH;
    for (int h = t; h < HH; h += 256) {
        float s = 0.f;
#pragma unroll 4
        for (int n = 0; n < NN; n++)
            s += aw[n] * eb[(size_t)n * HH + h];
        ctx[(size_t)b * HH + h] = s;
    }
}

// =================================================================================
// context mix + y_ctx = [prev_y | plan0*ctx_e + plan1*ctx_s]
// =================================================================================
__global__ void combine_kernel(const float* __restrict__ prev_y,
                               const float* __restrict__ plan,
                               const float* __restrict__ ctx_e,
                               const float* __restrict__ ctx_s,
                               float* __restrict__ yctx)
{
    const int idx = blockIdx.x * blockDim.x + threadIdx.x;
    if (idx >= BSZ * (EE + HH)) return;
    const int b = idx >> 10;            // E+H = 1024
    const int c = idx & 1023;
    float v;
    if (c < EE) {
        v = prev_y[(size_t)b * EE + c];
    } else {
        const float p0 = plan[2 * b], p1 = plan[2 * b + 1];
        const int h = c - EE;
        v = p0 * ctx_e[(size_t)b * HH + h] + p1 * ctx_s[(size_t)b * HH + h];
    }
    yctx[idx] = v;
}

// =================================================================================
// GRU cell elementwise
// =================================================================================
__global__ void gru_kernel(const float* __restrict__ gx,
                           const float* __restrict__ gh,
                           const float* __restrict__ prev_h,
                           float* __restrict__ h_new,
                           float* __restrict__ out_hid)
{
    const int idx = blockIdx.x * blockDim.x + threadIdx.x;
    if (idx >= BSZ * DD) return;
    const int b = idx / DD;
    const int d = idx - b * DD;
    const float* gxb = gx + (size_t)b * G3D;
    const float* ghb = gh + (size_t)b * G3D;
    const float r = 1.f / (1.f + expf(-(gxb[d] + ghb[d])));
    const float z = 1.f / (1.f + expf(-(gxb[DD + d] + ghb[DD + d])));
    const float n = tanhf(gxb[2 * DD + d] + r * ghb[2 * DD + d]);
    const float h = (1.f - z) * n + z * prev_h[idx];
    h_new[idx] = h;
    out_hid[idx] = h;
}

// =================================================================================
// host launcher — graph-capturable (kernel launches only, default stream)
// =================================================================================
extern "C" void kernel_launch(void* const* d_in, const int* in_sizes, int n_in,
                              void* d_out, int out_size)
{
    const float* prev_y  = (const float*)d_in[0];
    const float* prev_h  = (const float*)d_in[1];
    const float* equ_enc = (const float*)d_in[2];
    const float* sns_enc = (const float*)d_in[3];
    /* d_in[4] z_sample unused by the reference */
    const int* equ_mask = (const int*)d_in[5];
    const int* sns_mask = (const int*)d_in[6];
    const float* W1e    = (const float*)d_in[7];
    const float* W2e    = (const float*)d_in[8];
    const float* vte    = (const float*)d_in[9];
    const float* W1s    = (const float*)d_in[10];
    const float* W2s    = (const float*)d_in[11];
    const float* vts    = (const float*)d_in[12];
    const float* plan_W = (const float*)d_in[13];
    const float* plan_b = (const float*)d_in[14];
    const float* Wc     = (const float*)d_in[15];
    const float* bc     = (const float*)d_in[16];
    const float* w_ih   = (const float*)d_in[17];
    const float* w_hh   = (const float*)d_in[18];
    const float* b_ih   = (const float*)d_in[19];
    const float* b_hh   = (const float*)d_in[20];
    const float* Wout   = (const float*)d_in[21];
    const float* bout   = (const float*)d_in[22];

    float* out      = (float*)d_out;
    float* out_dec  = out;                                        // [256, 32000]
    float* out_hid  = out + (size_t)BSZ * VV;                     // [256, 1152]
    float* out_plan = out + (size_t)BSZ * VV + (size_t)BSZ * DD;  // [256, 2]

    float *dt_e, *dt_s, *u_e, *u_s, *ctx_e, *ctx_s, *plan, *yctx, *x, *gx, *gh, *hn;
    cudaGetSymbolAddress((void**)&dt_e,  g_dt_e);
    cudaGetSymbolAddress((void**)&dt_s,  g_dt_s);
    cudaGetSymbolAddress((void**)&u_e,   g_u_e);
    cudaGetSymbolAddress((void**)&u_s,   g_u_s);
    cudaGetSymbolAddress((void**)&ctx_e, g_ctx_e);
    cudaGetSymbolAddress((void**)&ctx_s, g_ctx_s);
    cudaGetSymbolAddress((void**)&plan,  g_plan);
    cudaGetSymbolAddress((void**)&yctx,  g_yctx);
    cudaGetSymbolAddress((void**)&x,     g_x);
    cudaGetSymbolAddress((void**)&gx,    g_gx);
    cudaGetSymbolAddress((void**)&gh,    g_gh);
    cudaGetSymbolAddress((void**)&hn,    g_h);

    const dim3 blk(256);

    // dt_e = prev_h @ W2e^T ;  dt_s = prev_h @ W2s^T
    gemm_bf16x3<<<dim3(HH / 128, BSZ / 128), blk>>>(prev_h, W2e, nullptr, dt_e, BSZ, HH, DD);
    gemm_bf16x3<<<dim3(HH / 128, BSZ / 128), blk>>>(prev_h, W2s, nullptr, dt_s, BSZ, HH, DD);
    // gh = prev_h @ w_hh^T + b_hh
    gemm_bf16x3<<<dim3(G3D / 128, BSZ / 128), blk>>>(prev_h, w_hh, b_hh, gh, BSZ, G3D, DD);
    // plan softmax (also writes output region)
    plan_kernel<<<BSZ, 128>>>(prev_h, plan_W, plan_b, plan, out_plan);

    // fused attention scores (tensor-core bf16x3, fused tanh.vt epilogue)
    attn_bf16x3<<<BSZ, blk>>>(equ_enc, W1e, dt_e, vte, equ_mask, u_e);
    attn_bf16x3<<<BSZ, blk>>>(sns_enc, W1s, dt_s, vts, sns_mask, u_s);

    // softmax + context
    softmax_ctx_kernel<<<BSZ, blk>>>(u_e, equ_enc, ctx_e);
    softmax_ctx_kernel<<<BSZ, blk>>>(u_s, sns_enc, ctx_s);

    // y_ctx assembly
    combine_kernel<<<(BSZ * (EE + HH)) / 256, blk>>>(prev_y, plan, ctx_e, ctx_s, yctx);

    // x = y_ctx @ Wc^T + bc ;  gx = x @ w_ih^T + b_ih
    gemm_bf16x3<<<dim3(HH / 128, BSZ / 128), blk>>>(yctx, Wc, bc, x, BSZ, HH, EE + HH);
    gemm_bf16x3<<<dim3(G3D / 128, BSZ / 128), blk>>>(x, w_ih, b_ih, gx, BSZ, G3D, HH);

    // GRU elementwise (writes h_new + output hidden region)
    gru_kernel<<<(BSZ * DD) / 256, blk>>>(gx, gh, prev_h, hn, out_hid);

    // dec_output = h_new @ Wout^T + bout  (written directly into output region)
    gemm_bf16x3<<<dim3(VV / 128, BSZ / 128), blk>>>(hn, Wout, bout, out_dec, BSZ, VV, DD);
}

// round 4
// speedup vs baseline: 1.7648x; 1.0211x over previous
#include <cuda_runtime.h>
#include <cuda_bf16.h>
#include <math.h>
#include <stdint.h>

#define HH   512
#define ZZ   128
#define EE   512
#define DD   1152      // 2H + Z
#define VV   32000
#define BSZ  256
#define NN   128
#define G3D  3456      // 3*D

// ---------------- scratch (device globals; no allocation allowed) ----------------
__device__ float g_dt_e [BSZ * HH];
__device__ float g_dt_s [BSZ * HH];
__device__ float g_u_e  [BSZ * NN];
__device__ float g_u_s  [BSZ * NN];
__device__ float g_ctx_e[BSZ * HH];
__device__ float g_ctx_s[BSZ * HH];
__device__ float g_plan [BSZ * 2];
__device__ float g_yctx [BSZ * (EE + HH)];
__device__ float g_x    [BSZ * HH];
__device__ float g_gx   [BSZ * G3D];
__device__ float g_gh   [BSZ * G3D];
__device__ float g_h    [BSZ * DD];
// pre-split attention weights (bf16 hi/lo)
__device__ __nv_bfloat16 g_w1e_hi[HH * HH];
__device__ __nv_bfloat16 g_w1e_lo[HH * HH];
__device__ __nv_bfloat16 g_w1s_hi[HH * HH];
__device__ __nv_bfloat16 g_w1s_lo[HH * HH];

// ---------------- helpers ----------------
__device__ __forceinline__ uint32_t pack_bf2(float a, float b) {
    __nv_bfloat162 t = __floats2bfloat162_rn(a, b);
    return *reinterpret_cast<uint32_t*>(&t);
}

__device__ __forceinline__ void mma16816(float c[4],
                                         uint32_t a0, uint32_t a1, uint32_t a2, uint32_t a3,
                                         uint32_t b0, uint32_t b1) {
    asm volatile(
        "mma.sync.aligned.m16n8k16.row.col.f32.bf16.bf16.f32 "
        "{%0,%1,%2,%3}, {%4,%5,%6,%7}, {%8,%9}, {%0,%1,%2,%3};\n"
        : "+f"(c[0]), "+f"(c[1]), "+f"(c[2]), "+f"(c[3])
        : "r"(a0), "r"(a1), "r"(a2), "r"(a3), "r"(b0), "r"(b1));
}

#define SMS 40                      // smem row stride in bf16 (conflict-free)
#define STG (128 * SMS)             // elements per array
#define STAGE4 (4 * STG)            // elements per stage (Ahi,Alo,Bhi,Blo)
#define SMEM_BYTES (2 * STAGE4 * 2) // 81920 bytes

// split 16 fp32 (4x float4) into hi/lo bf16 and store 32B to smem at [idx..idx+16)
__device__ __forceinline__ void split_store16(const float4* v,
                                              __nv_bfloat16* hi, __nv_bfloat16* lo,
                                              int idx) {
#pragma unroll
    for (int i = 0; i < 4; i++) {
        float x = v[i].x, y = v[i].y, z = v[i].z, w = v[i].w;
        __nv_bfloat16 hx = __float2bfloat16(x), hy = __float2bfloat16(y);
        __nv_bfloat16 hz = __float2bfloat16(z), hw = __float2bfloat16(w);
        uint2 vh, vl;
        vh.x = pack_bf2(x, y); vh.y = pack_bf2(z, w);
        vl.x = pack_bf2(x - __bfloat162float(hx), y - __bfloat162float(hy));
        vl.y = pack_bf2(z - __bfloat162float(hz), w - __bfloat162float(hw));
        *(uint2*)&hi[idx + i * 4] = vh;
        *(uint2*)&lo[idx + i * 4] = vl;
    }
}

// mma pass over one staged 32-K chunk (shared by both kernels)
__device__ __forceinline__ void mma_chunk(const __nv_bfloat16* pAhi, const __nv_bfloat16* pAlo,
                                          const __nv_bfloat16* pBhi, const __nv_bfloat16* pBlo,
                                          float acc[4][4][4],
                                          int wr, int wc, int g, int tg) {
#pragma unroll
    for (int ks = 0; ks < 2; ks++) {
        const int kb = ks * 16;
        uint32_t ahi[4][4], alo[4][4];
#pragma unroll
        for (int mi = 0; mi < 4; mi++) {
            const int row = wr * 64 + mi * 16;
            ahi[mi][0] = *(const uint32_t*)&pAhi[(row + g    ) * SMS + kb + tg * 2];
            ahi[mi][1] = *(const uint32_t*)&pAhi[(row + g + 8) * SMS + kb + tg * 2];
            ahi[mi][2] = *(const uint32_t*)&pAhi[(row + g    ) * SMS + kb + tg * 2 + 8];
            ahi[mi][3] = *(const uint32_t*)&pAhi[(row + g + 8) * SMS + kb + tg * 2 + 8];
            alo[mi][0] = *(const uint32_t*)&pAlo[(row + g    ) * SMS + kb + tg * 2];
            alo[mi][1] = *(const uint32_t*)&pAlo[(row + g + 8) * SMS + kb + tg * 2];
            alo[mi][2] = *(const uint32_t*)&pAlo[(row + g    ) * SMS + kb + tg * 2 + 8];
            alo[mi][3] = *(const uint32_t*)&pAlo[(row + g + 8) * SMS + kb + tg * 2 + 8];
        }
        uint32_t bhi[4][2], blo[4][2];
#pragma unroll
        for (int ni = 0; ni < 4; ni++) {
            const int row = wc * 32 + ni * 8 + g;
            bhi[ni][0] = *(const uint32_t*)&pBhi[row * SMS + kb + tg * 2];
            bhi[ni][1] = *(const uint32_t*)&pBhi[row * SMS + kb + tg * 2 + 8];
            blo[ni][0] = *(const uint32_t*)&pBlo[row * SMS + kb + tg * 2];
            blo[ni][1] = *(const uint32_t*)&pBlo[row * SMS + kb + tg * 2 + 8];
        }
#pragma unroll
        for (int mi = 0; mi < 4; mi++)
#pragma unroll
            for (int ni = 0; ni < 4; ni++) {
                mma16816(acc[mi][ni], ahi[mi][0], ahi[mi][1], ahi[mi][2], ahi[mi][3],
                         bhi[ni][0], bhi[ni][1]);
                mma16816(acc[mi][ni], ahi[mi][0], ahi[mi][1], ahi[mi][2], ahi[mi][3],
                         blo[ni][0], blo[ni][1]);
                mma16816(acc[mi][ni], alo[mi][0], alo[mi][1], alo[mi][2], alo[mi][3],
                         bhi[ni][0], bhi[ni][1]);
            }
    }
}

// =================================================================================
// bf16x3 GEMM, 2-stage pipelined: C[M,N] = A[M,K] @ B[N,K]^T (+ bias[n])
// 128x128 block tile, 8 warps, K chunks of 32, dynamic smem double buffer.
// =================================================================================
__global__ void __launch_bounds__(256) gemm_bf16x3(
    const float* __restrict__ A, const float* __restrict__ B,
    const float* __restrict__ bias, float* __restrict__ C,
    int M, int N, int K)
{
    extern __shared__ __nv_bfloat16 sm[];

    const int t    = threadIdx.x;
    const int m0   = blockIdx.y * 128;
    const int n0   = blockIdx.x * 128;
    const int lane = t & 31;
    const int wid  = t >> 5;
    const int g    = lane >> 2;
    const int tg   = lane & 3;
    const int wr   = wid & 1;
    const int wc   = wid >> 1;

    const int r   = t >> 1;
    const int hh  = (t & 1) * 16;
    const int idx = r * SMS + hh;
    const float* Ap = A + (size_t)(m0 + r) * K + hh;
    const float* Bp = B + (size_t)(n0 + r) * K + hh;

    float acc[4][4][4];
#pragma unroll
    for (int mi = 0; mi < 4; mi++)
#pragma unroll
        for (int ni = 0; ni < 4; ni++)
#pragma unroll
            for (int q = 0; q < 4; q++) acc[mi][ni][q] = 0.f;

    float4 ra[4], rb[4];
#pragma unroll
    for (int i = 0; i < 4; i++) {
        ra[i] = *(const float4*)(Ap + i * 4);
        rb[i] = *(const float4*)(Bp + i * 4);
    }
    // stage 0 fill
    split_store16(ra, sm + 0 * STG, sm + 1 * STG, idx);
    split_store16(rb, sm + 2 * STG, sm + 3 * STG, idx);
    __syncthreads();

    for (int k0 = 0; k0 < K; k0 += 32) {
        const int s = (k0 >> 5) & 1;
        __nv_bfloat16* st = sm + s * STAGE4;
        const bool more = (k0 + 32 < K);
        if (more) {
#pragma unroll
            for (int i = 0; i < 4; i++) {
                ra[i] = *(const float4*)(Ap + k0 + 32 + i * 4);
                rb[i] = *(const float4*)(Bp + k0 + 32 + i * 4);
            }
        }
        mma_chunk(st, st + STG, st + 2 * STG, st + 3 * STG, acc, wr, wc, g, tg);
        if (more) {
            __nv_bfloat16* nt = sm + (s ^ 1) * STAGE4;
            split_store16(ra, nt, nt + STG, idx);
            split_store16(rb, nt + 2 * STG, nt + 3 * STG, idx);
        }
        __syncthreads();
    }

    // epilogue
#pragma unroll
    for (int mi = 0; mi < 4; mi++) {
        const int row = m0 + wr * 64 + mi * 16 + g;
#pragma unroll
        for (int ni = 0; ni < 4; ni++) {
            const int col = n0 + wc * 32 + ni * 8 + tg * 2;
            float b0 = bias ? bias[col] : 0.f;
            float b1 = bias ? bias[col + 1] : 0.f;
            float2 v0 = make_float2(acc[mi][ni][0] + b0, acc[mi][ni][1] + b1);
            float2 v1 = make_float2(acc[mi][ni][2] + b0, acc[mi][ni][3] + b1);
            *(float2*)&C[(size_t)row * N + col]       = v0;
            *(float2*)&C[(size_t)(row + 8) * N + col] = v1;
        }
    }
}

// =================================================================================
// weight split: fp32 -> bf16 hi/lo (vectorized)
// =================================================================================
__global__ void split_kernel(const float* __restrict__ W,
                             __nv_bfloat16* __restrict__ hi,
                             __nv_bfloat16* __restrict__ lo, int n4)
{
    const int i = blockIdx.x * blockDim.x + threadIdx.x;
    if (i >= n4) return;
    float4 v = ((const float4*)W)[i];
    __nv_bfloat16 hx = __float2bfloat16(v.x), hy = __float2bfloat16(v.y);
    __nv_bfloat16 hz = __float2bfloat16(v.z), hw = __float2bfloat16(v.w);
    uint2 vh, vl;
    vh.x = pack_bf2(v.x, v.y); vh.y = pack_bf2(v.z, v.w);
    vl.x = pack_bf2(v.x - __bfloat162float(hx), v.y - __bfloat162float(hy));
    vl.y = pack_bf2(v.z - __bfloat162float(hz), v.w - __bfloat162float(hw));
    ((uint2*)hi)[i] = vh;
    ((uint2*)lo)[i] = vl;
}

// =================================================================================
// Fused attention scores, pipelined bf16x3 with pre-split W1:
//   u[b,n] = sum_k vt[k] * tanh( (enc[b] @ W1^T)[n,k] + dt[b,k] ), mask -> -inf
// =================================================================================
__global__ void __launch_bounds__(256) attn_bf16x3(
    const float* __restrict__ enc,              // [BS*NN, 512]
    const __nv_bfloat16* __restrict__ w1hi,     // [512, 512] pre-split
    const __nv_bfloat16* __restrict__ w1lo,
    const float* __restrict__ dt,               // [BS, 512]
    const float* __restrict__ vt,               // [512]
    const int* __restrict__ mask,               // [BS*NN] int32 bool
    float* __restrict__ u)                      // [BS*NN]
{
    extern __shared__ __nv_bfloat16 sm[];
    __shared__ float s_dt[512];
    __shared__ float s_vt[512];
    __shared__ float s_u[128];

    const int t    = threadIdx.x;
    const int b    = blockIdx.x;
    const int lane = t & 31;
    const int wid  = t >> 5;
    const int g    = lane >> 2;
    const int tg   = lane & 3;
    const int wr   = wid & 1;
    const int wc   = wid >> 1;

    for (int i = t; i < 512; i += 256) {
        s_dt[i] = dt[(size_t)b * 512 + i];
        s_vt[i] = vt[i];
    }
    if (t < 128) s_u[t] = 0.f;

    const int r   = t >> 1;
    const int hh  = (t & 1) * 16;
    const int idx = r * SMS + hh;
    const float* Ap = enc + (size_t)(b * 128 + r) * 512 + hh;

    float up[8];
#pragma unroll
    for (int i = 0; i < 8; i++) up[i] = 0.f;

    for (int nc = 0; nc < 4; nc++) {
        const __nv_bfloat16* Bhp = w1hi + (size_t)(nc * 128 + r) * 512 + hh;
        const __nv_bfloat16* Blp = w1lo + (size_t)(nc * 128 + r) * 512 + hh;

        float acc[4][4][4];
#pragma unroll
        for (int mi = 0; mi < 4; mi++)
#pragma unroll
            for (int ni = 0; ni < 4; ni++)
#pragma unroll
                for (int q = 0; q < 4; q++) acc[mi][ni][q] = 0.f;

        float4 ra[4];
        uint4 rbh[2], rbl[2];
#pragma unroll
        for (int i = 0; i < 4; i++) ra[i] = *(const float4*)(Ap + i * 4);
        rbh[0] = *(const uint4*)(Bhp);     rbh[1] = *(const uint4*)(Bhp + 8);
        rbl[0] = *(const uint4*)(Blp);     rbl[1] = *(const uint4*)(Blp + 8);

        // stage 0 fill  (safe: previous nc's loop ended with __syncthreads)
        split_store16(ra, sm, sm + STG, idx);
        *(uint4*)&sm[2 * STG + idx]     = rbh[0];
        *(uint4*)&sm[2 * STG + idx + 8] = rbh[1];
        *(uint4*)&sm[3 * STG + idx]     = rbl[0];
        *(uint4*)&sm[3 * STG + idx + 8] = rbl[1];
        __syncthreads();

        for (int k0 = 0; k0 < 512; k0 += 32) {
            const int s = (k0 >> 5) & 1;
            __nv_bfloat16* st = sm + s * STAGE4;
            const bool more = (k0 + 32 < 512);
            if (more) {
#pragma unroll
                for (int i = 0; i < 4; i++) ra[i] = *(const float4*)(Ap + k0 + 32 + i * 4);
                rbh[0] = *(const uint4*)(Bhp + k0 + 32);
                rbh[1] = *(const uint4*)(Bhp + k0 + 40);
                rbl[0] = *(const uint4*)(Blp + k0 + 32);
                rbl[1] = *(const uint4*)(Blp + k0 + 40);
            }
            mma_chunk(st, st + STG, st + 2 * STG, st + 3 * STG, acc, wr, wc, g, tg);
            if (more) {
                __nv_bfloat16* nt = sm + (s ^ 1) * STAGE4;
                split_store16(ra, nt, nt + STG, idx);
                *(uint4*)&nt[2 * STG + idx]     = rbh[0];
                *(uint4*)&nt[2 * STG + idx + 8] = rbh[1];
                *(uint4*)&nt[3 * STG + idx]     = rbl[0];
                *(uint4*)&nt[3 * STG + idx + 8] = rbl[1];
            }
            __syncthreads();
        }

        // fused epilogue for this n-chunk
#pragma unroll
        for (int mi = 0; mi < 4; mi++)
#pragma unroll
            for (int ni = 0; ni < 4; ni++) {
                const int col = nc * 128 + wc * 32 + ni * 8 + tg * 2;
                const float d0 = s_dt[col], d1 = s_dt[col + 1];
                const float v0 = s_vt[col], v1 = s_vt[col + 1];
                up[mi * 2 + 0] += v0 * tanhf(acc[mi][ni][0] + d0)
                                + v1 * tanhf(acc[mi][ni][1] + d1);
                up[mi * 2 + 1] += v0 * tanhf(acc[mi][ni][2] + d0)
                                + v1 * tanhf(acc[mi][ni][3] + d1);
            }
    }

    // reduce across the 4 lanes sharing g
#pragma unroll
    for (int mi = 0; mi < 4; mi++)
#pragma unroll
        for (int rr = 0; rr < 2; rr++) {
            float v = up[mi * 2 + rr];
            v += __shfl_down_sync(0xffffffffu, v, 1);
            v += __shfl_down_sync(0xffffffffu, v, 2);
            if (tg == 0)
                atomicAdd(&s_u[wr * 64 + mi * 16 + g + rr * 8], v);
        }
    __syncthreads();

    if (t < 128) {
        const int m = b * 128 + t;
        u[m] = (mask[(size_t)b * NN + t] != 0) ? -INFINITY : s_u[t];
    }
}

// =================================================================================
// plan = softmax(prev_h @ plan_W^T + plan_b)
// =================================================================================
__global__ void plan_kernel(const float* __restrict__ prev_h,
                            const float* __restrict__ plan_W,
                            const float* __restrict__ plan_b,
                            float* __restrict__ plan,
                            float* __restrict__ out_plan)
{
    const int b = blockIdx.x;
    const int t = threadIdx.x;          // 128 threads
    __shared__ float s0[128], s1[128];
    float a0 = 0.f, a1 = 0.f;
    const float* hb = prev_h + (size_t)b * DD;
    for (int k = t; k < DD; k += 128) {
        const float h = hb[k];
        a0 += h * plan_W[k];
        a1 += h * plan_W[DD + k];
    }
    s0[t] = a0; s1[t] = a1;
    __syncthreads();
    for (int s = 64; s > 0; s >>= 1) {
        if (t < s) { s0[t] += s0[t + s]; s1[t] += s1[t + s]; }
        __syncthreads();
    }
    if (t == 0) {
        const float l0 = s0[0] + plan_b[0];
        const float l1 = s1[0] + plan_b[1];
        const float mx = fmaxf(l0, l1);
        const float e0 = expf(l0 - mx), e1 = expf(l1 - mx);
        const float inv = 1.f / (e0 + e1);
        plan[2 * b] = e0 * inv;       plan[2 * b + 1] = e1 * inv;
        out_plan[2 * b] = e0 * inv;   out_plan[2 * b + 1] = e1 * inv;
    }
}

// =================================================================================
// softmax over u[b,:] then ctx[b,h] = sum_n aw[n] * enc[b,n,h]
// =================================================================================
__global__ void softmax_ctx_kernel(const float* __restrict__ u,
                                   const float* __restrict__ enc,
                                   float* __restrict__ ctx)
{
    const int b = blockIdx.x;
    const int t = threadIdx.x;          // 256 threads
    __shared__ float red[256];
    __shared__ float aw[NN];

    const float uv = (t < NN) ? u[(size_t)b * NN + t] : -INFINITY;
    red[t] = uv;
    __syncthreads();
    for (int s = 128; s > 0; s >>= 1) {
        if (t < s) red[t] = fmaxf(red[t], red[t + s]);
        __syncthreads();
    }
    const float mx = red[0];
    __syncthreads();
    const float e = (t < NN) ? expf(uv - mx) : 0.f;
    red[t] = e;
    __syncthreads();
    for (int s = 128; s > 0; s >>= 1) {
        if (t < s) red[t] += red[t + s];
        __syncthreads();
    }
    const float inv = 1.f / red[0];
    if (t < NN) aw[t] = e * inv;
    __syncthreads();

    const float* eb = enc + (size_t)b * NN * HH;
    for (int h = t; h < HH; h += 256) {
        float s = 0.f;
#pragma unroll 4
        for (int n = 0; n < NN; n++)
            s += aw[n] * eb[(size_t)n * HH + h];
        ctx[(size_t)b * HH + h] = s;
    }
}

// =================================================================================
// context mix + y_ctx = [prev_y | plan0*ctx_e + plan1*ctx_s]
// =================================================================================
__global__ void combine_kernel(const float* __restrict__ prev_y,
                               const float* __restrict__ plan,
                               const float* __restrict__ ctx_e,
                               const float* __restrict__ ctx_s,
                               float* __restrict__ yctx)
{
    const int idx = blockIdx.x * blockDim.x + threadIdx.x;
    if (idx >= BSZ * (EE + HH)) return;
    const int b = idx >> 10;            // E+H = 1024
    const int c = idx & 1023;
    float v;
    if (c < EE) {
        v = prev_y[(size_t)b * EE + c];
    } else {
        const float p0 = plan[2 * b], p1 = plan[2 * b + 1];
        const int h = c - EE;
        v = p0 * ctx_e[(size_t)b * HH + h] + p1 * ctx_s[(size_t)b * HH + h];
    }
    yctx[idx] = v;
}

// =================================================================================
// GRU cell elementwise
// =================================================================================
__global__ void gru_kernel(const float* __restrict__ gx,
                           const float* __restrict__ gh,
                           const float* __restrict__ prev_h,
                           float* __restrict__ h_new,
                           float* __restrict__ out_hid)
{
    const int idx = blockIdx.x * blockDim.x + threadIdx.x;
    if (idx >= BSZ * DD) return;
    const int b = idx / DD;
    const int d = idx - b * DD;
    const float* gxb = gx + (size_t)b * G3D;
    const float* ghb = gh + (size_t)b * G3D;
    const float r = 1.f / (1.f + expf(-(gxb[d] + ghb[d])));
    const float z = 1.f / (1.f + expf(-(gxb[DD + d] + ghb[DD + d])));
    const float n = tanhf(gxb[2 * DD + d] + r * ghb[2 * DD + d]);
    const float h = (1.f - z) * n + z * prev_h[idx];
    h_new[idx] = h;
    out_hid[idx] = h;
}

// =================================================================================
// host launcher — graph-capturable (kernel launches only, default stream)
// =================================================================================
extern "C" void kernel_launch(void* const* d_in, const int* in_sizes, int n_in,
                              void* d_out, int out_size)
{
    const float* prev_y  = (const float*)d_in[0];
    const float* prev_h  = (const float*)d_in[1];
    const float* equ_enc = (const float*)d_in[2];
    const float* sns_enc = (const float*)d_in[3];
    /* d_in[4] z_sample unused by the reference */
    const int* equ_mask = (const int*)d_in[5];
    const int* sns_mask = (const int*)d_in[6];
    const float* W1e    = (const float*)d_in[7];
    const float* W2e    = (const float*)d_in[8];
    const float* vte    = (const float*)d_in[9];
    const float* W1s    = (const float*)d_in[10];
    const float* W2s    = (const float*)d_in[11];
    const float* vts    = (const float*)d_in[12];
    const float* plan_W = (const float*)d_in[13];
    const float* plan_b = (const float*)d_in[14];
    const float* Wc     = (const float*)d_in[15];
    const float* bc     = (const float*)d_in[16];
    const float* w_ih   = (const float*)d_in[17];
    const float* w_hh   = (const float*)d_in[18];
    const float* b_ih   = (const float*)d_in[19];
    const float* b_hh   = (const float*)d_in[20];
    const float* Wout   = (const float*)d_in[21];
    const float* bout   = (const float*)d_in[22];

    float* out      = (float*)d_out;
    float* out_dec  = out;                                        // [256, 32000]
    float* out_hid  = out + (size_t)BSZ * VV;                     // [256, 1152]
    float* out_plan = out + (size_t)BSZ * VV + (size_t)BSZ * DD;  // [256, 2]

    float *dt_e, *dt_s, *u_e, *u_s, *ctx_e, *ctx_s, *plan, *yctx, *x, *gx, *gh, *hn;
    __nv_bfloat16 *w1e_hi, *w1e_lo, *w1s_hi, *w1s_lo;
    cudaGetSymbolAddress((void**)&dt_e,  g_dt_e);
    cudaGetSymbolAddress((void**)&dt_s,  g_dt_s);
    cudaGetSymbolAddress((void**)&u_e,   g_u_e);
    cudaGetSymbolAddress((void**)&u_s,   g_u_s);
    cudaGetSymbolAddress((void**)&ctx_e, g_ctx_e);
    cudaGetSymbolAddress((void**)&ctx_s, g_ctx_s);
    cudaGetSymbolAddress((void**)&plan,  g_plan);
    cudaGetSymbolAddress((void**)&yctx,  g_yctx);
    cudaGetSymbolAddress((void**)&x,     g_x);
    cudaGetSymbolAddress((void**)&gx,    g_gx);
    cudaGetSymbolAddress((void**)&gh,    g_gh);
    cudaGetSymbolAddress((void**)&hn,    g_h);
    cudaGetSymbolAddress((void**)&w1e_hi, g_w1e_hi);
    cudaGetSymbolAddress((void**)&w1e_lo, g_w1e_lo);
    cudaGetSymbolAddress((void**)&w1s_hi, g_w1s_hi);
    cudaGetSymbolAddress((void**)&w1s_lo, g_w1s_lo);

    // opt-in to >48KB dynamic smem (idempotent host calls, no allocation)
    cudaFuncSetAttribute(gemm_bf16x3, cudaFuncAttributeMaxDynamicSharedMemorySize, SMEM_BYTES);
    cudaFuncSetAttribute(attn_bf16x3, cudaFuncAttributeMaxDynamicSharedMemorySize, SMEM_BYTES);

    const dim3 blk(256);

    // pre-split attention weights (1MB each; ~2us)
    split_kernel<<<(HH * HH / 4 + 255) / 256, blk>>>(W1e, w1e_hi, w1e_lo, HH * HH / 4);
    split_kernel<<<(HH * HH / 4 + 255) / 256, blk>>>(W1s, w1s_hi, w1s_lo, HH * HH / 4);

    // dt_e = prev_h @ W2e^T ;  dt_s = prev_h @ W2s^T
    gemm_bf16x3<<<dim3(HH / 128, BSZ / 128), blk, SMEM_BYTES>>>(prev_h, W2e, nullptr, dt_e, BSZ, HH, DD);
    gemm_bf16x3<<<dim3(HH / 128, BSZ / 128), blk, SMEM_BYTES>>>(prev_h, W2s, nullptr, dt_s, BSZ, HH, DD);
    // gh = prev_h @ w_hh^T + b_hh
    gemm_bf16x3<<<dim3(G3D / 128, BSZ / 128), blk, SMEM_BYTES>>>(prev_h, w_hh, b_hh, gh, BSZ, G3D, DD);
    // plan softmax (also writes output region)
    plan_kernel<<<BSZ, 128>>>(prev_h, plan_W, plan_b, plan, out_plan);

    // fused attention scores (pipelined bf16x3, pre-split W1, fused tanh.vt epilogue)
    attn_bf16x3<<<BSZ, blk, SMEM_BYTES>>>(equ_enc, w1e_hi, w1e_lo, dt_e, vte, equ_mask, u_e);
    attn_bf16x3<<<BSZ, blk, SMEM_BYTES>>>(sns_enc, w1s_hi, w1s_lo, dt_s, vts, sns_mask, u_s);

    // softmax + context
    softmax_ctx_kernel<<<BSZ, blk>>>(u_e, equ_enc, ctx_e);
    softmax_ctx_kernel<<<BSZ, blk>>>(u_s, sns_enc, ctx_s);

    // y_ctx assembly
    combine_kernel<<<(BSZ * (EE + HH)) / 256, blk>>>(prev_y, plan, ctx_e, ctx_s, yctx);

    // x = y_ctx @ Wc^T + bc ;  gx = x @ w_ih^T + b_ih
    gemm_bf16x3<<<dim3(HH / 128, BSZ / 128), blk, SMEM_BYTES>>>(yctx, Wc, bc, x, BSZ, HH, EE + HH);
    gemm_bf16x3<<<dim3(G3D / 128, BSZ / 128), blk, SMEM_BYTES>>>(x, w_ih, b_ih, gx, BSZ, G3D, HH);

    // GRU elementwise (writes h_new + output hidden region)
    gru_kernel<<<(BSZ * DD) / 256, blk>>>(gx, gh, prev_h, hn, out_hid);

    // dec_output = h_new @ Wout^T + bout  (written directly into output region)
    gemm_bf16x3<<<dim3(VV / 128, BSZ / 128), blk, SMEM_BYTES>>>(hn, Wout, bout, out_dec, BSZ, VV, DD);
}

// round 5
// speedup vs baseline: 2.2557x; 1.2782x over previous
#include <cuda_runtime.h>
#include <cuda_bf16.h>
#include <math.h>
#include <stdint.h>

#define HH   512
#define ZZ   128
#define EE   512
#define DD   1152      // 2H + Z
#define VV   32000
#define BSZ  256
#define NN   128
#define G3D  3456      // 3*D
#define NCAT 4480      // 512 (dt_e) + 512 (dt_s) + 3456 (gh)

// ---------------- scratch (device globals; no allocation allowed) ----------------
__device__ float g_u_e  [BSZ * NN];
__device__ float g_u_s  [BSZ * NN];
__device__ float g_ctx_e[BSZ * HH];
__device__ float g_ctx_s[BSZ * HH];
__device__ float g_plan [BSZ * 2];
__device__ float g_yctx [BSZ * (EE + HH)];
__device__ float g_x    [BSZ * HH];
__device__ float g_gx   [BSZ * G3D];
__device__ float g_h    [BSZ * DD];
__device__ float g_dtgh [BSZ * NCAT];      // cols: [0,512) dt_e | [512,1024) dt_s | [1024,4480) gh
__device__ float g_Wcat [NCAT * DD];       // concat(W2e, W2s, w_hh)
// pre-split attention weights (bf16 hi/lo)
__device__ __nv_bfloat16 g_w1e_hi[HH * HH];
__device__ __nv_bfloat16 g_w1e_lo[HH * HH];
__device__ __nv_bfloat16 g_w1s_hi[HH * HH];
__device__ __nv_bfloat16 g_w1s_lo[HH * HH];

// ---------------- helpers ----------------
__device__ __forceinline__ uint32_t pack_bf2(float a, float b) {
    __nv_bfloat162 t = __floats2bfloat162_rn(a, b);
    return *reinterpret_cast<uint32_t*>(&t);
}

__device__ __forceinline__ void mma16816(float c[4],
                                         uint32_t a0, uint32_t a1, uint32_t a2, uint32_t a3,
                                         uint32_t b0, uint32_t b1) {
    asm volatile(
        "mma.sync.aligned.m16n8k16.row.col.f32.bf16.bf16.f32 "
        "{%0,%1,%2,%3}, {%4,%5,%6,%7}, {%8,%9}, {%0,%1,%2,%3};\n"
        : "+f"(c[0]), "+f"(c[1]), "+f"(c[2]), "+f"(c[3])
        : "r"(a0), "r"(a1), "r"(a2), "r"(a3), "r"(b0), "r"(b1));
}

__device__ __forceinline__ void ldsm_x4(uint32_t& r0, uint32_t& r1, uint32_t& r2, uint32_t& r3,
                                        uint32_t addr) {
    asm volatile("ldmatrix.sync.aligned.m8n8.x4.shared.b16 {%0,%1,%2,%3}, [%4];"
                 : "=r"(r0), "=r"(r1), "=r"(r2), "=r"(r3) : "r"(addr));
}
__device__ __forceinline__ void ldsm_x2(uint32_t& r0, uint32_t& r1, uint32_t addr) {
    asm volatile("ldmatrix.sync.aligned.m8n8.x2.shared.b16 {%0,%1}, [%2];"
                 : "=r"(r0), "=r"(r1) : "r"(addr));
}

#define SMS 40                      // smem row stride in bf16 (conflict-free, 80B = 5*16B)
#define STG (128 * SMS)             // elements per array
#define STAGE4 (4 * STG)            // elements per stage (Ahi,Alo,Bhi,Blo)
#define SMEM_BYTES (2 * STAGE4 * 2) // 81920 bytes

// split 16 fp32 (4x float4) into hi/lo bf16 and store 32B to smem at [idx..idx+16)
__device__ __forceinline__ void split_store16(const float4* v,
                                              __nv_bfloat16* hi, __nv_bfloat16* lo,
                                              int idx) {
#pragma unroll
    for (int i = 0; i < 4; i++) {
        float x = v[i].x, y = v[i].y, z = v[i].z, w = v[i].w;
        __nv_bfloat16 hx = __float2bfloat16(x), hy = __float2bfloat16(y);
        __nv_bfloat16 hz = __float2bfloat16(z), hw = __float2bfloat16(w);
        uint2 vh, vl;
        vh.x = pack_bf2(x, y); vh.y = pack_bf2(z, w);
        vl.x = pack_bf2(x - __bfloat162float(hx), y - __bfloat162float(hy));
        vl.y = pack_bf2(z - __bfloat162float(hz), w - __bfloat162float(hw));
        *(uint2*)&hi[idx + i * 4] = vh;
        *(uint2*)&lo[idx + i * 4] = vl;
    }
}

// mma pass over one staged 32-K chunk using ldmatrix fragment loads.
// stb: u32 smem byte address of stage base; aoff/boff: lane-dependent byte offsets.
__device__ __forceinline__ void mma_chunk(uint32_t stb, uint32_t aoff, uint32_t boff,
                                          float acc[4][4][4], int wr, int wc) {
#pragma unroll
    for (int ks = 0; ks < 2; ks++) {
        const uint32_t kb2 = ks * 32;   // 16 halfs = 32 bytes
        uint32_t ahi[4][4], alo[4][4], bhi[4][2], blo[4][2];
#pragma unroll
        for (int mi = 0; mi < 4; mi++) {
            const uint32_t rb = (uint32_t)(wr * 64 + mi * 16) * (SMS * 2) + kb2 + aoff;
            ldsm_x4(ahi[mi][0], ahi[mi][1], ahi[mi][2], ahi[mi][3], stb + rb);
            ldsm_x4(alo[mi][0], alo[mi][1], alo[mi][2], alo[mi][3], stb + STG * 2 + rb);
        }
#pragma unroll
        for (int ni = 0; ni < 4; ni++) {
            const uint32_t rb = (uint32_t)(wc * 32 + ni * 8) * (SMS * 2) + kb2 + boff;
            ldsm_x2(bhi[ni][0], bhi[ni][1], stb + 2 * STG * 2 + rb);
            ldsm_x2(blo[ni][0], blo[ni][1], stb + 3 * STG * 2 + rb);
        }
#pragma unroll
        for (int mi = 0; mi < 4; mi++)
#pragma unroll
            for (int ni = 0; ni < 4; ni++) {
                mma16816(acc[mi][ni], ahi[mi][0], ahi[mi][1], ahi[mi][2], ahi[mi][3],
                         bhi[ni][0], bhi[ni][1]);
                mma16816(acc[mi][ni], ahi[mi][0], ahi[mi][1], ahi[mi][2], ahi[mi][3],
                         blo[ni][0], blo[ni][1]);
                mma16816(acc[mi][ni], alo[mi][0], alo[mi][1], alo[mi][2], alo[mi][3],
                         bhi[ni][0], bhi[ni][1]);
            }
    }
}

// lane-dependent ldmatrix byte offsets
__device__ __forceinline__ uint32_t ldsm_aoff(int l) {
    return (uint32_t)((((l & 7) + ((l >> 3) & 1) * 8) * SMS + (l >> 4) * 8) * 2);
}
__device__ __forceinline__ uint32_t ldsm_boff(int l) {
    return (uint32_t)(((l & 7) * SMS + ((l >> 3) & 1) * 8) * 2);
}

// =================================================================================
// bf16x3 GEMM, 2-stage pipelined: C[M,N] = A[M,K] @ B[N,K]^T (+ bias[n])
// 128x128 block tile, 8 warps, K chunks of 32, dynamic smem double buffer, ldmatrix.
// =================================================================================
__global__ void __launch_bounds__(256) gemm_bf16x3(
    const float* __restrict__ A, const float* __restrict__ B,
    const float* __restrict__ bias, float* __restrict__ C,
    int M, int N, int K)
{
    extern __shared__ __nv_bfloat16 sm[];

    const int t    = threadIdx.x;
    const int m0   = blockIdx.y * 128;
    const int n0   = blockIdx.x * 128;
    const int lane = t & 31;
    const int wid  = t >> 5;
    const int g    = lane >> 2;
    const int tg   = lane & 3;
    const int wr   = wid & 1;
    const int wc   = wid >> 1;

    const uint32_t smb  = (uint32_t)__cvta_generic_to_shared(sm);
    const uint32_t aoff = ldsm_aoff(lane);
    const uint32_t boff = ldsm_boff(lane);

    const int r   = t >> 1;
    const int hh  = (t & 1) * 16;
    const int idx = r * SMS + hh;
    const float* Ap = A + (size_t)(m0 + r) * K + hh;
    const float* Bp = B + (size_t)(n0 + r) * K + hh;

    float acc[4][4][4];
#pragma unroll
    for (int mi = 0; mi < 4; mi++)
#pragma unroll
        for (int ni = 0; ni < 4; ni++)
#pragma unroll
            for (int q = 0; q < 4; q++) acc[mi][ni][q] = 0.f;

    float4 ra[4], rb[4];
#pragma unroll
    for (int i = 0; i < 4; i++) {
        ra[i] = *(const float4*)(Ap + i * 4);
        rb[i] = *(const float4*)(Bp + i * 4);
    }
    split_store16(ra, sm + 0 * STG, sm + 1 * STG, idx);
    split_store16(rb, sm + 2 * STG, sm + 3 * STG, idx);
    __syncthreads();

    for (int k0 = 0; k0 < K; k0 += 32) {
        const int s = (k0 >> 5) & 1;
        const bool more = (k0 + 32 < K);
        if (more) {
#pragma unroll
            for (int i = 0; i < 4; i++) {
                ra[i] = *(const float4*)(Ap + k0 + 32 + i * 4);
                rb[i] = *(const float4*)(Bp + k0 + 32 + i * 4);
            }
        }
        mma_chunk(smb + (uint32_t)s * (STAGE4 * 2), aoff, boff, acc, wr, wc);
        if (more) {
            __nv_bfloat16* nt = sm + (s ^ 1) * STAGE4;
            split_store16(ra, nt, nt + STG, idx);
            split_store16(rb, nt + 2 * STG, nt + 3 * STG, idx);
        }
        __syncthreads();
    }

    // epilogue
#pragma unroll
    for (int mi = 0; mi < 4; mi++) {
        const int row = m0 + wr * 64 + mi * 16 + g;
#pragma unroll
        for (int ni = 0; ni < 4; ni++) {
            const int col = n0 + wc * 32 + ni * 8 + tg * 2;
            float b0 = bias ? bias[col] : 0.f;
            float b1 = bias ? bias[col + 1] : 0.f;
            float2 v0 = make_float2(acc[mi][ni][0] + b0, acc[mi][ni][1] + b1);
            float2 v1 = make_float2(acc[mi][ni][2] + b0, acc[mi][ni][3] + b1);
            *(float2*)&C[(size_t)row * N + col]       = v0;
            *(float2*)&C[(size_t)(row + 8) * N + col] = v1;
        }
    }
}

// =================================================================================
// weight split: fp32 -> bf16 hi/lo (vectorized)
// =================================================================================
__global__ void split_kernel(const float* __restrict__ W,
                             __nv_bfloat16* __restrict__ hi,
                             __nv_bfloat16* __restrict__ lo, int n4)
{
    const int i = blockIdx.x * blockDim.x + threadIdx.x;
    if (i >= n4) return;
    float4 v = ((const float4*)W)[i];
    __nv_bfloat16 hx = __float2bfloat16(v.x), hy = __float2bfloat16(v.y);
    __nv_bfloat16 hz = __float2bfloat16(v.z), hw = __float2bfloat16(v.w);
    uint2 vh, vl;
    vh.x = pack_bf2(v.x, v.y); vh.y = pack_bf2(v.z, v.w);
    vl.x = pack_bf2(v.x - __bfloat162float(hx), v.y - __bfloat162float(hy));
    vl.y = pack_bf2(v.z - __bfloat162float(hz), v.w - __bfloat162float(hw));
    ((uint2*)hi)[i] = vh;
    ((uint2*)lo)[i] = vl;
}

// =================================================================================
// Fused attention scores, pipelined bf16x3 with pre-split W1 (ldmatrix):
//   u[b,n] = sum_k vt[k] * tanh( (enc[b] @ W1^T)[n,k] + dt[b,k] ), mask -> -inf
// dt has row stride ldDT (reads from the fused dtgh buffer).
// =================================================================================
__global__ void __launch_bounds__(256) attn_bf16x3(
    const float* __restrict__ enc,              // [BS*NN, 512]
    const __nv_bfloat16* __restrict__ w1hi,     // [512, 512] pre-split
    const __nv_bfloat16* __restrict__ w1lo,
    const float* __restrict__ dt,               // [BS, *] stride ldDT
    int ldDT,
    const float* __restrict__ vt,               // [512]
    const int* __restrict__ mask,               // [BS*NN] int32 bool
    float* __restrict__ u)                      // [BS*NN]
{
    extern __shared__ __nv_bfloat16 sm[];
    __shared__ float s_dt[512];
    __shared__ float s_vt[512];
    __shared__ float s_u[128];

    const int t    = threadIdx.x;
    const int b    = blockIdx.x;
    const int lane = t & 31;
    const int wid  = t >> 5;
    const int g    = lane >> 2;
    const int tg   = lane & 3;
    const int wr   = wid & 1;
    const int wc   = wid >> 1;

    const uint32_t smb  = (uint32_t)__cvta_generic_to_shared(sm);
    const uint32_t aoff = ldsm_aoff(lane);
    const uint32_t boff = ldsm_boff(lane);

    for (int i = t; i < 512; i += 256) {
        s_dt[i] = dt[(size_t)b * ldDT + i];
        s_vt[i] = vt[i];
    }
    if (t < 128) s_u[t] = 0.f;

    const int r   = t >> 1;
    const int hh  = (t & 1) * 16;
    const int idx = r * SMS + hh;
    const float* Ap = enc + (size_t)(b * 128 + r) * 512 + hh;

    float up[8];
#pragma unroll
    for (int i = 0; i < 8; i++) up[i] = 0.f;

    for (int nc = 0; nc < 4; nc++) {
        const __nv_bfloat16* Bhp = w1hi + (size_t)(nc * 128 + r) * 512 + hh;
        const __nv_bfloat16* Blp = w1lo + (size_t)(nc * 128 + r) * 512 + hh;

        float acc[4][4][4];
#pragma unroll
        for (int mi = 0; mi < 4; mi++)
#pragma unroll
            for (int ni = 0; ni < 4; ni++)
#pragma unroll
                for (int q = 0; q < 4; q++) acc[mi][ni][q] = 0.f;

        float4 ra[4];
        uint4 rbh[2], rbl[2];
#pragma unroll
        for (int i = 0; i < 4; i++) ra[i] = *(const float4*)(Ap + i * 4);
        rbh[0] = *(const uint4*)(Bhp);     rbh[1] = *(const uint4*)(Bhp + 8);
        rbl[0] = *(const uint4*)(Blp);     rbl[1] = *(const uint4*)(Blp + 8);

        split_store16(ra, sm, sm + STG, idx);
        *(uint4*)&sm[2 * STG + idx]     = rbh[0];
        *(uint4*)&sm[2 * STG + idx + 8] = rbh[1];
        *(uint4*)&sm[3 * STG + idx]     = rbl[0];
        *(uint4*)&sm[3 * STG + idx + 8] = rbl[1];
        __syncthreads();

        for (int k0 = 0; k0 < 512; k0 += 32) {
            const int s = (k0 >> 5) & 1;
            const bool more = (k0 + 32 < 512);
            if (more) {
#pragma unroll
                for (int i = 0; i < 4; i++) ra[i] = *(const float4*)(Ap + k0 + 32 + i * 4);
                rbh[0] = *(const uint4*)(Bhp + k0 + 32);
                rbh[1] = *(const uint4*)(Bhp + k0 + 40);
                rbl[0] = *(const uint4*)(Blp + k0 + 32);
                rbl[1] = *(const uint4*)(Blp + k0 + 40);
            }
            mma_chunk(smb + (uint32_t)s * (STAGE4 * 2), aoff, boff, acc, wr, wc);
            if (more) {
                __nv_bfloat16* nt = sm + (s ^ 1) * STAGE4;
                split_store16(ra, nt, nt + STG, idx);
                *(uint4*)&nt[2 * STG + idx]     = rbh[0];
                *(uint4*)&nt[2 * STG + idx + 8] = rbh[1];
                *(uint4*)&nt[3 * STG + idx]     = rbl[0];
                *(uint4*)&nt[3 * STG + idx + 8] = rbl[1];
            }
            __syncthreads();
        }

        // fused epilogue for this n-chunk
#pragma unroll
        for (int mi = 0; mi < 4; mi++)
#pragma unroll
            for (int ni = 0; ni < 4; ni++) {
                const int col = nc * 128 + wc * 32 + ni * 8 + tg * 2;
                const float d0 = s_dt[col], d1 = s_dt[col + 1];
                const float v0 = s_vt[col], v1 = s_vt[col + 1];
                up[mi * 2 + 0] += v0 * tanhf(acc[mi][ni][0] + d0)
                                + v1 * tanhf(acc[mi][ni][1] + d1);
                up[mi * 2 + 1] += v0 * tanhf(acc[mi][ni][2] + d0)
                                + v1 * tanhf(acc[mi][ni][3] + d1);
            }
    }

    // reduce across the 4 lanes sharing g
#pragma unroll
    for (int mi = 0; mi < 4; mi++)
#pragma unroll
        for (int rr = 0; rr < 2; rr++) {
            float v = up[mi * 2 + rr];
            v += __shfl_down_sync(0xffffffffu, v, 1);
            v += __shfl_down_sync(0xffffffffu, v, 2);
            if (tg == 0)
                atomicAdd(&s_u[wr * 64 + mi * 16 + g + rr * 8], v);
        }
    __syncthreads();

    if (t < 128) {
        const int m = b * 128 + t;
        u[m] = (mask[(size_t)b * NN + t] != 0) ? -INFINITY : s_u[t];
    }
}

// =================================================================================
// plan = softmax(prev_h @ plan_W^T + plan_b)
// =================================================================================
__global__ void plan_kernel(const float* __restrict__ prev_h,
                            const float* __restrict__ plan_W,
                            const float* __restrict__ plan_b,
                            float* __restrict__ plan,
                            float* __restrict__ out_plan)
{
    const int b = blockIdx.x;
    const int t = threadIdx.x;          // 128 threads
    __shared__ float s0[128], s1[128];
    float a0 = 0.f, a1 = 0.f;
    const float* hb = prev_h + (size_t)b * DD;
    for (int k = t; k < DD; k += 128) {
        const float h = hb[k];
        a0 += h * plan_W[k];
        a1 += h * plan_W[DD + k];
    }
    s0[t] = a0; s1[t] = a1;
    __syncthreads();
    for (int s = 64; s > 0; s >>= 1) {
        if (t < s) { s0[t] += s0[t + s]; s1[t] += s1[t + s]; }
        __syncthreads();
    }
    if (t == 0) {
        const float l0 = s0[0] + plan_b[0];
        const float l1 = s1[0] + plan_b[1];
        const float mx = fmaxf(l0, l1);
        const float e0 = expf(l0 - mx), e1 = expf(l1 - mx);
        const float inv = 1.f / (e0 + e1);
        plan[2 * b] = e0 * inv;       plan[2 * b + 1] = e1 * inv;
        out_plan[2 * b] = e0 * inv;   out_plan[2 * b + 1] = e1 * inv;
    }
}

// =================================================================================
// softmax over u[b,:] then ctx[b,h] = sum_n aw[n] * enc[b,n,h]
// =================================================================================
__global__ void softmax_ctx_kernel(const float* __restrict__ u,
                                   const float* __restrict__ enc,
                                   float* __restrict__ ctx)
{
    const int b = blockIdx.x;
    const int t = threadIdx.x;          // 256 threads
    __shared__ float red[256];
    __shared__ float aw[NN];

    const float uv = (t < NN) ? u[(size_t)b * NN + t] : -INFINITY;
    red[t] = uv;
    __syncthreads();
    for (int s = 128; s > 0; s >>= 1) {
        if (t < s) red[t] = fmaxf(red[t], red[t + s]);
        __syncthreads();
    }
    const float mx = red[0];
    __syncthreads();
    const float e = (t < NN) ? expf(uv - mx) : 0.f;
    red[t] = e;
    __syncthreads();
    for (int s = 128; s > 0; s >>= 1) {
        if (t < s) red[t] += red[t + s];
        __syncthreads();
    }
    const float inv = 1.f / red[0];
    if (t < NN) aw[t] = e * inv;
    __syncthreads();

    const float* eb = enc + (size_t)b * NN * HH;
    for (int h = t; h < HH; h += 256) {
        float s = 0.f;
#pragma unroll 4
        for (int n = 0; n < NN; n++)
            s += aw[n] * eb[(size_t)n * HH + h];
        ctx[(size_t)b * HH + h] = s;
    }
}

// =================================================================================
// context mix + y_ctx = [prev_y | plan0*ctx_e + plan1*ctx_s]
// =================================================================================
__global__ void combine_kernel(const float* __restrict__ prev_y,
                               const float* __restrict__ plan,
                               const float* __restrict__ ctx_e,
                               const float* __restrict__ ctx_s,
                               float* __restrict__ yctx)
{
    const int idx = blockIdx.x * blockDim.x + threadIdx.x;
    if (idx >= BSZ * (EE + HH)) return;
    const int b = idx >> 10;            // E+H = 1024
    const int c = idx & 1023;
    float v;
    if (c < EE) {
        v = prev_y[(size_t)b * EE + c];
    } else {
        const float p0 = plan[2 * b], p1 = plan[2 * b + 1];
        const int h = c - EE;
        v = p0 * ctx_e[(size_t)b * HH + h] + p1 * ctx_s[(size_t)b * HH + h];
    }
    yctx[idx] = v;
}

// =================================================================================
// GRU cell elementwise; gh read strided from fused dtgh buffer, b_hh added here
// =================================================================================
__global__ void gru_kernel(const float* __restrict__ gx,
                           const float* __restrict__ ghbase,   // dtgh + 1024, row stride NCAT
                           const float* __restrict__ b_hh,
                           const float* __restrict__ prev_h,
                           float* __restrict__ h_new,
                           float* __restrict__ out_hid)
{
    const int idx = blockIdx.x * blockDim.x + threadIdx.x;
    if (idx >= BSZ * DD) return;
    const int b = idx / DD;
    const int d = idx - b * DD;
    const float* gxb = gx + (size_t)b * G3D;
    const float* ghb = ghbase + (size_t)b * NCAT;
    const float ghr = ghb[d]          + b_hh[d];
    const float ghz = ghb[DD + d]     + b_hh[DD + d];
    const float ghn = ghb[2 * DD + d] + b_hh[2 * DD + d];
    const float r = 1.f / (1.f + expf(-(gxb[d] + ghr)));
    const float z = 1.f / (1.f + expf(-(gxb[DD + d] + ghz)));
    const float n = tanhf(gxb[2 * DD + d] + r * ghn);
    const float h = (1.f - z) * n + z * prev_h[idx];
    h_new[idx] = h;
    out_hid[idx] = h;
}

// =================================================================================
// host launcher — graph-capturable (kernel launches + D2D memcpy only)
// =================================================================================
extern "C" void kernel_launch(void* const* d_in, const int* in_sizes, int n_in,
                              void* d_out, int out_size)
{
    const float* prev_y  = (const float*)d_in[0];
    const float* prev_h  = (const float*)d_in[1];
    const float* equ_enc = (const float*)d_in[2];
    const float* sns_enc = (const float*)d_in[3];
    /* d_in[4] z_sample unused by the reference */
    const int* equ_mask = (const int*)d_in[5];
    const int* sns_mask = (const int*)d_in[6];
    const float* W1e    = (const float*)d_in[7];
    const float* W2e    = (const float*)d_in[8];
    const float* vte    = (const float*)d_in[9];
    const float* W1s    = (const float*)d_in[10];
    const float* W2s    = (const float*)d_in[11];
    const float* vts    = (const float*)d_in[12];
    const float* plan_W = (const float*)d_in[13];
    const float* plan_b = (const float*)d_in[14];
    const float* Wc     = (const float*)d_in[15];
    const float* bc     = (const float*)d_in[16];
    const float* w_ih   = (const float*)d_in[17];
    const float* w_hh   = (const float*)d_in[18];
    const float* b_ih   = (const float*)d_in[19];
    const float* b_hh   = (const float*)d_in[20];
    const float* Wout   = (const float*)d_in[21];
    const float* bout   = (const float*)d_in[22];

    float* out      = (float*)d_out;
    float* out_dec  = out;                                        // [256, 32000]
    float* out_hid  = out + (size_t)BSZ * VV;                     // [256, 1152]
    float* out_plan = out + (size_t)BSZ * VV + (size_t)BSZ * DD;  // [256, 2]

    float *u_e, *u_s, *ctx_e, *ctx_s, *plan, *yctx, *x, *gx, *hn, *dtgh, *Wcat;
    __nv_bfloat16 *w1e_hi, *w1e_lo, *w1s_hi, *w1s_lo;
    cudaGetSymbolAddress((void**)&u_e,   g_u_e);
    cudaGetSymbolAddress((void**)&u_s,   g_u_s);
    cudaGetSymbolAddress((void**)&ctx_e, g_ctx_e);
    cudaGetSymbolAddress((void**)&ctx_s, g_ctx_s);
    cudaGetSymbolAddress((void**)&plan,  g_plan);
    cudaGetSymbolAddress((void**)&yctx,  g_yctx);
    cudaGetSymbolAddress((void**)&x,     g_x);
    cudaGetSymbolAddress((void**)&gx,    g_gx);
    cudaGetSymbolAddress((void**)&hn,    g_h);
    cudaGetSymbolAddress((void**)&dtgh,  g_dtgh);
    cudaGetSymbolAddress((void**)&Wcat,  g_Wcat);
    cudaGetSymbolAddress((void**)&w1e_hi, g_w1e_hi);
    cudaGetSymbolAddress((void**)&w1e_lo, g_w1e_lo);
    cudaGetSymbolAddress((void**)&w1s_hi, g_w1s_hi);
    cudaGetSymbolAddress((void**)&w1s_lo, g_w1s_lo);

    cudaFuncSetAttribute(gemm_bf16x3, cudaFuncAttributeMaxDynamicSharedMemorySize, SMEM_BYTES);
    cudaFuncSetAttribute(attn_bf16x3, cudaFuncAttributeMaxDynamicSharedMemorySize, SMEM_BYTES);

    const dim3 blk(256);

    // concat weights for fused dt/gh GEMM (D2D copies are capture-legal)
    cudaMemcpyAsync(Wcat,                   W2e,  (size_t)HH  * DD * 4, cudaMemcpyDeviceToDevice);
    cudaMemcpyAsync(Wcat + (size_t)HH * DD, W2s,  (size_t)HH  * DD * 4, cudaMemcpyDeviceToDevice);
    cudaMemcpyAsync(Wcat + (size_t)2 * HH * DD, w_hh, (size_t)G3D * DD * 4, cudaMemcpyDeviceToDevice);

    // pre-split attention weights (1MB each)
    split_kernel<<<(HH * HH / 4 + 255) / 256, blk>>>(W1e, w1e_hi, w1e_lo, HH * HH / 4);
    split_kernel<<<(HH * HH / 4 + 255) / 256, blk>>>(W1s, w1s_hi, w1s_lo, HH * HH / 4);

    // fused [dt_e | dt_s | gh] = prev_h @ Wcat^T   (grid 70)
    gemm_bf16x3<<<dim3(NCAT / 128, BSZ / 128), blk, SMEM_BYTES>>>(prev_h, Wcat, nullptr, dtgh, BSZ, NCAT, DD);

    // plan softmax (also writes output region)
    plan_kernel<<<BSZ, 128>>>(prev_h, plan_W, plan_b, plan, out_plan);

    // fused attention scores (pipelined bf16x3, pre-split W1, ldmatrix, fused tanh.vt)
    attn_bf16x3<<<BSZ, blk, SMEM_BYTES>>>(equ_enc, w1e_hi, w1e_lo, dtgh,      NCAT, vte, equ_mask, u_e);
    attn_bf16x3<<<BSZ, blk, SMEM_BYTES>>>(sns_enc, w1s_hi, w1s_lo, dtgh + HH, NCAT, vts, sns_mask, u_s);

    // softmax + context
    softmax_ctx_kernel<<<BSZ, blk>>>(u_e, equ_enc, ctx_e);
    softmax_ctx_kernel<<<BSZ, blk>>>(u_s, sns_enc, ctx_s);

    // y_ctx assembly
    combine_kernel<<<(BSZ * (EE + HH)) / 256, blk>>>(prev_y, plan, ctx_e, ctx_s, yctx);

    // x = y_ctx @ Wc^T + bc ;  gx = x @ w_ih^T + b_ih
    gemm_bf16x3<<<dim3(HH / 128, BSZ / 128), blk, SMEM_BYTES>>>(yctx, Wc, bc, x, BSZ, HH, EE + HH);
    gemm_bf16x3<<<dim3(G3D / 128, BSZ / 128), blk, SMEM_BYTES>>>(x, w_ih, b_ih, gx, BSZ, G3D, HH);

    // GRU elementwise (reads gh strided from dtgh; writes h_new + output hidden)
    gru_kernel<<<(BSZ * DD) / 256, blk>>>(gx, dtgh + 2 * HH, b_hh, prev_h, hn, out_hid);

    // dec_output = h_new @ Wout^T + bout  (written directly into output region)
    gemm_bf16x3<<<dim3(VV / 128, BSZ / 128), blk, SMEM_BYTES>>>(hn, Wout, bout, out_dec, BSZ, VV, DD);
}

// round 6
// speedup vs baseline: 2.2840x; 1.0126x over previous
#include <cuda_runtime.h>
#include <cuda_bf16.h>
#include <math.h>
#include <stdint.h>

#define HH   512
#define ZZ   128
#define EE   512
#define DD   1152      // 2H + Z
#define VV   32000
#define BSZ  256
#define NN   128
#define G3D  3456      // 3*D
#define NCAT 4480      // 512 (dt_e) + 512 (dt_s) + 3456 (gh)
#define YC   1024      // E + H

// ---------------- scratch (device globals; no allocation allowed) ----------------
__device__ float g_u_e  [BSZ * NN];
__device__ float g_u_s  [BSZ * NN];
__device__ float g_ctx_e[BSZ * HH];
__device__ float g_ctx_s[BSZ * HH];
__device__ float g_plan [BSZ * 2];
__device__ float g_gx   [BSZ * G3D];
__device__ float g_dtgh [BSZ * NCAT];  // [0,512) dt_e | [512,1024) dt_s | [1024,4480) gh

// pre-split bf16 hi/lo operands (16B-aligned for cp.async / ldmatrix)
__device__ __align__(256) __nv_bfloat16 g_ph_hi [BSZ * DD];
__device__ __align__(256) __nv_bfloat16 g_ph_lo [BSZ * DD];
__device__ __align__(256) __nv_bfloat16 g_ee_hi [BSZ * NN * HH];
__device__ __align__(256) __nv_bfloat16 g_ee_lo [BSZ * NN * HH];
__device__ __align__(256) __nv_bfloat16 g_es_hi [BSZ * NN * HH];
__device__ __align__(256) __nv_bfloat16 g_es_lo [BSZ * NN * HH];
__device__ __align__(256) __nv_bfloat16 g_wcat_hi[NCAT * DD];
__device__ __align__(256) __nv_bfloat16 g_wcat_lo[NCAT * DD];
__device__ __align__(256) __nv_bfloat16 g_wc_hi [HH * YC];
__device__ __align__(256) __nv_bfloat16 g_wc_lo [HH * YC];
__device__ __align__(256) __nv_bfloat16 g_wih_hi[G3D * HH];
__device__ __align__(256) __nv_bfloat16 g_wih_lo[G3D * HH];
__device__ __align__(256) __nv_bfloat16 g_w1e_hi[HH * HH];
__device__ __align__(256) __nv_bfloat16 g_w1e_lo[HH * HH];
__device__ __align__(256) __nv_bfloat16 g_w1s_hi[HH * HH];
__device__ __align__(256) __nv_bfloat16 g_w1s_lo[HH * HH];
__device__ __align__(256) __nv_bfloat16 g_yc_hi [BSZ * YC];
__device__ __align__(256) __nv_bfloat16 g_yc_lo [BSZ * YC];
__device__ __align__(256) __nv_bfloat16 g_x_hi  [BSZ * HH];
__device__ __align__(256) __nv_bfloat16 g_x_lo  [BSZ * HH];
__device__ __align__(256) __nv_bfloat16 g_hn_hi [BSZ * DD];
__device__ __align__(256) __nv_bfloat16 g_hn_lo [BSZ * DD];

// ---------------- helpers ----------------
__device__ __forceinline__ uint32_t pack_bf2(float a, float b) {
    __nv_bfloat162 t = __floats2bfloat162_rn(a, b);
    return *reinterpret_cast<uint32_t*>(&t);
}

__device__ __forceinline__ void mma16816(float c[4],
                                         uint32_t a0, uint32_t a1, uint32_t a2, uint32_t a3,
                                         uint32_t b0, uint32_t b1) {
    asm volatile(
        "mma.sync.aligned.m16n8k16.row.col.f32.bf16.bf16.f32 "
        "{%0,%1,%2,%3}, {%4,%5,%6,%7}, {%8,%9}, {%0,%1,%2,%3};\n"
        : "+f"(c[0]), "+f"(c[1]), "+f"(c[2]), "+f"(c[3])
        : "r"(a0), "r"(a1), "r"(a2), "r"(a3), "r"(b0), "r"(b1));
}

__device__ __forceinline__ void ldsm_x4(uint32_t& r0, uint32_t& r1, uint32_t& r2, uint32_t& r3,
                                        uint32_t addr) {
    asm volatile("ldmatrix.sync.aligned.m8n8.x4.shared.b16 {%0,%1,%2,%3}, [%4];"
                 : "=r"(r0), "=r"(r1), "=r"(r2), "=r"(r3) : "r"(addr));
}
__device__ __forceinline__ void ldsm_x2(uint32_t& r0, uint32_t& r1, uint32_t addr) {
    asm volatile("ldmatrix.sync.aligned.m8n8.x2.shared.b16 {%0,%1}, [%2];"
                 : "=r"(r0), "=r"(r1) : "r"(addr));
}

#define CP16(dst, src) \
    asm volatile("cp.async.cg.shared.global [%0], [%1], 16;" :: "r"(dst), "l"(src))
#define CP_COMMIT() asm volatile("cp.async.commit_group;")
#define CP_WAIT0()  asm volatile("cp.async.wait_group 0;")
#define CP_WAIT1()  asm volatile("cp.async.wait_group 1;")

#define SMS 40                      // smem row stride in bf16 (conflict-free, 80B)
#define STG (128 * SMS)             // elements per array
#define STGB (STG * 2)              // bytes per array
#define STAGE4B (4 * STGB)          // bytes per stage (Ahi,Alo,Bhi,Blo)
#define SMEM_BYTES (2 * STAGE4B)    // 81920 bytes

// lane-dependent ldmatrix byte offsets
__device__ __forceinline__ uint32_t ldsm_aoff(int l) {
    return (uint32_t)((((l & 7) + ((l >> 3) & 1) * 8) * SMS + (l >> 4) * 8) * 2);
}
__device__ __forceinline__ uint32_t ldsm_boff(int l) {
    return (uint32_t)(((l & 7) * SMS + ((l >> 3) & 1) * 8) * 2);
}

// issue 8 cp.async: 32B each of Ahi/Alo/Bhi/Blo for this thread's (r,hh) slot
__device__ __forceinline__ void cp_stage4(uint32_t d,
                                          const __nv_bfloat16* ah, const __nv_bfloat16* al,
                                          const __nv_bfloat16* bh, const __nv_bfloat16* bl) {
    CP16(d + 0 * STGB,      ah);     CP16(d + 0 * STGB + 16, ah + 8);
    CP16(d + 1 * STGB,      al);     CP16(d + 1 * STGB + 16, al + 8);
    CP16(d + 2 * STGB,      bh);     CP16(d + 2 * STGB + 16, bh + 8);
    CP16(d + 3 * STGB,      bl);     CP16(d + 3 * STGB + 16, bl + 8);
}
__device__ __forceinline__ void cp_stageA(uint32_t d,
                                          const __nv_bfloat16* ah, const __nv_bfloat16* al) {
    CP16(d + 0 * STGB,      ah);     CP16(d + 0 * STGB + 16, ah + 8);
    CP16(d + 1 * STGB,      al);     CP16(d + 1 * STGB + 16, al + 8);
}

// mma pass over one staged 32-K chunk (low register live-range version)
__device__ __forceinline__ void mma_chunk(uint32_t stb, uint32_t aoff, uint32_t boff,
                                          float acc[4][4][4], int wr, int wc) {
#pragma unroll
    for (int ks = 0; ks < 2; ks++) {
        const uint32_t kb2 = ks * 32;
        uint32_t bhi[4][2], blo[4][2];
#pragma unroll
        for (int ni = 0; ni < 4; ni++) {
            const uint32_t rb = (uint32_t)(wc * 32 + ni * 8) * (SMS * 2) + kb2 + boff;
            ldsm_x2(bhi[ni][0], bhi[ni][1], stb + 2 * STGB + rb);
            ldsm_x2(blo[ni][0], blo[ni][1], stb + 3 * STGB + rb);
        }
#pragma unroll
        for (int mi = 0; mi < 4; mi++) {
            const uint32_t ra = (uint32_t)(wr * 64 + mi * 16) * (SMS * 2) + kb2 + aoff;
            uint32_t ah[4], al[4];
            ldsm_x4(ah[0], ah[1], ah[2], ah[3], stb + ra);
            ldsm_x4(al[0], al[1], al[2], al[3], stb + STGB + ra);
#pragma unroll
            for (int ni = 0; ni < 4; ni++) {
                mma16816(acc[mi][ni], ah[0], ah[1], ah[2], ah[3], bhi[ni][0], bhi[ni][1]);
                mma16816(acc[mi][ni], ah[0], ah[1], ah[2], ah[3], blo[ni][0], blo[ni][1]);
                mma16816(acc[mi][ni], al[0], al[1], al[2], al[3], bhi[ni][0], bhi[ni][1]);
            }
        }
    }
}

// =================================================================================
// gemm_sp: all-pre-split bf16x3 GEMM.  C = A @ B^T (+bias); optional split C out.
// 128x128 tile, 8 warps, cp.async 2-stage, 2 CTAs/SM.
// =================================================================================
__global__ void __launch_bounds__(256, 2) gemm_sp(
    const __nv_bfloat16* __restrict__ Ahi, const __nv_bfloat16* __restrict__ Alo,
    const __nv_bfloat16* __restrict__ Bhi, const __nv_bfloat16* __restrict__ Blo,
    const float* __restrict__ bias,
    float* __restrict__ C, __nv_bfloat16* __restrict__ Chi, __nv_bfloat16* __restrict__ Clo,
    int M, int N, int K)
{
    extern __shared__ __nv_bfloat16 sm[];

    const int t    = threadIdx.x;
    const int m0   = blockIdx.y * 128;
    const int n0   = blockIdx.x * 128;
    const int lane = t & 31;
    const int wid  = t >> 5;
    const int g    = lane >> 2;
    const int tg   = lane & 3;
    const int wr   = wid & 1;
    const int wc   = wid >> 1;

    const uint32_t smb  = (uint32_t)__cvta_generic_to_shared(sm);
    const uint32_t aoff = ldsm_aoff(lane);
    const uint32_t boff = ldsm_boff(lane);

    const int r  = t >> 1;
    const int hh = (t & 1) * 16;
    const uint32_t toff = (uint32_t)(r * SMS + hh) * 2;   // thread smem byte offset
    const __nv_bfloat16* ApH = Ahi + (size_t)(m0 + r) * K + hh;
    const __nv_bfloat16* ApL = Alo + (size_t)(m0 + r) * K + hh;
    const __nv_bfloat16* BpH = Bhi + (size_t)(n0 + r) * K + hh;
    const __nv_bfloat16* BpL = Blo + (size_t)(n0 + r) * K + hh;

    float acc[4][4][4];
#pragma unroll
    for (int mi = 0; mi < 4; mi++)
#pragma unroll
        for (int ni = 0; ni < 4; ni++)
#pragma unroll
            for (int q = 0; q < 4; q++) acc[mi][ni][q] = 0.f;

    cp_stage4(smb + toff, ApH, ApL, BpH, BpL);
    CP_COMMIT();

    for (int k0 = 0; k0 < K; k0 += 32) {
        const int s = (k0 >> 5) & 1;
        const bool more = (k0 + 32 < K);
        if (more) {
            const uint32_t d = smb + (uint32_t)(s ^ 1) * STAGE4B + toff;
            cp_stage4(d, ApH + k0 + 32, ApL + k0 + 32, BpH + k0 + 32, BpL + k0 + 32);
            CP_COMMIT();
            CP_WAIT1();
        } else {
            CP_WAIT0();
        }
        __syncthreads();
        mma_chunk(smb + (uint32_t)s * STAGE4B, aoff, boff, acc, wr, wc);
        __syncthreads();
    }

#pragma unroll
    for (int mi = 0; mi < 4; mi++) {
        const int row = m0 + wr * 64 + mi * 16 + g;
#pragma unroll
        for (int ni = 0; ni < 4; ni++) {
            const int col = n0 + wc * 32 + ni * 8 + tg * 2;
            float b0 = bias ? bias[col] : 0.f;
            float b1 = bias ? bias[col + 1] : 0.f;
            float c00 = acc[mi][ni][0] + b0, c01 = acc[mi][ni][1] + b1;
            float c10 = acc[mi][ni][2] + b0, c11 = acc[mi][ni][3] + b1;
            if (C) {
                *(float2*)&C[(size_t)row * N + col]       = make_float2(c00, c01);
                *(float2*)&C[(size_t)(row + 8) * N + col] = make_float2(c10, c11);
            }
            if (Chi) {
                __nv_bfloat16 h00 = __float2bfloat16(c00), h01 = __float2bfloat16(c01);
                __nv_bfloat16 h10 = __float2bfloat16(c10), h11 = __float2bfloat16(c11);
                *(uint32_t*)&Chi[(size_t)row * N + col]       = pack_bf2(c00, c01);
                *(uint32_t*)&Chi[(size_t)(row + 8) * N + col] = pack_bf2(c10, c11);
                *(uint32_t*)&Clo[(size_t)row * N + col] =
                    pack_bf2(c00 - __bfloat162float(h00), c01 - __bfloat162float(h01));
                *(uint32_t*)&Clo[(size_t)(row + 8) * N + col] =
                    pack_bf2(c10 - __bfloat162float(h10), c11 - __bfloat162float(h11));
            }
        }
    }
}

// =================================================================================
// gemm_mixed: split-A bf16 (cp.async) x fp32-B (in-loop split).  For Wout.
// =================================================================================
__global__ void __launch_bounds__(256, 2) gemm_mixed(
    const __nv_bfloat16* __restrict__ Ahi, const __nv_bfloat16* __restrict__ Alo,
    const float* __restrict__ B, const float* __restrict__ bias,
    float* __restrict__ C, int M, int N, int K)
{
    extern __shared__ __nv_bfloat16 sm[];

    const int t    = threadIdx.x;
    const int m0   = blockIdx.y * 128;
    const int n0   = blockIdx.x * 128;
    const int lane = t & 31;
    const int wid  = t >> 5;
    const int g    = lane >> 2;
    const int tg   = lane & 3;
    const int wr   = wid & 1;
    const int wc   = wid >> 1;

    const uint32_t smb  = (uint32_t)__cvta_generic_to_shared(sm);
    const uint32_t aoff = ldsm_aoff(lane);
    const uint32_t boff = ldsm_boff(lane);

    const int r  = t >> 1;
    const int hh = (t & 1) * 16;
    const uint32_t toff = (uint32_t)(r * SMS + hh) * 2;
    const int idx = r * SMS + hh;
    const __nv_bfloat16* ApH = Ahi + (size_t)(m0 + r) * K + hh;
    const __nv_bfloat16* ApL = Alo + (size_t)(m0 + r) * K + hh;
    const float* Bp = B + (size_t)(n0 + r) * K + hh;

    float acc[4][4][4];
#pragma unroll
    for (int mi = 0; mi < 4; mi++)
#pragma unroll
        for (int ni = 0; ni < 4; ni++)
#pragma unroll
            for (int q = 0; q < 4; q++) acc[mi][ni][q] = 0.f;

    // prologue: A chunk 0 via cp.async; B chunk 0 via regs+split
    cp_stageA(smb + toff, ApH, ApL);
    CP_COMMIT();
    {
        float4 rb[4];
#pragma unroll
        for (int i = 0; i < 4; i++) rb[i] = *(const float4*)(Bp + i * 4);
        __nv_bfloat16* bh = sm + 2 * STG;
        __nv_bfloat16* bl = sm + 3 * STG;
#pragma unroll
        for (int i = 0; i < 4; i++) {
            float x = rb[i].x, y = rb[i].y, z = rb[i].z, w = rb[i].w;
            __nv_bfloat16 hx = __float2bfloat16(x), hy = __float2bfloat16(y);
            __nv_bfloat16 hz = __float2bfloat16(z), hw = __float2bfloat16(w);
            uint2 vh, vl;
            vh.x = pack_bf2(x, y); vh.y = pack_bf2(z, w);
            vl.x = pack_bf2(x - __bfloat162float(hx), y - __bfloat162float(hy));
            vl.y = pack_bf2(z - __bfloat162float(hz), w - __bfloat162float(hw));
            *(uint2*)&bh[idx + i * 4] = vh;
            *(uint2*)&bl[idx + i * 4] = vl;
        }
    }

    for (int k0 = 0; k0 < K; k0 += 32) {
        const int s = (k0 >> 5) & 1;
        const bool more = (k0 + 32 < K);
        float4 rb[4];
        if (more) {
            const uint32_t d = smb + (uint32_t)(s ^ 1) * STAGE4B + toff;
            cp_stageA(d, ApH + k0 + 32, ApL + k0 + 32);
            CP_COMMIT();
#pragma unroll
            for (int i = 0; i < 4; i++) rb[i] = *(const float4*)(Bp + k0 + 32 + i * 4);
            CP_WAIT1();
        } else {
            CP_WAIT0();
        }
        __syncthreads();
        mma_chunk(smb + (uint32_t)s * STAGE4B, aoff, boff, acc, wr, wc);
        if (more) {
            __nv_bfloat16* bh = sm + (s ^ 1) * (STAGE4B / 2) + 2 * STG;
            __nv_bfloat16* bl = sm + (s ^ 1) * (STAGE4B / 2) + 3 * STG;
#pragma unroll
            for (int i = 0; i < 4; i++) {
                float x = rb[i].x, y = rb[i].y, z = rb[i].z, w = rb[i].w;
                __nv_bfloat16 hx = __float2bfloat16(x), hy = __float2bfloat16(y);
                __nv_bfloat16 hz = __float2bfloat16(z), hw = __float2bfloat16(w);
                uint2 vh, vl;
                vh.x = pack_bf2(x, y); vh.y = pack_bf2(z, w);
                vl.x = pack_bf2(x - __bfloat162float(hx), y - __bfloat162float(hy));
                vl.y = pack_bf2(z - __bfloat162float(hz), w - __bfloat162float(hw));
                *(uint2*)&bh[idx + i * 4] = vh;
                *(uint2*)&bl[idx + i * 4] = vl;
            }
        }
        __syncthreads();
    }

#pragma unroll
    for (int mi = 0; mi < 4; mi++) {
        const int row = m0 + wr * 64 + mi * 16 + g;
#pragma unroll
        for (int ni = 0; ni < 4; ni++) {
            const int col = n0 + wc * 32 + ni * 8 + tg * 2;
            float b0 = bias ? bias[col] : 0.f;
            float b1 = bias ? bias[col + 1] : 0.f;
            *(float2*)&C[(size_t)row * N + col] =
                make_float2(acc[mi][ni][0] + b0, acc[mi][ni][1] + b1);
            *(float2*)&C[(size_t)(row + 8) * N + col] =
                make_float2(acc[mi][ni][2] + b0, acc[mi][ni][3] + b1);
        }
    }
}

// =================================================================================
// split: fp32 -> bf16 hi/lo (vectorized)
// =================================================================================
__global__ void split_kernel(const float* __restrict__ W,
                             __nv_bfloat16* __restrict__ hi,
                             __nv_bfloat16* __restrict__ lo, int n4)
{
    const int i = blockIdx.x * blockDim.x + threadIdx.x;
    if (i >= n4) return;
    float4 v = ((const float4*)W)[i];
    __nv_bfloat16 hx = __float2bfloat16(v.x), hy = __float2bfloat16(v.y);
    __nv_bfloat16 hz = __float2bfloat16(v.z), hw = __float2bfloat16(v.w);
    uint2 vh, vl;
    vh.x = pack_bf2(v.x, v.y); vh.y = pack_bf2(v.z, v.w);
    vl.x = pack_bf2(v.x - __bfloat162float(hx), v.y - __bfloat162float(hy));
    vl.y = pack_bf2(v.z - __bfloat162float(hz), v.w - __bfloat162float(hw));
    ((uint2*)hi)[i] = vh;
    ((uint2*)lo)[i] = vl;
}

// =================================================================================
// attention scores, pre-split + cp.async:
//   u[b,n] = sum_k vt[k]*tanh((enc[b]@W1^T)[n,k] + dt[b,k]), mask -> -inf
// =================================================================================
__global__ void __launch_bounds__(256, 2) attn_sp(
    const __nv_bfloat16* __restrict__ encHi, const __nv_bfloat16* __restrict__ encLo,
    const __nv_bfloat16* __restrict__ w1hi,  const __nv_bfloat16* __restrict__ w1lo,
    const float* __restrict__ dt, int ldDT,
    const float* __restrict__ vt,
    const int* __restrict__ mask,
    float* __restrict__ u)
{
    extern __shared__ __nv_bfloat16 sm[];
    __shared__ float s_dt[512];
    __shared__ float s_vt[512];
    __shared__ float s_u[128];

    const int t    = threadIdx.x;
    const int b    = blockIdx.x;
    const int lane = t & 31;
    const int wid  = t >> 5;
    const int g    = lane >> 2;
    const int tg   = lane & 3;
    const int wr   = wid & 1;
    const int wc   = wid >> 1;

    const uint32_t smb  = (uint32_t)__cvta_generic_to_shared(sm);
    const uint32_t aoff = ldsm_aoff(lane);
    const uint32_t boff = ldsm_boff(lane);

    for (int i = t; i < 512; i += 256) {
        s_dt[i] = dt[(size_t)b * ldDT + i];
        s_vt[i] = vt[i];
    }
    if (t < 128) s_u[t] = 0.f;

    const int r  = t >> 1;
    const int hh = (t & 1) * 16;
    const uint32_t toff = (uint32_t)(r * SMS + hh) * 2;
    const __nv_bfloat16* ApH = encHi + (size_t)(b * 128 + r) * 512 + hh;
    const __nv_bfloat16* ApL = encLo + (size_t)(b * 128 + r) * 512 + hh;

    float up[8];
#pragma unroll
    for (int i = 0; i < 8; i++) up[i] = 0.f;

    for (int nc = 0; nc < 4; nc++) {
        const __nv_bfloat16* BpH = w1hi + (size_t)(nc * 128 + r) * 512 + hh;
        const __nv_bfloat16* BpL = w1lo + (size_t)(nc * 128 + r) * 512 + hh;

        float acc[4][4][4];
#pragma unroll
        for (int mi = 0; mi < 4; mi++)
#pragma unroll
            for (int ni = 0; ni < 4; ni++)
#pragma unroll
                for (int q = 0; q < 4; q++) acc[mi][ni][q] = 0.f;

        cp_stage4(smb + toff, ApH, ApL, BpH, BpL);
        CP_COMMIT();

        for (int k0 = 0; k0 < 512; k0 += 32) {
            const int s = (k0 >> 5) & 1;
            const bool more = (k0 + 32 < 512);
            if (more) {
                const uint32_t d = smb + (uint32_t)(s ^ 1) * STAGE4B + toff;
                cp_stage4(d, ApH + k0 + 32, ApL + k0 + 32, BpH + k0 + 32, BpL + k0 + 32);
                CP_COMMIT();
                CP_WAIT1();
            } else {
                CP_WAIT0();
            }
            __syncthreads();
            mma_chunk(smb + (uint32_t)s * STAGE4B, aoff, boff, acc, wr, wc);
            __syncthreads();
        }

#pragma unroll
        for (int mi = 0; mi < 4; mi++)
#pragma unroll
            for (int ni = 0; ni < 4; ni++) {
                const int col = nc * 128 + wc * 32 + ni * 8 + tg * 2;
                const float d0 = s_dt[col], d1 = s_dt[col + 1];
                const float v0 = s_vt[col], v1 = s_vt[col + 1];
                up[mi * 2 + 0] += v0 * tanhf(acc[mi][ni][0] + d0)
                                + v1 * tanhf(acc[mi][ni][1] + d1);
                up[mi * 2 + 1] += v0 * tanhf(acc[mi][ni][2] + d0)
                                + v1 * tanhf(acc[mi][ni][3] + d1);
            }
    }

#pragma unroll
    for (int mi = 0; mi < 4; mi++)
#pragma unroll
        for (int rr = 0; rr < 2; rr++) {
            float v = up[mi * 2 + rr];
            v += __shfl_down_sync(0xffffffffu, v, 1);
            v += __shfl_down_sync(0xffffffffu, v, 2);
            if (tg == 0)
                atomicAdd(&s_u[wr * 64 + mi * 16 + g + rr * 8], v);
        }
    __syncthreads();

    if (t < 128) {
        const int m = b * 128 + t;
        u[m] = (mask[(size_t)b * NN + t] != 0) ? -INFINITY : s_u[t];
    }
}

// =================================================================================
// plan = softmax(prev_h @ plan_W^T + plan_b)
// =================================================================================
__global__ void plan_kernel(const float* __restrict__ prev_h,
                            const float* __restrict__ plan_W,
                            const float* __restrict__ plan_b,
                            float* __restrict__ plan,
                            float* __restrict__ out_plan)
{
    const int b = blockIdx.x;
    const int t = threadIdx.x;
    __shared__ float s0[128], s1[128];
    float a0 = 0.f, a1 = 0.f;
    const float* hb = prev_h + (size_t)b * DD;
    for (int k = t; k < DD; k += 128) {
        const float h = hb[k];
        a0 += h * plan_W[k];
        a1 += h * plan_W[DD + k];
    }
    s0[t] = a0; s1[t] = a1;
    __syncthreads();
    for (int s = 64; s > 0; s >>= 1) {
        if (t < s) { s0[t] += s0[t + s]; s1[t] += s1[t + s]; }
        __syncthreads();
    }
    if (t == 0) {
        const float l0 = s0[0] + plan_b[0];
        const float l1 = s1[0] + plan_b[1];
        const float mx = fmaxf(l0, l1);
        const float e0 = expf(l0 - mx), e1 = expf(l1 - mx);
        const float inv = 1.f / (e0 + e1);
        plan[2 * b] = e0 * inv;       plan[2 * b + 1] = e1 * inv;
        out_plan[2 * b] = e0 * inv;   out_plan[2 * b + 1] = e1 * inv;
    }
}

// =================================================================================
// softmax over u[b,:] then ctx[b,h] = sum_n aw[n]*enc[b,n,h]
// =================================================================================
__global__ void softmax_ctx_kernel(const float* __restrict__ u,
                                   const float* __restrict__ enc,
                                   float* __restrict__ ctx)
{
    const int b = blockIdx.x;
    const int t = threadIdx.x;
    __shared__ float red[256];
    __shared__ float aw[NN];

    const float uv = (t < NN) ? u[(size_t)b * NN + t] : -INFINITY;
    red[t] = uv;
    __syncthreads();
    for (int s = 128; s > 0; s >>= 1) {
        if (t < s) red[t] = fmaxf(red[t], red[t + s]);
        __syncthreads();
    }
    const float mx = red[0];
    __syncthreads();
    const float e = (t < NN) ? expf(uv - mx) : 0.f;
    red[t] = e;
    __syncthreads();
    for (int s = 128; s > 0; s >>= 1) {
        if (t < s) red[t] += red[t + s];
        __syncthreads();
    }
    const float inv = 1.f / red[0];
    if (t < NN) aw[t] = e * inv;
    __syncthreads();

    const float* eb = enc + (size_t)b * NN * HH;
    for (int h = t; h < HH; h += 256) {
        float s = 0.f;
#pragma unroll 4
        for (int n = 0; n < NN; n++)
            s += aw[n] * eb[(size_t)n * HH + h];
        ctx[(size_t)b * HH + h] = s;
    }
}

// =================================================================================
// y_ctx = [prev_y | plan0*ctx_e + plan1*ctx_s], written pre-split
// =================================================================================
__global__ void combine_kernel(const float* __restrict__ prev_y,
                               const float* __restrict__ plan,
                               const float* __restrict__ ctx_e,
                               const float* __restrict__ ctx_s,
                               __nv_bfloat16* __restrict__ ychi,
                               __nv_bfloat16* __restrict__ yclo)
{
    const int idx = blockIdx.x * blockDim.x + threadIdx.x;
    if (idx >= BSZ * YC) return;
    const int b = idx >> 10;
    const int c = idx & 1023;
    float v;
    if (c < EE) {
        v = prev_y[(size_t)b * EE + c];
    } else {
        const float p0 = plan[2 * b], p1 = plan[2 * b + 1];
        const int h = c - EE;
        v = p0 * ctx_e[(size_t)b * HH + h] + p1 * ctx_s[(size_t)b * HH + h];
    }
    __nv_bfloat16 hv = __float2bfloat16(v);
    ychi[idx] = hv;
    yclo[idx] = __float2bfloat16(v - __bfloat162float(hv));
}

// =================================================================================
// GRU cell elementwise; outputs out_hid (fp32) + hn split (bf16 hi/lo)
// =================================================================================
__global__ void gru_kernel(const float* __restrict__ gx,
                           const float* __restrict__ ghbase,   // dtgh+1024, stride NCAT
                           const float* __restrict__ b_hh,
                           const float* __restrict__ prev_h,
                           float* __restrict__ out_hid,
                           __nv_bfloat16* __restrict__ hnhi,
                           __nv_bfloat16* __restrict__ hnlo)
{
    const int idx = blockIdx.x * blockDim.x + threadIdx.x;
    if (idx >= BSZ * DD) return;
    const int b = idx / DD;
    const int d = idx - b * DD;
    const float* gxb = gx + (size_t)b * G3D;
    const float* ghb = ghbase + (size_t)b * NCAT;
    const float ghr = ghb[d]          + b_hh[d];
    const float ghz = ghb[DD + d]     + b_hh[DD + d];
    const float ghn = ghb[2 * DD + d] + b_hh[2 * DD + d];
    const float r = 1.f / (1.f + expf(-(gxb[d] + ghr)));
    const float z = 1.f / (1.f + expf(-(gxb[DD + d] + ghz)));
    const float n = tanhf(gxb[2 * DD + d] + r * ghn);
    const float h = (1.f - z) * n + z * prev_h[idx];
    out_hid[idx] = h;
    __nv_bfloat16 hv = __float2bfloat16(h);
    hnhi[idx] = hv;
    hnlo[idx] = __float2bfloat16(h - __bfloat162float(hv));
}

// =================================================================================
// host launcher — graph-capturable
// =================================================================================
extern "C" void kernel_launch(void* const* d_in, const int* in_sizes, int n_in,
                              void* d_out, int out_size)
{
    const float* prev_y  = (const float*)d_in[0];
    const float* prev_h  = (const float*)d_in[1];
    const float* equ_enc = (const float*)d_in[2];
    const float* sns_enc = (const float*)d_in[3];
    const int* equ_mask = (const int*)d_in[5];
    const int* sns_mask = (const int*)d_in[6];
    const float* W1e    = (const float*)d_in[7];
    const float* W2e    = (const float*)d_in[8];
    const float* vte    = (const float*)d_in[9];
    const float* W1s    = (const float*)d_in[10];
    const float* W2s    = (const float*)d_in[11];
    const float* vts    = (const float*)d_in[12];
    const float* plan_W = (const float*)d_in[13];
    const float* plan_b = (const float*)d_in[14];
    const float* Wc     = (const float*)d_in[15];
    const float* bc     = (const float*)d_in[16];
    const float* w_ih   = (const float*)d_in[17];
    const float* w_hh   = (const float*)d_in[18];
    const float* b_ih   = (const float*)d_in[19];
    const float* b_hh   = (const float*)d_in[20];
    const float* Wout   = (const float*)d_in[21];
    const float* bout   = (const float*)d_in[22];

    float* out      = (float*)d_out;
    float* out_dec  = out;
    float* out_hid  = out + (size_t)BSZ * VV;
    float* out_plan = out + (size_t)BSZ * VV + (size_t)BSZ * DD;

    float *u_e, *u_s, *ctx_e, *ctx_s, *plan, *gx, *dtgh;
    __nv_bfloat16 *ph_hi, *ph_lo, *ee_hi, *ee_lo, *es_hi, *es_lo;
    __nv_bfloat16 *wcat_hi, *wcat_lo, *wc_hi, *wc_lo, *wih_hi, *wih_lo;
    __nv_bfloat16 *w1e_hi, *w1e_lo, *w1s_hi, *w1s_lo;
    __nv_bfloat16 *yc_hi, *yc_lo, *x_hi, *x_lo, *hn_hi, *hn_lo;
    cudaGetSymbolAddress((void**)&u_e,   g_u_e);
    cudaGetSymbolAddress((void**)&u_s,   g_u_s);
    cudaGetSymbolAddress((void**)&ctx_e, g_ctx_e);
    cudaGetSymbolAddress((void**)&ctx_s, g_ctx_s);
    cudaGetSymbolAddress((void**)&plan,  g_plan);
    cudaGetSymbolAddress((void**)&gx,    g_gx);
    cudaGetSymbolAddress((void**)&dtgh,  g_dtgh);
    cudaGetSymbolAddress((void**)&ph_hi, g_ph_hi);  cudaGetSymbolAddress((void**)&ph_lo, g_ph_lo);
    cudaGetSymbolAddress((void**)&ee_hi, g_ee_hi);  cudaGetSymbolAddress((void**)&ee_lo, g_ee_lo);
    cudaGetSymbolAddress((void**)&es_hi, g_es_hi);  cudaGetSymbolAddress((void**)&es_lo, g_es_lo);
    cudaGetSymbolAddress((void**)&wcat_hi, g_wcat_hi); cudaGetSymbolAddress((void**)&wcat_lo, g_wcat_lo);
    cudaGetSymbolAddress((void**)&wc_hi, g_wc_hi);  cudaGetSymbolAddress((void**)&wc_lo, g_wc_lo);
    cudaGetSymbolAddress((void**)&wih_hi, g_wih_hi); cudaGetSymbolAddress((void**)&wih_lo, g_wih_lo);
    cudaGetSymbolAddress((void**)&w1e_hi, g_w1e_hi); cudaGetSymbolAddress((void**)&w1e_lo, g_w1e_lo);
    cudaGetSymbolAddress((void**)&w1s_hi, g_w1s_hi); cudaGetSymbolAddress((void**)&w1s_lo, g_w1s_lo);
    cudaGetSymbolAddress((void**)&yc_hi, g_yc_hi);  cudaGetSymbolAddress((void**)&yc_lo, g_yc_lo);
    cudaGetSymbolAddress((void**)&x_hi,  g_x_hi);   cudaGetSymbolAddress((void**)&x_lo,  g_x_lo);
    cudaGetSymbolAddress((void**)&hn_hi, g_hn_hi);  cudaGetSymbolAddress((void**)&hn_lo, g_hn_lo);

    cudaFuncSetAttribute(gemm_sp,    cudaFuncAttributeMaxDynamicSharedMemorySize, SMEM_BYTES);
    cudaFuncSetAttribute(gemm_mixed, cudaFuncAttributeMaxDynamicSharedMemorySize, SMEM_BYTES);
    cudaFuncSetAttribute(attn_sp,    cudaFuncAttributeMaxDynamicSharedMemorySize, SMEM_BYTES);

    const dim3 blk(256);

    // ---- pre-splits ----
    split_kernel<<<(BSZ * DD / 4 + 255) / 256, blk>>>(prev_h, ph_hi, ph_lo, BSZ * DD / 4);
    split_kernel<<<(HH * DD / 4 + 255) / 256, blk>>>(W2e,  wcat_hi,               wcat_lo,               HH * DD / 4);
    split_kernel<<<(HH * DD / 4 + 255) / 256, blk>>>(W2s,  wcat_hi + (size_t)HH * DD,  wcat_lo + (size_t)HH * DD,  HH * DD / 4);
    split_kernel<<<(G3D * DD / 4 + 255) / 256, blk>>>(w_hh, wcat_hi + (size_t)2 * HH * DD, wcat_lo + (size_t)2 * HH * DD, G3D * DD / 4);
    split_kernel<<<(HH * YC / 4 + 255) / 256, blk>>>(Wc,   wc_hi,  wc_lo,  HH * YC / 4);
    split_kernel<<<(G3D * HH / 4 + 255) / 256, blk>>>(w_ih, wih_hi, wih_lo, G3D * HH / 4);
    split_kernel<<<(HH * HH / 4 + 255) / 256, blk>>>(W1e,  w1e_hi, w1e_lo, HH * HH / 4);
    split_kernel<<<(HH * HH / 4 + 255) / 256, blk>>>(W1s,  w1s_hi, w1s_lo, HH * HH / 4);
    split_kernel<<<(BSZ * NN * HH / 4 + 255) / 256, blk>>>(equ_enc, ee_hi, ee_lo, BSZ * NN * HH / 4);
    split_kernel<<<(BSZ * NN * HH / 4 + 255) / 256, blk>>>(sns_enc, es_hi, es_lo, BSZ * NN * HH / 4);

    // fused [dt_e | dt_s | gh] = prev_h @ Wcat^T
    gemm_sp<<<dim3(NCAT / 128, BSZ / 128), blk, SMEM_BYTES>>>(
        ph_hi, ph_lo, wcat_hi, wcat_lo, nullptr, dtgh, nullptr, nullptr, BSZ, NCAT, DD);

    plan_kernel<<<BSZ, 128>>>(prev_h, plan_W, plan_b, plan, out_plan);

    // attention scores
    attn_sp<<<BSZ, blk, SMEM_BYTES>>>(ee_hi, ee_lo, w1e_hi, w1e_lo, dtgh,      NCAT, vte, equ_mask, u_e);
    attn_sp<<<BSZ, blk, SMEM_BYTES>>>(es_hi, es_lo, w1s_hi, w1s_lo, dtgh + HH, NCAT, vts, sns_mask, u_s);

    softmax_ctx_kernel<<<BSZ, blk>>>(u_e, equ_enc, ctx_e);
    softmax_ctx_kernel<<<BSZ, blk>>>(u_s, sns_enc, ctx_s);

    combine_kernel<<<(BSZ * YC) / 256, blk>>>(prev_y, plan, ctx_e, ctx_s, yc_hi, yc_lo);

    // x = y_ctx @ Wc^T + bc  (split-only output) ; gx = x @ w_ih^T + b_ih
    gemm_sp<<<dim3(HH / 128, BSZ / 128), blk, SMEM_BYTES>>>(
        yc_hi, yc_lo, wc_hi, wc_lo, bc, nullptr, x_hi, x_lo, BSZ, HH, YC);
    gemm_sp<<<dim3(G3D / 128, BSZ / 128), blk, SMEM_BYTES>>>(
        x_hi, x_lo, wih_hi, wih_lo, b_ih, gx, nullptr, nullptr, BSZ, G3D, HH);

    gru_kernel<<<(BSZ * DD) / 256, blk>>>(gx, dtgh + 2 * HH, b_hh, prev_h, out_hid, hn_hi, hn_lo);

    // dec_output = h_new @ Wout^T + bout
    gemm_mixed<<<dim3(VV / 128, BSZ / 128), blk, SMEM_BYTES>>>(
        hn_hi, hn_lo, Wout, bout, out_dec, BSZ, VV, DD);
}

// round 7
// speedup vs baseline: 2.6729x; 1.1702x over previous
#include <cuda_runtime.h>
#include <cuda_bf16.h>
#include <math.h>
#include <stdint.h>

#define HH   512
#define ZZ   128
#define EE   512
#define DD   1152      // 2H + Z
#define VV   32000
#define BSZ  256
#define NN   128
#define G3D  3456      // 3*D
#define NCAT 4480      // 512 (dt_e) + 512 (dt_s) + 3456 (gh)
#define YC   1024      // E + H

// ---------------- scratch (device globals; no allocation allowed) ----------------
__device__ float g_u_e  [BSZ * NN];
__device__ float g_u_s  [BSZ * NN];
__device__ float g_ctx_e[BSZ * HH];
__device__ float g_ctx_s[BSZ * HH];
__device__ float g_plan [BSZ * 2];
__device__ float g_gx   [BSZ * G3D];
__device__ float g_dtgh [BSZ * NCAT];  // [0,512) dt_e | [512,1024) dt_s | [1024,4480) gh
__device__ int   g_offE [BSZ];
__device__ int   g_offS [BSZ];
__device__ int   g_rowE [BSZ * NN];    // compacted row -> b*128+n
__device__ int   g_rowS [BSZ * NN];
__device__ int   g_mtot [2];           // [0]=equ count, [1]=sns count

// pre-split bf16 hi/lo operands (16B-aligned for cp.async / ldmatrix)
__device__ __align__(256) __nv_bfloat16 g_ph_hi [BSZ * DD];
__device__ __align__(256) __nv_bfloat16 g_ph_lo [BSZ * DD];
__device__ __align__(256) __nv_bfloat16 g_ee_hi [BSZ * NN * HH];   // gathered (compacted)
__device__ __align__(256) __nv_bfloat16 g_ee_lo [BSZ * NN * HH];
__device__ __align__(256) __nv_bfloat16 g_es_hi [BSZ * NN * HH];
__device__ __align__(256) __nv_bfloat16 g_es_lo [BSZ * NN * HH];
__device__ __align__(256) __nv_bfloat16 g_wcat_hi[NCAT * DD];
__device__ __align__(256) __nv_bfloat16 g_wcat_lo[NCAT * DD];
__device__ __align__(256) __nv_bfloat16 g_wc_hi [HH * YC];
__device__ __align__(256) __nv_bfloat16 g_wc_lo [HH * YC];
__device__ __align__(256) __nv_bfloat16 g_wih_hi[G3D * HH];
__device__ __align__(256) __nv_bfloat16 g_wih_lo[G3D * HH];
__device__ __align__(256) __nv_bfloat16 g_w1e_hi[HH * HH];
__device__ __align__(256) __nv_bfloat16 g_w1e_lo[HH * HH];
__device__ __align__(256) __nv_bfloat16 g_w1s_hi[HH * HH];
__device__ __align__(256) __nv_bfloat16 g_w1s_lo[HH * HH];
__device__ __align__(256) __nv_bfloat16 g_yc_hi [BSZ * YC];
__device__ __align__(256) __nv_bfloat16 g_yc_lo [BSZ * YC];
__device__ __align__(256) __nv_bfloat16 g_x_hi  [BSZ * HH];
__device__ __align__(256) __nv_bfloat16 g_x_lo  [BSZ * HH];
__device__ __align__(256) __nv_bfloat16 g_hn_hi [BSZ * DD];
__device__ __align__(256) __nv_bfloat16 g_hn_lo [BSZ * DD];

// ---------------- helpers ----------------
__device__ __forceinline__ uint32_t pack_bf2(float a, float b) {
    __nv_bfloat162 t = __floats2bfloat162_rn(a, b);
    return *reinterpret_cast<uint32_t*>(&t);
}

__device__ __forceinline__ void mma16816(float c[4],
                                         uint32_t a0, uint32_t a1, uint32_t a2, uint32_t a3,
                                         uint32_t b0, uint32_t b1) {
    asm volatile(
        "mma.sync.aligned.m16n8k16.row.col.f32.bf16.bf16.f32 "
        "{%0,%1,%2,%3}, {%4,%5,%6,%7}, {%8,%9}, {%0,%1,%2,%3};\n"
        : "+f"(c[0]), "+f"(c[1]), "+f"(c[2]), "+f"(c[3])
        : "r"(a0), "r"(a1), "r"(a2), "r"(a3), "r"(b0), "r"(b1));
}

__device__ __forceinline__ void ldsm_x4(uint32_t& r0, uint32_t& r1, uint32_t& r2, uint32_t& r3,
                                        uint32_t addr) {
    asm volatile("ldmatrix.sync.aligned.m8n8.x4.shared.b16 {%0,%1,%2,%3}, [%4];"
                 : "=r"(r0), "=r"(r1), "=r"(r2), "=r"(r3) : "r"(addr));
}
__device__ __forceinline__ void ldsm_x2(uint32_t& r0, uint32_t& r1, uint32_t addr) {
    asm volatile("ldmatrix.sync.aligned.m8n8.x2.shared.b16 {%0,%1}, [%2];"
                 : "=r"(r0), "=r"(r1) : "r"(addr));
}

#define CP16(dst, src) \
    asm volatile("cp.async.cg.shared.global [%0], [%1], 16;" :: "r"(dst), "l"(src))
#define CP_COMMIT() asm volatile("cp.async.commit_group;")
#define CP_WAIT0()  asm volatile("cp.async.wait_group 0;")
#define CP_WAIT1()  asm volatile("cp.async.wait_group 1;")

#define SMS 40                      // smem row stride in bf16 (conflict-free, 80B)
#define STG (128 * SMS)             // elements per array
#define STGB (STG * 2)              // bytes per array
#define STAGE4B (4 * STGB)          // bytes per stage (Ahi,Alo,Bhi,Blo)
#define SMEM_BYTES (2 * STAGE4B)    // 81920 bytes

// lane-dependent ldmatrix byte offsets
__device__ __forceinline__ uint32_t ldsm_aoff(int l) {
    return (uint32_t)((((l & 7) + ((l >> 3) & 1) * 8) * SMS + (l >> 4) * 8) * 2);
}
__device__ __forceinline__ uint32_t ldsm_boff(int l) {
    return (uint32_t)(((l & 7) * SMS + ((l >> 3) & 1) * 8) * 2);
}

__device__ __forceinline__ void cp_stage4(uint32_t d,
                                          const __nv_bfloat16* ah, const __nv_bfloat16* al,
                                          const __nv_bfloat16* bh, const __nv_bfloat16* bl) {
    CP16(d + 0 * STGB,      ah);     CP16(d + 0 * STGB + 16, ah + 8);
    CP16(d + 1 * STGB,      al);     CP16(d + 1 * STGB + 16, al + 8);
    CP16(d + 2 * STGB,      bh);     CP16(d + 2 * STGB + 16, bh + 8);
    CP16(d + 3 * STGB,      bl);     CP16(d + 3 * STGB + 16, bl + 8);
}
__device__ __forceinline__ void cp_stageA(uint32_t d,
                                          const __nv_bfloat16* ah, const __nv_bfloat16* al) {
    CP16(d + 0 * STGB,      ah);     CP16(d + 0 * STGB + 16, ah + 8);
    CP16(d + 1 * STGB,      al);     CP16(d + 1 * STGB + 16, al + 8);
}

// mma pass over one staged 32-K chunk
__device__ __forceinline__ void mma_chunk(uint32_t stb, uint32_t aoff, uint32_t boff,
                                          float acc[4][4][4], int wr, int wc) {
#pragma unroll
    for (int ks = 0; ks < 2; ks++) {
        const uint32_t kb2 = ks * 32;
        uint32_t bhi[4][2], blo[4][2];
#pragma unroll
        for (int ni = 0; ni < 4; ni++) {
            const uint32_t rb = (uint32_t)(wc * 32 + ni * 8) * (SMS * 2) + kb2 + boff;
            ldsm_x2(bhi[ni][0], bhi[ni][1], stb + 2 * STGB + rb);
            ldsm_x2(blo[ni][0], blo[ni][1], stb + 3 * STGB + rb);
        }
#pragma unroll
        for (int mi = 0; mi < 4; mi++) {
            const uint32_t ra = (uint32_t)(wr * 64 + mi * 16) * (SMS * 2) + kb2 + aoff;
            uint32_t ah[4], al[4];
            ldsm_x4(ah[0], ah[1], ah[2], ah[3], stb + ra);
            ldsm_x4(al[0], al[1], al[2], al[3], stb + STGB + ra);
#pragma unroll
            for (int ni = 0; ni < 4; ni++) {
                mma16816(acc[mi][ni], ah[0], ah[1], ah[2], ah[3], bhi[ni][0], bhi[ni][1]);
                mma16816(acc[mi][ni], ah[0], ah[1], ah[2], ah[3], blo[ni][0], blo[ni][1]);
                mma16816(acc[mi][ni], al[0], al[1], al[2], al[3], bhi[ni][0], bhi[ni][1]);
            }
        }
    }
}

// =================================================================================
// gemm_sp: all-pre-split bf16x3 GEMM.  C = A @ B^T (+bias); optional split C out.
// =================================================================================
__global__ void __launch_bounds__(256, 2) gemm_sp(
    const __nv_bfloat16* __restrict__ Ahi, const __nv_bfloat16* __restrict__ Alo,
    const __nv_bfloat16* __restrict__ Bhi, const __nv_bfloat16* __restrict__ Blo,
    const float* __restrict__ bias,
    float* __restrict__ C, __nv_bfloat16* __restrict__ Chi, __nv_bfloat16* __restrict__ Clo,
    int M, int N, int K)
{
    extern __shared__ __nv_bfloat16 sm[];

    const int t    = threadIdx.x;
    const int m0   = blockIdx.y * 128;
    const int n0   = blockIdx.x * 128;
    const int lane = t & 31;
    const int wid  = t >> 5;
    const int g    = lane >> 2;
    const int tg   = lane & 3;
    const int wr   = wid & 1;
    const int wc   = wid >> 1;

    const uint32_t smb  = (uint32_t)__cvta_generic_to_shared(sm);
    const uint32_t aoff = ldsm_aoff(lane);
    const uint32_t boff = ldsm_boff(lane);

    const int r  = t >> 1;
    const int hh = (t & 1) * 16;
    const uint32_t toff = (uint32_t)(r * SMS + hh) * 2;
    const __nv_bfloat16* ApH = Ahi + (size_t)(m0 + r) * K + hh;
    const __nv_bfloat16* ApL = Alo + (size_t)(m0 + r) * K + hh;
    const __nv_bfloat16* BpH = Bhi + (size_t)(n0 + r) * K + hh;
    const __nv_bfloat16* BpL = Blo + (size_t)(n0 + r) * K + hh;

    float acc[4][4][4];
#pragma unroll
    for (int mi = 0; mi < 4; mi++)
#pragma unroll
        for (int ni = 0; ni < 4; ni++)
#pragma unroll
            for (int q = 0; q < 4; q++) acc[mi][ni][q] = 0.f;

    cp_stage4(smb + toff, ApH, ApL, BpH, BpL);
    CP_COMMIT();

    for (int k0 = 0; k0 < K; k0 += 32) {
        const int s = (k0 >> 5) & 1;
        const bool more = (k0 + 32 < K);
        if (more) {
            const uint32_t d = smb + (uint32_t)(s ^ 1) * STAGE4B + toff;
            cp_stage4(d, ApH + k0 + 32, ApL + k0 + 32, BpH + k0 + 32, BpL + k0 + 32);
            CP_COMMIT();
            CP_WAIT1();
        } else {
            CP_WAIT0();
        }
        __syncthreads();
        mma_chunk(smb + (uint32_t)s * STAGE4B, aoff, boff, acc, wr, wc);
        __syncthreads();
    }

#pragma unroll
    for (int mi = 0; mi < 4; mi++) {
        const int row = m0 + wr * 64 + mi * 16 + g;
#pragma unroll
        for (int ni = 0; ni < 4; ni++) {
            const int col = n0 + wc * 32 + ni * 8 + tg * 2;
            float b0 = bias ? bias[col] : 0.f;
            float b1 = bias ? bias[col + 1] : 0.f;
            float c00 = acc[mi][ni][0] + b0, c01 = acc[mi][ni][1] + b1;
            float c10 = acc[mi][ni][2] + b0, c11 = acc[mi][ni][3] + b1;
            if (C) {
                *(float2*)&C[(size_t)row * N + col]       = make_float2(c00, c01);
                *(float2*)&C[(size_t)(row + 8) * N + col] = make_float2(c10, c11);
            }
            if (Chi) {
                __nv_bfloat16 h00 = __float2bfloat16(c00), h01 = __float2bfloat16(c01);
                __nv_bfloat16 h10 = __float2bfloat16(c10), h11 = __float2bfloat16(c11);
                *(uint32_t*)&Chi[(size_t)row * N + col]       = pack_bf2(c00, c01);
                *(uint32_t*)&Chi[(size_t)(row + 8) * N + col] = pack_bf2(c10, c11);
                *(uint32_t*)&Clo[(size_t)row * N + col] =
                    pack_bf2(c00 - __bfloat162float(h00), c01 - __bfloat162float(h01));
                *(uint32_t*)&Clo[(size_t)(row + 8) * N + col] =
                    pack_bf2(c10 - __bfloat162float(h10), c11 - __bfloat162float(h11));
            }
        }
    }
}

// =================================================================================
// gemm_mixed: split-A bf16 (cp.async) x fp32-B (in-loop split).  For Wout.
// =================================================================================
__global__ void __launch_bounds__(256, 2) gemm_mixed(
    const __nv_bfloat16* __restrict__ Ahi, const __nv_bfloat16* __restrict__ Alo,
    const float* __restrict__ B, const float* __restrict__ bias,
    float* __restrict__ C, int M, int N, int K)
{
    extern __shared__ __nv_bfloat16 sm[];

    const int t    = threadIdx.x;
    const int m0   = blockIdx.y * 128;
    const int n0   = blockIdx.x * 128;
    const int lane = t & 31;
    const int wid  = t >> 5;
    const int g    = lane >> 2;
    const int tg   = lane & 3;
    const int wr   = wid & 1;
    const int wc   = wid >> 1;

    const uint32_t smb  = (uint32_t)__cvta_generic_to_shared(sm);
    const uint32_t aoff = ldsm_aoff(lane);
    const uint32_t boff = ldsm_boff(lane);

    const int r  = t >> 1;
    const int hh = (t & 1) * 16;
    const uint32_t toff = (uint32_t)(r * SMS + hh) * 2;
    const int idx = r * SMS + hh;
    const __nv_bfloat16* ApH = Ahi + (size_t)(m0 + r) * K + hh;
    const __nv_bfloat16* ApL = Alo + (size_t)(m0 + r) * K + hh;
    const float* Bp = B + (size_t)(n0 + r) * K + hh;

    float acc[4][4][4];
#pragma unroll
    for (int mi = 0; mi < 4; mi++)
#pragma unroll
        for (int ni = 0; ni < 4; ni++)
#pragma unroll
            for (int q = 0; q < 4; q++) acc[mi][ni][q] = 0.f;

    cp_stageA(smb + toff, ApH, ApL);
    CP_COMMIT();
    {
        float4 rb[4];
#pragma unroll
        for (int i = 0; i < 4; i++) rb[i] = *(const float4*)(Bp + i * 4);
        __nv_bfloat16* bh = sm + 2 * STG;
        __nv_bfloat16* bl = sm + 3 * STG;
#pragma unroll
        for (int i = 0; i < 4; i++) {
            float x = rb[i].x, y = rb[i].y, z = rb[i].z, w = rb[i].w;
            __nv_bfloat16 hx = __float2bfloat16(x), hy = __float2bfloat16(y);
            __nv_bfloat16 hz = __float2bfloat16(z), hw = __float2bfloat16(w);
            uint2 vh, vl;
            vh.x = pack_bf2(x, y); vh.y = pack_bf2(z, w);
            vl.x = pack_bf2(x - __bfloat162float(hx), y - __bfloat162float(hy));
            vl.y = pack_bf2(z - __bfloat162float(hz), w - __bfloat162float(hw));
            *(uint2*)&bh[idx + i * 4] = vh;
            *(uint2*)&bl[idx + i * 4] = vl;
        }
    }

    for (int k0 = 0; k0 < K; k0 += 32) {
        const int s = (k0 >> 5) & 1;
        const bool more = (k0 + 32 < K);
        float4 rb[4];
        if (more) {
            const uint32_t d = smb + (uint32_t)(s ^ 1) * STAGE4B + toff;
            cp_stageA(d, ApH + k0 + 32, ApL + k0 + 32);
            CP_COMMIT();
#pragma unroll
            for (int i = 0; i < 4; i++) rb[i] = *(const float4*)(Bp + k0 + 32 + i * 4);
            CP_WAIT1();
        } else {
            CP_WAIT0();
        }
        __syncthreads();
        mma_chunk(smb + (uint32_t)s * STAGE4B, aoff, boff, acc, wr, wc);
        if (more) {
            __nv_bfloat16* bh = sm + (s ^ 1) * (STAGE4B / 2) + 2 * STG;
            __nv_bfloat16* bl = sm + (s ^ 1) * (STAGE4B / 2) + 3 * STG;
#pragma unroll
            for (int i = 0; i < 4; i++) {
                float x = rb[i].x, y = rb[i].y, z = rb[i].z, w = rb[i].w;
                __nv_bfloat16 hx = __float2bfloat16(x), hy = __float2bfloat16(y);
                __nv_bfloat16 hz = __float2bfloat16(z), hw = __float2bfloat16(w);
                uint2 vh, vl;
                vh.x = pack_bf2(x, y); vh.y = pack_bf2(z, w);
                vl.x = pack_bf2(x - __bfloat162float(hx), y - __bfloat162float(hy));
                vl.y = pack_bf2(z - __bfloat162float(hz), w - __bfloat162float(hw));
                *(uint2*)&bh[idx + i * 4] = vh;
                *(uint2*)&bl[idx + i * 4] = vl;
            }
        }
        __syncthreads();
    }

#pragma unroll
    for (int mi = 0; mi < 4; mi++) {
        const int row = m0 + wr * 64 + mi * 16 + g;
#pragma unroll
        for (int ni = 0; ni < 4; ni++) {
            const int col = n0 + wc * 32 + ni * 8 + tg * 2;
            float b0 = bias ? bias[col] : 0.f;
            float b1 = bias ? bias[col + 1] : 0.f;
            *(float2*)&C[(size_t)row * N + col] =
                make_float2(acc[mi][ni][0] + b0, acc[mi][ni][1] + b1);
            *(float2*)&C[(size_t)(row + 8) * N + col] =
                make_float2(acc[mi][ni][2] + b0, acc[mi][ni][3] + b1);
        }
    }
}

// =================================================================================
// split: fp32 -> bf16 hi/lo (vectorized)
// =================================================================================
__global__ void split_kernel(const float* __restrict__ W,
                             __nv_bfloat16* __restrict__ hi,
                             __nv_bfloat16* __restrict__ lo, int n4)
{
    const int i = blockIdx.x * blockDim.x + threadIdx.x;
    if (i >= n4) return;
    float4 v = ((const float4*)W)[i];
    __nv_bfloat16 hx = __float2bfloat16(v.x), hy = __float2bfloat16(v.y);
    __nv_bfloat16 hz = __float2bfloat16(v.z), hw = __float2bfloat16(v.w);
    uint2 vh, vl;
    vh.x = pack_bf2(v.x, v.y); vh.y = pack_bf2(v.z, v.w);
    vl.x = pack_bf2(v.x - __bfloat162float(hx), v.y - __bfloat162float(hy));
    vl.y = pack_bf2(v.z - __bfloat162float(hz), v.w - __bfloat162float(hw));
    ((uint2*)hi)[i] = vh;
    ((uint2*)lo)[i] = vl;
}

// =================================================================================
// compact: per-batch exclusive offsets of unmasked positions (both masks)
// =================================================================================
__global__ void compact_kernel(const int* __restrict__ mE, const int* __restrict__ mS,
                               int* __restrict__ offE, int* __restrict__ offS,
                               int* __restrict__ mtot)
{
    __shared__ int sE[256], sS[256];
    const int b = threadIdx.x;
    int cE = 0, cS = 0;
    for (int n = 0; n < NN; n++) {
        cE += (mE[b * NN + n] == 0);
        cS += (mS[b * NN + n] == 0);
    }
    sE[b] = cE; sS[b] = cS;
    __syncthreads();
    for (int d = 1; d < 256; d <<= 1) {
        int vE = 0, vS = 0;
        if (b >= d) { vE = sE[b - d]; vS = sS[b - d]; }
        __syncthreads();
        sE[b] += vE; sS[b] += vS;
        __syncthreads();
    }
    offE[b] = sE[b] - cE;
    offS[b] = sS[b] - cS;
    if (b == 255) { mtot[0] = sE[255]; mtot[1] = sS[255]; }
}

// =================================================================================
// gather: compact unmasked enc rows (split to bf16 hi/lo), record rowinfo,
//         write u = -inf at masked positions.
// =================================================================================
__global__ void gather_kernel(const float* __restrict__ enc,
                              const int* __restrict__ mask,
                              const int* __restrict__ off,
                              __nv_bfloat16* __restrict__ ghi,
                              __nv_bfloat16* __restrict__ glo,
                              int* __restrict__ rowinfo,
                              float* __restrict__ u)
{
    __shared__ int s_list[NN];
    __shared__ int s_wtot[8];
    const int b = blockIdx.x;
    const int t = threadIdx.x;
    const int base = off[b];
    const bool in = t < NN;
    const bool valid = in && (mask[b * NN + t] == 0);
    const unsigned wm = __ballot_sync(0xffffffffu, valid);
    const int lane = t & 31, w = t >> 5;
    if (lane == 0) s_wtot[w] = __popc(wm);
    __syncthreads();
    int wbase = 0;
#pragma unroll
    for (int i = 0; i < 4; i++) if (i < w) wbase += s_wtot[i];
    const int rank = wbase + __popc(wm & ((1u << lane) - 1));
    if (valid) {
        s_list[rank] = t;
        rowinfo[base + rank] = b * NN + t;
    } else if (in) {
        u[b * NN + t] = -INFINITY;
    }
    __syncthreads();
    const int cnt = s_wtot[0] + s_wtot[1] + s_wtot[2] + s_wtot[3];

    for (int i = 0; i < cnt; i++) {
        const int n = s_list[i];
        const float2 v = *(const float2*)(enc + ((size_t)b * NN + n) * HH + t * 2);
        __nv_bfloat16 h0 = __float2bfloat16(v.x), h1 = __float2bfloat16(v.y);
        *(uint32_t*)&ghi[((size_t)base + i) * HH + t * 2] = pack_bf2(v.x, v.y);
        *(uint32_t*)&glo[((size_t)base + i) * HH + t * 2] =
            pack_bf2(v.x - __bfloat162float(h0), v.y - __bfloat162float(h1));
    }
}

// =================================================================================
// attention scores over COMPACTED rows:
//   u[rowinfo[m]] = sum_k vt[k]*tanh((enc_row[m]@W1^T)[k] + dt[b(m),k])
// =================================================================================
__global__ void __launch_bounds__(256, 2) attn_cmp(
    const __nv_bfloat16* __restrict__ gehi, const __nv_bfloat16* __restrict__ gelo,
    const __nv_bfloat16* __restrict__ w1hi, const __nv_bfloat16* __restrict__ w1lo,
    const float* __restrict__ dt, int ldDT,
    const float* __restrict__ vt,
    const int* __restrict__ rowinfo,
    const int* __restrict__ mtotp, int which,
    float* __restrict__ u)
{
    extern __shared__ __nv_bfloat16 sm[];
    __shared__ float s_vt[512];
    __shared__ float s_u[128];

    const int mtot = mtotp[which];
    const int m0 = blockIdx.x * 128;
    if (m0 >= mtot) return;

    const int t    = threadIdx.x;
    const int lane = t & 31;
    const int wid  = t >> 5;
    const int g    = lane >> 2;
    const int tg   = lane & 3;
    const int wr   = wid & 1;
    const int wc   = wid >> 1;

    const uint32_t smb  = (uint32_t)__cvta_generic_to_shared(sm);
    const uint32_t aoff = ldsm_aoff(lane);
    const uint32_t boff = ldsm_boff(lane);

    for (int i = t; i < 512; i += 256) s_vt[i] = vt[i];
    if (t < 128) s_u[t] = 0.f;

    // batch index per accumulator row (rows beyond mtot read stale/zero rowinfo -> b=0, discarded)
    int rb4[4][2];
#pragma unroll
    for (int mi = 0; mi < 4; mi++)
#pragma unroll
        for (int rr = 0; rr < 2; rr++)
            rb4[mi][rr] = rowinfo[m0 + wr * 64 + mi * 16 + g + rr * 8] >> 7;

    const int r  = t >> 1;
    const int hh = (t & 1) * 16;
    const uint32_t toff = (uint32_t)(r * SMS + hh) * 2;
    const __nv_bfloat16* ApH = gehi + (size_t)(m0 + r) * 512 + hh;
    const __nv_bfloat16* ApL = gelo + (size_t)(m0 + r) * 512 + hh;

    float up[8];
#pragma unroll
    for (int i = 0; i < 8; i++) up[i] = 0.f;

    for (int nc = 0; nc < 4; nc++) {
        const __nv_bfloat16* BpH = w1hi + (size_t)(nc * 128 + r) * 512 + hh;
        const __nv_bfloat16* BpL = w1lo + (size_t)(nc * 128 + r) * 512 + hh;

        float acc[4][4][4];
#pragma unroll
        for (int mi = 0; mi < 4; mi++)
#pragma unroll
            for (int ni = 0; ni < 4; ni++)
#pragma unroll
                for (int q = 0; q < 4; q++) acc[mi][ni][q] = 0.f;

        cp_stage4(smb + toff, ApH, ApL, BpH, BpL);
        CP_COMMIT();

        for (int k0 = 0; k0 < 512; k0 += 32) {
            const int s = (k0 >> 5) & 1;
            const bool more = (k0 + 32 < 512);
            if (more) {
                const uint32_t d = smb + (uint32_t)(s ^ 1) * STAGE4B + toff;
                cp_stage4(d, ApH + k0 + 32, ApL + k0 + 32, BpH + k0 + 32, BpL + k0 + 32);
                CP_COMMIT();
                CP_WAIT1();
            } else {
                CP_WAIT0();
            }
            __syncthreads();
            mma_chunk(smb + (uint32_t)s * STAGE4B, aoff, boff, acc, wr, wc);
            __syncthreads();
        }

#pragma unroll
        for (int mi = 0; mi < 4; mi++) {
            const float* dt0 = dt + (size_t)rb4[mi][0] * ldDT;
            const float* dt1 = dt + (size_t)rb4[mi][1] * ldDT;
#pragma unroll
            for (int ni = 0; ni < 4; ni++) {
                const int col = nc * 128 + wc * 32 + ni * 8 + tg * 2;
                const float v0 = s_vt[col], v1 = s_vt[col + 1];
                up[mi * 2 + 0] += v0 * tanhf(acc[mi][ni][0] + dt0[col])
                                + v1 * tanhf(acc[mi][ni][1] + dt0[col + 1]);
                up[mi * 2 + 1] += v0 * tanhf(acc[mi][ni][2] + dt1[col])
                                + v1 * tanhf(acc[mi][ni][3] + dt1[col + 1]);
            }
        }
    }

#pragma unroll
    for (int mi = 0; mi < 4; mi++)
#pragma unroll
        for (int rr = 0; rr < 2; rr++) {
            float v = up[mi * 2 + rr];
            v += __shfl_down_sync(0xffffffffu, v, 1);
            v += __shfl_down_sync(0xffffffffu, v, 2);
            if (tg == 0)
                atomicAdd(&s_u[wr * 64 + mi * 16 + g + rr * 8], v);
        }
    __syncthreads();

    if (t < 128 && m0 + t < mtot)
        u[rowinfo[m0 + t]] = s_u[t];
}

// =================================================================================
// plan = softmax(prev_h @ plan_W^T + plan_b)
// =================================================================================
__global__ void plan_kernel(const float* __restrict__ prev_h,
                            const float* __restrict__ plan_W,
                            const float* __restrict__ plan_b,
                            float* __restrict__ plan,
                            float* __restrict__ out_plan)
{
    const int b = blockIdx.x;
    const int t = threadIdx.x;
    __shared__ float s0[128], s1[128];
    float a0 = 0.f, a1 = 0.f;
    const float* hb = prev_h + (size_t)b * DD;
    for (int k = t; k < DD; k += 128) {
        const float h = hb[k];
        a0 += h * plan_W[k];
        a1 += h * plan_W[DD + k];
    }
    s0[t] = a0; s1[t] = a1;
    __syncthreads();
    for (int s = 64; s > 0; s >>= 1) {
        if (t < s) { s0[t] += s0[t + s]; s1[t] += s1[t + s]; }
        __syncthreads();
    }
    if (t == 0) {
        const float l0 = s0[0] + plan_b[0];
        const float l1 = s1[0] + plan_b[1];
        const float mx = fmaxf(l0, l1);
        const float e0 = expf(l0 - mx), e1 = expf(l1 - mx);
        const float inv = 1.f / (e0 + e1);
        plan[2 * b] = e0 * inv;       plan[2 * b + 1] = e1 * inv;
        out_plan[2 * b] = e0 * inv;   out_plan[2 * b + 1] = e1 * inv;
    }
}

// =================================================================================
// softmax over u[b,:] then ctx[b,h] = sum_n aw[n]*enc[b,n,h]
// =================================================================================
__global__ void softmax_ctx_kernel(const float* __restrict__ u,
                                   const float* __restrict__ enc,
                                   float* __restrict__ ctx)
{
    const int b = blockIdx.x;
    const int t = threadIdx.x;
    __shared__ float red[256];
    __shared__ float aw[NN];

    const float uv = (t < NN) ? u[(size_t)b * NN + t] : -INFINITY;
    red[t] = uv;
    __syncthreads();
    for (int s = 128; s > 0; s >>= 1) {
        if (t < s) red[t] = fmaxf(red[t], red[t + s]);
        __syncthreads();
    }
    const float mx = red[0];
    __syncthreads();
    const float e = (t < NN) ? expf(uv - mx) : 0.f;
    red[t] = e;
    __syncthreads();
    for (int s = 128; s > 0; s >>= 1) {
        if (t < s) red[t] += red[t + s];
        __syncthreads();
    }
    const float inv = 1.f / red[0];
    if (t < NN) aw[t] = e * inv;
    __syncthreads();

    const float* eb = enc + (size_t)b * NN * HH;
    for (int h = t; h < HH; h += 256) {
        float s = 0.f;
#pragma unroll 4
        for (int n = 0; n < NN; n++)
            s += aw[n] * eb[(size_t)n * HH + h];
        ctx[(size_t)b * HH + h] = s;
    }
}

// =================================================================================
// y_ctx = [prev_y | plan0*ctx_e + plan1*ctx_s], written pre-split
// =================================================================================
__global__ void combine_kernel(const float* __restrict__ prev_y,
                               const float* __restrict__ plan,
                               const float* __restrict__ ctx_e,
                               const float* __restrict__ ctx_s,
                               __nv_bfloat16* __restrict__ ychi,
                               __nv_bfloat16* __restrict__ yclo)
{
    const int idx = blockIdx.x * blockDim.x + threadIdx.x;
    if (idx >= BSZ * YC) return;
    const int b = idx >> 10;
    const int c = idx & 1023;
    float v;
    if (c < EE) {
        v = prev_y[(size_t)b * EE + c];
    } else {
        const float p0 = plan[2 * b], p1 = plan[2 * b + 1];
        const int h = c - EE;
        v = p0 * ctx_e[(size_t)b * HH + h] + p1 * ctx_s[(size_t)b * HH + h];
    }
    __nv_bfloat16 hv = __float2bfloat16(v);
    ychi[idx] = hv;
    yclo[idx] = __float2bfloat16(v - __bfloat162float(hv));
}

// =================================================================================
// GRU cell elementwise; outputs out_hid (fp32) + hn split (bf16 hi/lo)
// =================================================================================
__global__ void gru_kernel(const float* __restrict__ gx,
                           const float* __restrict__ ghbase,
                           const float* __restrict__ b_hh,
                           const float* __restrict__ prev_h,
                           float* __restrict__ out_hid,
                           __nv_bfloat16* __restrict__ hnhi,
                           __nv_bfloat16* __restrict__ hnlo)
{
    const int idx = blockIdx.x * blockDim.x + threadIdx.x;
    if (idx >= BSZ * DD) return;
    const int b = idx / DD;
    const int d = idx - b * DD;
    const float* gxb = gx + (size_t)b * G3D;
    const float* ghb = ghbase + (size_t)b * NCAT;
    const float ghr = ghb[d]          + b_hh[d];
    const float ghz = ghb[DD + d]     + b_hh[DD + d];
    const float ghn = ghb[2 * DD + d] + b_hh[2 * DD + d];
    const float r = 1.f / (1.f + expf(-(gxb[d] + ghr)));
    const float z = 1.f / (1.f + expf(-(gxb[DD + d] + ghz)));
    const float n = tanhf(gxb[2 * DD + d] + r * ghn);
    const float h = (1.f - z) * n + z * prev_h[idx];
    out_hid[idx] = h;
    __nv_bfloat16 hv = __float2bfloat16(h);
    hnhi[idx] = hv;
    hnlo[idx] = __float2bfloat16(h - __bfloat162float(hv));
}

// =================================================================================
// host launcher — graph-capturable
// =================================================================================
extern "C" void kernel_launch(void* const* d_in, const int* in_sizes, int n_in,
                              void* d_out, int out_size)
{
    const float* prev_y  = (const float*)d_in[0];
    const float* prev_h  = (const float*)d_in[1];
    const float* equ_enc = (const float*)d_in[2];
    const float* sns_enc = (const float*)d_in[3];
    const int* equ_mask = (const int*)d_in[5];
    const int* sns_mask = (const int*)d_in[6];
    const float* W1e    = (const float*)d_in[7];
    const float* W2e    = (const float*)d_in[8];
    const float* vte    = (const float*)d_in[9];
    const float* W1s    = (const float*)d_in[10];
    const float* W2s    = (const float*)d_in[11];
    const float* vts    = (const float*)d_in[12];
    const float* plan_W = (const float*)d_in[13];
    const float* plan_b = (const float*)d_in[14];
    const float* Wc     = (const float*)d_in[15];
    const float* bc     = (const float*)d_in[16];
    const float* w_ih   = (const float*)d_in[17];
    const float* w_hh   = (const float*)d_in[18];
    const float* b_ih   = (const float*)d_in[19];
    const float* b_hh   = (const float*)d_in[20];
    const float* Wout   = (const float*)d_in[21];
    const float* bout   = (const float*)d_in[22];

    float* out      = (float*)d_out;
    float* out_dec  = out;
    float* out_hid  = out + (size_t)BSZ * VV;
    float* out_plan = out + (size_t)BSZ * VV + (size_t)BSZ * DD;

    float *u_e, *u_s, *ctx_e, *ctx_s, *plan, *gx, *dtgh;
    int *offE, *offS, *rowE, *rowS, *mtot;
    __nv_bfloat16 *ph_hi, *ph_lo, *ee_hi, *ee_lo, *es_hi, *es_lo;
    __nv_bfloat16 *wcat_hi, *wcat_lo, *wc_hi, *wc_lo, *wih_hi, *wih_lo;
    __nv_bfloat16 *w1e_hi, *w1e_lo, *w1s_hi, *w1s_lo;
    __nv_bfloat16 *yc_hi, *yc_lo, *x_hi, *x_lo, *hn_hi, *hn_lo;
    cudaGetSymbolAddress((void**)&u_e,   g_u_e);
    cudaGetSymbolAddress((void**)&u_s,   g_u_s);
    cudaGetSymbolAddress((void**)&ctx_e, g_ctx_e);
    cudaGetSymbolAddress((void**)&ctx_s, g_ctx_s);
    cudaGetSymbolAddress((void**)&plan,  g_plan);
    cudaGetSymbolAddress((void**)&gx,    g_gx);
    cudaGetSymbolAddress((void**)&dtgh,  g_dtgh);
    cudaGetSymbolAddress((void**)&offE,  g_offE);
    cudaGetSymbolAddress((void**)&offS,  g_offS);
    cudaGetSymbolAddress((void**)&rowE,  g_rowE);
    cudaGetSymbolAddress((void**)&rowS,  g_rowS);
    cudaGetSymbolAddress((void**)&mtot,  g_mtot);
    cudaGetSymbolAddress((void**)&ph_hi, g_ph_hi);  cudaGetSymbolAddress((void**)&ph_lo, g_ph_lo);
    cudaGetSymbolAddress((void**)&ee_hi, g_ee_hi);  cudaGetSymbolAddress((void**)&ee_lo, g_ee_lo);
    cudaGetSymbolAddress((void**)&es_hi, g_es_hi);  cudaGetSymbolAddress((void**)&es_lo, g_es_lo);
    cudaGetSymbolAddress((void**)&wcat_hi, g_wcat_hi); cudaGetSymbolAddress((void**)&wcat_lo, g_wcat_lo);
    cudaGetSymbolAddress((void**)&wc_hi, g_wc_hi);  cudaGetSymbolAddress((void**)&wc_lo, g_wc_lo);
    cudaGetSymbolAddress((void**)&wih_hi, g_wih_hi); cudaGetSymbolAddress((void**)&wih_lo, g_wih_lo);
    cudaGetSymbolAddress((void**)&w1e_hi, g_w1e_hi); cudaGetSymbolAddress((void**)&w1e_lo, g_w1e_lo);
    cudaGetSymbolAddress((void**)&w1s_hi, g_w1s_hi); cudaGetSymbolAddress((void**)&w1s_lo, g_w1s_lo);
    cudaGetSymbolAddress((void**)&yc_hi, g_yc_hi);  cudaGetSymbolAddress((void**)&yc_lo, g_yc_lo);
    cudaGetSymbolAddress((void**)&x_hi,  g_x_hi);   cudaGetSymbolAddress((void**)&x_lo,  g_x_lo);
    cudaGetSymbolAddress((void**)&hn_hi, g_hn_hi);  cudaGetSymbolAddress((void**)&hn_lo, g_hn_lo);

    cudaFuncSetAttribute(gemm_sp,    cudaFuncAttributeMaxDynamicSharedMemorySize, SMEM_BYTES);
    cudaFuncSetAttribute(gemm_mixed, cudaFuncAttributeMaxDynamicSharedMemorySize, SMEM_BYTES);
    cudaFuncSetAttribute(attn_cmp,   cudaFuncAttributeMaxDynamicSharedMemorySize, SMEM_BYTES);

    const dim3 blk(256);

    // ---- mask compaction + gathered enc split ----
    compact_kernel<<<1, 256>>>(equ_mask, sns_mask, offE, offS, mtot);
    gather_kernel<<<BSZ, 256>>>(equ_enc, equ_mask, offE, ee_hi, ee_lo, rowE, u_e);
    gather_kernel<<<BSZ, 256>>>(sns_enc, sns_mask, offS, es_hi, es_lo, rowS, u_s);

    // ---- weight / activation pre-splits ----
    split_kernel<<<(BSZ * DD / 4 + 255) / 256, blk>>>(prev_h, ph_hi, ph_lo, BSZ * DD / 4);
    split_kernel<<<(HH * DD / 4 + 255) / 256, blk>>>(W2e,  wcat_hi,                    wcat_lo,                    HH * DD / 4);
    split_kernel<<<(HH * DD / 4 + 255) / 256, blk>>>(W2s,  wcat_hi + (size_t)HH * DD,  wcat_lo + (size_t)HH * DD,  HH * DD / 4);
    split_kernel<<<(G3D * DD / 4 + 255) / 256, blk>>>(w_hh, wcat_hi + (size_t)2 * HH * DD, wcat_lo + (size_t)2 * HH * DD, G3D * DD / 4);
    split_kernel<<<(HH * YC / 4 + 255) / 256, blk>>>(Wc,   wc_hi,  wc_lo,  HH * YC / 4);
    split_kernel<<<(G3D * HH / 4 + 255) / 256, blk>>>(w_ih, wih_hi, wih_lo, G3D * HH / 4);
    split_kernel<<<(HH * HH / 4 + 255) / 256, blk>>>(W1e,  w1e_hi, w1e_lo, HH * HH / 4);
    split_kernel<<<(HH * HH / 4 + 255) / 256, blk>>>(W1s,  w1s_hi, w1s_lo, HH * HH / 4);

    // fused [dt_e | dt_s | gh] = prev_h @ Wcat^T
    gemm_sp<<<dim3(NCAT / 128, BSZ / 128), blk, SMEM_BYTES>>>(
        ph_hi, ph_lo, wcat_hi, wcat_lo, nullptr, dtgh, nullptr, nullptr, BSZ, NCAT, DD);

    plan_kernel<<<BSZ, 128>>>(prev_h, plan_W, plan_b, plan, out_plan);

    // attention scores over compacted rows (grid fixed 256; tail blocks exit)
    attn_cmp<<<BSZ, blk, SMEM_BYTES>>>(ee_hi, ee_lo, w1e_hi, w1e_lo, dtgh,      NCAT, vte, rowE, mtot, 0, u_e);
    attn_cmp<<<BSZ, blk, SMEM_BYTES>>>(es_hi, es_lo, w1s_hi, w1s_lo, dtgh + HH, NCAT, vts, rowS, mtot, 1, u_s);

    softmax_ctx_kernel<<<BSZ, blk>>>(u_e, equ_enc, ctx_e);
    softmax_ctx_kernel<<<BSZ, blk>>>(u_s, sns_enc, ctx_s);

    combine_kernel<<<(BSZ * YC) / 256, blk>>>(prev_y, plan, ctx_e, ctx_s, yc_hi, yc_lo);

    gemm_sp<<<dim3(HH / 128, BSZ / 128), blk, SMEM_BYTES>>>(
        yc_hi, yc_lo, wc_hi, wc_lo, bc, nullptr, x_hi, x_lo, BSZ, HH, YC);
    gemm_sp<<<dim3(G3D / 128, BSZ / 128), blk, SMEM_BYTES>>>(
        x_hi, x_lo, wih_hi, wih_lo, b_ih, gx, nullptr, nullptr, BSZ, G3D, HH);

    gru_kernel<<<(BSZ * DD) / 256, blk>>>(gx, dtgh + 2 * HH, b_hh, prev_h, out_hid, hn_hi, hn_lo);

    gemm_mixed<<<dim3(VV / 128, BSZ / 128), blk, SMEM_BYTES>>>(
        hn_hi, hn_lo, Wout, bout, out_dec, BSZ, VV, DD);
}

// round 9
// speedup vs baseline: 2.9664x; 1.1098x over previous
#include <cuda_runtime.h>
#include <cuda_bf16.h>
#include <math.h>
#include <stdint.h>

#define HH   512
#define ZZ   128
#define EE   512
#define DD   1152      // 2H + Z
#define VV   32000
#define BSZ  256
#define NN   128
#define G3D  3456      // 3*D
#define NCAT 4480      // 512 (dt_e) + 512 (dt_s) + 3456 (gh)
#define YC   1024      // E + H

// ---------------- scratch (device globals; no allocation allowed) ----------------
__device__ float g_u_e  [BSZ * NN];
__device__ float g_u_s  [BSZ * NN];
__device__ float g_ctx_e[BSZ * NN * 4];     // oversized ok
__device__ float g_ctx_s[BSZ * NN * 4];
__device__ float g_plan [BSZ * 2];
__device__ float g_gx   [BSZ * G3D];
__device__ float g_dtgh [BSZ * NCAT];
__device__ int   g_offE [BSZ];
__device__ int   g_offS [BSZ];
__device__ int   g_rowE [BSZ * NN];
__device__ int   g_rowS [BSZ * NN];
__device__ int   g_mtot [2];

__device__ __align__(256) __nv_bfloat16 g_ph_hi [BSZ * DD];
__device__ __align__(256) __nv_bfloat16 g_ph_lo [BSZ * DD];
__device__ __align__(256) __nv_bfloat16 g_ee_hi [BSZ * NN * HH];
__device__ __align__(256) __nv_bfloat16 g_ee_lo [BSZ * NN * HH];
__device__ __align__(256) __nv_bfloat16 g_es_hi [BSZ * NN * HH];
__device__ __align__(256) __nv_bfloat16 g_es_lo [BSZ * NN * HH];
__device__ __align__(256) __nv_bfloat16 g_wcat_hi[NCAT * DD];
__device__ __align__(256) __nv_bfloat16 g_wcat_lo[NCAT * DD];
__device__ __align__(256) __nv_bfloat16 g_wc_hi [HH * YC];
__device__ __align__(256) __nv_bfloat16 g_wc_lo [HH * YC];
__device__ __align__(256) __nv_bfloat16 g_wih_hi[G3D * HH];
__device__ __align__(256) __nv_bfloat16 g_wih_lo[G3D * HH];
__device__ __align__(256) __nv_bfloat16 g_w1e_hi[HH * HH];
__device__ __align__(256) __nv_bfloat16 g_w1e_lo[HH * HH];
__device__ __align__(256) __nv_bfloat16 g_w1s_hi[HH * HH];
__device__ __align__(256) __nv_bfloat16 g_w1s_lo[HH * HH];
__device__ __align__(256) __nv_bfloat16 g_yc_hi [BSZ * YC];
__device__ __align__(256) __nv_bfloat16 g_yc_lo [BSZ * YC];
__device__ __align__(256) __nv_bfloat16 g_x_hi  [BSZ * HH];
__device__ __align__(256) __nv_bfloat16 g_x_lo  [BSZ * HH];
__device__ __align__(256) __nv_bfloat16 g_hn_hi [BSZ * DD];
__device__ __align__(256) __nv_bfloat16 g_hn_lo [BSZ * DD];

// ---------------- helpers ----------------
__device__ __forceinline__ uint32_t pack_bf2(float a, float b) {
    __nv_bfloat162 t = __floats2bfloat162_rn(a, b);
    return *reinterpret_cast<uint32_t*>(&t);
}

__device__ __forceinline__ void mma16816(float c[4],
                                         uint32_t a0, uint32_t a1, uint32_t a2, uint32_t a3,
                                         uint32_t b0, uint32_t b1) {
    asm volatile(
        "mma.sync.aligned.m16n8k16.row.col.f32.bf16.bf16.f32 "
        "{%0,%1,%2,%3}, {%4,%5,%6,%7}, {%8,%9}, {%0,%1,%2,%3};\n"
        : "+f"(c[0]), "+f"(c[1]), "+f"(c[2]), "+f"(c[3])
        : "r"(a0), "r"(a1), "r"(a2), "r"(a3), "r"(b0), "r"(b1));
}

__device__ __forceinline__ void ldsm_x4(uint32_t& r0, uint32_t& r1, uint32_t& r2, uint32_t& r3,
                                        uint32_t addr) {
    asm volatile("ldmatrix.sync.aligned.m8n8.x4.shared.b16 {%0,%1,%2,%3}, [%4];"
                 : "=r"(r0), "=r"(r1), "=r"(r2), "=r"(r3) : "r"(addr));
}
__device__ __forceinline__ void ldsm_x2(uint32_t& r0, uint32_t& r1, uint32_t addr) {
    asm volatile("ldmatrix.sync.aligned.m8n8.x2.shared.b16 {%0,%1}, [%2];"
                 : "=r"(r0), "=r"(r1) : "r"(addr));
}

#define CP16(dst, src) \
    asm volatile("cp.async.cg.shared.global [%0], [%1], 16;" :: "r"(dst), "l"(src))
#define CP_COMMIT() asm volatile("cp.async.commit_group;")
#define CP_WAIT0()  asm volatile("cp.async.wait_group 0;")
#define CP_WAIT1()  asm volatile("cp.async.wait_group 1;")

#define SMS 40
#define STG (128 * SMS)
#define STGB (STG * 2)
#define STAGE4B (4 * STGB)
#define SMEM_BYTES (2 * STAGE4B)

__device__ __forceinline__ uint32_t ldsm_aoff(int l) {
    return (uint32_t)((((l & 7) + ((l >> 3) & 1) * 8) * SMS + (l >> 4) * 8) * 2);
}
__device__ __forceinline__ uint32_t ldsm_boff(int l) {
    return (uint32_t)(((l & 7) * SMS + ((l >> 3) & 1) * 8) * 2);
}

__device__ __forceinline__ void cp_stage4(uint32_t d,
                                          const __nv_bfloat16* ah, const __nv_bfloat16* al,
                                          const __nv_bfloat16* bh, const __nv_bfloat16* bl) {
    CP16(d + 0 * STGB,      ah);     CP16(d + 0 * STGB + 16, ah + 8);
    CP16(d + 1 * STGB,      al);     CP16(d + 1 * STGB + 16, al + 8);
    CP16(d + 2 * STGB,      bh);     CP16(d + 2 * STGB + 16, bh + 8);
    CP16(d + 3 * STGB,      bl);     CP16(d + 3 * STGB + 16, bl + 8);
}
__device__ __forceinline__ void cp_stageA(uint32_t d,
                                          const __nv_bfloat16* ah, const __nv_bfloat16* al) {
    CP16(d + 0 * STGB,      ah);     CP16(d + 0 * STGB + 16, ah + 8);
    CP16(d + 1 * STGB,      al);     CP16(d + 1 * STGB + 16, al + 8);
}

__device__ __forceinline__ void mma_chunk(uint32_t stb, uint32_t aoff, uint32_t boff,
                                          float acc[4][4][4], int wr, int wc) {
#pragma unroll
    for (int ks = 0; ks < 2; ks++) {
        const uint32_t kb2 = ks * 32;
        uint32_t bhi[4][2], blo[4][2];
#pragma unroll
        for (int ni = 0; ni < 4; ni++) {
            const uint32_t rb = (uint32_t)(wc * 32 + ni * 8) * (SMS * 2) + kb2 + boff;
            ldsm_x2(bhi[ni][0], bhi[ni][1], stb + 2 * STGB + rb);
            ldsm_x2(blo[ni][0], blo[ni][1], stb + 3 * STGB + rb);
        }
#pragma unroll
        for (int mi = 0; mi < 4; mi++) {
            const uint32_t ra = (uint32_t)(wr * 64 + mi * 16) * (SMS * 2) + kb2 + aoff;
            uint32_t ah[4], al[4];
            ldsm_x4(ah[0], ah[1], ah[2], ah[3], stb + ra);
            ldsm_x4(al[0], al[1], al[2], al[3], stb + STGB + ra);
#pragma unroll
            for (int ni = 0; ni < 4; ni++) {
                mma16816(acc[mi][ni], ah[0], ah[1], ah[2], ah[3], bhi[ni][0], bhi[ni][1]);
                mma16816(acc[mi][ni], ah[0], ah[1], ah[2], ah[3], blo[ni][0], blo[ni][1]);
                mma16816(acc[mi][ni], al[0], al[1], al[2], al[3], bhi[ni][0], bhi[ni][1]);
            }
        }
    }
}

// =================================================================================
// gemm_sp: all-pre-split bf16x3 GEMM
// =================================================================================
__global__ void __launch_bounds__(256, 2) gemm_sp(
    const __nv_bfloat16* __restrict__ Ahi, const __nv_bfloat16* __restrict__ Alo,
    const __nv_bfloat16* __restrict__ Bhi, const __nv_bfloat16* __restrict__ Blo,
    const float* __restrict__ bias,
    float* __restrict__ C, __nv_bfloat16* __restrict__ Chi, __nv_bfloat16* __restrict__ Clo,
    int M, int N, int K)
{
    extern __shared__ __nv_bfloat16 sm[];

    const int t    = threadIdx.x;
    const int m0   = blockIdx.y * 128;
    const int n0   = blockIdx.x * 128;
    const int lane = t & 31;
    const int wid  = t >> 5;
    const int g    = lane >> 2;
    const int tg   = lane & 3;
    const int wr   = wid & 1;
    const int wc   = wid >> 1;

    const uint32_t smb  = (uint32_t)__cvta_generic_to_shared(sm);
    const uint32_t aoff = ldsm_aoff(lane);
    const uint32_t boff = ldsm_boff(lane);

    const int r  = t >> 1;
    const int hh = (t & 1) * 16;
    const uint32_t toff = (uint32_t)(r * SMS + hh) * 2;
    const __nv_bfloat16* ApH = Ahi + (size_t)(m0 + r) * K + hh;
    const __nv_bfloat16* ApL = Alo + (size_t)(m0 + r) * K + hh;
    const __nv_bfloat16* BpH = Bhi + (size_t)(n0 + r) * K + hh;
    const __nv_bfloat16* BpL = Blo + (size_t)(n0 + r) * K + hh;

    float acc[4][4][4];
#pragma unroll
    for (int mi = 0; mi < 4; mi++)
#pragma unroll
        for (int ni = 0; ni < 4; ni++)
#pragma unroll
            for (int q = 0; q < 4; q++) acc[mi][ni][q] = 0.f;

    cp_stage4(smb + toff, ApH, ApL, BpH, BpL);
    CP_COMMIT();

    for (int k0 = 0; k0 < K; k0 += 32) {
        const int s = (k0 >> 5) & 1;
        const bool more = (k0 + 32 < K);
        if (more) {
            const uint32_t d = smb + (uint32_t)(s ^ 1) * STAGE4B + toff;
            cp_stage4(d, ApH + k0 + 32, ApL + k0 + 32, BpH + k0 + 32, BpL + k0 + 32);
            CP_COMMIT();
            CP_WAIT1();
        } else {
            CP_WAIT0();
        }
        __syncthreads();
        mma_chunk(smb + (uint32_t)s * STAGE4B, aoff, boff, acc, wr, wc);
        __syncthreads();
    }

#pragma unroll
    for (int mi = 0; mi < 4; mi++) {
        const int row = m0 + wr * 64 + mi * 16 + g;
#pragma unroll
        for (int ni = 0; ni < 4; ni++) {
            const int col = n0 + wc * 32 + ni * 8 + tg * 2;
            float b0 = bias ? bias[col] : 0.f;
            float b1 = bias ? bias[col + 1] : 0.f;
            float c00 = acc[mi][ni][0] + b0, c01 = acc[mi][ni][1] + b1;
            float c10 = acc[mi][ni][2] + b0, c11 = acc[mi][ni][3] + b1;
            if (C) {
                *(float2*)&C[(size_t)row * N + col]       = make_float2(c00, c01);
                *(float2*)&C[(size_t)(row + 8) * N + col] = make_float2(c10, c11);
            }
            if (Chi) {
                __nv_bfloat16 h00 = __float2bfloat16(c00), h01 = __float2bfloat16(c01);
                __nv_bfloat16 h10 = __float2bfloat16(c10), h11 = __float2bfloat16(c11);
                *(uint32_t*)&Chi[(size_t)row * N + col]       = pack_bf2(c00, c01);
                *(uint32_t*)&Chi[(size_t)(row + 8) * N + col] = pack_bf2(c10, c11);
                *(uint32_t*)&Clo[(size_t)row * N + col] =
                    pack_bf2(c00 - __bfloat162float(h00), c01 - __bfloat162float(h01));
                *(uint32_t*)&Clo[(size_t)(row + 8) * N + col] =
                    pack_bf2(c10 - __bfloat162float(h10), c11 - __bfloat162float(h11));
            }
        }
    }
}

// =================================================================================
// gemm_mixed: split-A bf16 (cp.async) x fp32-B (in-loop split).  For Wout.
// =================================================================================
__global__ void __launch_bounds__(256, 2) gemm_mixed(
    const __nv_bfloat16* __restrict__ Ahi, const __nv_bfloat16* __restrict__ Alo,
    const float* __restrict__ B, const float* __restrict__ bias,
    float* __restrict__ C, int M, int N, int K)
{
    extern __shared__ __nv_bfloat16 sm[];

    const int t    = threadIdx.x;
    const int m0   = blockIdx.y * 128;
    const int n0   = blockIdx.x * 128;
    const int lane = t & 31;
    const int wid  = t >> 5;
    const int g    = lane >> 2;
    const int tg   = lane & 3;
    const int wr   = wid & 1;
    const int wc   = wid >> 1;

    const uint32_t smb  = (uint32_t)__cvta_generic_to_shared(sm);
    const uint32_t aoff = ldsm_aoff(lane);
    const uint32_t boff = ldsm_boff(lane);

    const int r  = t >> 1;
    const int hh = (t & 1) * 16;
    const uint32_t toff = (uint32_t)(r * SMS + hh) * 2;
    const int idx = r * SMS + hh;
    const __nv_bfloat16* ApH = Ahi + (size_t)(m0 + r) * K + hh;
    const __nv_bfloat16* ApL = Alo + (size_t)(m0 + r) * K + hh;
    const float* Bp = B + (size_t)(n0 + r) * K + hh;

    float acc[4][4][4];
#pragma unroll
    for (int mi = 0; mi < 4; mi++)
#pragma unroll
        for (int ni = 0; ni < 4; ni++)
#pragma unroll
            for (int q = 0; q < 4; q++) acc[mi][ni][q] = 0.f;

    cp_stageA(smb + toff, ApH, ApL);
    CP_COMMIT();
    {
        float4 rb[4];
#pragma unroll
        for (int i = 0; i < 4; i++) rb[i] = *(const float4*)(Bp + i * 4);
        __nv_bfloat16* bh = sm + 2 * STG;
        __nv_bfloat16* bl = sm + 3 * STG;
#pragma unroll
        for (int i = 0; i < 4; i++) {
            float x = rb[i].x, y = rb[i].y, z = rb[i].z, w = rb[i].w;
            __nv_bfloat16 hx = __float2bfloat16(x), hy = __float2bfloat16(y);
            __nv_bfloat16 hz = __float2bfloat16(z), hw = __float2bfloat16(w);
            uint2 vh, vl;
            vh.x = pack_bf2(x, y); vh.y = pack_bf2(z, w);
            vl.x = pack_bf2(x - __bfloat162float(hx), y - __bfloat162float(hy));
            vl.y = pack_bf2(z - __bfloat162float(hz), w - __bfloat162float(hw));
            *(uint2*)&bh[idx + i * 4] = vh;
            *(uint2*)&bl[idx + i * 4] = vl;
        }
    }

    for (int k0 = 0; k0 < K; k0 += 32) {
        const int s = (k0 >> 5) & 1;
        const bool more = (k0 + 32 < K);
        float4 rb[4];
        if (more) {
            const uint32_t d = smb + (uint32_t)(s ^ 1) * STAGE4B + toff;
            cp_stageA(d, ApH + k0 + 32, ApL + k0 + 32);
            CP_COMMIT();
#pragma unroll
            for (int i = 0; i < 4; i++) rb[i] = *(const float4*)(Bp + k0 + 32 + i * 4);
            CP_WAIT1();
        } else {
            CP_WAIT0();
        }
        __syncthreads();
        mma_chunk(smb + (uint32_t)s * STAGE4B, aoff, boff, acc, wr, wc);
        if (more) {
            __nv_bfloat16* bh = sm + (s ^ 1) * (STAGE4B / 2) + 2 * STG;
            __nv_bfloat16* bl = sm + (s ^ 1) * (STAGE4B / 2) + 3 * STG;
#pragma unroll
            for (int i = 0; i < 4; i++) {
                float x = rb[i].x, y = rb[i].y, z = rb[i].z, w = rb[i].w;
                __nv_bfloat16 hx = __float2bfloat16(x), hy = __float2bfloat16(y);
                __nv_bfloat16 hz = __float2bfloat16(z), hw = __float2bfloat16(w);
                uint2 vh, vl;
                vh.x = pack_bf2(x, y); vh.y = pack_bf2(z, w);
                vl.x = pack_bf2(x - __bfloat162float(hx), y - __bfloat162float(hy));
                vl.y = pack_bf2(z - __bfloat162float(hz), w - __bfloat162float(hw));
                *(uint2*)&bh[idx + i * 4] = vh;
                *(uint2*)&bl[idx + i * 4] = vl;
            }
        }
        __syncthreads();
    }

#pragma unroll
    for (int mi = 0; mi < 4; mi++) {
        const int row = m0 + wr * 64 + mi * 16 + g;
#pragma unroll
        for (int ni = 0; ni < 4; ni++) {
            const int col = n0 + wc * 32 + ni * 8 + tg * 2;
            float b0 = bias ? bias[col] : 0.f;
            float b1 = bias ? bias[col + 1] : 0.f;
            *(float2*)&C[(size_t)row * N + col] =
                make_float2(acc[mi][ni][0] + b0, acc[mi][ni][1] + b1);
            *(float2*)&C[(size_t)(row + 8) * N + col] =
                make_float2(acc[mi][ni][2] + b0, acc[mi][ni][3] + b1);
        }
    }
}

// =================================================================================
// batched split: one launch does all fp32 -> bf16 hi/lo segments (grid.y = segment)
// =================================================================================
struct SplitSeg { const float* src; __nv_bfloat16* hi; __nv_bfloat16* lo; int n4; };
struct SplitArgs { SplitSeg seg[8]; };

__global__ void split_all(SplitArgs a)
{
    const SplitSeg s = a.seg[blockIdx.y];
    const int i = blockIdx.x * blockDim.x + threadIdx.x;
    if (i >= s.n4) return;
    float4 v = ((const float4*)s.src)[i];
    __nv_bfloat16 hx = __float2bfloat16(v.x), hy = __float2bfloat16(v.y);
    __nv_bfloat16 hz = __float2bfloat16(v.z), hw = __float2bfloat16(v.w);
    uint2 vh, vl;
    vh.x = pack_bf2(v.x, v.y); vh.y = pack_bf2(v.z, v.w);
    vl.x = pack_bf2(v.x - __bfloat162float(hx), v.y - __bfloat162float(hy));
    vl.y = pack_bf2(v.z - __bfloat162float(hz), v.w - __bfloat162float(hw));
    ((uint2*)s.hi)[i] = vh;
    ((uint2*)s.lo)[i] = vl;
}

// =================================================================================
// compact: per-batch exclusive offsets of unmasked positions (both masks)
// =================================================================================
__global__ void compact_kernel(const int* __restrict__ mE, const int* __restrict__ mS,
                               int* __restrict__ offE, int* __restrict__ offS,
                               int* __restrict__ mtot)
{
    __shared__ int sE[256], sS[256];
    const int b = threadIdx.x;
    int cE = 0, cS = 0;
    for (int n = 0; n < NN; n++) {
        cE += (mE[b * NN + n] == 0);
        cS += (mS[b * NN + n] == 0);
    }
    sE[b] = cE; sS[b] = cS;
    __syncthreads();
    for (int d = 1; d < 256; d <<= 1) {
        int vE = 0, vS = 0;
        if (b >= d) { vE = sE[b - d]; vS = sS[b - d]; }
        __syncthreads();
        sE[b] += vE; sS[b] += vS;
        __syncthreads();
    }
    offE[b] = sE[b] - cE;
    offS[b] = sS[b] - cS;
    if (b == 255) { mtot[0] = sE[255]; mtot[1] = sS[255]; }
}

// =================================================================================
// merged gather (grid.y = side): compact unmasked enc rows, split to bf16 hi/lo
// =================================================================================
__global__ void gather2(const float* __restrict__ encE, const float* __restrict__ encS,
                        const int* __restrict__ mE, const int* __restrict__ mS,
                        const int* __restrict__ offE, const int* __restrict__ offS,
                        __nv_bfloat16* __restrict__ geh, __nv_bfloat16* __restrict__ gel,
                        __nv_bfloat16* __restrict__ gsh, __nv_bfloat16* __restrict__ gsl,
                        int* __restrict__ rowE, int* __restrict__ rowS,
                        float* __restrict__ uE, float* __restrict__ uS)
{
    const int side = blockIdx.y;
    const float* enc = side ? encS : encE;
    const int* mask  = side ? mS : mE;
    const int* off   = side ? offS : offE;
    __nv_bfloat16* ghi = side ? gsh : geh;
    __nv_bfloat16* glo = side ? gsl : gel;
    int* rowinfo = side ? rowS : rowE;
    float* u     = side ? uS : uE;

    __shared__ int s_list[NN];
    __shared__ int s_wtot[8];
    const int b = blockIdx.x;
    const int t = threadIdx.x;
    const int base = off[b];
    const bool in = t < NN;
    const bool valid = in && (mask[b * NN + t] == 0);
    const unsigned wm = __ballot_sync(0xffffffffu, valid);
    const int lane = t & 31, w = t >> 5;
    if (lane == 0) s_wtot[w] = __popc(wm);
    __syncthreads();
    int wbase = 0;
#pragma unroll
    for (int i = 0; i < 4; i++) if (i < w) wbase += s_wtot[i];
    const int rank = wbase + __popc(wm & ((1u << lane) - 1));
    if (valid) {
        s_list[rank] = t;
        rowinfo[base + rank] = b * NN + t;
    } else if (in) {
        u[b * NN + t] = -INFINITY;
    }
    __syncthreads();
    const int cnt = s_wtot[0] + s_wtot[1] + s_wtot[2] + s_wtot[3];

    for (int i = 0; i < cnt; i++) {
        const int n = s_list[i];
        const float2 v = *(const float2*)(enc + ((size_t)b * NN + n) * HH + t * 2);
        __nv_bfloat16 h0 = __float2bfloat16(v.x), h1 = __float2bfloat16(v.y);
        *(uint32_t*)&ghi[((size_t)base + i) * HH + t * 2] = pack_bf2(v.x, v.y);
        *(uint32_t*)&glo[((size_t)base + i) * HH + t * 2] =
            pack_bf2(v.x - __bfloat162float(h0), v.y - __bfloat162float(h1));
    }
}

// =================================================================================
// merged attention (grid = (256, 2); blockIdx.y = side).  Over compacted rows.
// =================================================================================
__global__ void __launch_bounds__(256, 2) attn2(
    const __nv_bfloat16* __restrict__ geh, const __nv_bfloat16* __restrict__ gel,
    const __nv_bfloat16* __restrict__ gsh, const __nv_bfloat16* __restrict__ gsl,
    const __nv_bfloat16* __restrict__ w1eh, const __nv_bfloat16* __restrict__ w1el,
    const __nv_bfloat16* __restrict__ w1sh, const __nv_bfloat16* __restrict__ w1sl,
    const float* __restrict__ dtg,          // dtgh base; side offset HH, stride NCAT
    const float* __restrict__ vte, const float* __restrict__ vts,
    const int* __restrict__ rowE, const int* __restrict__ rowS,
    const int* __restrict__ mtotp,
    float* __restrict__ uE, float* __restrict__ uS)
{
    extern __shared__ __nv_bfloat16 sm[];
    __shared__ float s_vt[512];
    __shared__ float s_u[128];

    const int side = blockIdx.y;
    const int mtot = mtotp[side];
    const int m0 = blockIdx.x * 128;
    if (m0 >= mtot) return;

    const __nv_bfloat16* gehi = side ? gsh : geh;
    const __nv_bfloat16* gelo = side ? gsl : gel;
    const __nv_bfloat16* w1hi = side ? w1sh : w1eh;
    const __nv_bfloat16* w1lo = side ? w1sl : w1el;
    const float* dt = dtg + (side ? HH : 0);
    const float* vt = side ? vts : vte;
    const int* rowinfo = side ? rowS : rowE;
    float* u = side ? uS : uE;

    const int t    = threadIdx.x;
    const int lane = t & 31;
    const int wid  = t >> 5;
    const int g    = lane >> 2;
    const int tg   = lane & 3;
    const int wr   = wid & 1;
    const int wc   = wid >> 1;

    const uint32_t smb  = (uint32_t)__cvta_generic_to_shared(sm);
    const uint32_t aoff = ldsm_aoff(lane);
    const uint32_t boff = ldsm_boff(lane);

    for (int i = t; i < 512; i += 256) s_vt[i] = vt[i];
    if (t < 128) s_u[t] = 0.f;

    int rb4[4][2];
#pragma unroll
    for (int mi = 0; mi < 4; mi++)
#pragma unroll
        for (int rr = 0; rr < 2; rr++)
            rb4[mi][rr] = rowinfo[m0 + wr * 64 + mi * 16 + g + rr * 8] >> 7;

    const int r  = t >> 1;
    const int hh = (t & 1) * 16;
    const uint32_t toff = (uint32_t)(r * SMS + hh) * 2;
    const __nv_bfloat16* ApH = gehi + (size_t)(m0 + r) * 512 + hh;
    const __nv_bfloat16* ApL = gelo + (size_t)(m0 + r) * 512 + hh;

    float up[8];
#pragma unroll
    for (int i = 0; i < 8; i++) up[i] = 0.f;

    for (int nc = 0; nc < 4; nc++) {
        const __nv_bfloat16* BpH = w1hi + (size_t)(nc * 128 + r) * 512 + hh;
        const __nv_bfloat16* BpL = w1lo + (size_t)(nc * 128 + r) * 512 + hh;

        float acc[4][4][4];
#pragma unroll
        for (int mi = 0; mi < 4; mi++)
#pragma unroll
            for (int ni = 0; ni < 4; ni++)
#pragma unroll
                for (int q = 0; q < 4; q++) acc[mi][ni][q] = 0.f;

        cp_stage4(smb + toff, ApH, ApL, BpH, BpL);
        CP_COMMIT();

        for (int k0 = 0; k0 < 512; k0 += 32) {
            const int s = (k0 >> 5) & 1;
            const bool more = (k0 + 32 < 512);
            if (more) {
                const uint32_t d = smb + (uint32_t)(s ^ 1) * STAGE4B + toff;
                cp_stage4(d, ApH + k0 + 32, ApL + k0 + 32, BpH + k0 + 32, BpL + k0 + 32);
                CP_COMMIT();
                CP_WAIT1();
            } else {
                CP_WAIT0();
            }
            __syncthreads();
            mma_chunk(smb + (uint32_t)s * STAGE4B, aoff, boff, acc, wr, wc);
            __syncthreads();
        }

#pragma unroll
        for (int mi = 0; mi < 4; mi++) {
            const float* dt0 = dt + (size_t)rb4[mi][0] * NCAT;
            const float* dt1 = dt + (size_t)rb4[mi][1] * NCAT;
#pragma unroll
            for (int ni = 0; ni < 4; ni++) {
                const int col = nc * 128 + wc * 32 + ni * 8 + tg * 2;
                const float v0 = s_vt[col], v1 = s_vt[col + 1];
                up[mi * 2 + 0] += v0 * tanhf(acc[mi][ni][0] + dt0[col])
                                + v1 * tanhf(acc[mi][ni][1] + dt0[col + 1]);
                up[mi * 2 + 1] += v0 * tanhf(acc[mi][ni][2] + dt1[col])
                                + v1 * tanhf(acc[mi][ni][3] + dt1[col + 1]);
            }
        }
    }

#pragma unroll
    for (int mi = 0; mi < 4; mi++)
#pragma unroll
        for (int rr = 0; rr < 2; rr++) {
            float v = up[mi * 2 + rr];
            v += __shfl_down_sync(0xffffffffu, v, 1);
            v += __shfl_down_sync(0xffffffffu, v, 2);
            if (tg == 0)
                atomicAdd(&s_u[wr * 64 + mi * 16 + g + rr * 8], v);
        }
    __syncthreads();

    if (t < 128 && m0 + t < mtot)
        u[rowinfo[m0 + t]] = s_u[t];
}

// =================================================================================
// plan = softmax(prev_h @ plan_W^T + plan_b)
// =================================================================================
__global__ void plan_kernel(const float* __restrict__ prev_h,
                            const float* __restrict__ plan_W,
                            const float* __restrict__ plan_b,
                            float* __restrict__ plan,
                            float* __restrict__ out_plan)
{
    const int b = blockIdx.x;
    const int t = threadIdx.x;
    __shared__ float s0[128], s1[128];
    float a0 = 0.f, a1 = 0.f;
    const float* hb = prev_h + (size_t)b * DD;
    for (int k = t; k < DD; k += 128) {
        const float h = hb[k];
        a0 += h * plan_W[k];
        a1 += h * plan_W[DD + k];
    }
    s0[t] = a0; s1[t] = a1;
    __syncthreads();
    for (int s = 64; s > 0; s >>= 1) {
        if (t < s) { s0[t] += s0[t + s]; s1[t] += s1[t + s]; }
        __syncthreads();
    }
    if (t == 0) {
        const float l0 = s0[0] + plan_b[0];
        const float l1 = s1[0] + plan_b[1];
        const float mx = fmaxf(l0, l1);
        const float e0 = expf(l0 - mx), e1 = expf(l1 - mx);
        const float inv = 1.f / (e0 + e1);
        plan[2 * b] = e0 * inv;       plan[2 * b + 1] = e1 * inv;
        out_plan[2 * b] = e0 * inv;   out_plan[2 * b + 1] = e1 * inv;
    }
}

// =================================================================================
// merged softmax+context (grid = (BSZ, 2))
// =================================================================================
__global__ void softmax_ctx2(const float* __restrict__ uE, const float* __restrict__ uS,
                             const float* __restrict__ encE, const float* __restrict__ encS,
                             float* __restrict__ ctxE, float* __restrict__ ctxS)
{
    const int side = blockIdx.y;
    const float* u   = side ? uS : uE;
    const float* enc = side ? encS : encE;
    float* ctx       = side ? ctxS : ctxE;

    const int b = blockIdx.x;
    const int t = threadIdx.x;
    __shared__ float red[256];
    __shared__ float aw[NN];

    const float uv = (t < NN) ? u[(size_t)b * NN + t] : -INFINITY;
    red[t] = uv;
    __syncthreads();
    for (int s = 128; s > 0; s >>= 1) {
        if (t < s) red[t] = fmaxf(red[t], red[t + s]);
        __syncthreads();
    }
    const float mx = red[0];
    __syncthreads();
    const float e = (t < NN) ? expf(uv - mx) : 0.f;
    red[t] = e;
    __syncthreads();
    for (int s = 128; s > 0; s >>= 1) {
        if (t < s) red[t] += red[t + s];
        __syncthreads();
    }
    const float inv = 1.f / red[0];
    if (t < NN) aw[t] = e * inv;
    __syncthreads();

    const float* eb = enc + (size_t)b * NN * HH;
    for (int h = t; h < HH; h += 256) {
        float s = 0.f;
#pragma unroll 4
        for (int n = 0; n < NN; n++)
            s += aw[n] * eb[(size_t)n * HH + h];
        ctx[(size_t)b * HH + h] = s;
    }
}

// =================================================================================
// y_ctx = [prev_y | plan0*ctx_e + plan1*ctx_s], written pre-split
// =================================================================================
__global__ void combine_kernel(const float* __restrict__ prev_y,
                               const float* __restrict__ plan,
                               const float* __restrict__ ctx_e,
                               const float* __restrict__ ctx_s,
                               __nv_bfloat16* __restrict__ ychi,
                               __nv_bfloat16* __restrict__ yclo)
{
    const int idx = blockIdx.x * blockDim.x + threadIdx.x;
    if (idx >= BSZ * YC) return;
    const int b = idx >> 10;
    const int c = idx & 1023;
    float v;
    if (c < EE) {
        v = prev_y[(size_t)b * EE + c];
    } else {
        const float p0 = plan[2 * b], p1 = plan[2 * b + 1];
        const int h = c - EE;
        v = p0 * ctx_e[(size_t)b * HH + h] + p1 * ctx_s[(size_t)b * HH + h];
    }
    __nv_bfloat16 hv = __float2bfloat16(v);
    ychi[idx] = hv;
    yclo[idx] = __float2bfloat16(v - __bfloat162float(hv));
}

// =================================================================================
// GRU cell elementwise; outputs out_hid (fp32) + hn split (bf16 hi/lo)
// =================================================================================
__global__ void gru_kernel(const float* __restrict__ gx,
                           const float* __restrict__ ghbase,
                           const float* __restrict__ b_hh,
                           const float* __restrict__ prev_h,
                           float* __restrict__ out_hid,
                           __nv_bfloat16* __restrict__ hnhi,
                           __nv_bfloat16* __restrict__ hnlo)
{
    const int idx = blockIdx.x * blockDim.x + threadIdx.x;
    if (idx >= BSZ * DD) return;
    const int b = idx / DD;
    const int d = idx - b * DD;
    const float* gxb = gx + (size_t)b * G3D;
    const float* ghb = ghbase + (size_t)b * NCAT;
    const float ghr = ghb[d]          + b_hh[d];
    const float ghz = ghb[DD + d]     + b_hh[DD + d];
    const float ghn = ghb[2 * DD + d] + b_hh[2 * DD + d];
    const float r = 1.f / (1.f + expf(-(gxb[d] + ghr)));
    const float z = 1.f / (1.f + expf(-(gxb[DD + d] + ghz)));
    const float n = tanhf(gxb[2 * DD + d] + r * ghn);
    const float h = (1.f - z) * n + z * prev_h[idx];
    out_hid[idx] = h;
    __nv_bfloat16 hv = __float2bfloat16(h);
    hnhi[idx] = hv;
    hnlo[idx] = __float2bfloat16(h - __bfloat162float(hv));
}

// =================================================================================
// host launcher — graph-capturable
// =================================================================================
extern "C" void kernel_launch(void* const* d_in, const int* in_sizes, int n_in,
                              void* d_out, int out_size)
{
    const float* prev_y  = (const float*)d_in[0];
    const float* prev_h  = (const float*)d_in[1];
    const float* equ_enc = (const float*)d_in[2];
    const float* sns_enc = (const float*)d_in[3];
    const int* equ_mask = (const int*)d_in[5];
    const int* sns_mask = (const int*)d_in[6];
    const float* W1e    = (const float*)d_in[7];
    const float* W2e    = (const float*)d_in[8];
    const float* vte    = (const float*)d_in[9];
    const float* W1s    = (const float*)d_in[10];
    const float* W2s    = (const float*)d_in[11];
    const float* vts    = (const float*)d_in[12];
    const float* plan_W = (const float*)d_in[13];
    const float* plan_b = (const float*)d_in[14];
    const float* Wc     = (const float*)d_in[15];
    const float* bc     = (const float*)d_in[16];
    const float* w_ih   = (const float*)d_in[17];
    const float* w_hh   = (const float*)d_in[18];
    const float* b_ih   = (const float*)d_in[19];
    const float* b_hh   = (const float*)d_in[20];
    const float* Wout   = (const float*)d_in[21];
    const float* bout   = (const float*)d_in[22];

    float* out      = (float*)d_out;
    float* out_dec  = out;
    float* out_hid  = out + (size_t)BSZ * VV;
    float* out_plan = out + (size_t)BSZ * VV + (size_t)BSZ * DD;

    float *u_e, *u_s, *ctx_e, *ctx_s, *plan, *gx, *dtgh;
    int *offE, *offS, *rowE, *rowS, *mtot;
    __nv_bfloat16 *ph_hi, *ph_lo, *ee_hi, *ee_lo, *es_hi, *es_lo;
    __nv_bfloat16 *wcat_hi, *wcat_lo, *wc_hi, *wc_lo, *wih_hi, *wih_lo;
    __nv_bfloat16 *w1e_hi, *w1e_lo, *w1s_hi, *w1s_lo;
    __nv_bfloat16 *yc_hi, *yc_lo, *x_hi, *x_lo, *hn_hi, *hn_lo;
    cudaGetSymbolAddress((void**)&u_e,   g_u_e);
    cudaGetSymbolAddress((void**)&u_s,   g_u_s);
    cudaGetSymbolAddress((void**)&ctx_e, g_ctx_e);
    cudaGetSymbolAddress((void**)&ctx_s, g_ctx_s);
    cudaGetSymbolAddress((void**)&plan,  g_plan);
    cudaGetSymbolAddress((void**)&gx,    g_gx);
    cudaGetSymbolAddress((void**)&dtgh,  g_dtgh);
    cudaGetSymbolAddress((void**)&offE,  g_offE);
    cudaGetSymbolAddress((void**)&offS,  g_offS);
    cudaGetSymbolAddress((void**)&rowE,  g_rowE);
    cudaGetSymbolAddress((void**)&rowS,  g_rowS);
    cudaGetSymbolAddress((void**)&mtot,  g_mtot);
    cudaGetSymbolAddress((void**)&ph_hi, g_ph_hi);  cudaGetSymbolAddress((void**)&ph_lo, g_ph_lo);
    cudaGetSymbolAddress((void**)&ee_hi, g_ee_hi);  cudaGetSymbolAddress((void**)&ee_lo, g_ee_lo);
    cudaGetSymbolAddress((void**)&es_hi, g_es_hi);  cudaGetSymbolAddress((void**)&es_lo, g_es_lo);
    cudaGetSymbolAddress((void**)&wcat_hi, g_wcat_hi); cudaGetSymbolAddress((void**)&wcat_lo, g_wcat_lo);
    cudaGetSymbolAddress((void**)&wc_hi, g_wc_hi);  cudaGetSymbolAddress((void**)&wc_lo, g_wc_lo);
    cudaGetSymbolAddress((void**)&wih_hi, g_wih_hi); cudaGetSymbolAddress((void**)&wih_lo, g_wih_lo);
    cudaGetSymbolAddress((void**)&w1e_hi, g_w1e_hi); cudaGetSymbolAddress((void**)&w1e_lo, g_w1e_lo);
    cudaGetSymbolAddress((void**)&w1s_hi, g_w1s_hi); cudaGetSymbolAddress((void**)&w1s_lo, g_w1s_lo);
    cudaGetSymbolAddress((void**)&yc_hi, g_yc_hi);  cudaGetSymbolAddress((void**)&yc_lo, g_yc_lo);
    cudaGetSymbolAddress((void**)&x_hi,  g_x_hi);   cudaGetSymbolAddress((void**)&x_lo,  g_x_lo);
    cudaGetSymbolAddress((void**)&hn_hi, g_hn_hi);  cudaGetSymbolAddress((void**)&hn_lo, g_hn_lo);

    cudaFuncSetAttribute(gemm_sp,    cudaFuncAttributeMaxDynamicSharedMemorySize, SMEM_BYTES);
    cudaFuncSetAttribute(gemm_mixed, cudaFuncAttributeMaxDynamicSharedMemorySize, SMEM_BYTES);
    cudaFuncSetAttribute(attn2,      cudaFuncAttributeMaxDynamicSharedMemorySize, SMEM_BYTES);

    const dim3 blk(256);

    // compaction + merged gathers
    compact_kernel<<<1, 256>>>(equ_mask, sns_mask, offE, offS, mtot);
    gather2<<<dim3(BSZ, 2), 256>>>(equ_enc, sns_enc, equ_mask, sns_mask, offE, offS,
                                   ee_hi, ee_lo, es_hi, es_lo, rowE, rowS, u_e, u_s);

    // one batched split launch for all weights + prev_h
    {
        SplitArgs sa;
        sa.seg[0] = { prev_h, ph_hi, ph_lo, BSZ * DD / 4 };
        sa.seg[1] = { W2e,  wcat_hi,                       wcat_lo,                       HH * DD / 4 };
        sa.seg[2] = { W2s,  wcat_hi + (size_t)HH * DD,     wcat_lo + (size_t)HH * DD,     HH * DD / 4 };
        sa.seg[3] = { w_hh, wcat_hi + (size_t)2 * HH * DD, wcat_lo + (size_t)2 * HH * DD, G3D * DD / 4 };
        sa.seg[4] = { Wc,   wc_hi,  wc_lo,  HH * YC / 4 };
        sa.seg[5] = { w_ih, wih_hi, wih_lo, G3D * HH / 4 };
        sa.seg[6] = { W1e,  w1e_hi, w1e_lo, HH * HH / 4 };
        sa.seg[7] = { W1s,  w1s_hi, w1s_lo, HH * HH / 4 };
        const int maxb = (G3D * DD / 4 + 255) / 256;   // largest segment (w_hh)
        split_all<<<dim3(maxb, 8), blk>>>(sa);
    }

    // fused [dt_e | dt_s | gh] = prev_h @ Wcat^T
    gemm_sp<<<dim3(NCAT / 128, BSZ / 128), blk, SMEM_BYTES>>>(
        ph_hi, ph_lo, wcat_hi, wcat_lo, nullptr, dtgh, nullptr, nullptr, BSZ, NCAT, DD);

    plan_kernel<<<BSZ, 128>>>(prev_h, plan_W, plan_b, plan, out_plan);

    // merged attention: both sides in one launch -> full chip
    attn2<<<dim3(BSZ, 2), blk, SMEM_BYTES>>>(
        ee_hi, ee_lo, es_hi, es_lo,
        w1e_hi, w1e_lo, w1s_hi, w1s_lo,
        dtgh, vte, vts, rowE, rowS, mtot, u_e, u_s);

    // merged softmax + context
    softmax_ctx2<<<dim3(BSZ, 2), blk>>>(u_e, u_s, equ_enc, sns_enc, ctx_e, ctx_s);

    combine_kernel<<<(BSZ * YC) / 256, blk>>>(prev_y, plan, ctx_e, ctx_s, yc_hi, yc_lo);

    gemm_sp<<<dim3(HH / 128, BSZ / 128), blk, SMEM_BYTES>>>(
        yc_hi, yc_lo, wc_hi, wc_lo, bc, nullptr, x_hi, x_lo, BSZ, HH, YC);
    gemm_sp<<<dim3(G3D / 128, BSZ / 128), blk, SMEM_BYTES>>>(
        x_hi, x_lo, wih_hi, wih_lo, b_ih, gx, nullptr, nullptr, BSZ, G3D, HH);

    gru_kernel<<<(BSZ * DD) / 256, blk>>>(gx, dtgh + 2 * HH, b_hh, prev_h, out_hid, hn_hi, hn_lo);

    // dec_output = h_new @ Wout^T + bout (proven R7 path)
    gemm_mixed<<<dim3(VV / 128, BSZ / 128), blk, SMEM_BYTES>>>(
        hn_hi, hn_lo, Wout, bout, out_dec, BSZ, VV, DD);
}

// round 10
// speedup vs baseline: 3.3165x; 1.1180x over previous
#include <cuda_runtime.h>
#include <cuda_bf16.h>
#include <math.h>
#include <stdint.h>

#define HH   512
#define ZZ   128
#define EE   512
#define DD   1152      // 2H + Z
#define VV   32000
#define BSZ  256
#define NN   128
#define G3D  3456      // 3*D
#define NCAT 4480      // 512 (dt_e) + 512 (dt_s) + 3456 (gh)
#define YC   1024      // E + H

// ---------------- scratch (device globals; no allocation allowed) ----------------
__device__ float g_u_e  [BSZ * NN];
__device__ float g_u_s  [BSZ * NN];
__device__ float g_ctx_e[BSZ * HH];
__device__ float g_ctx_s[BSZ * HH];
__device__ float g_plan [BSZ * 2];
__device__ float g_gx   [BSZ * G3D];
__device__ float g_dtgh [BSZ * NCAT];
__device__ int   g_offE [BSZ];
__device__ int   g_offS [BSZ];
__device__ int   g_rowE [BSZ * NN];
__device__ int   g_rowS [BSZ * NN];
__device__ int   g_mtot [2];

__device__ __align__(256) __nv_bfloat16 g_ph_hi [BSZ * DD];
__device__ __align__(256) __nv_bfloat16 g_ph_lo [BSZ * DD];
__device__ __align__(256) __nv_bfloat16 g_ee_hi [BSZ * NN * HH];
__device__ __align__(256) __nv_bfloat16 g_ee_lo [BSZ * NN * HH];
__device__ __align__(256) __nv_bfloat16 g_es_hi [BSZ * NN * HH];
__device__ __align__(256) __nv_bfloat16 g_es_lo [BSZ * NN * HH];
__device__ __align__(256) __nv_bfloat16 g_wcat_hi[NCAT * DD];
__device__ __align__(256) __nv_bfloat16 g_wcat_lo[NCAT * DD];
__device__ __align__(256) __nv_bfloat16 g_wc_hi [HH * YC];
__device__ __align__(256) __nv_bfloat16 g_wc_lo [HH * YC];
__device__ __align__(256) __nv_bfloat16 g_wih_hi[G3D * HH];
__device__ __align__(256) __nv_bfloat16 g_wih_lo[G3D * HH];
__device__ __align__(256) __nv_bfloat16 g_w1e_hi[HH * HH];
__device__ __align__(256) __nv_bfloat16 g_w1e_lo[HH * HH];
__device__ __align__(256) __nv_bfloat16 g_w1s_hi[HH * HH];
__device__ __align__(256) __nv_bfloat16 g_w1s_lo[HH * HH];
__device__ __align__(256) __nv_bfloat16 g_yc_hi [BSZ * YC];
__device__ __align__(256) __nv_bfloat16 g_yc_lo [BSZ * YC];
__device__ __align__(256) __nv_bfloat16 g_x_hi  [BSZ * HH];
__device__ __align__(256) __nv_bfloat16 g_x_lo  [BSZ * HH];
__device__ __align__(256) __nv_bfloat16 g_hn_hi [BSZ * DD];
__device__ __align__(256) __nv_bfloat16 g_hn_lo [BSZ * DD];

// ---------------- helpers ----------------
__device__ __forceinline__ uint32_t pack_bf2(float a, float b) {
    __nv_bfloat162 t = __floats2bfloat162_rn(a, b);
    return *reinterpret_cast<uint32_t*>(&t);
}

__device__ __forceinline__ void mma16816(float c[4],
                                         uint32_t a0, uint32_t a1, uint32_t a2, uint32_t a3,
                                         uint32_t b0, uint32_t b1) {
    asm volatile(
        "mma.sync.aligned.m16n8k16.row.col.f32.bf16.bf16.f32 "
        "{%0,%1,%2,%3}, {%4,%5,%6,%7}, {%8,%9}, {%0,%1,%2,%3};\n"
        : "+f"(c[0]), "+f"(c[1]), "+f"(c[2]), "+f"(c[3])
        : "r"(a0), "r"(a1), "r"(a2), "r"(a3), "r"(b0), "r"(b1));
}

__device__ __forceinline__ void ldsm_x4(uint32_t& r0, uint32_t& r1, uint32_t& r2, uint32_t& r3,
                                        uint32_t addr) {
    asm volatile("ldmatrix.sync.aligned.m8n8.x4.shared.b16 {%0,%1,%2,%3}, [%4];"
                 : "=r"(r0), "=r"(r1), "=r"(r2), "=r"(r3) : "r"(addr));
}
__device__ __forceinline__ void ldsm_x2(uint32_t& r0, uint32_t& r1, uint32_t addr) {
    asm volatile("ldmatrix.sync.aligned.m8n8.x2.shared.b16 {%0,%1}, [%2];"
                 : "=r"(r0), "=r"(r1) : "r"(addr));
}

#define CP16(dst, src) \
    asm volatile("cp.async.cg.shared.global [%0], [%1], 16;" :: "r"(dst), "l"(src))
#define CP_COMMIT() asm volatile("cp.async.commit_group;")
#define CP_WAIT0()  asm volatile("cp.async.wait_group 0;")
#define CP_WAIT1()  asm volatile("cp.async.wait_group 1;")

#define SMS 40
#define STG (128 * SMS)
#define STGB (STG * 2)
#define STAGE4B (4 * STGB)
#define SMEM_BYTES (2 * STAGE4B)

// BM=64 variant constants
#define A64  (64 * SMS)             // elems per A array
#define A64B (A64 * 2)              // bytes
#define S64B (2 * A64B + 2 * STGB)  // 30720 bytes per stage
#define SMEM64 (2 * S64B)           // 61440

__device__ __forceinline__ uint32_t ldsm_aoff(int l) {
    return (uint32_t)((((l & 7) + ((l >> 3) & 1) * 8) * SMS + (l >> 4) * 8) * 2);
}
__device__ __forceinline__ uint32_t ldsm_boff(int l) {
    return (uint32_t)(((l & 7) * SMS + ((l >> 3) & 1) * 8) * 2);
}

__device__ __forceinline__ void cp_stage4(uint32_t d,
                                          const __nv_bfloat16* ah, const __nv_bfloat16* al,
                                          const __nv_bfloat16* bh, const __nv_bfloat16* bl) {
    CP16(d + 0 * STGB,      ah);     CP16(d + 0 * STGB + 16, ah + 8);
    CP16(d + 1 * STGB,      al);     CP16(d + 1 * STGB + 16, al + 8);
    CP16(d + 2 * STGB,      bh);     CP16(d + 2 * STGB + 16, bh + 8);
    CP16(d + 3 * STGB,      bl);     CP16(d + 3 * STGB + 16, bl + 8);
}
__device__ __forceinline__ void cp_stageA(uint32_t d,
                                          const __nv_bfloat16* ah, const __nv_bfloat16* al) {
    CP16(d + 0 * STGB,      ah);     CP16(d + 0 * STGB + 16, ah + 8);
    CP16(d + 1 * STGB,      al);     CP16(d + 1 * STGB + 16, al + 8);
}

__device__ __forceinline__ void mma_chunk(uint32_t stb, uint32_t aoff, uint32_t boff,
                                          float acc[4][4][4], int wr, int wc) {
#pragma unroll
    for (int ks = 0; ks < 2; ks++) {
        const uint32_t kb2 = ks * 32;
        uint32_t bhi[4][2], blo[4][2];
#pragma unroll
        for (int ni = 0; ni < 4; ni++) {
            const uint32_t rb = (uint32_t)(wc * 32 + ni * 8) * (SMS * 2) + kb2 + boff;
            ldsm_x2(bhi[ni][0], bhi[ni][1], stb + 2 * STGB + rb);
            ldsm_x2(blo[ni][0], blo[ni][1], stb + 3 * STGB + rb);
        }
#pragma unroll
        for (int mi = 0; mi < 4; mi++) {
            const uint32_t ra = (uint32_t)(wr * 64 + mi * 16) * (SMS * 2) + kb2 + aoff;
            uint32_t ah[4], al[4];
            ldsm_x4(ah[0], ah[1], ah[2], ah[3], stb + ra);
            ldsm_x4(al[0], al[1], al[2], al[3], stb + STGB + ra);
#pragma unroll
            for (int ni = 0; ni < 4; ni++) {
                mma16816(acc[mi][ni], ah[0], ah[1], ah[2], ah[3], bhi[ni][0], bhi[ni][1]);
                mma16816(acc[mi][ni], ah[0], ah[1], ah[2], ah[3], blo[ni][0], blo[ni][1]);
                mma16816(acc[mi][ni], al[0], al[1], al[2], al[3], bhi[ni][0], bhi[ni][1]);
            }
        }
    }
}

// =================================================================================
// gemm_sp64: BM=64 x BN=128 pre-split bf16x3 GEMM (for small-M GEMMs: better fill)
// 8 warps as 2x4, warp tile 32x32.
// =================================================================================
__global__ void __launch_bounds__(256, 2) gemm_sp64(
    const __nv_bfloat16* __restrict__ Ahi, const __nv_bfloat16* __restrict__ Alo,
    const __nv_bfloat16* __restrict__ Bhi, const __nv_bfloat16* __restrict__ Blo,
    const float* __restrict__ bias,
    float* __restrict__ C, __nv_bfloat16* __restrict__ Chi, __nv_bfloat16* __restrict__ Clo,
    int M, int N, int K)
{
    extern __shared__ __nv_bfloat16 sm[];

    const int t    = threadIdx.x;
    const int m0   = blockIdx.y * 64;
    const int n0   = blockIdx.x * 128;
    const int lane = t & 31;
    const int wid  = t >> 5;
    const int g    = lane >> 2;
    const int tg   = lane & 3;
    const int wr   = wid & 1;
    const int wc   = wid >> 1;

    const uint32_t smb  = (uint32_t)__cvta_generic_to_shared(sm);
    const uint32_t aoff = ldsm_aoff(lane);
    const uint32_t boff = ldsm_boff(lane);

    // staging indices
    const int ar = t >> 2;                 // 0..63
    const int ac = (t & 3) * 8;            // halfs 0,8,16,24
    const uint32_t atoff = (uint32_t)(ar * SMS + ac) * 2;
    const int br = t >> 1;                 // 0..127
    const int bc = (t & 1) * 16;
    const uint32_t btoff = (uint32_t)(br * SMS + bc) * 2;

    const __nv_bfloat16* ApH = Ahi + (size_t)(m0 + ar) * K + ac;
    const __nv_bfloat16* ApL = Alo + (size_t)(m0 + ar) * K + ac;
    const __nv_bfloat16* BpH = Bhi + (size_t)(n0 + br) * K + bc;
    const __nv_bfloat16* BpL = Blo + (size_t)(n0 + br) * K + bc;

    float acc[2][4][4];
#pragma unroll
    for (int mi = 0; mi < 2; mi++)
#pragma unroll
        for (int ni = 0; ni < 4; ni++)
#pragma unroll
            for (int q = 0; q < 4; q++) acc[mi][ni][q] = 0.f;

#define FILL64(D, K0)                                            \
    do {                                                         \
        CP16((D) + atoff,                    ApH + (K0));        \
        CP16((D) + A64B + atoff,             ApL + (K0));        \
        CP16((D) + 2 * A64B + btoff,         BpH + (K0));        \
        CP16((D) + 2 * A64B + btoff + 16,    BpH + (K0) + 8);    \
        CP16((D) + 2 * A64B + STGB + btoff,      BpL + (K0));    \
        CP16((D) + 2 * A64B + STGB + btoff + 16, BpL + (K0) + 8);\
    } while (0)

    FILL64(smb, 0);
    CP_COMMIT();

    for (int k0 = 0; k0 < K; k0 += 32) {
        const int s = (k0 >> 5) & 1;
        const bool more = (k0 + 32 < K);
        if (more) {
            FILL64(smb + (uint32_t)(s ^ 1) * S64B, k0 + 32);
            CP_COMMIT();
            CP_WAIT1();
        } else {
            CP_WAIT0();
        }
        __syncthreads();
        const uint32_t stb = smb + (uint32_t)s * S64B;
#pragma unroll
        for (int ks = 0; ks < 2; ks++) {
            const uint32_t kb2 = ks * 32;
            uint32_t bhi[4][2], blo[4][2];
#pragma unroll
            for (int ni = 0; ni < 4; ni++) {
                const uint32_t rb = (uint32_t)(wc * 32 + ni * 8) * (SMS * 2) + kb2 + boff;
                ldsm_x2(bhi[ni][0], bhi[ni][1], stb + 2 * A64B + rb);
                ldsm_x2(blo[ni][0], blo[ni][1], stb + 2 * A64B + STGB + rb);
            }
#pragma unroll
            for (int mi = 0; mi < 2; mi++) {
                const uint32_t ra = (uint32_t)(wr * 32 + mi * 16) * (SMS * 2) + kb2 + aoff;
                uint32_t ah[4], al[4];
                ldsm_x4(ah[0], ah[1], ah[2], ah[3], stb + ra);
                ldsm_x4(al[0], al[1], al[2], al[3], stb + A64B + ra);
#pragma unroll
                for (int ni = 0; ni < 4; ni++) {
                    mma16816(acc[mi][ni], ah[0], ah[1], ah[2], ah[3], bhi[ni][0], bhi[ni][1]);
                    mma16816(acc[mi][ni], ah[0], ah[1], ah[2], ah[3], blo[ni][0], blo[ni][1]);
                    mma16816(acc[mi][ni], al[0], al[1], al[2], al[3], bhi[ni][0], bhi[ni][1]);
                }
            }
        }
        __syncthreads();
    }

#pragma unroll
    for (int mi = 0; mi < 2; mi++) {
        const int row = m0 + wr * 32 + mi * 16 + g;
#pragma unroll
        for (int ni = 0; ni < 4; ni++) {
            const int col = n0 + wc * 32 + ni * 8 + tg * 2;
            float b0 = bias ? bias[col] : 0.f;
            float b1 = bias ? bias[col + 1] : 0.f;
            float c00 = acc[mi][ni][0] + b0, c01 = acc[mi][ni][1] + b1;
            float c10 = acc[mi][ni][2] + b0, c11 = acc[mi][ni][3] + b1;
            if (C) {
                *(float2*)&C[(size_t)row * N + col]       = make_float2(c00, c01);
                *(float2*)&C[(size_t)(row + 8) * N + col] = make_float2(c10, c11);
            }
            if (Chi) {
                __nv_bfloat16 h00 = __float2bfloat16(c00), h01 = __float2bfloat16(c01);
                __nv_bfloat16 h10 = __float2bfloat16(c10), h11 = __float2bfloat16(c11);
                *(uint32_t*)&Chi[(size_t)row * N + col]       = pack_bf2(c00, c01);
                *(uint32_t*)&Chi[(size_t)(row + 8) * N + col] = pack_bf2(c10, c11);
                *(uint32_t*)&Clo[(size_t)row * N + col] =
                    pack_bf2(c00 - __bfloat162float(h00), c01 - __bfloat162float(h01));
                *(uint32_t*)&Clo[(size_t)(row + 8) * N + col] =
                    pack_bf2(c10 - __bfloat162float(h10), c11 - __bfloat162float(h11));
            }
        }
    }
}

// =================================================================================
// gemm_mixed: split-A bf16 (cp.async) x fp32-B (in-loop split).  For Wout.
// =================================================================================
__global__ void __launch_bounds__(256, 2) gemm_mixed(
    const __nv_bfloat16* __restrict__ Ahi, const __nv_bfloat16* __restrict__ Alo,
    const float* __restrict__ B, const float* __restrict__ bias,
    float* __restrict__ C, int M, int N, int K)
{
    extern __shared__ __nv_bfloat16 sm[];

    const int t    = threadIdx.x;
    const int m0   = blockIdx.y * 128;
    const int n0   = blockIdx.x * 128;
    const int lane = t & 31;
    const int wid  = t >> 5;
    const int g    = lane >> 2;
    const int tg   = lane & 3;
    const int wr   = wid & 1;
    const int wc   = wid >> 1;

    const uint32_t smb  = (uint32_t)__cvta_generic_to_shared(sm);
    const uint32_t aoff = ldsm_aoff(lane);
    const uint32_t boff = ldsm_boff(lane);

    const int r  = t >> 1;
    const int hh = (t & 1) * 16;
    const uint32_t toff = (uint32_t)(r * SMS + hh) * 2;
    const int idx = r * SMS + hh;
    const __nv_bfloat16* ApH = Ahi + (size_t)(m0 + r) * K + hh;
    const __nv_bfloat16* ApL = Alo + (size_t)(m0 + r) * K + hh;
    const float* Bp = B + (size_t)(n0 + r) * K + hh;

    float acc[4][4][4];
#pragma unroll
    for (int mi = 0; mi < 4; mi++)
#pragma unroll
        for (int ni = 0; ni < 4; ni++)
#pragma unroll
            for (int q = 0; q < 4; q++) acc[mi][ni][q] = 0.f;

    cp_stageA(smb + toff, ApH, ApL);
    CP_COMMIT();
    {
        float4 rb[4];
#pragma unroll
        for (int i = 0; i < 4; i++) rb[i] = *(const float4*)(Bp + i * 4);
        __nv_bfloat16* bh = sm + 2 * STG;
        __nv_bfloat16* bl = sm + 3 * STG;
#pragma unroll
        for (int i = 0; i < 4; i++) {
            float x = rb[i].x, y = rb[i].y, z = rb[i].z, w = rb[i].w;
            __nv_bfloat16 hx = __float2bfloat16(x), hy = __float2bfloat16(y);
            __nv_bfloat16 hz = __float2bfloat16(z), hw = __float2bfloat16(w);
            uint2 vh, vl;
            vh.x = pack_bf2(x, y); vh.y = pack_bf2(z, w);
            vl.x = pack_bf2(x - __bfloat162float(hx), y - __bfloat162float(hy));
            vl.y = pack_bf2(z - __bfloat162float(hz), w - __bfloat162float(hw));
            *(uint2*)&bh[idx + i * 4] = vh;
            *(uint2*)&bl[idx + i * 4] = vl;
        }
    }

    for (int k0 = 0; k0 < K; k0 += 32) {
        const int s = (k0 >> 5) & 1;
        const bool more = (k0 + 32 < K);
        float4 rb[4];
        if (more) {
            const uint32_t d = smb + (uint32_t)(s ^ 1) * STAGE4B + toff;
            cp_stageA(d, ApH + k0 + 32, ApL + k0 + 32);
            CP_COMMIT();
#pragma unroll
            for (int i = 0; i < 4; i++) rb[i] = *(const float4*)(Bp + k0 + 32 + i * 4);
            CP_WAIT1();
        } else {
            CP_WAIT0();
        }
        __syncthreads();
        mma_chunk(smb + (uint32_t)s * STAGE4B, aoff, boff, acc, wr, wc);
        if (more) {
            __nv_bfloat16* bh = sm + (s ^ 1) * (STAGE4B / 2) + 2 * STG;
            __nv_bfloat16* bl = sm + (s ^ 1) * (STAGE4B / 2) + 3 * STG;
#pragma unroll
            for (int i = 0; i < 4; i++) {
                float x = rb[i].x, y = rb[i].y, z = rb[i].z, w = rb[i].w;
                __nv_bfloat16 hx = __float2bfloat16(x), hy = __float2bfloat16(y);
                __nv_bfloat16 hz = __float2bfloat16(z), hw = __float2bfloat16(w);
                uint2 vh, vl;
                vh.x = pack_bf2(x, y); vh.y = pack_bf2(z, w);
                vl.x = pack_bf2(x - __bfloat162float(hx), y - __bfloat162float(hy));
                vl.y = pack_bf2(z - __bfloat162float(hz), w - __bfloat162float(hw));
                *(uint2*)&bh[idx + i * 4] = vh;
                *(uint2*)&bl[idx + i * 4] = vl;
            }
        }
        __syncthreads();
    }

#pragma unroll
    for (int mi = 0; mi < 4; mi++) {
        const int row = m0 + wr * 64 + mi * 16 + g;
#pragma unroll
        for (int ni = 0; ni < 4; ni++) {
            const int col = n0 + wc * 32 + ni * 8 + tg * 2;
            float b0 = bias ? bias[col] : 0.f;
            float b1 = bias ? bias[col + 1] : 0.f;
            *(float2*)&C[(size_t)row * N + col] =
                make_float2(acc[mi][ni][0] + b0, acc[mi][ni][1] + b1);
            *(float2*)&C[(size_t)(row + 8) * N + col] =
                make_float2(acc[mi][ni][2] + b0, acc[mi][ni][3] + b1);
        }
    }
}

// =================================================================================
// batched split: one launch does all fp32 -> bf16 hi/lo segments (grid.y = segment)
// =================================================================================
struct SplitSeg { const float* src; __nv_bfloat16* hi; __nv_bfloat16* lo; int n4; };
struct SplitArgs { SplitSeg seg[8]; };

__global__ void split_all(SplitArgs a)
{
    const SplitSeg s = a.seg[blockIdx.y];
    const int i = blockIdx.x * blockDim.x + threadIdx.x;
    if (i >= s.n4) return;
    float4 v = ((const float4*)s.src)[i];
    __nv_bfloat16 hx = __float2bfloat16(v.x), hy = __float2bfloat16(v.y);
    __nv_bfloat16 hz = __float2bfloat16(v.z), hw = __float2bfloat16(v.w);
    uint2 vh, vl;
    vh.x = pack_bf2(v.x, v.y); vh.y = pack_bf2(v.z, v.w);
    vl.x = pack_bf2(v.x - __bfloat162float(hx), v.y - __bfloat162float(hy));
    vl.y = pack_bf2(v.z - __bfloat162float(hz), v.w - __bfloat162float(hw));
    ((uint2*)s.hi)[i] = vh;
    ((uint2*)s.lo)[i] = vl;
}

// =================================================================================
// compact: per-batch exclusive offsets of unmasked positions (both masks)
// =================================================================================
__global__ void compact_kernel(const int* __restrict__ mE, const int* __restrict__ mS,
                               int* __restrict__ offE, int* __restrict__ offS,
                               int* __restrict__ mtot)
{
    __shared__ int sE[256], sS[256];
    const int b = threadIdx.x;
    int cE = 0, cS = 0;
    for (int n = 0; n < NN; n++) {
        cE += (mE[b * NN + n] == 0);
        cS += (mS[b * NN + n] == 0);
    }
    sE[b] = cE; sS[b] = cS;
    __syncthreads();
    for (int d = 1; d < 256; d <<= 1) {
        int vE = 0, vS = 0;
        if (b >= d) { vE = sE[b - d]; vS = sS[b - d]; }
        __syncthreads();
        sE[b] += vE; sS[b] += vS;
        __syncthreads();
    }
    offE[b] = sE[b] - cE;
    offS[b] = sS[b] - cS;
    if (b == 255) { mtot[0] = sE[255]; mtot[1] = sS[255]; }
}

// =================================================================================
// merged gather (grid.y = side): compact unmasked enc rows, split to bf16 hi/lo
// =================================================================================
__global__ void gather2(const float* __restrict__ encE, const float* __restrict__ encS,
                        const int* __restrict__ mE, const int* __restrict__ mS,
                        const int* __restrict__ offE, const int* __restrict__ offS,
                        __nv_bfloat16* __restrict__ geh, __nv_bfloat16* __restrict__ gel,
                        __nv_bfloat16* __restrict__ gsh, __nv_bfloat16* __restrict__ gsl,
                        int* __restrict__ rowE, int* __restrict__ rowS,
                        float* __restrict__ uE, float* __restrict__ uS)
{
    const int side = blockIdx.y;
    const float* enc = side ? encS : encE;
    const int* mask  = side ? mS : mE;
    const int* off   = side ? offS : offE;
    __nv_bfloat16* ghi = side ? gsh : geh;
    __nv_bfloat16* glo = side ? gsl : gel;
    int* rowinfo = side ? rowS : rowE;
    float* u     = side ? uS : uE;

    __shared__ int s_list[NN];
    __shared__ int s_wtot[8];
    const int b = blockIdx.x;
    const int t = threadIdx.x;
    const int base = off[b];
    const bool in = t < NN;
    const bool valid = in && (mask[b * NN + t] == 0);
    const unsigned wm = __ballot_sync(0xffffffffu, valid);
    const int lane = t & 31, w = t >> 5;
    if (lane == 0) s_wtot[w] = __popc(wm);
    __syncthreads();
    int wbase = 0;
#pragma unroll
    for (int i = 0; i < 4; i++) if (i < w) wbase += s_wtot[i];
    const int rank = wbase + __popc(wm & ((1u << lane) - 1));
    if (valid) {
        s_list[rank] = t;
        rowinfo[base + rank] = b * NN + t;
    } else if (in) {
        u[b * NN + t] = -INFINITY;
    }
    __syncthreads();
    const int cnt = s_wtot[0] + s_wtot[1] + s_wtot[2] + s_wtot[3];

    for (int i = 0; i < cnt; i++) {
        const int n = s_list[i];
        const float2 v = *(const float2*)(enc + ((size_t)b * NN + n) * HH + t * 2);
        __nv_bfloat16 h0 = __float2bfloat16(v.x), h1 = __float2bfloat16(v.y);
        *(uint32_t*)&ghi[((size_t)base + i) * HH + t * 2] = pack_bf2(v.x, v.y);
        *(uint32_t*)&glo[((size_t)base + i) * HH + t * 2] =
            pack_bf2(v.x - __bfloat162float(h0), v.y - __bfloat162float(h1));
    }
}

// =================================================================================
// merged attention (grid = (256, 2); blockIdx.y = side).  Over compacted rows.
// =================================================================================
__global__ void __launch_bounds__(256, 2) attn2(
    const __nv_bfloat16* __restrict__ geh, const __nv_bfloat16* __restrict__ gel,
    const __nv_bfloat16* __restrict__ gsh, const __nv_bfloat16* __restrict__ gsl,
    const __nv_bfloat16* __restrict__ w1eh, const __nv_bfloat16* __restrict__ w1el,
    const __nv_bfloat16* __restrict__ w1sh, const __nv_bfloat16* __restrict__ w1sl,
    const float* __restrict__ dtg,
    const float* __restrict__ vte, const float* __restrict__ vts,
    const int* __restrict__ rowE, const int* __restrict__ rowS,
    const int* __restrict__ mtotp,
    float* __restrict__ uE, float* __restrict__ uS)
{
    extern __shared__ __nv_bfloat16 sm[];
    __shared__ float s_vt[512];
    __shared__ float s_u[128];

    const int side = blockIdx.y;
    const int mtot = mtotp[side];
    const int m0 = blockIdx.x * 128;
    if (m0 >= mtot) return;

    const __nv_bfloat16* gehi = side ? gsh : geh;
    const __nv_bfloat16* gelo = side ? gsl : gel;
    const __nv_bfloat16* w1hi = side ? w1sh : w1eh;
    const __nv_bfloat16* w1lo = side ? w1sl : w1el;
    const float* dt = dtg + (side ? HH : 0);
    const float* vt = side ? vts : vte;
    const int* rowinfo = side ? rowS : rowE;
    float* u = side ? uS : uE;

    const int t    = threadIdx.x;
    const int lane = t & 31;
    const int wid  = t >> 5;
    const int g    = lane >> 2;
    const int tg   = lane & 3;
    const int wr   = wid & 1;
    const int wc   = wid >> 1;

    const uint32_t smb  = (uint32_t)__cvta_generic_to_shared(sm);
    const uint32_t aoff = ldsm_aoff(lane);
    const uint32_t boff = ldsm_boff(lane);

    for (int i = t; i < 512; i += 256) s_vt[i] = vt[i];
    if (t < 128) s_u[t] = 0.f;

    int rb4[4][2];
#pragma unroll
    for (int mi = 0; mi < 4; mi++)
#pragma unroll
        for (int rr = 0; rr < 2; rr++)
            rb4[mi][rr] = rowinfo[m0 + wr * 64 + mi * 16 + g + rr * 8] >> 7;

    const int r  = t >> 1;
    const int hh = (t & 1) * 16;
    const uint32_t toff = (uint32_t)(r * SMS + hh) * 2;
    const __nv_bfloat16* ApH = gehi + (size_t)(m0 + r) * 512 + hh;
    const __nv_bfloat16* ApL = gelo + (size_t)(m0 + r) * 512 + hh;

    float up[8];
#pragma unroll
    for (int i = 0; i < 8; i++) up[i] = 0.f;

    for (int nc = 0; nc < 4; nc++) {
        const __nv_bfloat16* BpH = w1hi + (size_t)(nc * 128 + r) * 512 + hh;
        const __nv_bfloat16* BpL = w1lo + (size_t)(nc * 128 + r) * 512 + hh;

        float acc[4][4][4];
#pragma unroll
        for (int mi = 0; mi < 4; mi++)
#pragma unroll
            for (int ni = 0; ni < 4; ni++)
#pragma unroll
                for (int q = 0; q < 4; q++) acc[mi][ni][q] = 0.f;

        cp_stage4(smb + toff, ApH, ApL, BpH, BpL);
        CP_COMMIT();

        for (int k0 = 0; k0 < 512; k0 += 32) {
            const int s = (k0 >> 5) & 1;
            const bool more = (k0 + 32 < 512);
            if (more) {
                const uint32_t d = smb + (uint32_t)(s ^ 1) * STAGE4B + toff;
                cp_stage4(d, ApH + k0 + 32, ApL + k0 + 32, BpH + k0 + 32, BpL + k0 + 32);
                CP_COMMIT();
                CP_WAIT1();
            } else {
                CP_WAIT0();
            }
            __syncthreads();
            mma_chunk(smb + (uint32_t)s * STAGE4B, aoff, boff, acc, wr, wc);
            __syncthreads();
        }

#pragma unroll
        for (int mi = 0; mi < 4; mi++) {
            const float* dt0 = dt + (size_t)rb4[mi][0] * NCAT;
            const float* dt1 = dt + (size_t)rb4[mi][1] * NCAT;
#pragma unroll
            for (int ni = 0; ni < 4; ni++) {
                const int col = nc * 128 + wc * 32 + ni * 8 + tg * 2;
                const float v0 = s_vt[col], v1 = s_vt[col + 1];
                up[mi * 2 + 0] += v0 * tanhf(acc[mi][ni][0] + dt0[col])
                                + v1 * tanhf(acc[mi][ni][1] + dt0[col + 1]);
                up[mi * 2 + 1] += v0 * tanhf(acc[mi][ni][2] + dt1[col])
                                + v1 * tanhf(acc[mi][ni][3] + dt1[col + 1]);
            }
        }
    }

#pragma unroll
    for (int mi = 0; mi < 4; mi++)
#pragma unroll
        for (int rr = 0; rr < 2; rr++) {
            float v = up[mi * 2 + rr];
            v += __shfl_down_sync(0xffffffffu, v, 1);
            v += __shfl_down_sync(0xffffffffu, v, 2);
            if (tg == 0)
                atomicAdd(&s_u[wr * 64 + mi * 16 + g + rr * 8], v);
        }
    __syncthreads();

    if (t < 128 && m0 + t < mtot)
        u[rowinfo[m0 + t]] = s_u[t];
}

// =================================================================================
// plan = softmax(prev_h @ plan_W^T + plan_b)
// =================================================================================
__global__ void plan_kernel(const float* __restrict__ prev_h,
                            const float* __restrict__ plan_W,
                            const float* __restrict__ plan_b,
                            float* __restrict__ plan,
                            float* __restrict__ out_plan)
{
    const int b = blockIdx.x;
    const int t = threadIdx.x;
    __shared__ float s0[128], s1[128];
    float a0 = 0.f, a1 = 0.f;
    const float* hb = prev_h + (size_t)b * DD;
    for (int k = t; k < DD; k += 128) {
        const float h = hb[k];
        a0 += h * plan_W[k];
        a1 += h * plan_W[DD + k];
    }
    s0[t] = a0; s1[t] = a1;
    __syncthreads();
    for (int s = 64; s > 0; s >>= 1) {
        if (t < s) { s0[t] += s0[t + s]; s1[t] += s1[t + s]; }
        __syncthreads();
    }
    if (t == 0) {
        const float l0 = s0[0] + plan_b[0];
        const float l1 = s1[0] + plan_b[1];
        const float mx = fmaxf(l0, l1);
        const float e0 = expf(l0 - mx), e1 = expf(l1 - mx);
        const float inv = 1.f / (e0 + e1);
        plan[2 * b] = e0 * inv;       plan[2 * b + 1] = e1 * inv;
        out_plan[2 * b] = e0 * inv;   out_plan[2 * b + 1] = e1 * inv;
    }
}

// =================================================================================
// merged softmax+context (grid = (BSZ, 2)) — skips masked rows (aw == 0 exactly)
// =================================================================================
__global__ void softmax_ctx2(const float* __restrict__ uE, const float* __restrict__ uS,
                             const float* __restrict__ encE, const float* __restrict__ encS,
                             float* __restrict__ ctxE, float* __restrict__ ctxS)
{
    const int side = blockIdx.y;
    const float* u   = side ? uS : uE;
    const float* enc = side ? encS : encE;
    float* ctx       = side ? ctxS : ctxE;

    const int b = blockIdx.x;
    const int t = threadIdx.x;
    __shared__ float red[256];
    __shared__ float s_aw[NN];
    __shared__ int   s_list[NN];
    __shared__ int   s_wtot[4];

    const float uv = (t < NN) ? u[(size_t)b * NN + t] : -INFINITY;
    red[t] = uv;
    __syncthreads();
    for (int s = 128; s > 0; s >>= 1) {
        if (t < s) red[t] = fmaxf(red[t], red[t + s]);
        __syncthreads();
    }
    const float mx = red[0];
    __syncthreads();
    const float e = (t < NN) ? expf(uv - mx) : 0.f;
    red[t] = e;
    __syncthreads();
    for (int s = 128; s > 0; s >>= 1) {
        if (t < s) red[t] += red[t + s];
        __syncthreads();
    }
    const float inv = 1.f / red[0];

    // compact nonzero-weight rows (masked -> uv == -inf -> weight exactly 0)
    const bool valid = (t < NN) && (uv != -INFINITY);
    const unsigned wm = __ballot_sync(0xffffffffu, valid);
    const int lane = t & 31, w = t >> 5;
    if (lane == 0 && w < 4) s_wtot[w] = __popc(wm);
    __syncthreads();
    int wbase = 0;
#pragma unroll
    for (int i = 0; i < 4; i++) if (i < w) wbase += s_wtot[i];
    if (valid) {
        const int rank = wbase + __popc(wm & ((1u << lane) - 1));
        s_list[rank] = t;
        s_aw[rank] = e * inv;
    }
    __syncthreads();
    const int cnt = s_wtot[0] + s_wtot[1] + s_wtot[2] + s_wtot[3];

    const float* eb = enc + (size_t)b * NN * HH;
    for (int h = t; h < HH; h += 256) {
        float s = 0.f;
        for (int i = 0; i < cnt; i++)
            s += s_aw[i] * eb[(size_t)s_list[i] * HH + h];
        ctx[(size_t)b * HH + h] = s;
    }
}

// =================================================================================
// y_ctx = [prev_y | plan0*ctx_e + plan1*ctx_s], written pre-split
// =================================================================================
__global__ void combine_kernel(const float* __restrict__ prev_y,
                               const float* __restrict__ plan,
                               const float* __restrict__ ctx_e,
                               const float* __restrict__ ctx_s,
                               __nv_bfloat16* __restrict__ ychi,
                               __nv_bfloat16* __restrict__ yclo)
{
    const int idx = blockIdx.x * blockDim.x + threadIdx.x;
    if (idx >= BSZ * YC) return;
    const int b = idx >> 10;
    const int c = idx & 1023;
    float v;
    if (c < EE) {
        v = prev_y[(size_t)b * EE + c];
    } else {
        const float p0 = plan[2 * b], p1 = plan[2 * b + 1];
        const int h = c - EE;
        v = p0 * ctx_e[(size_t)b * HH + h] + p1 * ctx_s[(size_t)b * HH + h];
    }
    __nv_bfloat16 hv = __float2bfloat16(v);
    ychi[idx] = hv;
    yclo[idx] = __float2bfloat16(v - __bfloat162float(hv));
}

// =================================================================================
// GRU cell elementwise; outputs out_hid (fp32) + hn split (bf16 hi/lo)
// =================================================================================
__global__ void gru_kernel(const float* __restrict__ gx,
                           const float* __restrict__ ghbase,
                           const float* __restrict__ b_hh,
                           const float* __restrict__ prev_h,
                           float* __restrict__ out_hid,
                           __nv_bfloat16* __restrict__ hnhi,
                           __nv_bfloat16* __restrict__ hnlo)
{
    const int idx = blockIdx.x * blockDim.x + threadIdx.x;
    if (idx >= BSZ * DD) return;
    const int b = idx / DD;
    const int d = idx - b * DD;
    const float* gxb = gx + (size_t)b * G3D;
    const float* ghb = ghbase + (size_t)b * NCAT;
    const float ghr = ghb[d]          + b_hh[d];
    const float ghz = ghb[DD + d]     + b_hh[DD + d];
    const float ghn = ghb[2 * DD + d] + b_hh[2 * DD + d];
    const float r = 1.f / (1.f + expf(-(gxb[d] + ghr)));
    const float z = 1.f / (1.f + expf(-(gxb[DD + d] + ghz)));
    const float n = tanhf(gxb[2 * DD + d] + r * ghn);
    const float h = (1.f - z) * n + z * prev_h[idx];
    out_hid[idx] = h;
    __nv_bfloat16 hv = __float2bfloat16(h);
    hnhi[idx] = hv;
    hnlo[idx] = __float2bfloat16(h - __bfloat162float(hv));
}

// =================================================================================
// host launcher — graph-capturable
// =================================================================================
extern "C" void kernel_launch(void* const* d_in, const int* in_sizes, int n_in,
                              void* d_out, int out_size)
{
    const float* prev_y  = (const float*)d_in[0];
    const float* prev_h  = (const float*)d_in[1];
    const float* equ_enc = (const float*)d_in[2];
    const float* sns_enc = (const float*)d_in[3];
    const int* equ_mask = (const int*)d_in[5];
    const int* sns_mask = (const int*)d_in[6];
    const float* W1e    = (const float*)d_in[7];
    const float* W2e    = (const float*)d_in[8];
    const float* vte    = (const float*)d_in[9];
    const float* W1s    = (const float*)d_in[10];
    const float* W2s    = (const float*)d_in[11];
    const float* vts    = (const float*)d_in[12];
    const float* plan_W = (const float*)d_in[13];
    const float* plan_b = (const float*)d_in[14];
    const float* Wc     = (const float*)d_in[15];
    const float* bc     = (const float*)d_in[16];
    const float* w_ih   = (const float*)d_in[17];
    const float* w_hh   = (const float*)d_in[18];
    const float* b_ih   = (const float*)d_in[19];
    const float* b_hh   = (const float*)d_in[20];
    const float* Wout   = (const float*)d_in[21];
    const float* bout   = (const float*)d_in[22];

    float* out      = (float*)d_out;
    float* out_dec  = out;
    float* out_hid  = out + (size_t)BSZ * VV;
    float* out_plan = out + (size_t)BSZ * VV + (size_t)BSZ * DD;

    float *u_e, *u_s, *ctx_e, *ctx_s, *plan, *gx, *dtgh;
    int *offE, *offS, *rowE, *rowS, *mtot;
    __nv_bfloat16 *ph_hi, *ph_lo, *ee_hi, *ee_lo, *es_hi, *es_lo;
    __nv_bfloat16 *wcat_hi, *wcat_lo, *wc_hi, *wc_lo, *wih_hi, *wih_lo;
    __nv_bfloat16 *w1e_hi, *w1e_lo, *w1s_hi, *w1s_lo;
    __nv_bfloat16 *yc_hi, *yc_lo, *x_hi, *x_lo, *hn_hi, *hn_lo;
    cudaGetSymbolAddress((void**)&u_e,   g_u_e);
    cudaGetSymbolAddress((void**)&u_s,   g_u_s);
    cudaGetSymbolAddress((void**)&ctx_e, g_ctx_e);
    cudaGetSymbolAddress((void**)&ctx_s, g_ctx_s);
    cudaGetSymbolAddress((void**)&plan,  g_plan);
    cudaGetSymbolAddress((void**)&gx,    g_gx);
    cudaGetSymbolAddress((void**)&dtgh,  g_dtgh);
    cudaGetSymbolAddress((void**)&offE,  g_offE);
    cudaGetSymbolAddress((void**)&offS,  g_offS);
    cudaGetSymbolAddress((void**)&rowE,  g_rowE);
    cudaGetSymbolAddress((void**)&rowS,  g_rowS);
    cudaGetSymbolAddress((void**)&mtot,  g_mtot);
    cudaGetSymbolAddress((void**)&ph_hi, g_ph_hi);  cudaGetSymbolAddress((void**)&ph_lo, g_ph_lo);
    cudaGetSymbolAddress((void**)&ee_hi, g_ee_hi);  cudaGetSymbolAddress((void**)&ee_lo, g_ee_lo);
    cudaGetSymbolAddress((void**)&es_hi, g_es_hi);  cudaGetSymbolAddress((void**)&es_lo, g_es_lo);
    cudaGetSymbolAddress((void**)&wcat_hi, g_wcat_hi); cudaGetSymbolAddress((void**)&wcat_lo, g_wcat_lo);
    cudaGetSymbolAddress((void**)&wc_hi, g_wc_hi);  cudaGetSymbolAddress((void**)&wc_lo, g_wc_lo);
    cudaGetSymbolAddress((void**)&wih_hi, g_wih_hi); cudaGetSymbolAddress((void**)&wih_lo, g_wih_lo);
    cudaGetSymbolAddress((void**)&w1e_hi, g_w1e_hi); cudaGetSymbolAddress((void**)&w1e_lo, g_w1e_lo);
    cudaGetSymbolAddress((void**)&w1s_hi, g_w1s_hi); cudaGetSymbolAddress((void**)&w1s_lo, g_w1s_lo);
    cudaGetSymbolAddress((void**)&yc_hi, g_yc_hi);  cudaGetSymbolAddress((void**)&yc_lo, g_yc_lo);
    cudaGetSymbolAddress((void**)&x_hi,  g_x_hi);   cudaGetSymbolAddress((void**)&x_lo,  g_x_lo);
    cudaGetSymbolAddress((void**)&hn_hi, g_hn_hi);  cudaGetSymbolAddress((void**)&hn_lo, g_hn_lo);

    cudaFuncSetAttribute(gemm_sp64,  cudaFuncAttributeMaxDynamicSharedMemorySize, SMEM64);
    cudaFuncSetAttribute(gemm_mixed, cudaFuncAttributeMaxDynamicSharedMemorySize, SMEM_BYTES);
    cudaFuncSetAttribute(attn2,      cudaFuncAttributeMaxDynamicSharedMemorySize, SMEM_BYTES);

    const dim3 blk(256);

    // compaction + merged gathers
    compact_kernel<<<1, 256>>>(equ_mask, sns_mask, offE, offS, mtot);
    gather2<<<dim3(BSZ, 2), 256>>>(equ_enc, sns_enc, equ_mask, sns_mask, offE, offS,
                                   ee_hi, ee_lo, es_hi, es_lo, rowE, rowS, u_e, u_s);

    // one batched split launch for all weights + prev_h
    {
        SplitArgs sa;
        sa.seg[0] = { prev_h, ph_hi, ph_lo, BSZ * DD / 4 };
        sa.seg[1] = { W2e,  wcat_hi,                       wcat_lo,                       HH * DD / 4 };
        sa.seg[2] = { W2s,  wcat_hi + (size_t)HH * DD,     wcat_lo + (size_t)HH * DD,     HH * DD / 4 };
        sa.seg[3] = { w_hh, wcat_hi + (size_t)2 * HH * DD, wcat_lo + (size_t)2 * HH * DD, G3D * DD / 4 };
        sa.seg[4] = { Wc,   wc_hi,  wc_lo,  HH * YC / 4 };
        sa.seg[5] = { w_ih, wih_hi, wih_lo, G3D * HH / 4 };
        sa.seg[6] = { W1e,  w1e_hi, w1e_lo, HH * HH / 4 };
        sa.seg[7] = { W1s,  w1s_hi, w1s_lo, HH * HH / 4 };
        const int maxb = (G3D * DD / 4 + 255) / 256;   // largest segment (w_hh)
        split_all<<<dim3(maxb, 8), blk>>>(sa);
    }

    // fused [dt_e | dt_s | gh] = prev_h @ Wcat^T  (BM=64: grid (35,4) fills chip)
    gemm_sp64<<<dim3(NCAT / 128, BSZ / 64), blk, SMEM64>>>(
        ph_hi, ph_lo, wcat_hi, wcat_lo, nullptr, dtgh, nullptr, nullptr, BSZ, NCAT, DD);

    plan_kernel<<<BSZ, 128>>>(prev_h, plan_W, plan_b, plan, out_plan);

    // merged attention: both sides in one launch -> full chip
    attn2<<<dim3(BSZ, 2), blk, SMEM_BYTES>>>(
        ee_hi, ee_lo, es_hi, es_lo,
        w1e_hi, w1e_lo, w1s_hi, w1s_lo,
        dtgh, vte, vts, rowE, rowS, mtot, u_e, u_s);

    // merged softmax + context (masked rows skipped)
    softmax_ctx2<<<dim3(BSZ, 2), blk>>>(u_e, u_s, equ_enc, sns_enc, ctx_e, ctx_s);

    combine_kernel<<<(BSZ * YC) / 256, blk>>>(prev_y, plan, ctx_e, ctx_s, yc_hi, yc_lo);

    // x = y_ctx @ Wc^T + bc (split out) ; gx = x @ w_ih^T + b_ih   (BM=64 variants)
    gemm_sp64<<<dim3(HH / 128, BSZ / 64), blk, SMEM64>>>(
        yc_hi, yc_lo, wc_hi, wc_lo, bc, nullptr, x_hi, x_lo, BSZ, HH, YC);
    gemm_sp64<<<dim3(G3D / 128, BSZ / 64), blk, SMEM64>>>(
        x_hi, x_lo, wih_hi, wih_lo, b_ih, gx, nullptr, nullptr, BSZ, G3D, HH);

    gru_kernel<<<(BSZ * DD) / 256, blk>>>(gx, dtgh + 2 * HH, b_hh, prev_h, out_hid, hn_hi, hn_lo);

    // dec_output = h_new @ Wout^T + bout (proven R7 path)
    gemm_mixed<<<dim3(VV / 128, BSZ / 128), blk, SMEM_BYTES>>>(
        hn_hi, hn_lo, Wout, bout, out_dec, BSZ, VV, DD);
}

// round 11
// speedup vs baseline: 3.3586x; 1.0127x over previous
#include <cuda_runtime.h>
#include <cuda_bf16.h>
#include <math.h>
#include <stdint.h>

#define HH   512
#define ZZ   128
#define EE   512
#define DD   1152      // 2H + Z
#define VV   32000
#define BSZ  256
#define NN   128
#define G3D  3456      // 3*D
#define NCAT 4480      // 512 (dt_e) + 512 (dt_s) + 3456 (gh)
#define YC   1024      // E + H

// ---------------- scratch (device globals; no allocation allowed) ----------------
__device__ float g_u_e  [BSZ * NN];
__device__ float g_u_s  [BSZ * NN];
__device__ float g_ctx_e[BSZ * HH];
__device__ float g_ctx_s[BSZ * HH];
__device__ float g_plan [BSZ * 2];
__device__ float g_gx   [BSZ * G3D];
__device__ float g_dtgh [BSZ * NCAT];
__device__ int   g_offE [BSZ];
__device__ int   g_offS [BSZ];
__device__ int   g_rowE [BSZ * NN];
__device__ int   g_rowS [BSZ * NN];
__device__ int   g_mtot [2];

__device__ __align__(256) __nv_bfloat16 g_ph_hi [BSZ * DD];
__device__ __align__(256) __nv_bfloat16 g_ph_lo [BSZ * DD];
__device__ __align__(256) __nv_bfloat16 g_ee_hi [BSZ * NN * HH];
__device__ __align__(256) __nv_bfloat16 g_ee_lo [BSZ * NN * HH];
__device__ __align__(256) __nv_bfloat16 g_es_hi [BSZ * NN * HH];
__device__ __align__(256) __nv_bfloat16 g_es_lo [BSZ * NN * HH];
__device__ __align__(256) __nv_bfloat16 g_wcat_hi[NCAT * DD];
__device__ __align__(256) __nv_bfloat16 g_wcat_lo[NCAT * DD];
__device__ __align__(256) __nv_bfloat16 g_wc_hi [HH * YC];
__device__ __align__(256) __nv_bfloat16 g_wc_lo [HH * YC];
__device__ __align__(256) __nv_bfloat16 g_wih_hi[G3D * HH];
__device__ __align__(256) __nv_bfloat16 g_wih_lo[G3D * HH];
__device__ __align__(256) __nv_bfloat16 g_w1e_hi[HH * HH];
__device__ __align__(256) __nv_bfloat16 g_w1e_lo[HH * HH];
__device__ __align__(256) __nv_bfloat16 g_w1s_hi[HH * HH];
__device__ __align__(256) __nv_bfloat16 g_w1s_lo[HH * HH];
__device__ __align__(256) __nv_bfloat16 g_yc_hi [BSZ * YC];
__device__ __align__(256) __nv_bfloat16 g_yc_lo [BSZ * YC];
__device__ __align__(256) __nv_bfloat16 g_x_hi  [BSZ * HH];
__device__ __align__(256) __nv_bfloat16 g_x_lo  [BSZ * HH];
__device__ __align__(256) __nv_bfloat16 g_hn_hi [BSZ * DD];
__device__ __align__(256) __nv_bfloat16 g_hn_lo [BSZ * DD];

// ---------------- helpers ----------------
__device__ __forceinline__ uint32_t pack_bf2(float a, float b) {
    __nv_bfloat162 t = __floats2bfloat162_rn(a, b);
    return *reinterpret_cast<uint32_t*>(&t);
}

__device__ __forceinline__ void mma16816(float c[4],
                                         uint32_t a0, uint32_t a1, uint32_t a2, uint32_t a3,
                                         uint32_t b0, uint32_t b1) {
    asm volatile(
        "mma.sync.aligned.m16n8k16.row.col.f32.bf16.bf16.f32 "
        "{%0,%1,%2,%3}, {%4,%5,%6,%7}, {%8,%9}, {%0,%1,%2,%3};\n"
        : "+f"(c[0]), "+f"(c[1]), "+f"(c[2]), "+f"(c[3])
        : "r"(a0), "r"(a1), "r"(a2), "r"(a3), "r"(b0), "r"(b1));
}

__device__ __forceinline__ void ldsm_x4(uint32_t& r0, uint32_t& r1, uint32_t& r2, uint32_t& r3,
                                        uint32_t addr) {
    asm volatile("ldmatrix.sync.aligned.m8n8.x4.shared.b16 {%0,%1,%2,%3}, [%4];"
                 : "=r"(r0), "=r"(r1), "=r"(r2), "=r"(r3) : "r"(addr));
}
__device__ __forceinline__ void ldsm_x2(uint32_t& r0, uint32_t& r1, uint32_t addr) {
    asm volatile("ldmatrix.sync.aligned.m8n8.x2.shared.b16 {%0,%1}, [%2];"
                 : "=r"(r0), "=r"(r1) : "r"(addr));
}

#define CP16(dst, src) \
    asm volatile("cp.async.cg.shared.global [%0], [%1], 16;" :: "r"(dst), "l"(src))
#define CP_COMMIT() asm volatile("cp.async.commit_group;")
#define CP_WAIT0()  asm volatile("cp.async.wait_group 0;")

#define SMS 40
#define STG (128 * SMS)
#define STGB (STG * 2)
#define STAGE4B (4 * STGB)
#define SMEM_BYTES (2 * STAGE4B)

// BM=64 variant constants
#define A64  (64 * SMS)
#define A64B (A64 * 2)
#define S64B (2 * A64B + 2 * STGB)  // 30720 bytes per stage
#define SMEM64 (2 * S64B)

__device__ __forceinline__ uint32_t ldsm_aoff(int l) {
    return (uint32_t)((((l & 7) + ((l >> 3) & 1) * 8) * SMS + (l >> 4) * 8) * 2);
}
__device__ __forceinline__ uint32_t ldsm_boff(int l) {
    return (uint32_t)(((l & 7) * SMS + ((l >> 3) & 1) * 8) * 2);
}

__device__ __forceinline__ void cp_stage4(uint32_t d,
                                          const __nv_bfloat16* ah, const __nv_bfloat16* al,
                                          const __nv_bfloat16* bh, const __nv_bfloat16* bl) {
    CP16(d + 0 * STGB,      ah);     CP16(d + 0 * STGB + 16, ah + 8);
    CP16(d + 1 * STGB,      al);     CP16(d + 1 * STGB + 16, al + 8);
    CP16(d + 2 * STGB,      bh);     CP16(d + 2 * STGB + 16, bh + 8);
    CP16(d + 3 * STGB,      bl);     CP16(d + 3 * STGB + 16, bl + 8);
}
__device__ __forceinline__ void cp_stageA(uint32_t d,
                                          const __nv_bfloat16* ah, const __nv_bfloat16* al) {
    CP16(d + 0 * STGB,      ah);     CP16(d + 0 * STGB + 16, ah + 8);
    CP16(d + 1 * STGB,      al);     CP16(d + 1 * STGB + 16, al + 8);
}

__device__ __forceinline__ void mma_chunk(uint32_t stb, uint32_t aoff, uint32_t boff,
                                          float acc[4][4][4], int wr, int wc) {
#pragma unroll
    for (int ks = 0; ks < 2; ks++) {
        const uint32_t kb2 = ks * 32;
        uint32_t bhi[4][2], blo[4][2];
#pragma unroll
        for (int ni = 0; ni < 4; ni++) {
            const uint32_t rb = (uint32_t)(wc * 32 + ni * 8) * (SMS * 2) + kb2 + boff;
            ldsm_x2(bhi[ni][0], bhi[ni][1], stb + 2 * STGB + rb);
            ldsm_x2(blo[ni][0], blo[ni][1], stb + 3 * STGB + rb);
        }
#pragma unroll
        for (int mi = 0; mi < 4; mi++) {
            const uint32_t ra = (uint32_t)(wr * 64 + mi * 16) * (SMS * 2) + kb2 + aoff;
            uint32_t ah[4], al[4];
            ldsm_x4(ah[0], ah[1], ah[2], ah[3], stb + ra);
            ldsm_x4(al[0], al[1], al[2], al[3], stb + STGB + ra);
#pragma unroll
            for (int ni = 0; ni < 4; ni++) {
                mma16816(acc[mi][ni], ah[0], ah[1], ah[2], ah[3], bhi[ni][0], bhi[ni][1]);
                mma16816(acc[mi][ni], ah[0], ah[1], ah[2], ah[3], blo[ni][0], blo[ni][1]);
                mma16816(acc[mi][ni], al[0], al[1], al[2], al[3], bhi[ni][0], bhi[ni][1]);
            }
        }
    }
}

// =================================================================================
// gemm_sp64: BM=64 x BN=128 pre-split bf16x3 GEMM; single barrier per K-chunk.
// Fill for stage s^1 issued AFTER the barrier: all warps completed the previous
// iteration's mma (the last reader of s^1) before any warp can issue the fill.
// =================================================================================
__global__ void __launch_bounds__(256, 2) gemm_sp64(
    const __nv_bfloat16* __restrict__ Ahi, const __nv_bfloat16* __restrict__ Alo,
    const __nv_bfloat16* __restrict__ Bhi, const __nv_bfloat16* __restrict__ Blo,
    const float* __restrict__ bias,
    float* __restrict__ C, __nv_bfloat16* __restrict__ Chi, __nv_bfloat16* __restrict__ Clo,
    int M, int N, int K)
{
    extern __shared__ __nv_bfloat16 sm[];

    const int t    = threadIdx.x;
    const int m0   = blockIdx.y * 64;
    const int n0   = blockIdx.x * 128;
    const int lane = t & 31;
    const int wid  = t >> 5;
    const int g    = lane >> 2;
    const int tg   = lane & 3;
    const int wr   = wid & 1;
    const int wc   = wid >> 1;

    const uint32_t smb  = (uint32_t)__cvta_generic_to_shared(sm);
    const uint32_t aoff = ldsm_aoff(lane);
    const uint32_t boff = ldsm_boff(lane);

    const int ar = t >> 2;
    const int ac = (t & 3) * 8;
    const uint32_t atoff = (uint32_t)(ar * SMS + ac) * 2;
    const int br = t >> 1;
    const int bc = (t & 1) * 16;
    const uint32_t btoff = (uint32_t)(br * SMS + bc) * 2;

    const __nv_bfloat16* ApH = Ahi + (size_t)(m0 + ar) * K + ac;
    const __nv_bfloat16* ApL = Alo + (size_t)(m0 + ar) * K + ac;
    const __nv_bfloat16* BpH = Bhi + (size_t)(n0 + br) * K + bc;
    const __nv_bfloat16* BpL = Blo + (size_t)(n0 + br) * K + bc;

    float acc[2][4][4];
#pragma unroll
    for (int mi = 0; mi < 2; mi++)
#pragma unroll
        for (int ni = 0; ni < 4; ni++)
#pragma unroll
            for (int q = 0; q < 4; q++) acc[mi][ni][q] = 0.f;

#define FILL64(D, K0)                                            \
    do {                                                         \
        CP16((D) + atoff,                    ApH + (K0));        \
        CP16((D) + A64B + atoff,             ApL + (K0));        \
        CP16((D) + 2 * A64B + btoff,         BpH + (K0));        \
        CP16((D) + 2 * A64B + btoff + 16,    BpH + (K0) + 8);    \
        CP16((D) + 2 * A64B + STGB + btoff,      BpL + (K0));    \
        CP16((D) + 2 * A64B + STGB + btoff + 16, BpL + (K0) + 8);\
    } while (0)

    FILL64(smb, 0);
    CP_COMMIT();

    for (int k0 = 0; k0 < K; k0 += 32) {
        const int s = (k0 >> 5) & 1;
        const bool more = (k0 + 32 < K);
        CP_WAIT0();                       // stage s complete (own copies)
        __syncthreads();                  // all copies visible; all prev mma done
        if (more) {
            FILL64(smb + (uint32_t)(s ^ 1) * S64B, k0 + 32);
            CP_COMMIT();
        }
        const uint32_t stb = smb + (uint32_t)s * S64B;
#pragma unroll
        for (int ks = 0; ks < 2; ks++) {
            const uint32_t kb2 = ks * 32;
            uint32_t bhi[4][2], blo[4][2];
#pragma unroll
            for (int ni = 0; ni < 4; ni++) {
                const uint32_t rb = (uint32_t)(wc * 32 + ni * 8) * (SMS * 2) + kb2 + boff;
                ldsm_x2(bhi[ni][0], bhi[ni][1], stb + 2 * A64B + rb);
                ldsm_x2(blo[ni][0], blo[ni][1], stb + 2 * A64B + STGB + rb);
            }
#pragma unroll
            for (int mi = 0; mi < 2; mi++) {
                const uint32_t ra = (uint32_t)(wr * 32 + mi * 16) * (SMS * 2) + kb2 + aoff;
                uint32_t ah[4], al[4];
                ldsm_x4(ah[0], ah[1], ah[2], ah[3], stb + ra);
                ldsm_x4(al[0], al[1], al[2], al[3], stb + A64B + ra);
#pragma unroll
                for (int ni = 0; ni < 4; ni++) {
                    mma16816(acc[mi][ni], ah[0], ah[1], ah[2], ah[3], bhi[ni][0], bhi[ni][1]);
                    mma16816(acc[mi][ni], ah[0], ah[1], ah[2], ah[3], blo[ni][0], blo[ni][1]);
                    mma16816(acc[mi][ni], al[0], al[1], al[2], al[3], bhi[ni][0], bhi[ni][1]);
                }
            }
        }
    }

#pragma unroll
    for (int mi = 0; mi < 2; mi++) {
        const int row = m0 + wr * 32 + mi * 16 + g;
#pragma unroll
        for (int ni = 0; ni < 4; ni++) {
            const int col = n0 + wc * 32 + ni * 8 + tg * 2;
            float b0 = bias ? bias[col] : 0.f;
            float b1 = bias ? bias[col + 1] : 0.f;
            float c00 = acc[mi][ni][0] + b0, c01 = acc[mi][ni][1] + b1;
            float c10 = acc[mi][ni][2] + b0, c11 = acc[mi][ni][3] + b1;
            if (C) {
                *(float2*)&C[(size_t)row * N + col]       = make_float2(c00, c01);
                *(float2*)&C[(size_t)(row + 8) * N + col] = make_float2(c10, c11);
            }
            if (Chi) {
                __nv_bfloat16 h00 = __float2bfloat16(c00), h01 = __float2bfloat16(c01);
                __nv_bfloat16 h10 = __float2bfloat16(c10), h11 = __float2bfloat16(c11);
                *(uint32_t*)&Chi[(size_t)row * N + col]       = pack_bf2(c00, c01);
                *(uint32_t*)&Chi[(size_t)(row + 8) * N + col] = pack_bf2(c10, c11);
                *(uint32_t*)&Clo[(size_t)row * N + col] =
                    pack_bf2(c00 - __bfloat162float(h00), c01 - __bfloat162float(h01));
                *(uint32_t*)&Clo[(size_t)(row + 8) * N + col] =
                    pack_bf2(c10 - __bfloat162float(h10), c11 - __bfloat162float(h11));
            }
        }
    }
}

// =================================================================================
// gemm_mixed: split-A bf16 (cp.async) x fp32-B (in-loop split); single barrier.
// B regs loaded before mma (LDG hides under mma); split-store after mma targets
// stage s^1 — safe post-barrier by the same argument.
// =================================================================================
__global__ void __launch_bounds__(256, 2) gemm_mixed(
    const __nv_bfloat16* __restrict__ Ahi, const __nv_bfloat16* __restrict__ Alo,
    const float* __restrict__ B, const float* __restrict__ bias,
    float* __restrict__ C, int M, int N, int K)
{
    extern __shared__ __nv_bfloat16 sm[];

    const int t    = threadIdx.x;
    const int m0   = blockIdx.y * 128;
    const int n0   = blockIdx.x * 128;
    const int lane = t & 31;
    const int wid  = t >> 5;
    const int g    = lane >> 2;
    const int tg   = lane & 3;
    const int wr   = wid & 1;
    const int wc   = wid >> 1;

    const uint32_t smb  = (uint32_t)__cvta_generic_to_shared(sm);
    const uint32_t aoff = ldsm_aoff(lane);
    const uint32_t boff = ldsm_boff(lane);

    const int r  = t >> 1;
    const int hh = (t & 1) * 16;
    const uint32_t toff = (uint32_t)(r * SMS + hh) * 2;
    const int idx = r * SMS + hh;
    const __nv_bfloat16* ApH = Ahi + (size_t)(m0 + r) * K + hh;
    const __nv_bfloat16* ApL = Alo + (size_t)(m0 + r) * K + hh;
    const float* Bp = B + (size_t)(n0 + r) * K + hh;

    float acc[4][4][4];
#pragma unroll
    for (int mi = 0; mi < 4; mi++)
#pragma unroll
        for (int ni = 0; ni < 4; ni++)
#pragma unroll
            for (int q = 0; q < 4; q++) acc[mi][ni][q] = 0.f;

#define SPLITB(ST, RB)                                                         \
    do {                                                                       \
        __nv_bfloat16* bh = sm + (ST) * (STAGE4B / 2) + 2 * STG;               \
        __nv_bfloat16* bl = sm + (ST) * (STAGE4B / 2) + 3 * STG;               \
        _Pragma("unroll")                                                      \
        for (int i = 0; i < 4; i++) {                                          \
            float x = (RB)[i].x, y = (RB)[i].y, z = (RB)[i].z, w = (RB)[i].w;  \
            __nv_bfloat16 hx = __float2bfloat16(x), hy = __float2bfloat16(y);  \
            __nv_bfloat16 hz = __float2bfloat16(z), hw = __float2bfloat16(w);  \
            uint2 vh, vl;                                                      \
            vh.x = pack_bf2(x, y); vh.y = pack_bf2(z, w);                      \
            vl.x = pack_bf2(x - __bfloat162float(hx), y - __bfloat162float(hy));\
            vl.y = pack_bf2(z - __bfloat162float(hz), w - __bfloat162float(hw));\
            *(uint2*)&bh[idx + i * 4] = vh;                                    \
            *(uint2*)&bl[idx + i * 4] = vl;                                    \
        }                                                                      \
    } while (0)

    // prologue: stage 0
    cp_stageA(smb + toff, ApH, ApL);
    CP_COMMIT();
    {
        float4 rb0[4];
#pragma unroll
        for (int i = 0; i < 4; i++) rb0[i] = *(const float4*)(Bp + i * 4);
        SPLITB(0, rb0);
    }

    for (int k0 = 0; k0 < K; k0 += 32) {
        const int s = (k0 >> 5) & 1;
        const bool more = (k0 + 32 < K);
        CP_WAIT0();                       // A stage s done (own copies)
        __syncthreads();                  // A visible + B STS visible + prev mma done
        float4 rb[4];
        if (more) {
            cp_stageA(smb + (uint32_t)(s ^ 1) * STAGE4B + toff, ApH + k0 + 32, ApL + k0 + 32);
            CP_COMMIT();
#pragma unroll
            for (int i = 0; i < 4; i++) rb[i] = *(const float4*)(Bp + k0 + 32 + i * 4);
        }
        mma_chunk(smb + (uint32_t)s * STAGE4B, aoff, boff, acc, wr, wc);
        if (more) SPLITB(s ^ 1, rb);
    }

#pragma unroll
    for (int mi = 0; mi < 4; mi++) {
        const int row = m0 + wr * 64 + mi * 16 + g;
#pragma unroll
        for (int ni = 0; ni < 4; ni++) {
            const int col = n0 + wc * 32 + ni * 8 + tg * 2;
            float b0 = bias ? bias[col] : 0.f;
            float b1 = bias ? bias[col + 1] : 0.f;
            *(float2*)&C[(size_t)row * N + col] =
                make_float2(acc[mi][ni][0] + b0, acc[mi][ni][1] + b1);
            *(float2*)&C[(size_t)(row + 8) * N + col] =
                make_float2(acc[mi][ni][2] + b0, acc[mi][ni][3] + b1);
        }
    }
}

// =================================================================================
// batched split: one launch does all fp32 -> bf16 hi/lo segments (grid.y = segment)
// =================================================================================
struct SplitSeg { const float* src; __nv_bfloat16* hi; __nv_bfloat16* lo; int n4; };
struct SplitArgs { SplitSeg seg[8]; };

__global__ void split_all(SplitArgs a)
{
    const SplitSeg s = a.seg[blockIdx.y];
    const int i = blockIdx.x * blockDim.x + threadIdx.x;
    if (i >= s.n4) return;
    float4 v = ((const float4*)s.src)[i];
    __nv_bfloat16 hx = __float2bfloat16(v.x), hy = __float2bfloat16(v.y);
    __nv_bfloat16 hz = __float2bfloat16(v.z), hw = __float2bfloat16(v.w);
    uint2 vh, vl;
    vh.x = pack_bf2(v.x, v.y); vh.y = pack_bf2(v.z, v.w);
    vl.x = pack_bf2(v.x - __bfloat162float(hx), v.y - __bfloat162float(hy));
    vl.y = pack_bf2(v.z - __bfloat162float(hz), v.w - __bfloat162float(hw));
    ((uint2*)s.hi)[i] = vh;
    ((uint2*)s.lo)[i] = vl;
}

// =================================================================================
// compact: per-batch exclusive offsets of unmasked positions (both masks)
// =================================================================================
__global__ void compact_kernel(const int* __restrict__ mE, const int* __restrict__ mS,
                               int* __restrict__ offE, int* __restrict__ offS,
                               int* __restrict__ mtot)
{
    __shared__ int sE[256], sS[256];
    const int b = threadIdx.x;
    int cE = 0, cS = 0;
    for (int n = 0; n < NN; n++) {
        cE += (mE[b * NN + n] == 0);
        cS += (mS[b * NN + n] == 0);
    }
    sE[b] = cE; sS[b] = cS;
    __syncthreads();
    for (int d = 1; d < 256; d <<= 1) {
        int vE = 0, vS = 0;
        if (b >= d) { vE = sE[b - d]; vS = sS[b - d]; }
        __syncthreads();
        sE[b] += vE; sS[b] += vS;
        __syncthreads();
    }
    offE[b] = sE[b] - cE;
    offS[b] = sS[b] - cS;
    if (b == 255) { mtot[0] = sE[255]; mtot[1] = sS[255]; }
}

// =================================================================================
// merged gather (grid.y = side)
// =================================================================================
__global__ void gather2(const float* __restrict__ encE, const float* __restrict__ encS,
                        const int* __restrict__ mE, const int* __restrict__ mS,
                        const int* __restrict__ offE, const int* __restrict__ offS,
                        __nv_bfloat16* __restrict__ geh, __nv_bfloat16* __restrict__ gel,
                        __nv_bfloat16* __restrict__ gsh, __nv_bfloat16* __restrict__ gsl,
                        int* __restrict__ rowE, int* __restrict__ rowS,
                        float* __restrict__ uE, float* __restrict__ uS)
{
    const int side = blockIdx.y;
    const float* enc = side ? encS : encE;
    const int* mask  = side ? mS : mE;
    const int* off   = side ? offS : offE;
    __nv_bfloat16* ghi = side ? gsh : geh;
    __nv_bfloat16* glo = side ? gsl : gel;
    int* rowinfo = side ? rowS : rowE;
    float* u     = side ? uS : uE;

    __shared__ int s_list[NN];
    __shared__ int s_wtot[8];
    const int b = blockIdx.x;
    const int t = threadIdx.x;
    const int base = off[b];
    const bool in = t < NN;
    const bool valid = in && (mask[b * NN + t] == 0);
    const unsigned wm = __ballot_sync(0xffffffffu, valid);
    const int lane = t & 31, w = t >> 5;
    if (lane == 0) s_wtot[w] = __popc(wm);
    __syncthreads();
    int wbase = 0;
#pragma unroll
    for (int i = 0; i < 4; i++) if (i < w) wbase += s_wtot[i];
    const int rank = wbase + __popc(wm & ((1u << lane) - 1));
    if (valid) {
        s_list[rank] = t;
        rowinfo[base + rank] = b * NN + t;
    } else if (in) {
        u[b * NN + t] = -INFINITY;
    }
    __syncthreads();
    const int cnt = s_wtot[0] + s_wtot[1] + s_wtot[2] + s_wtot[3];

    for (int i = 0; i < cnt; i++) {
        const int n = s_list[i];
        const float2 v = *(const float2*)(enc + ((size_t)b * NN + n) * HH + t * 2);
        __nv_bfloat16 h0 = __float2bfloat16(v.x), h1 = __float2bfloat16(v.y);
        *(uint32_t*)&ghi[((size_t)base + i) * HH + t * 2] = pack_bf2(v.x, v.y);
        *(uint32_t*)&glo[((size_t)base + i) * HH + t * 2] =
            pack_bf2(v.x - __bfloat162float(h0), v.y - __bfloat162float(h1));
    }
}

// =================================================================================
// merged attention (grid = (256, 2)); single barrier per K-chunk.
// =================================================================================
__global__ void __launch_bounds__(256, 2) attn2(
    const __nv_bfloat16* __restrict__ geh, const __nv_bfloat16* __restrict__ gel,
    const __nv_bfloat16* __restrict__ gsh, const __nv_bfloat16* __restrict__ gsl,
    const __nv_bfloat16* __restrict__ w1eh, const __nv_bfloat16* __restrict__ w1el,
    const __nv_bfloat16* __restrict__ w1sh, const __nv_bfloat16* __restrict__ w1sl,
    const float* __restrict__ dtg,
    const float* __restrict__ vte, const float* __restrict__ vts,
    const int* __restrict__ rowE, const int* __restrict__ rowS,
    const int* __restrict__ mtotp,
    float* __restrict__ uE, float* __restrict__ uS)
{
    extern __shared__ __nv_bfloat16 sm[];
    __shared__ float s_vt[512];
    __shared__ float s_u[128];

    const int side = blockIdx.y;
    const int mtot = mtotp[side];
    const int m0 = blockIdx.x * 128;
    if (m0 >= mtot) return;

    const __nv_bfloat16* gehi = side ? gsh : geh;
    const __nv_bfloat16* gelo = side ? gsl : gel;
    const __nv_bfloat16* w1hi = side ? w1sh : w1eh;
    const __nv_bfloat16* w1lo = side ? w1sl : w1el;
    const float* dt = dtg + (side ? HH : 0);
    const float* vt = side ? vts : vte;
    const int* rowinfo = side ? rowS : rowE;
    float* u = side ? uS : uE;

    const int t    = threadIdx.x;
    const int lane = t & 31;
    const int wid  = t >> 5;
    const int g    = lane >> 2;
    const int tg   = lane & 3;
    const int wr   = wid & 1;
    const int wc   = wid >> 1;

    const uint32_t smb  = (uint32_t)__cvta_generic_to_shared(sm);
    const uint32_t aoff = ldsm_aoff(lane);
    const uint32_t boff = ldsm_boff(lane);

    for (int i = t; i < 512; i += 256) s_vt[i] = vt[i];
    if (t < 128) s_u[t] = 0.f;

    int rb4[4][2];
#pragma unroll
    for (int mi = 0; mi < 4; mi++)
#pragma unroll
        for (int rr = 0; rr < 2; rr++)
            rb4[mi][rr] = rowinfo[m0 + wr * 64 + mi * 16 + g + rr * 8] >> 7;

    const int r  = t >> 1;
    const int hh = (t & 1) * 16;
    const uint32_t toff = (uint32_t)(r * SMS + hh) * 2;
    const __nv_bfloat16* ApH = gehi + (size_t)(m0 + r) * 512 + hh;
    const __nv_bfloat16* ApL = gelo + (size_t)(m0 + r) * 512 + hh;

    float up[8];
#pragma unroll
    for (int i = 0; i < 8; i++) up[i] = 0.f;

    for (int nc = 0; nc < 4; nc++) {
        const __nv_bfloat16* BpH = w1hi + (size_t)(nc * 128 + r) * 512 + hh;
        const __nv_bfloat16* BpL = w1lo + (size_t)(nc * 128 + r) * 512 + hh;

        float acc[4][4][4];
#pragma unroll
        for (int mi = 0; mi < 4; mi++)
#pragma unroll
            for (int ni = 0; ni < 4; ni++)
#pragma unroll
                for (int q = 0; q < 4; q++) acc[mi][ni][q] = 0.f;

        cp_stage4(smb + toff, ApH, ApL, BpH, BpL);
        CP_COMMIT();

        for (int k0 = 0; k0 < 512; k0 += 32) {
            const int s = (k0 >> 5) & 1;
            const bool more = (k0 + 32 < 512);
            CP_WAIT0();
            __syncthreads();
            if (more) {
                cp_stage4(smb + (uint32_t)(s ^ 1) * STAGE4B + toff,
                          ApH + k0 + 32, ApL + k0 + 32, BpH + k0 + 32, BpL + k0 + 32);
                CP_COMMIT();
            }
            mma_chunk(smb + (uint32_t)s * STAGE4B, aoff, boff, acc, wr, wc);
        }

#pragma unroll
        for (int mi = 0; mi < 4; mi++) {
            const float* dt0 = dt + (size_t)rb4[mi][0] * NCAT;
            const float* dt1 = dt + (size_t)rb4[mi][1] * NCAT;
#pragma unroll
            for (int ni = 0; ni < 4; ni++) {
                const int col = nc * 128 + wc * 32 + ni * 8 + tg * 2;
                const float v0 = s_vt[col], v1 = s_vt[col + 1];
                up[mi * 2 + 0] += v0 * tanhf(acc[mi][ni][0] + dt0[col])
                                + v1 * tanhf(acc[mi][ni][1] + dt0[col + 1]);
                up[mi * 2 + 1] += v0 * tanhf(acc[mi][ni][2] + dt1[col])
                                + v1 * tanhf(acc[mi][ni][3] + dt1[col + 1]);
            }
        }
    }

#pragma unroll
    for (int mi = 0; mi < 4; mi++)
#pragma unroll
        for (int rr = 0; rr < 2; rr++) {
            float v = up[mi * 2 + rr];
            v += __shfl_down_sync(0xffffffffu, v, 1);
            v += __shfl_down_sync(0xffffffffu, v, 2);
            if (tg == 0)
                atomicAdd(&s_u[wr * 64 + mi * 16 + g + rr * 8], v);
        }
    __syncthreads();

    if (t < 128 && m0 + t < mtot)
        u[rowinfo[m0 + t]] = s_u[t];
}

// =================================================================================
// plan = softmax(prev_h @ plan_W^T + plan_b)
// =================================================================================
__global__ void plan_kernel(const float* __restrict__ prev_h,
                            const float* __restrict__ plan_W,
                            const float* __restrict__ plan_b,
                            float* __restrict__ plan,
                            float* __restrict__ out_plan)
{
    const int b = blockIdx.x;
    const int t = threadIdx.x;
    __shared__ float s0[128], s1[128];
    float a0 = 0.f, a1 = 0.f;
    const float* hb = prev_h + (size_t)b * DD;
    for (int k = t; k < DD; k += 128) {
        const float h = hb[k];
        a0 += h * plan_W[k];
        a1 += h * plan_W[DD + k];
    }
    s0[t] = a0; s1[t] = a1;
    __syncthreads();
    for (int s = 64; s > 0; s >>= 1) {
        if (t < s) { s0[t] += s0[t + s]; s1[t] += s1[t + s]; }
        __syncthreads();
    }
    if (t == 0) {
        const float l0 = s0[0] + plan_b[0];
        const float l1 = s1[0] + plan_b[1];
        const float mx = fmaxf(l0, l1);
        const float e0 = expf(l0 - mx), e1 = expf(l1 - mx);
        const float inv = 1.f / (e0 + e1);
        plan[2 * b] = e0 * inv;       plan[2 * b + 1] = e1 * inv;
        out_plan[2 * b] = e0 * inv;   out_plan[2 * b + 1] = e1 * inv;
    }
}

// =================================================================================
// merged softmax+context (grid = (BSZ, 2)) — skips masked rows (aw == 0 exactly)
// =================================================================================
__global__ void softmax_ctx2(const float* __restrict__ uE, const float* __restrict__ uS,
                             const float* __restrict__ encE, const float* __restrict__ encS,
                             float* __restrict__ ctxE, float* __restrict__ ctxS)
{
    const int side = blockIdx.y;
    const float* u   = side ? uS : uE;
    const float* enc = side ? encS : encE;
    float* ctx       = side ? ctxS : ctxE;

    const int b = blockIdx.x;
    const int t = threadIdx.x;
    __shared__ float red[256];
    __shared__ float s_aw[NN];
    __shared__ int   s_list[NN];
    __shared__ int   s_wtot[4];

    const float uv = (t < NN) ? u[(size_t)b * NN + t] : -INFINITY;
    red[t] = uv;
    __syncthreads();
    for (int s = 128; s > 0; s >>= 1) {
        if (t < s) red[t] = fmaxf(red[t], red[t + s]);
        __syncthreads();
    }
    const float mx = red[0];
    __syncthreads();
    const float e = (t < NN) ? expf(uv - mx) : 0.f;
    red[t] = e;
    __syncthreads();
    for (int s = 128; s > 0; s >>= 1) {
        if (t < s) red[t] += red[t + s];
        __syncthreads();
    }
    const float inv = 1.f / red[0];

    const bool valid = (t < NN) && (uv != -INFINITY);
    const unsigned wm = __ballot_sync(0xffffffffu, valid);
    const int lane = t & 31, w = t >> 5;
    if (lane == 0 && w < 4) s_wtot[w] = __popc(wm);
    __syncthreads();
    int wbase = 0;
#pragma unroll
    for (int i = 0; i < 4; i++) if (i < w) wbase += s_wtot[i];
    if (valid) {
        const int rank = wbase + __popc(wm & ((1u << lane) - 1));
        s_list[rank] = t;
        s_aw[rank] = e * inv;
    }
    __syncthreads();
    const int cnt = s_wtot[0] + s_wtot[1] + s_wtot[2] + s_wtot[3];

    const float* eb = enc + (size_t)b * NN * HH;
    for (int h = t; h < HH; h += 256) {
        float s = 0.f;
        for (int i = 0; i < cnt; i++)
            s += s_aw[i] * eb[(size_t)s_list[i] * HH + h];
        ctx[(size_t)b * HH + h] = s;
    }
}

// =================================================================================
// y_ctx = [prev_y | plan0*ctx_e + plan1*ctx_s], written pre-split
// =================================================================================
__global__ void combine_kernel(const float* __restrict__ prev_y,
                               const float* __restrict__ plan,
                               const float* __restrict__ ctx_e,
                               const float* __restrict__ ctx_s,
                               __nv_bfloat16* __restrict__ ychi,
                               __nv_bfloat16* __restrict__ yclo)
{
    const int idx = blockIdx.x * blockDim.x + threadIdx.x;
    if (idx >= BSZ * YC) return;
    const int b = idx >> 10;
    const int c = idx & 1023;
    float v;
    if (c < EE) {
        v = prev_y[(size_t)b * EE + c];
    } else {
        const float p0 = plan[2 * b], p1 = plan[2 * b + 1];
        const int h = c - EE;
        v = p0 * ctx_e[(size_t)b * HH + h] + p1 * ctx_s[(size_t)b * HH + h];
    }
    __nv_bfloat16 hv = __float2bfloat16(v);
    ychi[idx] = hv;
    yclo[idx] = __float2bfloat16(v - __bfloat162float(hv));
}

// =================================================================================
// GRU cell elementwise; outputs out_hid (fp32) + hn split (bf16 hi/lo)
// =================================================================================
__global__ void gru_kernel(const float* __restrict__ gx,
                           const float* __restrict__ ghbase,
                           const float* __restrict__ b_hh,
                           const float* __restrict__ prev_h,
                           float* __restrict__ out_hid,
                           __nv_bfloat16* __restrict__ hnhi,
                           __nv_bfloat16* __restrict__ hnlo)
{
    const int idx = blockIdx.x * blockDim.x + threadIdx.x;
    if (idx >= BSZ * DD) return;
    const int b = idx / DD;
    const int d = idx - b * DD;
    const float* gxb = gx + (size_t)b * G3D;
    const float* ghb = ghbase + (size_t)b * NCAT;
    const float ghr = ghb[d]          + b_hh[d];
    const float ghz = ghb[DD + d]     + b_hh[DD + d];
    const float ghn = ghb[2 * DD + d] + b_hh[2 * DD + d];
    const float r = 1.f / (1.f + expf(-(gxb[d] + ghr)));
    const float z = 1.f / (1.f + expf(-(gxb[DD + d] + ghz)));
    const float n = tanhf(gxb[2 * DD + d] + r * ghn);
    const float h = (1.f - z) * n + z * prev_h[idx];
    out_hid[idx] = h;
    __nv_bfloat16 hv = __float2bfloat16(h);
    hnhi[idx] = hv;
    hnlo[idx] = __float2bfloat16(h - __bfloat162float(hv));
}

// =================================================================================
// host launcher — graph-capturable
// =================================================================================
extern "C" void kernel_launch(void* const* d_in, const int* in_sizes, int n_in,
                              void* d_out, int out_size)
{
    const float* prev_y  = (const float*)d_in[0];
    const float* prev_h  = (const float*)d_in[1];
    const float* equ_enc = (const float*)d_in[2];
    const float* sns_enc = (const float*)d_in[3];
    const int* equ_mask = (const int*)d_in[5];
    const int* sns_mask = (const int*)d_in[6];
    const float* W1e    = (const float*)d_in[7];
    const float* W2e    = (const float*)d_in[8];
    const float* vte    = (const float*)d_in[9];
    const float* W1s    = (const float*)d_in[10];
    const float* W2s    = (const float*)d_in[11];
    const float* vts    = (const float*)d_in[12];
    const float* plan_W = (const float*)d_in[13];
    const float* plan_b = (const float*)d_in[14];
    const float* Wc     = (const float*)d_in[15];
    const float* bc     = (const float*)d_in[16];
    const float* w_ih   = (const float*)d_in[17];
    const float* w_hh   = (const float*)d_in[18];
    const float* b_ih   = (const float*)d_in[19];
    const float* b_hh   = (const float*)d_in[20];
    const float* Wout   = (const float*)d_in[21];
    const float* bout   = (const float*)d_in[22];

    float* out      = (float*)d_out;
    float* out_dec  = out;
    float* out_hid  = out + (size_t)BSZ * VV;
    float* out_plan = out + (size_t)BSZ * VV + (size_t)BSZ * DD;

    float *u_e, *u_s, *ctx_e, *ctx_s, *plan, *gx, *dtgh;
    int *offE, *offS, *rowE, *rowS, *mtot;
    __nv_bfloat16 *ph_hi, *ph_lo, *ee_hi, *ee_lo, *es_hi, *es_lo;
    __nv_bfloat16 *wcat_hi, *wcat_lo, *wc_hi, *wc_lo, *wih_hi, *wih_lo;
    __nv_bfloat16 *w1e_hi, *w1e_lo, *w1s_hi, *w1s_lo;
    __nv_bfloat16 *yc_hi, *yc_lo, *x_hi, *x_lo, *hn_hi, *hn_lo;
    cudaGetSymbolAddress((void**)&u_e,   g_u_e);
    cudaGetSymbolAddress((void**)&u_s,   g_u_s);
    cudaGetSymbolAddress((void**)&ctx_e, g_ctx_e);
    cudaGetSymbolAddress((void**)&ctx_s, g_ctx_s);
    cudaGetSymbolAddress((void**)&plan,  g_plan);
    cudaGetSymbolAddress((void**)&gx,    g_gx);
    cudaGetSymbolAddress((void**)&dtgh,  g_dtgh);
    cudaGetSymbolAddress((void**)&offE,  g_offE);
    cudaGetSymbolAddress((void**)&offS,  g_offS);
    cudaGetSymbolAddress((void**)&rowE,  g_rowE);
    cudaGetSymbolAddress((void**)&rowS,  g_rowS);
    cudaGetSymbolAddress((void**)&mtot,  g_mtot);
    cudaGetSymbolAddress((void**)&ph_hi, g_ph_hi);  cudaGetSymbolAddress((void**)&ph_lo, g_ph_lo);
    cudaGetSymbolAddress((void**)&ee_hi, g_ee_hi);  cudaGetSymbolAddress((void**)&ee_lo, g_ee_lo);
    cudaGetSymbolAddress((void**)&es_hi, g_es_hi);  cudaGetSymbolAddress((void**)&es_lo, g_es_lo);
    cudaGetSymbolAddress((void**)&wcat_hi, g_wcat_hi); cudaGetSymbolAddress((void**)&wcat_lo, g_wcat_lo);
    cudaGetSymbolAddress((void**)&wc_hi, g_wc_hi);  cudaGetSymbolAddress((void**)&wc_lo, g_wc_lo);
    cudaGetSymbolAddress((void**)&wih_hi, g_wih_hi); cudaGetSymbolAddress((void**)&wih_lo, g_wih_lo);
    cudaGetSymbolAddress((void**)&w1e_hi, g_w1e_hi); cudaGetSymbolAddress((void**)&w1e_lo, g_w1e_lo);
    cudaGetSymbolAddress((void**)&w1s_hi, g_w1s_hi); cudaGetSymbolAddress((void**)&w1s_lo, g_w1s_lo);
    cudaGetSymbolAddress((void**)&yc_hi, g_yc_hi);  cudaGetSymbolAddress((void**)&yc_lo, g_yc_lo);
    cudaGetSymbolAddress((void**)&x_hi,  g_x_hi);   cudaGetSymbolAddress((void**)&x_lo,  g_x_lo);
    cudaGetSymbolAddress((void**)&hn_hi, g_hn_hi);  cudaGetSymbolAddress((void**)&hn_lo, g_hn_lo);

    cudaFuncSetAttribute(gemm_sp64,  cudaFuncAttributeMaxDynamicSharedMemorySize, SMEM64);
    cudaFuncSetAttribute(gemm_mixed, cudaFuncAttributeMaxDynamicSharedMemorySize, SMEM_BYTES);
    cudaFuncSetAttribute(attn2,      cudaFuncAttributeMaxDynamicSharedMemorySize, SMEM_BYTES);

    const dim3 blk(256);

    // compaction + merged gathers
    compact_kernel<<<1, 256>>>(equ_mask, sns_mask, offE, offS, mtot);
    gather2<<<dim3(BSZ, 2), 256>>>(equ_enc, sns_enc, equ_mask, sns_mask, offE, offS,
                                   ee_hi, ee_lo, es_hi, es_lo, rowE, rowS, u_e, u_s);

    // one batched split launch for all weights + prev_h
    {
        SplitArgs sa;
        sa.seg[0] = { prev_h, ph_hi, ph_lo, BSZ * DD / 4 };
        sa.seg[1] = { W2e,  wcat_hi,                       wcat_lo,                       HH * DD / 4 };
        sa.seg[2] = { W2s,  wcat_hi + (size_t)HH * DD,     wcat_lo + (size_t)HH * DD,     HH * DD / 4 };
        sa.seg[3] = { w_hh, wcat_hi + (size_t)2 * HH * DD, wcat_lo + (size_t)2 * HH * DD, G3D * DD / 4 };
        sa.seg[4] = { Wc,   wc_hi,  wc_lo,  HH * YC / 4 };
        sa.seg[5] = { w_ih, wih_hi, wih_lo, G3D * HH / 4 };
        sa.seg[6] = { W1e,  w1e_hi, w1e_lo, HH * HH / 4 };
        sa.seg[7] = { W1s,  w1s_hi, w1s_lo, HH * HH / 4 };
        const int maxb = (G3D * DD / 4 + 255) / 256;
        split_all<<<dim3(maxb, 8), blk>>>(sa);
    }

    // fused [dt_e | dt_s | gh] = prev_h @ Wcat^T
    gemm_sp64<<<dim3(NCAT / 128, BSZ / 64), blk, SMEM64>>>(
        ph_hi, ph_lo, wcat_hi, wcat_lo, nullptr, dtgh, nullptr, nullptr, BSZ, NCAT, DD);

    plan_kernel<<<BSZ, 128>>>(prev_h, plan_W, plan_b, plan, out_plan);

    // merged attention
    attn2<<<dim3(BSZ, 2), blk, SMEM_BYTES>>>(
        ee_hi, ee_lo, es_hi, es_lo,
        w1e_hi, w1e_lo, w1s_hi, w1s_lo,
        dtgh, vte, vts, rowE, rowS, mtot, u_e, u_s);

    // merged softmax + context (masked rows skipped)
    softmax_ctx2<<<dim3(BSZ, 2), blk>>>(u_e, u_s, equ_enc, sns_enc, ctx_e, ctx_s);

    combine_kernel<<<(BSZ * YC) / 256, blk>>>(prev_y, plan, ctx_e, ctx_s, yc_hi, yc_lo);

    gemm_sp64<<<dim3(HH / 128, BSZ / 64), blk, SMEM64>>>(
        yc_hi, yc_lo, wc_hi, wc_lo, bc, nullptr, x_hi, x_lo, BSZ, HH, YC);
    gemm_sp64<<<dim3(G3D / 128, BSZ / 64), blk, SMEM64>>>(
        x_hi, x_lo, wih_hi, wih_lo, b_ih, gx, nullptr, nullptr, BSZ, G3D, HH);

    gru_kernel<<<(BSZ * DD) / 256, blk>>>(gx, dtgh + 2 * HH, b_hh, prev_h, out_hid, hn_hi, hn_lo);

    // dec_output = h_new @ Wout^T + bout
    gemm_mixed<<<dim3(VV / 128, BSZ / 128), blk, SMEM_BYTES>>>(
        hn_hi, hn_lo, Wout, bout, out_dec, BSZ, VV, DD);
}

// round 12
// speedup vs baseline: 4.0148x; 1.1954x over previous
#include <cuda_runtime.h>
#include <cuda_bf16.h>
#include <cuda_fp16.h>
#include <math.h>
#include <stdint.h>

#define HH   512
#define ZZ   128
#define EE   512
#define DD   1152      // 2H + Z
#define VV   32000
#define BSZ  256
#define NN   128
#define G3D  3456      // 3*D
#define NCAT 4480      // 512 (dt_e) + 512 (dt_s) + 3456 (gh)
#define YC   1024      // E + H

// ---------------- scratch (device globals; no allocation allowed) ----------------
__device__ float g_u_e  [BSZ * NN];
__device__ float g_u_s  [BSZ * NN];
__device__ float g_ctx_e[BSZ * HH];
__device__ float g_ctx_s[BSZ * HH];
__device__ float g_plan [BSZ * 2];
__device__ float g_gx   [BSZ * G3D];
__device__ float g_dtgh [BSZ * NCAT];
__device__ int   g_offE [BSZ];
__device__ int   g_offS [BSZ];
__device__ int   g_rowE [BSZ * NN];
__device__ int   g_rowS [BSZ * NN];
__device__ int   g_mtot [2];

__device__ __align__(256) __nv_bfloat16 g_ph_hi [BSZ * DD];
__device__ __align__(256) __nv_bfloat16 g_ph_lo [BSZ * DD];
__device__ __align__(256) __nv_bfloat16 g_ee_hi [BSZ * NN * HH];
__device__ __align__(256) __nv_bfloat16 g_ee_lo [BSZ * NN * HH];
__device__ __align__(256) __nv_bfloat16 g_es_hi [BSZ * NN * HH];
__device__ __align__(256) __nv_bfloat16 g_es_lo [BSZ * NN * HH];
__device__ __align__(256) __nv_bfloat16 g_wcat_hi[NCAT * DD];
__device__ __align__(256) __nv_bfloat16 g_wcat_lo[NCAT * DD];
__device__ __align__(256) __nv_bfloat16 g_wc_hi [HH * YC];
__device__ __align__(256) __nv_bfloat16 g_wc_lo [HH * YC];
__device__ __align__(256) __nv_bfloat16 g_wih_hi[G3D * HH];
__device__ __align__(256) __nv_bfloat16 g_wih_lo[G3D * HH];
__device__ __align__(256) __nv_bfloat16 g_w1e_hi[HH * HH];
__device__ __align__(256) __nv_bfloat16 g_w1e_lo[HH * HH];
__device__ __align__(256) __nv_bfloat16 g_w1s_hi[HH * HH];
__device__ __align__(256) __nv_bfloat16 g_w1s_lo[HH * HH];
__device__ __align__(256) __nv_bfloat16 g_yc_hi [BSZ * YC];
__device__ __align__(256) __nv_bfloat16 g_yc_lo [BSZ * YC];
__device__ __align__(256) __nv_bfloat16 g_x_hi  [BSZ * HH];
__device__ __align__(256) __nv_bfloat16 g_x_lo  [BSZ * HH];
__device__ __align__(256) __half        g_hn_h  [BSZ * DD];   // h_new as fp16 (Wout A)

// ---------------- helpers ----------------
__device__ __forceinline__ uint32_t pack_bf2(float a, float b) {
    __nv_bfloat162 t = __floats2bfloat162_rn(a, b);
    return *reinterpret_cast<uint32_t*>(&t);
}
__device__ __forceinline__ uint32_t pack_h2(float a, float b) {
    __half2 t = __floats2half2_rn(a, b);
    return *reinterpret_cast<uint32_t*>(&t);
}

__device__ __forceinline__ void mma16816(float c[4],
                                         uint32_t a0, uint32_t a1, uint32_t a2, uint32_t a3,
                                         uint32_t b0, uint32_t b1) {
    asm volatile(
        "mma.sync.aligned.m16n8k16.row.col.f32.bf16.bf16.f32 "
        "{%0,%1,%2,%3}, {%4,%5,%6,%7}, {%8,%9}, {%0,%1,%2,%3};\n"
        : "+f"(c[0]), "+f"(c[1]), "+f"(c[2]), "+f"(c[3])
        : "r"(a0), "r"(a1), "r"(a2), "r"(a3), "r"(b0), "r"(b1));
}
__device__ __forceinline__ void mma16816h(float c[4],
                                          uint32_t a0, uint32_t a1, uint32_t a2, uint32_t a3,
                                          uint32_t b0, uint32_t b1) {
    asm volatile(
        "mma.sync.aligned.m16n8k16.row.col.f32.f16.f16.f32 "
        "{%0,%1,%2,%3}, {%4,%5,%6,%7}, {%8,%9}, {%0,%1,%2,%3};\n"
        : "+f"(c[0]), "+f"(c[1]), "+f"(c[2]), "+f"(c[3])
        : "r"(a0), "r"(a1), "r"(a2), "r"(a3), "r"(b0), "r"(b1));
}

__device__ __forceinline__ void ldsm_x4(uint32_t& r0, uint32_t& r1, uint32_t& r2, uint32_t& r3,
                                        uint32_t addr) {
    asm volatile("ldmatrix.sync.aligned.m8n8.x4.shared.b16 {%0,%1,%2,%3}, [%4];"
                 : "=r"(r0), "=r"(r1), "=r"(r2), "=r"(r3) : "r"(addr));
}
__device__ __forceinline__ void ldsm_x2(uint32_t& r0, uint32_t& r1, uint32_t addr) {
    asm volatile("ldmatrix.sync.aligned.m8n8.x2.shared.b16 {%0,%1}, [%2];"
                 : "=r"(r0), "=r"(r1) : "r"(addr));
}

#define CP16(dst, src) \
    asm volatile("cp.async.cg.shared.global [%0], [%1], 16;" :: "r"(dst), "l"(src))
#define CP_COMMIT() asm volatile("cp.async.commit_group;")
#define CP_WAIT0()  asm volatile("cp.async.wait_group 0;")

#define SMS 40
#define STG (128 * SMS)
#define STGB (STG * 2)
#define STAGE4B (4 * STGB)
#define SMEM_BYTES (2 * STAGE4B)

// BM=64 variant constants
#define A64  (64 * SMS)
#define A64B (A64 * 2)
#define S64B (2 * A64B + 2 * STGB)
#define SMEM64 (2 * S64B)

// fp16 single-pass constants (Wout)
#define STGB_H STGB                 // one fp16 array = 10240 bytes
#define STAGE_H (2 * STGB_H)        // A + B per stage = 20480
#define SMEM_H (2 * STAGE_H)        // 40960

__device__ __forceinline__ uint32_t ldsm_aoff(int l) {
    return (uint32_t)((((l & 7) + ((l >> 3) & 1) * 8) * SMS + (l >> 4) * 8) * 2);
}
__device__ __forceinline__ uint32_t ldsm_boff(int l) {
    return (uint32_t)(((l & 7) * SMS + ((l >> 3) & 1) * 8) * 2);
}

__device__ __forceinline__ void cp_stage4(uint32_t d,
                                          const __nv_bfloat16* ah, const __nv_bfloat16* al,
                                          const __nv_bfloat16* bh, const __nv_bfloat16* bl) {
    CP16(d + 0 * STGB,      ah);     CP16(d + 0 * STGB + 16, ah + 8);
    CP16(d + 1 * STGB,      al);     CP16(d + 1 * STGB + 16, al + 8);
    CP16(d + 2 * STGB,      bh);     CP16(d + 2 * STGB + 16, bh + 8);
    CP16(d + 3 * STGB,      bl);     CP16(d + 3 * STGB + 16, bl + 8);
}

__device__ __forceinline__ void mma_chunk(uint32_t stb, uint32_t aoff, uint32_t boff,
                                          float acc[4][4][4], int wr, int wc) {
#pragma unroll
    for (int ks = 0; ks < 2; ks++) {
        const uint32_t kb2 = ks * 32;
        uint32_t bhi[4][2], blo[4][2];
#pragma unroll
        for (int ni = 0; ni < 4; ni++) {
            const uint32_t rb = (uint32_t)(wc * 32 + ni * 8) * (SMS * 2) + kb2 + boff;
            ldsm_x2(bhi[ni][0], bhi[ni][1], stb + 2 * STGB + rb);
            ldsm_x2(blo[ni][0], blo[ni][1], stb + 3 * STGB + rb);
        }
#pragma unroll
        for (int mi = 0; mi < 4; mi++) {
            const uint32_t ra = (uint32_t)(wr * 64 + mi * 16) * (SMS * 2) + kb2 + aoff;
            uint32_t ah[4], al[4];
            ldsm_x4(ah[0], ah[1], ah[2], ah[3], stb + ra);
            ldsm_x4(al[0], al[1], al[2], al[3], stb + STGB + ra);
#pragma unroll
            for (int ni = 0; ni < 4; ni++) {
                mma16816(acc[mi][ni], ah[0], ah[1], ah[2], ah[3], bhi[ni][0], bhi[ni][1]);
                mma16816(acc[mi][ni], ah[0], ah[1], ah[2], ah[3], blo[ni][0], blo[ni][1]);
                mma16816(acc[mi][ni], al[0], al[1], al[2], al[3], bhi[ni][0], bhi[ni][1]);
            }
        }
    }
}

// =================================================================================
// gemm_sp64: BM=64 x BN=128 pre-split bf16x3 GEMM; single barrier per K-chunk.
// =================================================================================
__global__ void __launch_bounds__(256, 2) gemm_sp64(
    const __nv_bfloat16* __restrict__ Ahi, const __nv_bfloat16* __restrict__ Alo,
    const __nv_bfloat16* __restrict__ Bhi, const __nv_bfloat16* __restrict__ Blo,
    const float* __restrict__ bias,
    float* __restrict__ C, __nv_bfloat16* __restrict__ Chi, __nv_bfloat16* __restrict__ Clo,
    int M, int N, int K)
{
    extern __shared__ __nv_bfloat16 sm[];

    const int t    = threadIdx.x;
    const int m0   = blockIdx.y * 64;
    const int n0   = blockIdx.x * 128;
    const int lane = t & 31;
    const int wid  = t >> 5;
    const int g    = lane >> 2;
    const int tg   = lane & 3;
    const int wr   = wid & 1;
    const int wc   = wid >> 1;

    const uint32_t smb  = (uint32_t)__cvta_generic_to_shared(sm);
    const uint32_t aoff = ldsm_aoff(lane);
    const uint32_t boff = ldsm_boff(lane);

    const int ar = t >> 2;
    const int ac = (t & 3) * 8;
    const uint32_t atoff = (uint32_t)(ar * SMS + ac) * 2;
    const int br = t >> 1;
    const int bc = (t & 1) * 16;
    const uint32_t btoff = (uint32_t)(br * SMS + bc) * 2;

    const __nv_bfloat16* ApH = Ahi + (size_t)(m0 + ar) * K + ac;
    const __nv_bfloat16* ApL = Alo + (size_t)(m0 + ar) * K + ac;
    const __nv_bfloat16* BpH = Bhi + (size_t)(n0 + br) * K + bc;
    const __nv_bfloat16* BpL = Blo + (size_t)(n0 + br) * K + bc;

    float acc[2][4][4];
#pragma unroll
    for (int mi = 0; mi < 2; mi++)
#pragma unroll
        for (int ni = 0; ni < 4; ni++)
#pragma unroll
            for (int q = 0; q < 4; q++) acc[mi][ni][q] = 0.f;

#define FILL64(D, K0)                                            \
    do {                                                         \
        CP16((D) + atoff,                    ApH + (K0));        \
        CP16((D) + A64B + atoff,             ApL + (K0));        \
        CP16((D) + 2 * A64B + btoff,         BpH + (K0));        \
        CP16((D) + 2 * A64B + btoff + 16,    BpH + (K0) + 8);    \
        CP16((D) + 2 * A64B + STGB + btoff,      BpL + (K0));    \
        CP16((D) + 2 * A64B + STGB + btoff + 16, BpL + (K0) + 8);\
    } while (0)

    FILL64(smb, 0);
    CP_COMMIT();

    for (int k0 = 0; k0 < K; k0 += 32) {
        const int s = (k0 >> 5) & 1;
        const bool more = (k0 + 32 < K);
        CP_WAIT0();
        __syncthreads();
        if (more) {
            FILL64(smb + (uint32_t)(s ^ 1) * S64B, k0 + 32);
            CP_COMMIT();
        }
        const uint32_t stb = smb + (uint32_t)s * S64B;
#pragma unroll
        for (int ks = 0; ks < 2; ks++) {
            const uint32_t kb2 = ks * 32;
            uint32_t bhi[4][2], blo[4][2];
#pragma unroll
            for (int ni = 0; ni < 4; ni++) {
                const uint32_t rb = (uint32_t)(wc * 32 + ni * 8) * (SMS * 2) + kb2 + boff;
                ldsm_x2(bhi[ni][0], bhi[ni][1], stb + 2 * A64B + rb);
                ldsm_x2(blo[ni][0], blo[ni][1], stb + 2 * A64B + STGB + rb);
            }
#pragma unroll
            for (int mi = 0; mi < 2; mi++) {
                const uint32_t ra = (uint32_t)(wr * 32 + mi * 16) * (SMS * 2) + kb2 + aoff;
                uint32_t ah[4], al[4];
                ldsm_x4(ah[0], ah[1], ah[2], ah[3], stb + ra);
                ldsm_x4(al[0], al[1], al[2], al[3], stb + A64B + ra);
#pragma unroll
                for (int ni = 0; ni < 4; ni++) {
                    mma16816(acc[mi][ni], ah[0], ah[1], ah[2], ah[3], bhi[ni][0], bhi[ni][1]);
                    mma16816(acc[mi][ni], ah[0], ah[1], ah[2], ah[3], blo[ni][0], blo[ni][1]);
                    mma16816(acc[mi][ni], al[0], al[1], al[2], al[3], bhi[ni][0], bhi[ni][1]);
                }
            }
        }
    }

#pragma unroll
    for (int mi = 0; mi < 2; mi++) {
        const int row = m0 + wr * 32 + mi * 16 + g;
#pragma unroll
        for (int ni = 0; ni < 4; ni++) {
            const int col = n0 + wc * 32 + ni * 8 + tg * 2;
            float b0 = bias ? bias[col] : 0.f;
            float b1 = bias ? bias[col + 1] : 0.f;
            float c00 = acc[mi][ni][0] + b0, c01 = acc[mi][ni][1] + b1;
            float c10 = acc[mi][ni][2] + b0, c11 = acc[mi][ni][3] + b1;
            if (C) {
                *(float2*)&C[(size_t)row * N + col]       = make_float2(c00, c01);
                *(float2*)&C[(size_t)(row + 8) * N + col] = make_float2(c10, c11);
            }
            if (Chi) {
                __nv_bfloat16 h00 = __float2bfloat16(c00), h01 = __float2bfloat16(c01);
                __nv_bfloat16 h10 = __float2bfloat16(c10), h11 = __float2bfloat16(c11);
                *(uint32_t*)&Chi[(size_t)row * N + col]       = pack_bf2(c00, c01);
                *(uint32_t*)&Chi[(size_t)(row + 8) * N + col] = pack_bf2(c10, c11);
                *(uint32_t*)&Clo[(size_t)row * N + col] =
                    pack_bf2(c00 - __bfloat162float(h00), c01 - __bfloat162float(h01));
                *(uint32_t*)&Clo[(size_t)(row + 8) * N + col] =
                    pack_bf2(c10 - __bfloat162float(h10), c11 - __bfloat162float(h11));
            }
        }
    }
}

// =================================================================================
// gemm_fp16: SINGLE-PASS fp16 GEMM for Wout.  C = A @ B^T + bias.
// A fp16 (pre-converted h_new), B fp32 -> fp16 in-kernel.  3x fewer mma ops
// than bf16x3; norm error ~4e-4 (fp16 11-bit mantissa), acceptable for the
// final linear layer only.
// =================================================================================
__global__ void __launch_bounds__(256, 2) gemm_fp16(
    const __half* __restrict__ A, const float* __restrict__ B,
    const float* __restrict__ bias, float* __restrict__ C,
    int M, int N, int K)
{
    extern __shared__ __half smh[];

    const int t    = threadIdx.x;
    const int m0   = blockIdx.y * 128;
    const int n0   = blockIdx.x * 128;
    const int lane = t & 31;
    const int wid  = t >> 5;
    const int g    = lane >> 2;
    const int tg   = lane & 3;
    const int wr   = wid & 1;
    const int wc   = wid >> 1;

    const uint32_t smb  = (uint32_t)__cvta_generic_to_shared(smh);
    const uint32_t aoff = ldsm_aoff(lane);
    const uint32_t boff = ldsm_boff(lane);

    const int r  = t >> 1;
    const int hh = (t & 1) * 16;
    const uint32_t toff = (uint32_t)(r * SMS + hh) * 2;
    const int idx = r * SMS + hh;
    const __half* Ap = A + (size_t)(m0 + r) * K + hh;
    const float*  Bp = B + (size_t)(n0 + r) * K + hh;

    float acc[4][4][4];
#pragma unroll
    for (int mi = 0; mi < 4; mi++)
#pragma unroll
        for (int ni = 0; ni < 4; ni++)
#pragma unroll
            for (int q = 0; q < 4; q++) acc[mi][ni][q] = 0.f;

#define CVTB_H(ST, RB)                                                        \
    do {                                                                      \
        __half* bdst = smh + (ST) * (STAGE_H / 2) + (STGB_H / 2) + idx;       \
        uint4 v0, v1;                                                         \
        v0.x = pack_h2((RB)[0].x, (RB)[0].y); v0.y = pack_h2((RB)[0].z, (RB)[0].w); \
        v0.z = pack_h2((RB)[1].x, (RB)[1].y); v0.w = pack_h2((RB)[1].z, (RB)[1].w); \
        v1.x = pack_h2((RB)[2].x, (RB)[2].y); v1.y = pack_h2((RB)[2].z, (RB)[2].w); \
        v1.z = pack_h2((RB)[3].x, (RB)[3].y); v1.w = pack_h2((RB)[3].z, (RB)[3].w); \
        *(uint4*)bdst       = v0;                                             \
        *(uint4*)(bdst + 8) = v1;                                             \
    } while (0)

    // prologue: stage 0 (A via cp.async, B via LDG+cvt)
    CP16(smb + toff,      Ap);
    CP16(smb + toff + 16, Ap + 8);
    CP_COMMIT();
    {
        float4 rb0[4];
#pragma unroll
        for (int i = 0; i < 4; i++) rb0[i] = *(const float4*)(Bp + i * 4);
        CVTB_H(0, rb0);
    }

    for (int k0 = 0; k0 < K; k0 += 32) {
        const int s = (k0 >> 5) & 1;
        const bool more = (k0 + 32 < K);
        CP_WAIT0();
        __syncthreads();
        float4 rb[4];
        if (more) {
            const uint32_t d = smb + (uint32_t)(s ^ 1) * STAGE_H + toff;
            CP16(d,      Ap + k0 + 32);
            CP16(d + 16, Ap + k0 + 40);
            CP_COMMIT();
#pragma unroll
            for (int i = 0; i < 4; i++) rb[i] = *(const float4*)(Bp + k0 + 32 + i * 4);
        }
        // mma over staged chunk
        const uint32_t stb = smb + (uint32_t)s * STAGE_H;
#pragma unroll
        for (int ks = 0; ks < 2; ks++) {
            const uint32_t kb2 = ks * 32;
            uint32_t bf[4][2];
#pragma unroll
            for (int ni = 0; ni < 4; ni++) {
                const uint32_t rbo = (uint32_t)(wc * 32 + ni * 8) * (SMS * 2) + kb2 + boff;
                ldsm_x2(bf[ni][0], bf[ni][1], stb + STGB_H + rbo);
            }
#pragma unroll
            for (int mi = 0; mi < 4; mi++) {
                const uint32_t ra = (uint32_t)(wr * 64 + mi * 16) * (SMS * 2) + kb2 + aoff;
                uint32_t a0, a1, a2, a3;
                ldsm_x4(a0, a1, a2, a3, stb + ra);
#pragma unroll
                for (int ni = 0; ni < 4; ni++)
                    mma16816h(acc[mi][ni], a0, a1, a2, a3, bf[ni][0], bf[ni][1]);
            }
        }
        if (more) CVTB_H(s ^ 1, rb);
    }

#pragma unroll
    for (int mi = 0; mi < 4; mi++) {
        const int row = m0 + wr * 64 + mi * 16 + g;
#pragma unroll
        for (int ni = 0; ni < 4; ni++) {
            const int col = n0 + wc * 32 + ni * 8 + tg * 2;
            const float b0 = bias[col], b1 = bias[col + 1];
            *(float2*)&C[(size_t)row * N + col] =
                make_float2(acc[mi][ni][0] + b0, acc[mi][ni][1] + b1);
            *(float2*)&C[(size_t)(row + 8) * N + col] =
                make_float2(acc[mi][ni][2] + b0, acc[mi][ni][3] + b1);
        }
    }
}

// =================================================================================
// batched split: one launch does all fp32 -> bf16 hi/lo segments (grid.y = segment)
// =================================================================================
struct SplitSeg { const float* src; __nv_bfloat16* hi; __nv_bfloat16* lo; int n4; };
struct SplitArgs { SplitSeg seg[8]; };

__global__ void split_all(SplitArgs a)
{
    const SplitSeg s = a.seg[blockIdx.y];
    const int i = blockIdx.x * blockDim.x + threadIdx.x;
    if (i >= s.n4) return;
    float4 v = ((const float4*)s.src)[i];
    __nv_bfloat16 hx = __float2bfloat16(v.x), hy = __float2bfloat16(v.y);
    __nv_bfloat16 hz = __float2bfloat16(v.z), hw = __float2bfloat16(v.w);
    uint2 vh, vl;
    vh.x = pack_bf2(v.x, v.y); vh.y = pack_bf2(v.z, v.w);
    vl.x = pack_bf2(v.x - __bfloat162float(hx), v.y - __bfloat162float(hy));
    vl.y = pack_bf2(v.z - __bfloat162float(hz), v.w - __bfloat162float(hw));
    ((uint2*)s.hi)[i] = vh;
    ((uint2*)s.lo)[i] = vl;
}

// =================================================================================
// compact: per-batch exclusive offsets of unmasked positions (both masks)
// =================================================================================
__global__ void compact_kernel(const int* __restrict__ mE, const int* __restrict__ mS,
                               int* __restrict__ offE, int* __restrict__ offS,
                               int* __restrict__ mtot)
{
    __shared__ int sE[256], sS[256];
    const int b = threadIdx.x;
    int cE = 0, cS = 0;
    for (int n = 0; n < NN; n++) {
        cE += (mE[b * NN + n] == 0);
        cS += (mS[b * NN + n] == 0);
    }
    sE[b] = cE; sS[b] = cS;
    __syncthreads();
    for (int d = 1; d < 256; d <<= 1) {
        int vE = 0, vS = 0;
        if (b >= d) { vE = sE[b - d]; vS = sS[b - d]; }
        __syncthreads();
        sE[b] += vE; sS[b] += vS;
        __syncthreads();
    }
    offE[b] = sE[b] - cE;
    offS[b] = sS[b] - cS;
    if (b == 255) { mtot[0] = sE[255]; mtot[1] = sS[255]; }
}

// =================================================================================
// merged gather (grid.y = side)
// =================================================================================
__global__ void gather2(const float* __restrict__ encE, const float* __restrict__ encS,
                        const int* __restrict__ mE, const int* __restrict__ mS,
                        const int* __restrict__ offE, const int* __restrict__ offS,
                        __nv_bfloat16* __restrict__ geh, __nv_bfloat16* __restrict__ gel,
                        __nv_bfloat16* __restrict__ gsh, __nv_bfloat16* __restrict__ gsl,
                        int* __restrict__ rowE, int* __restrict__ rowS,
                        float* __restrict__ uE, float* __restrict__ uS)
{
    const int side = blockIdx.y;
    const float* enc = side ? encS : encE;
    const int* mask  = side ? mS : mE;
    const int* off   = side ? offS : offE;
    __nv_bfloat16* ghi = side ? gsh : geh;
    __nv_bfloat16* glo = side ? gsl : gel;
    int* rowinfo = side ? rowS : rowE;
    float* u     = side ? uS : uE;

    __shared__ int s_list[NN];
    __shared__ int s_wtot[8];
    const int b = blockIdx.x;
    const int t = threadIdx.x;
    const int base = off[b];
    const bool in = t < NN;
    const bool valid = in && (mask[b * NN + t] == 0);
    const unsigned wm = __ballot_sync(0xffffffffu, valid);
    const int lane = t & 31, w = t >> 5;
    if (lane == 0) s_wtot[w] = __popc(wm);
    __syncthreads();
    int wbase = 0;
#pragma unroll
    for (int i = 0; i < 4; i++) if (i < w) wbase += s_wtot[i];
    const int rank = wbase + __popc(wm & ((1u << lane) - 1));
    if (valid) {
        s_list[rank] = t;
        rowinfo[base + rank] = b * NN + t;
    } else if (in) {
        u[b * NN + t] = -INFINITY;
    }
    __syncthreads();
    const int cnt = s_wtot[0] + s_wtot[1] + s_wtot[2] + s_wtot[3];

    for (int i = 0; i < cnt; i++) {
        const int n = s_list[i];
        const float2 v = *(const float2*)(enc + ((size_t)b * NN + n) * HH + t * 2);
        __nv_bfloat16 h0 = __float2bfloat16(v.x), h1 = __float2bfloat16(v.y);
        *(uint32_t*)&ghi[((size_t)base + i) * HH + t * 2] = pack_bf2(v.x, v.y);
        *(uint32_t*)&glo[((size_t)base + i) * HH + t * 2] =
            pack_bf2(v.x - __bfloat162float(h0), v.y - __bfloat162float(h1));
    }
}

// =================================================================================
// merged attention (grid = (256, 2)); single barrier per K-chunk.
// =================================================================================
__global__ void __launch_bounds__(256, 2) attn2(
    const __nv_bfloat16* __restrict__ geh, const __nv_bfloat16* __restrict__ gel,
    const __nv_bfloat16* __restrict__ gsh, const __nv_bfloat16* __restrict__ gsl,
    const __nv_bfloat16* __restrict__ w1eh, const __nv_bfloat16* __restrict__ w1el,
    const __nv_bfloat16* __restrict__ w1sh, const __nv_bfloat16* __restrict__ w1sl,
    const float* __restrict__ dtg,
    const float* __restrict__ vte, const float* __restrict__ vts,
    const int* __restrict__ rowE, const int* __restrict__ rowS,
    const int* __restrict__ mtotp,
    float* __restrict__ uE, float* __restrict__ uS)
{
    extern __shared__ __nv_bfloat16 sm[];
    __shared__ float s_vt[512];
    __shared__ float s_u[128];

    const int side = blockIdx.y;
    const int mtot = mtotp[side];
    const int m0 = blockIdx.x * 128;
    if (m0 >= mtot) return;

    const __nv_bfloat16* gehi = side ? gsh : geh;
    const __nv_bfloat16* gelo = side ? gsl : gel;
    const __nv_bfloat16* w1hi = side ? w1sh : w1eh;
    const __nv_bfloat16* w1lo = side ? w1sl : w1el;
    const float* dt = dtg + (side ? HH : 0);
    const float* vt = side ? vts : vte;
    const int* rowinfo = side ? rowS : rowE;
    float* u = side ? uS : uE;

    const int t    = threadIdx.x;
    const int lane = t & 31;
    const int wid  = t >> 5;
    const int g    = lane >> 2;
    const int tg   = lane & 3;
    const int wr   = wid & 1;
    const int wc   = wid >> 1;

    const uint32_t smb  = (uint32_t)__cvta_generic_to_shared(sm);
    const uint32_t aoff = ldsm_aoff(lane);
    const uint32_t boff = ldsm_boff(lane);

    for (int i = t; i < 512; i += 256) s_vt[i] = vt[i];
    if (t < 128) s_u[t] = 0.f;

    int rb4[4][2];
#pragma unroll
    for (int mi = 0; mi < 4; mi++)
#pragma unroll
        for (int rr = 0; rr < 2; rr++)
            rb4[mi][rr] = rowinfo[m0 + wr * 64 + mi * 16 + g + rr * 8] >> 7;

    const int r  = t >> 1;
    const int hh = (t & 1) * 16;
    const uint32_t toff = (uint32_t)(r * SMS + hh) * 2;
    const __nv_bfloat16* ApH = gehi + (size_t)(m0 + r) * 512 + hh;
    const __nv_bfloat16* ApL = gelo + (size_t)(m0 + r) * 512 + hh;

    float up[8];
#pragma unroll
    for (int i = 0; i < 8; i++) up[i] = 0.f;

    for (int nc = 0; nc < 4; nc++) {
        const __nv_bfloat16* BpH = w1hi + (size_t)(nc * 128 + r) * 512 + hh;
        const __nv_bfloat16* BpL = w1lo + (size_t)(nc * 128 + r) * 512 + hh;

        float acc[4][4][4];
#pragma unroll
        for (int mi = 0; mi < 4; mi++)
#pragma unroll
            for (int ni = 0; ni < 4; ni++)
#pragma unroll
                for (int q = 0; q < 4; q++) acc[mi][ni][q] = 0.f;

        cp_stage4(smb + toff, ApH, ApL, BpH, BpL);
        CP_COMMIT();

        for (int k0 = 0; k0 < 512; k0 += 32) {
            const int s = (k0 >> 5) & 1;
            const bool more = (k0 + 32 < 512);
            CP_WAIT0();
            __syncthreads();
            if (more) {
                cp_stage4(smb + (uint32_t)(s ^ 1) * STAGE4B + toff,
                          ApH + k0 + 32, ApL + k0 + 32, BpH + k0 + 32, BpL + k0 + 32);
                CP_COMMIT();
            }
            mma_chunk(smb + (uint32_t)s * STAGE4B, aoff, boff, acc, wr, wc);
        }

#pragma unroll
        for (int mi = 0; mi < 4; mi++) {
            const float* dt0 = dtg + (size_t)rb4[mi][0] * NCAT + (side ? HH : 0);
            const float* dt1 = dtg + (size_t)rb4[mi][1] * NCAT + (side ? HH : 0);
#pragma unroll
            for (int ni = 0; ni < 4; ni++) {
                const int col = nc * 128 + wc * 32 + ni * 8 + tg * 2;
                const float v0 = s_vt[col], v1 = s_vt[col + 1];
                up[mi * 2 + 0] += v0 * tanhf(acc[mi][ni][0] + dt0[col])
                                + v1 * tanhf(acc[mi][ni][1] + dt0[col + 1]);
                up[mi * 2 + 1] += v0 * tanhf(acc[mi][ni][2] + dt1[col])
                                + v1 * tanhf(acc[mi][ni][3] + dt1[col + 1]);
            }
        }
    }

#pragma unroll
    for (int mi = 0; mi < 4; mi++)
#pragma unroll
        for (int rr = 0; rr < 2; rr++) {
            float v = up[mi * 2 + rr];
            v += __shfl_down_sync(0xffffffffu, v, 1);
            v += __shfl_down_sync(0xffffffffu, v, 2);
            if (tg == 0)
                atomicAdd(&s_u[wr * 64 + mi * 16 + g + rr * 8], v);
        }
    __syncthreads();

    if (t < 128 && m0 + t < mtot)
        u[rowinfo[m0 + t]] = s_u[t];
}

// =================================================================================
// plan = softmax(prev_h @ plan_W^T + plan_b)
// =================================================================================
__global__ void plan_kernel(const float* __restrict__ prev_h,
                            const float* __restrict__ plan_W,
                            const float* __restrict__ plan_b,
                            float* __restrict__ plan,
                            float* __restrict__ out_plan)
{
    const int b = blockIdx.x;
    const int t = threadIdx.x;
    __shared__ float s0[128], s1[128];
    float a0 = 0.f, a1 = 0.f;
    const float* hb = prev_h + (size_t)b * DD;
    for (int k = t; k < DD; k += 128) {
        const float h = hb[k];
        a0 += h * plan_W[k];
        a1 += h * plan_W[DD + k];
    }
    s0[t] = a0; s1[t] = a1;
    __syncthreads();
    for (int s = 64; s > 0; s >>= 1) {
        if (t < s) { s0[t] += s0[t + s]; s1[t] += s1[t + s]; }
        __syncthreads();
    }
    if (t == 0) {
        const float l0 = s0[0] + plan_b[0];
        const float l1 = s1[0] + plan_b[1];
        const float mx = fmaxf(l0, l1);
        const float e0 = expf(l0 - mx), e1 = expf(l1 - mx);
        const float inv = 1.f / (e0 + e1);
        plan[2 * b] = e0 * inv;       plan[2 * b + 1] = e1 * inv;
        out_plan[2 * b] = e0 * inv;   out_plan[2 * b + 1] = e1 * inv;
    }
}

// =================================================================================
// merged softmax+context (grid = (BSZ, 2)) — skips masked rows (aw == 0 exactly)
// =================================================================================
__global__ void softmax_ctx2(const float* __restrict__ uE, const float* __restrict__ uS,
                             const float* __restrict__ encE, const float* __restrict__ encS,
                             float* __restrict__ ctxE, float* __restrict__ ctxS)
{
    const int side = blockIdx.y;
    const float* u   = side ? uS : uE;
    const float* enc = side ? encS : encE;
    float* ctx       = side ? ctxS : ctxE;

    const int b = blockIdx.x;
    const int t = threadIdx.x;
    __shared__ float red[256];
    __shared__ float s_aw[NN];
    __shared__ int   s_list[NN];
    __shared__ int   s_wtot[4];

    const float uv = (t < NN) ? u[(size_t)b * NN + t] : -INFINITY;
    red[t] = uv;
    __syncthreads();
    for (int s = 128; s > 0; s >>= 1) {
        if (t < s) red[t] = fmaxf(red[t], red[t + s]);
        __syncthreads();
    }
    const float mx = red[0];
    __syncthreads();
    const float e = (t < NN) ? expf(uv - mx) : 0.f;
    red[t] = e;
    __syncthreads();
    for (int s = 128; s > 0; s >>= 1) {
        if (t < s) red[t] += red[t + s];
        __syncthreads();
    }
    const float inv = 1.f / red[0];

    const bool valid = (t < NN) && (uv != -INFINITY);
    const unsigned wm = __ballot_sync(0xffffffffu, valid);
    const int lane = t & 31, w = t >> 5;
    if (lane == 0 && w < 4) s_wtot[w] = __popc(wm);
    __syncthreads();
    int wbase = 0;
#pragma unroll
    for (int i = 0; i < 4; i++) if (i < w) wbase += s_wtot[i];
    if (valid) {
        const int rank = wbase + __popc(wm & ((1u << lane) - 1));
        s_list[rank] = t;
        s_aw[rank] = e * inv;
    }
    __syncthreads();
    const int cnt = s_wtot[0] + s_wtot[1] + s_wtot[2] + s_wtot[3];

    const float* eb = enc + (size_t)b * NN * HH;
    for (int h = t; h < HH; h += 256) {
        float s = 0.f;
        for (int i = 0; i < cnt; i++)
            s += s_aw[i] * eb[(size_t)s_list[i] * HH + h];
        ctx[(size_t)b * HH + h] = s;
    }
}

// =================================================================================
// y_ctx = [prev_y | plan0*ctx_e + plan1*ctx_s], written pre-split
// =================================================================================
__global__ void combine_kernel(const float* __restrict__ prev_y,
                               const float* __restrict__ plan,
                               const float* __restrict__ ctx_e,
                               const float* __restrict__ ctx_s,
                               __nv_bfloat16* __restrict__ ychi,
                               __nv_bfloat16* __restrict__ yclo)
{
    const int idx = blockIdx.x * blockDim.x + threadIdx.x;
    if (idx >= BSZ * YC) return;
    const int b = idx >> 10;
    const int c = idx & 1023;
    float v;
    if (c < EE) {
        v = prev_y[(size_t)b * EE + c];
    } else {
        const float p0 = plan[2 * b], p1 = plan[2 * b + 1];
        const int h = c - EE;
        v = p0 * ctx_e[(size_t)b * HH + h] + p1 * ctx_s[(size_t)b * HH + h];
    }
    __nv_bfloat16 hv = __float2bfloat16(v);
    ychi[idx] = hv;
    yclo[idx] = __float2bfloat16(v - __bfloat162float(hv));
}

// =================================================================================
// GRU cell elementwise; outputs out_hid (fp32) + hn fp16 (Wout A operand)
// =================================================================================
__global__ void gru_kernel(const float* __restrict__ gx,
                           const float* __restrict__ ghbase,
                           const float* __restrict__ b_hh,
                           const float* __restrict__ prev_h,
                           float* __restrict__ out_hid,
                           __half* __restrict__ hnh)
{
    const int idx = blockIdx.x * blockDim.x + threadIdx.x;
    if (idx >= BSZ * DD) return;
    const int b = idx / DD;
    const int d = idx - b * DD;
    const float* gxb = gx + (size_t)b * G3D;
    const float* ghb = ghbase + (size_t)b * NCAT;
    const float ghr = ghb[d]          + b_hh[d];
    const float ghz = ghb[DD + d]     + b_hh[DD + d];
    const float ghn = ghb[2 * DD + d] + b_hh[2 * DD + d];
    const float r = 1.f / (1.f + expf(-(gxb[d] + ghr)));
    const float z = 1.f / (1.f + expf(-(gxb[DD + d] + ghz)));
    const float n = tanhf(gxb[2 * DD + d] + r * ghn);
    const float h = (1.f - z) * n + z * prev_h[idx];
    out_hid[idx] = h;
    hnh[idx] = __float2half_rn(h);
}

// =================================================================================
// host launcher — graph-capturable
// =================================================================================
extern "C" void kernel_launch(void* const* d_in, const int* in_sizes, int n_in,
                              void* d_out, int out_size)
{
    const float* prev_y  = (const float*)d_in[0];
    const float* prev_h  = (const float*)d_in[1];
    const float* equ_enc = (const float*)d_in[2];
    const float* sns_enc = (const float*)d_in[3];
    const int* equ_mask = (const int*)d_in[5];
    const int* sns_mask = (const int*)d_in[6];
    const float* W1e    = (const float*)d_in[7];
    const float* W2e    = (const float*)d_in[8];
    const float* vte    = (const float*)d_in[9];
    const float* W1s    = (const float*)d_in[10];
    const float* W2s    = (const float*)d_in[11];
    const float* vts    = (const float*)d_in[12];
    const float* plan_W = (const float*)d_in[13];
    const float* plan_b = (const float*)d_in[14];
    const float* Wc     = (const float*)d_in[15];
    const float* bc     = (const float*)d_in[16];
    const float* w_ih   = (const float*)d_in[17];
    const float* w_hh   = (const float*)d_in[18];
    const float* b_ih   = (const float*)d_in[19];
    const float* b_hh   = (const float*)d_in[20];
    const float* Wout   = (const float*)d_in[21];
    const float* bout   = (const float*)d_in[22];

    float* out      = (float*)d_out;
    float* out_dec  = out;
    float* out_hid  = out + (size_t)BSZ * VV;
    float* out_plan = out + (size_t)BSZ * VV + (size_t)BSZ * DD;

    float *u_e, *u_s, *ctx_e, *ctx_s, *plan, *gx, *dtgh;
    int *offE, *offS, *rowE, *rowS, *mtot;
    __nv_bfloat16 *ph_hi, *ph_lo, *ee_hi, *ee_lo, *es_hi, *es_lo;
    __nv_bfloat16 *wcat_hi, *wcat_lo, *wc_hi, *wc_lo, *wih_hi, *wih_lo;
    __nv_bfloat16 *w1e_hi, *w1e_lo, *w1s_hi, *w1s_lo;
    __nv_bfloat16 *yc_hi, *yc_lo, *x_hi, *x_lo;
    __half *hn_h;
    cudaGetSymbolAddress((void**)&u_e,   g_u_e);
    cudaGetSymbolAddress((void**)&u_s,   g_u_s);
    cudaGetSymbolAddress((void**)&ctx_e, g_ctx_e);
    cudaGetSymbolAddress((void**)&ctx_s, g_ctx_s);
    cudaGetSymbolAddress((void**)&plan,  g_plan);
    cudaGetSymbolAddress((void**)&gx,    g_gx);
    cudaGetSymbolAddress((void**)&dtgh,  g_dtgh);
    cudaGetSymbolAddress((void**)&offE,  g_offE);
    cudaGetSymbolAddress((void**)&offS,  g_offS);
    cudaGetSymbolAddress((void**)&rowE,  g_rowE);
    cudaGetSymbolAddress((void**)&rowS,  g_rowS);
    cudaGetSymbolAddress((void**)&mtot,  g_mtot);
    cudaGetSymbolAddress((void**)&ph_hi, g_ph_hi);  cudaGetSymbolAddress((void**)&ph_lo, g_ph_lo);
    cudaGetSymbolAddress((void**)&ee_hi, g_ee_hi);  cudaGetSymbolAddress((void**)&ee_lo, g_ee_lo);
    cudaGetSymbolAddress((void**)&es_hi, g_es_hi);  cudaGetSymbolAddress((void**)&es_lo, g_es_lo);
    cudaGetSymbolAddress((void**)&wcat_hi, g_wcat_hi); cudaGetSymbolAddress((void**)&wcat_lo, g_wcat_lo);
    cudaGetSymbolAddress((void**)&wc_hi, g_wc_hi);  cudaGetSymbolAddress((void**)&wc_lo, g_wc_lo);
    cudaGetSymbolAddress((void**)&wih_hi, g_wih_hi); cudaGetSymbolAddress((void**)&wih_lo, g_wih_lo);
    cudaGetSymbolAddress((void**)&w1e_hi, g_w1e_hi); cudaGetSymbolAddress((void**)&w1e_lo, g_w1e_lo);
    cudaGetSymbolAddress((void**)&w1s_hi, g_w1s_hi); cudaGetSymbolAddress((void**)&w1s_lo, g_w1s_lo);
    cudaGetSymbolAddress((void**)&yc_hi, g_yc_hi);  cudaGetSymbolAddress((void**)&yc_lo, g_yc_lo);
    cudaGetSymbolAddress((void**)&x_hi,  g_x_hi);   cudaGetSymbolAddress((void**)&x_lo,  g_x_lo);
    cudaGetSymbolAddress((void**)&hn_h,  g_hn_h);

    cudaFuncSetAttribute(gemm_sp64, cudaFuncAttributeMaxDynamicSharedMemorySize, SMEM64);
    cudaFuncSetAttribute(gemm_fp16, cudaFuncAttributeMaxDynamicSharedMemorySize, SMEM_H);
    cudaFuncSetAttribute(attn2,     cudaFuncAttributeMaxDynamicSharedMemorySize, SMEM_BYTES);

    const dim3 blk(256);

    // compaction + merged gathers
    compact_kernel<<<1, 256>>>(equ_mask, sns_mask, offE, offS, mtot);
    gather2<<<dim3(BSZ, 2), 256>>>(equ_enc, sns_enc, equ_mask, sns_mask, offE, offS,
                                   ee_hi, ee_lo, es_hi, es_lo, rowE, rowS, u_e, u_s);

    // one batched split launch for all weights + prev_h
    {
        SplitArgs sa;
        sa.seg[0] = { prev_h, ph_hi, ph_lo, BSZ * DD / 4 };
        sa.seg[1] = { W2e,  wcat_hi,                       wcat_lo,                       HH * DD / 4 };
        sa.seg[2] = { W2s,  wcat_hi + (size_t)HH * DD,     wcat_lo + (size_t)HH * DD,     HH * DD / 4 };
        sa.seg[3] = { w_hh, wcat_hi + (size_t)2 * HH * DD, wcat_lo + (size_t)2 * HH * DD, G3D * DD / 4 };
        sa.seg[4] = { Wc,   wc_hi,  wc_lo,  HH * YC / 4 };
        sa.seg[5] = { w_ih, wih_hi, wih_lo, G3D * HH / 4 };
        sa.seg[6] = { W1e,  w1e_hi, w1e_lo, HH * HH / 4 };
        sa.seg[7] = { W1s,  w1s_hi, w1s_lo, HH * HH / 4 };
        const int maxb = (G3D * DD / 4 + 255) / 256;
        split_all<<<dim3(maxb, 8), blk>>>(sa);
    }

    // fused [dt_e | dt_s | gh] = prev_h @ Wcat^T
    gemm_sp64<<<dim3(NCAT / 128, BSZ / 64), blk, SMEM64>>>(
        ph_hi, ph_lo, wcat_hi, wcat_lo, nullptr, dtgh, nullptr, nullptr, BSZ, NCAT, DD);

    plan_kernel<<<BSZ, 128>>>(prev_h, plan_W, plan_b, plan, out_plan);

    // merged attention
    attn2<<<dim3(BSZ, 2), blk, SMEM_BYTES>>>(
        ee_hi, ee_lo, es_hi, es_lo,
        w1e_hi, w1e_lo, w1s_hi, w1s_lo,
        dtgh, vte, vts, rowE, rowS, mtot, u_e, u_s);

    // merged softmax + context (masked rows skipped)
    softmax_ctx2<<<dim3(BSZ, 2), blk>>>(u_e, u_s, equ_enc, sns_enc, ctx_e, ctx_s);

    combine_kernel<<<(BSZ * YC) / 256, blk>>>(prev_y, plan, ctx_e, ctx_s, yc_hi, yc_lo);

    gemm_sp64<<<dim3(HH / 128, BSZ / 64), blk, SMEM64>>>(
        yc_hi, yc_lo, wc_hi, wc_lo, bc, nullptr, x_hi, x_lo, BSZ, HH, YC);
    gemm_sp64<<<dim3(G3D / 128, BSZ / 64), blk, SMEM64>>>(
        x_hi, x_lo, wih_hi, wih_lo, b_ih, gx, nullptr, nullptr, BSZ, G3D, HH);

    gru_kernel<<<(BSZ * DD) / 256, blk>>>(gx, dtgh + 2 * HH, b_hh, prev_h, out_hid, hn_h);

    // dec_output = h_new @ Wout^T + bout — SINGLE-PASS fp16 (3x fewer mma)
    gemm_fp16<<<dim3(VV / 128, BSZ / 128), blk, SMEM_H>>>(
        hn_h, Wout, bout, out_dec, BSZ, VV, DD);
}

// round 13
// speedup vs baseline: 5.1118x; 1.2732x over previous
#include <cuda_runtime.h>
#include <cuda_bf16.h>
#include <cuda_fp16.h>
#include <math.h>
#include <stdint.h>

#define HH   512
#define ZZ   128
#define EE   512
#define DD   1152      // 2H + Z
#define VV   32000
#define BSZ  256
#define NN   128
#define G3D  3456      // 3*D
#define NCAT 4480      // 512 (dt_e) + 512 (dt_s) + 3456 (gh)
#define YC   1024      // E + H

// ---------------- scratch (device globals; no allocation allowed) ----------------
__device__ float g_u_e  [BSZ * NN];
__device__ float g_u_s  [BSZ * NN];
__device__ float g_ctx_e[BSZ * HH];
__device__ float g_ctx_s[BSZ * HH];
__device__ float g_plan [BSZ * 2];
__device__ float g_gx   [BSZ * G3D];
__device__ float g_dtgh [BSZ * NCAT];
__device__ int   g_offE [BSZ];
__device__ int   g_offS [BSZ];
__device__ int   g_rowE [BSZ * NN];
__device__ int   g_rowS [BSZ * NN];
__device__ int   g_mtot [2];

__device__ __align__(256) __nv_bfloat16 g_ph_hi [BSZ * DD];
__device__ __align__(256) __nv_bfloat16 g_ph_lo [BSZ * DD];
__device__ __align__(256) __half        g_ee_h  [BSZ * NN * HH];   // gathered enc, fp16
__device__ __align__(256) __half        g_es_h  [BSZ * NN * HH];
__device__ __align__(256) __half        g_w1e_h [HH * HH];         // W1, fp16
__device__ __align__(256) __half        g_w1s_h [HH * HH];
__device__ __align__(256) __nv_bfloat16 g_wcat_hi[NCAT * DD];
__device__ __align__(256) __nv_bfloat16 g_wcat_lo[NCAT * DD];
__device__ __align__(256) __nv_bfloat16 g_wc_hi [HH * YC];
__device__ __align__(256) __nv_bfloat16 g_wc_lo [HH * YC];
__device__ __align__(256) __nv_bfloat16 g_wih_hi[G3D * HH];
__device__ __align__(256) __nv_bfloat16 g_wih_lo[G3D * HH];
__device__ __align__(256) __nv_bfloat16 g_yc_hi [BSZ * YC];
__device__ __align__(256) __nv_bfloat16 g_yc_lo [BSZ * YC];
__device__ __align__(256) __nv_bfloat16 g_x_hi  [BSZ * HH];
__device__ __align__(256) __nv_bfloat16 g_x_lo  [BSZ * HH];
__device__ __align__(256) __half        g_hn_h  [BSZ * DD];        // h_new fp16 (Wout A)

// ---------------- helpers ----------------
__device__ __forceinline__ uint32_t pack_bf2(float a, float b) {
    __nv_bfloat162 t = __floats2bfloat162_rn(a, b);
    return *reinterpret_cast<uint32_t*>(&t);
}
__device__ __forceinline__ uint32_t pack_h2(float a, float b) {
    __half2 t = __floats2half2_rn(a, b);
    return *reinterpret_cast<uint32_t*>(&t);
}

__device__ __forceinline__ void mma16816(float c[4],
                                         uint32_t a0, uint32_t a1, uint32_t a2, uint32_t a3,
                                         uint32_t b0, uint32_t b1) {
    asm volatile(
        "mma.sync.aligned.m16n8k16.row.col.f32.bf16.bf16.f32 "
        "{%0,%1,%2,%3}, {%4,%5,%6,%7}, {%8,%9}, {%0,%1,%2,%3};\n"
        : "+f"(c[0]), "+f"(c[1]), "+f"(c[2]), "+f"(c[3])
        : "r"(a0), "r"(a1), "r"(a2), "r"(a3), "r"(b0), "r"(b1));
}
__device__ __forceinline__ void mma16816h(float c[4],
                                          uint32_t a0, uint32_t a1, uint32_t a2, uint32_t a3,
                                          uint32_t b0, uint32_t b1) {
    asm volatile(
        "mma.sync.aligned.m16n8k16.row.col.f32.f16.f16.f32 "
        "{%0,%1,%2,%3}, {%4,%5,%6,%7}, {%8,%9}, {%0,%1,%2,%3};\n"
        : "+f"(c[0]), "+f"(c[1]), "+f"(c[2]), "+f"(c[3])
        : "r"(a0), "r"(a1), "r"(a2), "r"(a3), "r"(b0), "r"(b1));
}

__device__ __forceinline__ void ldsm_x4(uint32_t& r0, uint32_t& r1, uint32_t& r2, uint32_t& r3,
                                        uint32_t addr) {
    asm volatile("ldmatrix.sync.aligned.m8n8.x4.shared.b16 {%0,%1,%2,%3}, [%4];"
                 : "=r"(r0), "=r"(r1), "=r"(r2), "=r"(r3) : "r"(addr));
}
__device__ __forceinline__ void ldsm_x2(uint32_t& r0, uint32_t& r1, uint32_t addr) {
    asm volatile("ldmatrix.sync.aligned.m8n8.x2.shared.b16 {%0,%1}, [%2];"
                 : "=r"(r0), "=r"(r1) : "r"(addr));
}

#define CP16(dst, src) \
    asm volatile("cp.async.cg.shared.global [%0], [%1], 16;" :: "r"(dst), "l"(src))
#define CP_COMMIT() asm volatile("cp.async.commit_group;")
#define CP_WAIT0()  asm volatile("cp.async.wait_group 0;")

#define SMS 40
#define STG (128 * SMS)
#define STGB (STG * 2)

// BM=64 bf16x3 constants
#define A64  (64 * SMS)
#define A64B (A64 * 2)
#define S64B (2 * A64B + 2 * STGB)
#define SMEM64 (2 * S64B)

// fp16 single-pass constants (Wout + attention)
#define STGB_H STGB                 // one fp16 array = 10240 bytes
#define STAGE_H (2 * STGB_H)        // A + B per stage = 20480
#define SMEM_H (2 * STAGE_H)        // 40960

__device__ __forceinline__ uint32_t ldsm_aoff(int l) {
    return (uint32_t)((((l & 7) + ((l >> 3) & 1) * 8) * SMS + (l >> 4) * 8) * 2);
}
__device__ __forceinline__ uint32_t ldsm_boff(int l) {
    return (uint32_t)(((l & 7) * SMS + ((l >> 3) & 1) * 8) * 2);
}

// =================================================================================
// gemm_sp64: BM=64 x BN=128 pre-split bf16x3 GEMM; single barrier per K-chunk.
// Used for the GRU-path GEMMs (dtgh, x, gx) whose error feeds dec_hidden.
// =================================================================================
__global__ void __launch_bounds__(256, 2) gemm_sp64(
    const __nv_bfloat16* __restrict__ Ahi, const __nv_bfloat16* __restrict__ Alo,
    const __nv_bfloat16* __restrict__ Bhi, const __nv_bfloat16* __restrict__ Blo,
    const float* __restrict__ bias,
    float* __restrict__ C, __nv_bfloat16* __restrict__ Chi, __nv_bfloat16* __restrict__ Clo,
    int M, int N, int K)
{
    extern __shared__ __nv_bfloat16 sm[];

    const int t    = threadIdx.x;
    const int m0   = blockIdx.y * 64;
    const int n0   = blockIdx.x * 128;
    const int lane = t & 31;
    const int wid  = t >> 5;
    const int g    = lane >> 2;
    const int tg   = lane & 3;
    const int wr   = wid & 1;
    const int wc   = wid >> 1;

    const uint32_t smb  = (uint32_t)__cvta_generic_to_shared(sm);
    const uint32_t aoff = ldsm_aoff(lane);
    const uint32_t boff = ldsm_boff(lane);

    const int ar = t >> 2;
    const int ac = (t & 3) * 8;
    const uint32_t atoff = (uint32_t)(ar * SMS + ac) * 2;
    const int br = t >> 1;
    const int bc = (t & 1) * 16;
    const uint32_t btoff = (uint32_t)(br * SMS + bc) * 2;

    const __nv_bfloat16* ApH = Ahi + (size_t)(m0 + ar) * K + ac;
    const __nv_bfloat16* ApL = Alo + (size_t)(m0 + ar) * K + ac;
    const __nv_bfloat16* BpH = Bhi + (size_t)(n0 + br) * K + bc;
    const __nv_bfloat16* BpL = Blo + (size_t)(n0 + br) * K + bc;

    float acc[2][4][4];
#pragma unroll
    for (int mi = 0; mi < 2; mi++)
#pragma unroll
        for (int ni = 0; ni < 4; ni++)
#pragma unroll
            for (int q = 0; q < 4; q++) acc[mi][ni][q] = 0.f;

#define FILL64(D, K0)                                            \
    do {                                                         \
        CP16((D) + atoff,                    ApH + (K0));        \
        CP16((D) + A64B + atoff,             ApL + (K0));        \
        CP16((D) + 2 * A64B + btoff,         BpH + (K0));        \
        CP16((D) + 2 * A64B + btoff + 16,    BpH + (K0) + 8);    \
        CP16((D) + 2 * A64B + STGB + btoff,      BpL + (K0));    \
        CP16((D) + 2 * A64B + STGB + btoff + 16, BpL + (K0) + 8);\
    } while (0)

    FILL64(smb, 0);
    CP_COMMIT();

    for (int k0 = 0; k0 < K; k0 += 32) {
        const int s = (k0 >> 5) & 1;
        const bool more = (k0 + 32 < K);
        CP_WAIT0();
        __syncthreads();
        if (more) {
            FILL64(smb + (uint32_t)(s ^ 1) * S64B, k0 + 32);
            CP_COMMIT();
        }
        const uint32_t stb = smb + (uint32_t)s * S64B;
#pragma unroll
        for (int ks = 0; ks < 2; ks++) {
            const uint32_t kb2 = ks * 32;
            uint32_t bhi[4][2], blo[4][2];
#pragma unroll
            for (int ni = 0; ni < 4; ni++) {
                const uint32_t rb = (uint32_t)(wc * 32 + ni * 8) * (SMS * 2) + kb2 + boff;
                ldsm_x2(bhi[ni][0], bhi[ni][1], stb + 2 * A64B + rb);
                ldsm_x2(blo[ni][0], blo[ni][1], stb + 2 * A64B + STGB + rb);
            }
#pragma unroll
            for (int mi = 0; mi < 2; mi++) {
                const uint32_t ra = (uint32_t)(wr * 32 + mi * 16) * (SMS * 2) + kb2 + aoff;
                uint32_t ah[4], al[4];
                ldsm_x4(ah[0], ah[1], ah[2], ah[3], stb + ra);
                ldsm_x4(al[0], al[1], al[2], al[3], stb + A64B + ra);
#pragma unroll
                for (int ni = 0; ni < 4; ni++) {
                    mma16816(acc[mi][ni], ah[0], ah[1], ah[2], ah[3], bhi[ni][0], bhi[ni][1]);
                    mma16816(acc[mi][ni], ah[0], ah[1], ah[2], ah[3], blo[ni][0], blo[ni][1]);
                    mma16816(acc[mi][ni], al[0], al[1], al[2], al[3], bhi[ni][0], bhi[ni][1]);
                }
            }
        }
    }

#pragma unroll
    for (int mi = 0; mi < 2; mi++) {
        const int row = m0 + wr * 32 + mi * 16 + g;
#pragma unroll
        for (int ni = 0; ni < 4; ni++) {
            const int col = n0 + wc * 32 + ni * 8 + tg * 2;
            float b0 = bias ? bias[col] : 0.f;
            float b1 = bias ? bias[col + 1] : 0.f;
            float c00 = acc[mi][ni][0] + b0, c01 = acc[mi][ni][1] + b1;
            float c10 = acc[mi][ni][2] + b0, c11 = acc[mi][ni][3] + b1;
            if (C) {
                *(float2*)&C[(size_t)row * N + col]       = make_float2(c00, c01);
                *(float2*)&C[(size_t)(row + 8) * N + col] = make_float2(c10, c11);
            }
            if (Chi) {
                __nv_bfloat16 h00 = __float2bfloat16(c00), h01 = __float2bfloat16(c01);
                __nv_bfloat16 h10 = __float2bfloat16(c10), h11 = __float2bfloat16(c11);
                *(uint32_t*)&Chi[(size_t)row * N + col]       = pack_bf2(c00, c01);
                *(uint32_t*)&Chi[(size_t)(row + 8) * N + col] = pack_bf2(c10, c11);
                *(uint32_t*)&Clo[(size_t)row * N + col] =
                    pack_bf2(c00 - __bfloat162float(h00), c01 - __bfloat162float(h01));
                *(uint32_t*)&Clo[(size_t)(row + 8) * N + col] =
                    pack_bf2(c10 - __bfloat162float(h10), c11 - __bfloat162float(h11));
            }
        }
    }
}

// =================================================================================
// gemm_fp16: SINGLE-PASS fp16 GEMM for Wout.  A fp16, B fp32 -> fp16 in-kernel.
// =================================================================================
__global__ void __launch_bounds__(256, 2) gemm_fp16(
    const __half* __restrict__ A, const float* __restrict__ B,
    const float* __restrict__ bias, float* __restrict__ C,
    int M, int N, int K)
{
    extern __shared__ __half smh[];

    const int t    = threadIdx.x;
    const int m0   = blockIdx.y * 128;
    const int n0   = blockIdx.x * 128;
    const int lane = t & 31;
    const int wid  = t >> 5;
    const int g    = lane >> 2;
    const int tg   = lane & 3;
    const int wr   = wid & 1;
    const int wc   = wid >> 1;

    const uint32_t smb  = (uint32_t)__cvta_generic_to_shared(smh);
    const uint32_t aoff = ldsm_aoff(lane);
    const uint32_t boff = ldsm_boff(lane);

    const int r  = t >> 1;
    const int hh = (t & 1) * 16;
    const uint32_t toff = (uint32_t)(r * SMS + hh) * 2;
    const int idx = r * SMS + hh;
    const __half* Ap = A + (size_t)(m0 + r) * K + hh;
    const float*  Bp = B + (size_t)(n0 + r) * K + hh;

    float acc[4][4][4];
#pragma unroll
    for (int mi = 0; mi < 4; mi++)
#pragma unroll
        for (int ni = 0; ni < 4; ni++)
#pragma unroll
            for (int q = 0; q < 4; q++) acc[mi][ni][q] = 0.f;

#define CVTB_H(ST, RB)                                                        \
    do {                                                                      \
        __half* bdst = smh + (ST) * (STAGE_H / 2) + (STGB_H / 2) + idx;       \
        uint4 v0, v1;                                                         \
        v0.x = pack_h2((RB)[0].x, (RB)[0].y); v0.y = pack_h2((RB)[0].z, (RB)[0].w); \
        v0.z = pack_h2((RB)[1].x, (RB)[1].y); v0.w = pack_h2((RB)[1].z, (RB)[1].w); \
        v1.x = pack_h2((RB)[2].x, (RB)[2].y); v1.y = pack_h2((RB)[2].z, (RB)[2].w); \
        v1.z = pack_h2((RB)[3].x, (RB)[3].y); v1.w = pack_h2((RB)[3].z, (RB)[3].w); \
        *(uint4*)bdst       = v0;                                             \
        *(uint4*)(bdst + 8) = v1;                                             \
    } while (0)

    CP16(smb + toff,      Ap);
    CP16(smb + toff + 16, Ap + 8);
    CP_COMMIT();
    {
        float4 rb0[4];
#pragma unroll
        for (int i = 0; i < 4; i++) rb0[i] = *(const float4*)(Bp + i * 4);
        CVTB_H(0, rb0);
    }

    for (int k0 = 0; k0 < K; k0 += 32) {
        const int s = (k0 >> 5) & 1;
        const bool more = (k0 + 32 < K);
        CP_WAIT0();
        __syncthreads();
        float4 rb[4];
        if (more) {
            const uint32_t d = smb + (uint32_t)(s ^ 1) * STAGE_H + toff;
            CP16(d,      Ap + k0 + 32);
            CP16(d + 16, Ap + k0 + 40);
            CP_COMMIT();
#pragma unroll
            for (int i = 0; i < 4; i++) rb[i] = *(const float4*)(Bp + k0 + 32 + i * 4);
        }
        const uint32_t stb = smb + (uint32_t)s * STAGE_H;
#pragma unroll
        for (int ks = 0; ks < 2; ks++) {
            const uint32_t kb2 = ks * 32;
            uint32_t bf[4][2];
#pragma unroll
            for (int ni = 0; ni < 4; ni++) {
                const uint32_t rbo = (uint32_t)(wc * 32 + ni * 8) * (SMS * 2) + kb2 + boff;
                ldsm_x2(bf[ni][0], bf[ni][1], stb + STGB_H + rbo);
            }
#pragma unroll
            for (int mi = 0; mi < 4; mi++) {
                const uint32_t ra = (uint32_t)(wr * 64 + mi * 16) * (SMS * 2) + kb2 + aoff;
                uint32_t a0, a1, a2, a3;
                ldsm_x4(a0, a1, a2, a3, stb + ra);
#pragma unroll
                for (int ni = 0; ni < 4; ni++)
                    mma16816h(acc[mi][ni], a0, a1, a2, a3, bf[ni][0], bf[ni][1]);
            }
        }
        if (more) CVTB_H(s ^ 1, rb);
    }

#pragma unroll
    for (int mi = 0; mi < 4; mi++) {
        const int row = m0 + wr * 64 + mi * 16 + g;
#pragma unroll
        for (int ni = 0; ni < 4; ni++) {
            const int col = n0 + wc * 32 + ni * 8 + tg * 2;
            const float b0 = bias[col], b1 = bias[col + 1];
            *(float2*)&C[(size_t)row * N + col] =
                make_float2(acc[mi][ni][0] + b0, acc[mi][ni][1] + b1);
            *(float2*)&C[(size_t)(row + 8) * N + col] =
                make_float2(acc[mi][ni][2] + b0, acc[mi][ni][3] + b1);
        }
    }
}

// =================================================================================
// batched split: fp32 -> bf16 hi/lo segments (grid.y = segment); 6 segments now
// =================================================================================
struct SplitSeg { const float* src; __nv_bfloat16* hi; __nv_bfloat16* lo; int n4; };
struct SplitArgs { SplitSeg seg[6]; };

__global__ void split_all(SplitArgs a)
{
    const SplitSeg s = a.seg[blockIdx.y];
    const int i = blockIdx.x * blockDim.x + threadIdx.x;
    if (i >= s.n4) return;
    float4 v = ((const float4*)s.src)[i];
    __nv_bfloat16 hx = __float2bfloat16(v.x), hy = __float2bfloat16(v.y);
    __nv_bfloat16 hz = __float2bfloat16(v.z), hw = __float2bfloat16(v.w);
    uint2 vh, vl;
    vh.x = pack_bf2(v.x, v.y); vh.y = pack_bf2(v.z, v.w);
    vl.x = pack_bf2(v.x - __bfloat162float(hx), v.y - __bfloat162float(hy));
    vl.y = pack_bf2(v.z - __bfloat162float(hz), v.w - __bfloat162float(hw));
    ((uint2*)s.hi)[i] = vh;
    ((uint2*)s.lo)[i] = vl;
}

// W1e/W1s fp32 -> fp16 (grid.y = side)
__global__ void cvt_h2(const float* __restrict__ We, const float* __restrict__ Ws,
                       __half* __restrict__ he, __half* __restrict__ hs, int n4)
{
    const int side = blockIdx.y;
    const float* src = side ? Ws : We;
    __half* dst = side ? hs : he;
    const int i = blockIdx.x * blockDim.x + threadIdx.x;
    if (i >= n4) return;
    float4 v = ((const float4*)src)[i];
    uint2 o;
    o.x = pack_h2(v.x, v.y);
    o.y = pack_h2(v.z, v.w);
    ((uint2*)dst)[i] = o;
}

// =================================================================================
// compact: per-batch exclusive offsets of unmasked positions (both masks)
// =================================================================================
__global__ void compact_kernel(const int* __restrict__ mE, const int* __restrict__ mS,
                               int* __restrict__ offE, int* __restrict__ offS,
                               int* __restrict__ mtot)
{
    __shared__ int sE[256], sS[256];
    const int b = threadIdx.x;
    int cE = 0, cS = 0;
    for (int n = 0; n < NN; n++) {
        cE += (mE[b * NN + n] == 0);
        cS += (mS[b * NN + n] == 0);
    }
    sE[b] = cE; sS[b] = cS;
    __syncthreads();
    for (int d = 1; d < 256; d <<= 1) {
        int vE = 0, vS = 0;
        if (b >= d) { vE = sE[b - d]; vS = sS[b - d]; }
        __syncthreads();
        sE[b] += vE; sS[b] += vS;
        __syncthreads();
    }
    offE[b] = sE[b] - cE;
    offS[b] = sS[b] - cS;
    if (b == 255) { mtot[0] = sE[255]; mtot[1] = sS[255]; }
}

// =================================================================================
// merged gather (grid.y = side): compact unmasked enc rows -> fp16 (single array)
// =================================================================================
__global__ void gather2(const float* __restrict__ encE, const float* __restrict__ encS,
                        const int* __restrict__ mE, const int* __restrict__ mS,
                        const int* __restrict__ offE, const int* __restrict__ offS,
                        __half* __restrict__ geh, __half* __restrict__ gsh,
                        int* __restrict__ rowE, int* __restrict__ rowS,
                        float* __restrict__ uE, float* __restrict__ uS)
{
    const int side = blockIdx.y;
    const float* enc = side ? encS : encE;
    const int* mask  = side ? mS : mE;
    const int* off   = side ? offS : offE;
    __half* gh = side ? gsh : geh;
    int* rowinfo = side ? rowS : rowE;
    float* u     = side ? uS : uE;

    __shared__ int s_list[NN];
    __shared__ int s_wtot[8];
    const int b = blockIdx.x;
    const int t = threadIdx.x;
    const int base = off[b];
    const bool in = t < NN;
    const bool valid = in && (mask[b * NN + t] == 0);
    const unsigned wm = __ballot_sync(0xffffffffu, valid);
    const int lane = t & 31, w = t >> 5;
    if (lane == 0) s_wtot[w] = __popc(wm);
    __syncthreads();
    int wbase = 0;
#pragma unroll
    for (int i = 0; i < 4; i++) if (i < w) wbase += s_wtot[i];
    const int rank = wbase + __popc(wm & ((1u << lane) - 1));
    if (valid) {
        s_list[rank] = t;
        rowinfo[base + rank] = b * NN + t;
    } else if (in) {
        u[b * NN + t] = -INFINITY;
    }
    __syncthreads();
    const int cnt = s_wtot[0] + s_wtot[1] + s_wtot[2] + s_wtot[3];

    for (int i = 0; i < cnt; i++) {
        const int n = s_list[i];
        const float2 v = *(const float2*)(enc + ((size_t)b * NN + n) * HH + t * 2);
        *(uint32_t*)&gh[((size_t)base + i) * HH + t * 2] = pack_h2(v.x, v.y);
    }
}

// =================================================================================
// merged attention, SINGLE-PASS fp16 (grid = (256, 2)); compacted rows.
// =================================================================================
__global__ void __launch_bounds__(256, 2) attn2h(
    const __half* __restrict__ geh, const __half* __restrict__ gsh,
    const __half* __restrict__ w1eh, const __half* __restrict__ w1sh,
    const float* __restrict__ dtg,
    const float* __restrict__ vte, const float* __restrict__ vts,
    const int* __restrict__ rowE, const int* __restrict__ rowS,
    const int* __restrict__ mtotp,
    float* __restrict__ uE, float* __restrict__ uS)
{
    extern __shared__ __half smh[];
    __shared__ float s_vt[512];
    __shared__ float s_u[128];

    const int side = blockIdx.y;
    const int mtot = mtotp[side];
    const int m0 = blockIdx.x * 128;
    if (m0 >= mtot) return;

    const __half* ge  = side ? gsh : geh;
    const __half* w1h = side ? w1sh : w1eh;
    const float* vt = side ? vts : vte;
    const int* rowinfo = side ? rowS : rowE;
    float* u = side ? uS : uE;

    const int t    = threadIdx.x;
    const int lane = t & 31;
    const int wid  = t >> 5;
    const int g    = lane >> 2;
    const int tg   = lane & 3;
    const int wr   = wid & 1;
    const int wc   = wid >> 1;

    const uint32_t smb  = (uint32_t)__cvta_generic_to_shared(smh);
    const uint32_t aoff = ldsm_aoff(lane);
    const uint32_t boff = ldsm_boff(lane);

    for (int i = t; i < 512; i += 256) s_vt[i] = vt[i];
    if (t < 128) s_u[t] = 0.f;

    int rb4[4][2];
#pragma unroll
    for (int mi = 0; mi < 4; mi++)
#pragma unroll
        for (int rr = 0; rr < 2; rr++)
            rb4[mi][rr] = rowinfo[m0 + wr * 64 + mi * 16 + g + rr * 8] >> 7;

    const int r  = t >> 1;
    const int hh = (t & 1) * 16;
    const uint32_t toff = (uint32_t)(r * SMS + hh) * 2;
    const __half* Ap = ge + (size_t)(m0 + r) * 512 + hh;

    float up[8];
#pragma unroll
    for (int i = 0; i < 8; i++) up[i] = 0.f;

    for (int nc = 0; nc < 4; nc++) {
        const __half* Bp = w1h + (size_t)(nc * 128 + r) * 512 + hh;

        float acc[4][4][4];
#pragma unroll
        for (int mi = 0; mi < 4; mi++)
#pragma unroll
            for (int ni = 0; ni < 4; ni++)
#pragma unroll
                for (int q = 0; q < 4; q++) acc[mi][ni][q] = 0.f;

        // stage 0
        CP16(smb + toff,               Ap);
        CP16(smb + toff + 16,          Ap + 8);
        CP16(smb + STGB_H + toff,      Bp);
        CP16(smb + STGB_H + toff + 16, Bp + 8);
        CP_COMMIT();

        for (int k0 = 0; k0 < 512; k0 += 32) {
            const int s = (k0 >> 5) & 1;
            const bool more = (k0 + 32 < 512);
            CP_WAIT0();
            __syncthreads();
            if (more) {
                const uint32_t d = smb + (uint32_t)(s ^ 1) * STAGE_H;
                CP16(d + toff,               Ap + k0 + 32);
                CP16(d + toff + 16,          Ap + k0 + 40);
                CP16(d + STGB_H + toff,      Bp + k0 + 32);
                CP16(d + STGB_H + toff + 16, Bp + k0 + 40);
                CP_COMMIT();
            }
            const uint32_t stb = smb + (uint32_t)s * STAGE_H;
#pragma unroll
            for (int ks = 0; ks < 2; ks++) {
                const uint32_t kb2 = ks * 32;
                uint32_t bf[4][2];
#pragma unroll
                for (int ni = 0; ni < 4; ni++) {
                    const uint32_t rbo = (uint32_t)(wc * 32 + ni * 8) * (SMS * 2) + kb2 + boff;
                    ldsm_x2(bf[ni][0], bf[ni][1], stb + STGB_H + rbo);
                }
#pragma unroll
                for (int mi = 0; mi < 4; mi++) {
                    const uint32_t ra = (uint32_t)(wr * 64 + mi * 16) * (SMS * 2) + kb2 + aoff;
                    uint32_t a0, a1, a2, a3;
                    ldsm_x4(a0, a1, a2, a3, stb + ra);
#pragma unroll
                    for (int ni = 0; ni < 4; ni++)
                        mma16816h(acc[mi][ni], a0, a1, a2, a3, bf[ni][0], bf[ni][1]);
                }
            }
        }

#pragma unroll
        for (int mi = 0; mi < 4; mi++) {
            const float* dt0 = dtg + (size_t)rb4[mi][0] * NCAT + (side ? HH : 0);
            const float* dt1 = dtg + (size_t)rb4[mi][1] * NCAT + (side ? HH : 0);
#pragma unroll
            for (int ni = 0; ni < 4; ni++) {
                const int col = nc * 128 + wc * 32 + ni * 8 + tg * 2;
                const float v0 = s_vt[col], v1 = s_vt[col + 1];
                up[mi * 2 + 0] += v0 * tanhf(acc[mi][ni][0] + dt0[col])
                                + v1 * tanhf(acc[mi][ni][1] + dt0[col + 1]);
                up[mi * 2 + 1] += v0 * tanhf(acc[mi][ni][2] + dt1[col])
                                + v1 * tanhf(acc[mi][ni][3] + dt1[col + 1]);
            }
        }
    }

#pragma unroll
    for (int mi = 0; mi < 4; mi++)
#pragma unroll
        for (int rr = 0; rr < 2; rr++) {
            float v = up[mi * 2 + rr];
            v += __shfl_down_sync(0xffffffffu, v, 1);
            v += __shfl_down_sync(0xffffffffu, v, 2);
            if (tg == 0)
                atomicAdd(&s_u[wr * 64 + mi * 16 + g + rr * 8], v);
        }
    __syncthreads();

    if (t < 128 && m0 + t < mtot)
        u[rowinfo[m0 + t]] = s_u[t];
}

// =================================================================================
// plan = softmax(prev_h @ plan_W^T + plan_b)
// =================================================================================
__global__ void plan_kernel(const float* __restrict__ prev_h,
                            const float* __restrict__ plan_W,
                            const float* __restrict__ plan_b,
                            float* __restrict__ plan,
                            float* __restrict__ out_plan)
{
    const int b = blockIdx.x;
    const int t = threadIdx.x;
    __shared__ float s0[128], s1[128];
    float a0 = 0.f, a1 = 0.f;
    const float* hb = prev_h + (size_t)b * DD;
    for (int k = t; k < DD; k += 128) {
        const float h = hb[k];
        a0 += h * plan_W[k];
        a1 += h * plan_W[DD + k];
    }
    s0[t] = a0; s1[t] = a1;
    __syncthreads();
    for (int s = 64; s > 0; s >>= 1) {
        if (t < s) { s0[t] += s0[t + s]; s1[t] += s1[t + s]; }
        __syncthreads();
    }
    if (t == 0) {
        const float l0 = s0[0] + plan_b[0];
        const float l1 = s1[0] + plan_b[1];
        const float mx = fmaxf(l0, l1);
        const float e0 = expf(l0 - mx), e1 = expf(l1 - mx);
        const float inv = 1.f / (e0 + e1);
        plan[2 * b] = e0 * inv;       plan[2 * b + 1] = e1 * inv;
        out_plan[2 * b] = e0 * inv;   out_plan[2 * b + 1] = e1 * inv;
    }
}

// =================================================================================
// merged softmax+context (grid = (BSZ, 2)) — skips masked rows (aw == 0 exactly)
// =================================================================================
__global__ void softmax_ctx2(const float* __restrict__ uE, const float* __restrict__ uS,
                             const float* __restrict__ encE, const float* __restrict__ encS,
                             float* __restrict__ ctxE, float* __restrict__ ctxS)
{
    const int side = blockIdx.y;
    const float* u   = side ? uS : uE;
    const float* enc = side ? encS : encE;
    float* ctx       = side ? ctxS : ctxE;

    const int b = blockIdx.x;
    const int t = threadIdx.x;
    __shared__ float red[256];
    __shared__ float s_aw[NN];
    __shared__ int   s_list[NN];
    __shared__ int   s_wtot[4];

    const float uv = (t < NN) ? u[(size_t)b * NN + t] : -INFINITY;
    red[t] = uv;
    __syncthreads();
    for (int s = 128; s > 0; s >>= 1) {
        if (t < s) red[t] = fmaxf(red[t], red[t + s]);
        __syncthreads();
    }
    const float mx = red[0];
    __syncthreads();
    const float e = (t < NN) ? expf(uv - mx) : 0.f;
    red[t] = e;
    __syncthreads();
    for (int s = 128; s > 0; s >>= 1) {
        if (t < s) red[t] += red[t + s];
        __syncthreads();
    }
    const float inv = 1.f / red[0];

    const bool valid = (t < NN) && (uv != -INFINITY);
    const unsigned wm = __ballot_sync(0xffffffffu, valid);
    const int lane = t & 31, w = t >> 5;
    if (lane == 0 && w < 4) s_wtot[w] = __popc(wm);
    __syncthreads();
    int wbase = 0;
#pragma unroll
    for (int i = 0; i < 4; i++) if (i < w) wbase += s_wtot[i];
    if (valid) {
        const int rank = wbase + __popc(wm & ((1u << lane) - 1));
        s_list[rank] = t;
        s_aw[rank] = e * inv;
    }
    __syncthreads();
    const int cnt = s_wtot[0] + s_wtot[1] + s_wtot[2] + s_wtot[3];

    const float* eb = enc + (size_t)b * NN * HH;
    for (int h = t; h < HH; h += 256) {
        float s = 0.f;
        for (int i = 0; i < cnt; i++)
            s += s_aw[i] * eb[(size_t)s_list[i] * HH + h];
        ctx[(size_t)b * HH + h] = s;
    }
}

// =================================================================================
// y_ctx = [prev_y | plan0*ctx_e + plan1*ctx_s], written pre-split
// =================================================================================
__global__ void combine_kernel(const float* __restrict__ prev_y,
                               const float* __restrict__ plan,
                               const float* __restrict__ ctx_e,
                               const float* __restrict__ ctx_s,
                               __nv_bfloat16* __restrict__ ychi,
                               __nv_bfloat16* __restrict__ yclo)
{
    const int idx = blockIdx.x * blockDim.x + threadIdx.x;
    if (idx >= BSZ * YC) return;
    const int b = idx >> 10;
    const int c = idx & 1023;
    float v;
    if (c < EE) {
        v = prev_y[(size_t)b * EE + c];
    } else {
        const float p0 = plan[2 * b], p1 = plan[2 * b + 1];
        const int h = c - EE;
        v = p0 * ctx_e[(size_t)b * HH + h] + p1 * ctx_s[(size_t)b * HH + h];
    }
    __nv_bfloat16 hv = __float2bfloat16(v);
    ychi[idx] = hv;
    yclo[idx] = __float2bfloat16(v - __bfloat162float(hv));
}

// =================================================================================
// GRU cell elementwise; outputs out_hid (fp32) + hn fp16 (Wout A operand)
// =================================================================================
__global__ void gru_kernel(const float* __restrict__ gx,
                           const float* __restrict__ ghbase,
                           const float* __restrict__ b_hh,
                           const float* __restrict__ prev_h,
                           float* __restrict__ out_hid,
                           __half* __restrict__ hnh)
{
    const int idx = blockIdx.x * blockDim.x + threadIdx.x;
    if (idx >= BSZ * DD) return;
    const int b = idx / DD;
    const int d = idx - b * DD;
    const float* gxb = gx + (size_t)b * G3D;
    const float* ghb = ghbase + (size_t)b * NCAT;
    const float ghr = ghb[d]          + b_hh[d];
    const float ghz = ghb[DD + d]     + b_hh[DD + d];
    const float ghn = ghb[2 * DD + d] + b_hh[2 * DD + d];
    const float r = 1.f / (1.f + expf(-(gxb[d] + ghr)));
    const float z = 1.f / (1.f + expf(-(gxb[DD + d] + ghz)));
    const float n = tanhf(gxb[2 * DD + d] + r * ghn);
    const float h = (1.f - z) * n + z * prev_h[idx];
    out_hid[idx] = h;
    hnh[idx] = __float2half_rn(h);
}

// =================================================================================
// host launcher — graph-capturable
// =================================================================================
extern "C" void kernel_launch(void* const* d_in, const int* in_sizes, int n_in,
                              void* d_out, int out_size)
{
    const float* prev_y  = (const float*)d_in[0];
    const float* prev_h  = (const float*)d_in[1];
    const float* equ_enc = (const float*)d_in[2];
    const float* sns_enc = (const float*)d_in[3];
    const int* equ_mask = (const int*)d_in[5];
    const int* sns_mask = (const int*)d_in[6];
    const float* W1e    = (const float*)d_in[7];
    const float* W2e    = (const float*)d_in[8];
    const float* vte    = (const float*)d_in[9];
    const float* W1s    = (const float*)d_in[10];
    const float* W2s    = (const float*)d_in[11];
    const float* vts    = (const float*)d_in[12];
    const float* plan_W = (const float*)d_in[13];
    const float* plan_b = (const float*)d_in[14];
    const float* Wc     = (const float*)d_in[15];
    const float* bc     = (const float*)d_in[16];
    const float* w_ih   = (const float*)d_in[17];
    const float* w_hh   = (const float*)d_in[18];
    const float* b_ih   = (const float*)d_in[19];
    const float* b_hh   = (const float*)d_in[20];
    const float* Wout   = (const float*)d_in[21];
    const float* bout   = (const float*)d_in[22];

    float* out      = (float*)d_out;
    float* out_dec  = out;
    float* out_hid  = out + (size_t)BSZ * VV;
    float* out_plan = out + (size_t)BSZ * VV + (size_t)BSZ * DD;

    float *u_e, *u_s, *ctx_e, *ctx_s, *plan, *gx, *dtgh;
    int *offE, *offS, *rowE, *rowS, *mtot;
    __nv_bfloat16 *ph_hi, *ph_lo;
    __nv_bfloat16 *wcat_hi, *wcat_lo, *wc_hi, *wc_lo, *wih_hi, *wih_lo;
    __nv_bfloat16 *yc_hi, *yc_lo, *x_hi, *x_lo;
    __half *ee_h, *es_h, *w1e_h, *w1s_h, *hn_h;
    cudaGetSymbolAddress((void**)&u_e,   g_u_e);
    cudaGetSymbolAddress((void**)&u_s,   g_u_s);
    cudaGetSymbolAddress((void**)&ctx_e, g_ctx_e);
    cudaGetSymbolAddress((void**)&ctx_s, g_ctx_s);
    cudaGetSymbolAddress((void**)&plan,  g_plan);
    cudaGetSymbolAddress((void**)&gx,    g_gx);
    cudaGetSymbolAddress((void**)&dtgh,  g_dtgh);
    cudaGetSymbolAddress((void**)&offE,  g_offE);
    cudaGetSymbolAddress((void**)&offS,  g_offS);
    cudaGetSymbolAddress((void**)&rowE,  g_rowE);
    cudaGetSymbolAddress((void**)&rowS,  g_rowS);
    cudaGetSymbolAddress((void**)&mtot,  g_mtot);
    cudaGetSymbolAddress((void**)&ph_hi, g_ph_hi);  cudaGetSymbolAddress((void**)&ph_lo, g_ph_lo);
    cudaGetSymbolAddress((void**)&ee_h,  g_ee_h);   cudaGetSymbolAddress((void**)&es_h,  g_es_h);
    cudaGetSymbolAddress((void**)&w1e_h, g_w1e_h);  cudaGetSymbolAddress((void**)&w1s_h, g_w1s_h);
    cudaGetSymbolAddress((void**)&wcat_hi, g_wcat_hi); cudaGetSymbolAddress((void**)&wcat_lo, g_wcat_lo);
    cudaGetSymbolAddress((void**)&wc_hi, g_wc_hi);  cudaGetSymbolAddress((void**)&wc_lo, g_wc_lo);
    cudaGetSymbolAddress((void**)&wih_hi, g_wih_hi); cudaGetSymbolAddress((void**)&wih_lo, g_wih_lo);
    cudaGetSymbolAddress((void**)&yc_hi, g_yc_hi);  cudaGetSymbolAddress((void**)&yc_lo, g_yc_lo);
    cudaGetSymbolAddress((void**)&x_hi,  g_x_hi);   cudaGetSymbolAddress((void**)&x_lo,  g_x_lo);
    cudaGetSymbolAddress((void**)&hn_h,  g_hn_h);

    cudaFuncSetAttribute(gemm_sp64, cudaFuncAttributeMaxDynamicSharedMemorySize, SMEM64);
    cudaFuncSetAttribute(gemm_fp16, cudaFuncAttributeMaxDynamicSharedMemorySize, SMEM_H);
    cudaFuncSetAttribute(attn2h,    cudaFuncAttributeMaxDynamicSharedMemorySize, SMEM_H);

    const dim3 blk(256);

    // compaction + merged fp16 gathers
    compact_kernel<<<1, 256>>>(equ_mask, sns_mask, offE, offS, mtot);
    gather2<<<dim3(BSZ, 2), 256>>>(equ_enc, sns_enc, equ_mask, sns_mask, offE, offS,
                                   ee_h, es_h, rowE, rowS, u_e, u_s);

    // W1 -> fp16 (one launch, both sides)
    cvt_h2<<<dim3((HH * HH / 4 + 255) / 256, 2), blk>>>(W1e, W1s, w1e_h, w1s_h, HH * HH / 4);

    // batched bf16 hi/lo splits (GRU-path operands only)
    {
        SplitArgs sa;
        sa.seg[0] = { prev_h, ph_hi, ph_lo, BSZ * DD / 4 };
        sa.seg[1] = { W2e,  wcat_hi,                       wcat_lo,                       HH * DD / 4 };
        sa.seg[2] = { W2s,  wcat_hi + (size_t)HH * DD,     wcat_lo + (size_t)HH * DD,     HH * DD / 4 };
        sa.seg[3] = { w_hh, wcat_hi + (size_t)2 * HH * DD, wcat_lo + (size_t)2 * HH * DD, G3D * DD / 4 };
        sa.seg[4] = { Wc,   wc_hi,  wc_lo,  HH * YC / 4 };
        sa.seg[5] = { w_ih, wih_hi, wih_lo, G3D * HH / 4 };
        const int maxb = (G3D * DD / 4 + 255) / 256;
        split_all<<<dim3(maxb, 6), blk>>>(sa);
    }

    // fused [dt_e | dt_s | gh] = prev_h @ Wcat^T
    gemm_sp64<<<dim3(NCAT / 128, BSZ / 64), blk, SMEM64>>>(
        ph_hi, ph_lo, wcat_hi, wcat_lo, nullptr, dtgh, nullptr, nullptr, BSZ, NCAT, DD);

    plan_kernel<<<BSZ, 128>>>(prev_h, plan_W, plan_b, plan, out_plan);

    // merged attention, fp16 single-pass
    attn2h<<<dim3(BSZ, 2), blk, SMEM_H>>>(
        ee_h, es_h, w1e_h, w1s_h, dtgh, vte, vts, rowE, rowS, mtot, u_e, u_s);

    // merged softmax + context (masked rows skipped)
    softmax_ctx2<<<dim3(BSZ, 2), blk>>>(u_e, u_s, equ_enc, sns_enc, ctx_e, ctx_s);

    combine_kernel<<<(BSZ * YC) / 256, blk>>>(prev_y, plan, ctx_e, ctx_s, yc_hi, yc_lo);

    gemm_sp64<<<dim3(HH / 128, BSZ / 64), blk, SMEM64>>>(
        yc_hi, yc_lo, wc_hi, wc_lo, bc, nullptr, x_hi, x_lo, BSZ, HH, YC);
    gemm_sp64<<<dim3(G3D / 128, BSZ / 64), blk, SMEM64>>>(
        x_hi, x_lo, wih_hi, wih_lo, b_ih, gx, nullptr, nullptr, BSZ, G3D, HH);

    gru_kernel<<<(BSZ * DD) / 256, blk>>>(gx, dtgh + 2 * HH, b_hh, prev_h, out_hid, hn_h);

    // dec_output = h_new @ Wout^T + bout — single-pass fp16
    gemm_fp16<<<dim3(VV / 128, BSZ / 128), blk, SMEM_H>>>(
        hn_h, Wout, bout, out_dec, BSZ, VV, DD);
}

// round 14
// speedup vs baseline: 5.5059x; 1.0771x over previous
#include <cuda_runtime.h>
#include <cuda_fp16.h>
#include <math.h>
#include <stdint.h>

#define HH   512
#define ZZ   128
#define EE   512
#define DD   1152      // 2H + Z
#define VV   32000
#define BSZ  256
#define NN   128
#define G3D  3456      // 3*D
#define NCAT 4480      // 512 (dt_e) + 512 (dt_s) + 3456 (gh)
#define YC   1024      // E + H

// ---------------- scratch (device globals; no allocation allowed) ----------------
__device__ float g_u_e  [BSZ * NN];
__device__ float g_u_s  [BSZ * NN];
__device__ float g_ctx_e[BSZ * HH];
__device__ float g_ctx_s[BSZ * HH];
__device__ float g_plan [BSZ * 2];
__device__ float g_gx   [BSZ * G3D];
__device__ float g_dtgh [BSZ * NCAT];
__device__ int   g_offE [BSZ];
__device__ int   g_offS [BSZ];
__device__ int   g_rowE [BSZ * NN];
__device__ int   g_rowS [BSZ * NN];
__device__ int   g_mtot [2];

// fp16 operands (16B-aligned for cp.async / ldmatrix)
__device__ __align__(256) __half g_ph_h  [BSZ * DD];
__device__ __align__(256) __half g_ee_h  [BSZ * NN * HH];
__device__ __align__(256) __half g_es_h  [BSZ * NN * HH];
__device__ __align__(256) __half g_w1e_h [HH * HH];
__device__ __align__(256) __half g_w1s_h [HH * HH];
__device__ __align__(256) __half g_wcat_h[NCAT * DD];
__device__ __align__(256) __half g_wc_h  [HH * YC];
__device__ __align__(256) __half g_wih_h [G3D * HH];
__device__ __align__(256) __half g_yc_h  [BSZ * YC];
__device__ __align__(256) __half g_x_h   [BSZ * HH];
__device__ __align__(256) __half g_hn_h  [BSZ * DD];

// ---------------- helpers ----------------
__device__ __forceinline__ uint32_t pack_h2(float a, float b) {
    __half2 t = __floats2half2_rn(a, b);
    return *reinterpret_cast<uint32_t*>(&t);
}

__device__ __forceinline__ void mma16816h(float c[4],
                                          uint32_t a0, uint32_t a1, uint32_t a2, uint32_t a3,
                                          uint32_t b0, uint32_t b1) {
    asm volatile(
        "mma.sync.aligned.m16n8k16.row.col.f32.f16.f16.f32 "
        "{%0,%1,%2,%3}, {%4,%5,%6,%7}, {%8,%9}, {%0,%1,%2,%3};\n"
        : "+f"(c[0]), "+f"(c[1]), "+f"(c[2]), "+f"(c[3])
        : "r"(a0), "r"(a1), "r"(a2), "r"(a3), "r"(b0), "r"(b1));
}

__device__ __forceinline__ void ldsm_x4(uint32_t& r0, uint32_t& r1, uint32_t& r2, uint32_t& r3,
                                        uint32_t addr) {
    asm volatile("ldmatrix.sync.aligned.m8n8.x4.shared.b16 {%0,%1,%2,%3}, [%4];"
                 : "=r"(r0), "=r"(r1), "=r"(r2), "=r"(r3) : "r"(addr));
}
__device__ __forceinline__ void ldsm_x2(uint32_t& r0, uint32_t& r1, uint32_t addr) {
    asm volatile("ldmatrix.sync.aligned.m8n8.x2.shared.b16 {%0,%1}, [%2];"
                 : "=r"(r0), "=r"(r1) : "r"(addr));
}

#define CP16(dst, src) \
    asm volatile("cp.async.cg.shared.global [%0], [%1], 16;" :: "r"(dst), "l"(src))
#define CP_COMMIT() asm volatile("cp.async.commit_group;")
#define CP_WAIT0()  asm volatile("cp.async.wait_group 0;")

#define SMS 40
#define STG (128 * SMS)
#define STGB_H (STG * 2)            // 128-row fp16 array = 10240 bytes
#define STAGE_H (2 * STGB_H)        // A(128) + B(128) per stage = 20480
#define SMEM_H (2 * STAGE_H)        // 40960

// BM=64 fp16 constants
#define A64HB (64 * SMS * 2)        // 5120 bytes
#define S64HB (A64HB + STGB_H)      // 15360 per stage
#define SMEM64H (2 * S64HB)         // 30720

__device__ __forceinline__ uint32_t ldsm_aoff(int l) {
    return (uint32_t)((((l & 7) + ((l >> 3) & 1) * 8) * SMS + (l >> 4) * 8) * 2);
}
__device__ __forceinline__ uint32_t ldsm_boff(int l) {
    return (uint32_t)(((l & 7) * SMS + ((l >> 3) & 1) * 8) * 2);
}

// =================================================================================
// gemm_h64: BM=64 x BN=128 fp16 single-pass GEMM, both operands pre-converted.
// Pure cp.async staging, single barrier per K-chunk.  C fp32 and/or Ch fp16 out.
// =================================================================================
__global__ void __launch_bounds__(256, 2) gemm_h64(
    const __half* __restrict__ A, const __half* __restrict__ B,
    const float* __restrict__ bias,
    float* __restrict__ C, __half* __restrict__ Ch,
    int M, int N, int K)
{
    extern __shared__ __half smh[];

    const int t    = threadIdx.x;
    const int m0   = blockIdx.y * 64;
    const int n0   = blockIdx.x * 128;
    const int lane = t & 31;
    const int wid  = t >> 5;
    const int g    = lane >> 2;
    const int tg   = lane & 3;
    const int wr   = wid & 1;
    const int wc   = wid >> 1;

    const uint32_t smb  = (uint32_t)__cvta_generic_to_shared(smh);
    const uint32_t aoff = ldsm_aoff(lane);
    const uint32_t boff = ldsm_boff(lane);

    const int ar = t >> 2;
    const int ac = (t & 3) * 8;
    const uint32_t atoff = (uint32_t)(ar * SMS + ac) * 2;
    const int br = t >> 1;
    const int bc = (t & 1) * 16;
    const uint32_t btoff = (uint32_t)(br * SMS + bc) * 2;

    const __half* Ap = A + (size_t)(m0 + ar) * K + ac;
    const __half* Bp = B + (size_t)(n0 + br) * K + bc;

    float acc[2][4][4];
#pragma unroll
    for (int mi = 0; mi < 2; mi++)
#pragma unroll
        for (int ni = 0; ni < 4; ni++)
#pragma unroll
            for (int q = 0; q < 4; q++) acc[mi][ni][q] = 0.f;

#define FILLH64(D, K0)                                   \
    do {                                                 \
        CP16((D) + atoff,              Ap + (K0));       \
        CP16((D) + A64HB + btoff,      Bp + (K0));       \
        CP16((D) + A64HB + btoff + 16, Bp + (K0) + 8);   \
    } while (0)

    FILLH64(smb, 0);
    CP_COMMIT();

    for (int k0 = 0; k0 < K; k0 += 32) {
        const int s = (k0 >> 5) & 1;
        const bool more = (k0 + 32 < K);
        CP_WAIT0();
        __syncthreads();
        if (more) {
            FILLH64(smb + (uint32_t)(s ^ 1) * S64HB, k0 + 32);
            CP_COMMIT();
        }
        const uint32_t stb = smb + (uint32_t)s * S64HB;
#pragma unroll
        for (int ks = 0; ks < 2; ks++) {
            const uint32_t kb2 = ks * 32;
            uint32_t bf[4][2];
#pragma unroll
            for (int ni = 0; ni < 4; ni++) {
                const uint32_t rb = (uint32_t)(wc * 32 + ni * 8) * (SMS * 2) + kb2 + boff;
                ldsm_x2(bf[ni][0], bf[ni][1], stb + A64HB + rb);
            }
#pragma unroll
            for (int mi = 0; mi < 2; mi++) {
                const uint32_t ra = (uint32_t)(wr * 32 + mi * 16) * (SMS * 2) + kb2 + aoff;
                uint32_t a0, a1, a2, a3;
                ldsm_x4(a0, a1, a2, a3, stb + ra);
#pragma unroll
                for (int ni = 0; ni < 4; ni++)
                    mma16816h(acc[mi][ni], a0, a1, a2, a3, bf[ni][0], bf[ni][1]);
            }
        }
    }

#pragma unroll
    for (int mi = 0; mi < 2; mi++) {
        const int row = m0 + wr * 32 + mi * 16 + g;
#pragma unroll
        for (int ni = 0; ni < 4; ni++) {
            const int col = n0 + wc * 32 + ni * 8 + tg * 2;
            float b0 = bias ? bias[col] : 0.f;
            float b1 = bias ? bias[col + 1] : 0.f;
            float c00 = acc[mi][ni][0] + b0, c01 = acc[mi][ni][1] + b1;
            float c10 = acc[mi][ni][2] + b0, c11 = acc[mi][ni][3] + b1;
            if (C) {
                *(float2*)&C[(size_t)row * N + col]       = make_float2(c00, c01);
                *(float2*)&C[(size_t)(row + 8) * N + col] = make_float2(c10, c11);
            }
            if (Ch) {
                *(uint32_t*)&Ch[(size_t)row * N + col]       = pack_h2(c00, c01);
                *(uint32_t*)&Ch[(size_t)(row + 8) * N + col] = pack_h2(c10, c11);
            }
        }
    }
}

// =================================================================================
// gemm_fp16: fp16 GEMM for Wout (BM=128).  A fp16, B fp32 -> fp16 in-kernel.
// =================================================================================
__global__ void __launch_bounds__(256, 2) gemm_fp16(
    const __half* __restrict__ A, const float* __restrict__ B,
    const float* __restrict__ bias, float* __restrict__ C,
    int M, int N, int K)
{
    extern __shared__ __half smh[];

    const int t    = threadIdx.x;
    const int m0   = blockIdx.y * 128;
    const int n0   = blockIdx.x * 128;
    const int lane = t & 31;
    const int wid  = t >> 5;
    const int g    = lane >> 2;
    const int tg   = lane & 3;
    const int wr   = wid & 1;
    const int wc   = wid >> 1;

    const uint32_t smb  = (uint32_t)__cvta_generic_to_shared(smh);
    const uint32_t aoff = ldsm_aoff(lane);
    const uint32_t boff = ldsm_boff(lane);

    const int r  = t >> 1;
    const int hh = (t & 1) * 16;
    const uint32_t toff = (uint32_t)(r * SMS + hh) * 2;
    const int idx = r * SMS + hh;
    const __half* Ap = A + (size_t)(m0 + r) * K + hh;
    const float*  Bp = B + (size_t)(n0 + r) * K + hh;

    float acc[4][4][4];
#pragma unroll
    for (int mi = 0; mi < 4; mi++)
#pragma unroll
        for (int ni = 0; ni < 4; ni++)
#pragma unroll
            for (int q = 0; q < 4; q++) acc[mi][ni][q] = 0.f;

#define CVTB_H(ST, RB)                                                        \
    do {                                                                      \
        __half* bdst = smh + (ST) * (STAGE_H / 2) + (STGB_H / 2) + idx;       \
        uint4 v0, v1;                                                         \
        v0.x = pack_h2((RB)[0].x, (RB)[0].y); v0.y = pack_h2((RB)[0].z, (RB)[0].w); \
        v0.z = pack_h2((RB)[1].x, (RB)[1].y); v0.w = pack_h2((RB)[1].z, (RB)[1].w); \
        v1.x = pack_h2((RB)[2].x, (RB)[2].y); v1.y = pack_h2((RB)[2].z, (RB)[2].w); \
        v1.z = pack_h2((RB)[3].x, (RB)[3].y); v1.w = pack_h2((RB)[3].z, (RB)[3].w); \
        *(uint4*)bdst       = v0;                                             \
        *(uint4*)(bdst + 8) = v1;                                             \
    } while (0)

    CP16(smb + toff,      Ap);
    CP16(smb + toff + 16, Ap + 8);
    CP_COMMIT();
    {
        float4 rb0[4];
#pragma unroll
        for (int i = 0; i < 4; i++) rb0[i] = *(const float4*)(Bp + i * 4);
        CVTB_H(0, rb0);
    }

    for (int k0 = 0; k0 < K; k0 += 32) {
        const int s = (k0 >> 5) & 1;
        const bool more = (k0 + 32 < K);
        CP_WAIT0();
        __syncthreads();
        float4 rb[4];
        if (more) {
            const uint32_t d = smb + (uint32_t)(s ^ 1) * STAGE_H + toff;
            CP16(d,      Ap + k0 + 32);
            CP16(d + 16, Ap + k0 + 40);
            CP_COMMIT();
#pragma unroll
            for (int i = 0; i < 4; i++) rb[i] = *(const float4*)(Bp + k0 + 32 + i * 4);
        }
        const uint32_t stb = smb + (uint32_t)s * STAGE_H;
#pragma unroll
        for (int ks = 0; ks < 2; ks++) {
            const uint32_t kb2 = ks * 32;
            uint32_t bf[4][2];
#pragma unroll
            for (int ni = 0; ni < 4; ni++) {
                const uint32_t rbo = (uint32_t)(wc * 32 + ni * 8) * (SMS * 2) + kb2 + boff;
                ldsm_x2(bf[ni][0], bf[ni][1], stb + STGB_H + rbo);
            }
#pragma unroll
            for (int mi = 0; mi < 4; mi++) {
                const uint32_t ra = (uint32_t)(wr * 64 + mi * 16) * (SMS * 2) + kb2 + aoff;
                uint32_t a0, a1, a2, a3;
                ldsm_x4(a0, a1, a2, a3, stb + ra);
#pragma unroll
                for (int ni = 0; ni < 4; ni++)
                    mma16816h(acc[mi][ni], a0, a1, a2, a3, bf[ni][0], bf[ni][1]);
            }
        }
        if (more) CVTB_H(s ^ 1, rb);
    }

#pragma unroll
    for (int mi = 0; mi < 4; mi++) {
        const int row = m0 + wr * 64 + mi * 16 + g;
#pragma unroll
        for (int ni = 0; ni < 4; ni++) {
            const int col = n0 + wc * 32 + ni * 8 + tg * 2;
            const float b0 = bias[col], b1 = bias[col + 1];
            *(float2*)&C[(size_t)row * N + col] =
                make_float2(acc[mi][ni][0] + b0, acc[mi][ni][1] + b1);
            *(float2*)&C[(size_t)(row + 8) * N + col] =
                make_float2(acc[mi][ni][2] + b0, acc[mi][ni][3] + b1);
        }
    }
}

// =================================================================================
// cvt_all: batched fp32 -> fp16 conversion (grid.y = segment)
// =================================================================================
struct CvtSeg { const float* src; __half* dst; int n4; };
struct CvtArgs { CvtSeg seg[8]; };

__global__ void cvt_all(CvtArgs a)
{
    const CvtSeg s = a.seg[blockIdx.y];
    const int i = blockIdx.x * blockDim.x + threadIdx.x;
    if (i >= s.n4) return;
    float4 v = ((const float4*)s.src)[i];
    uint2 o;
    o.x = pack_h2(v.x, v.y);
    o.y = pack_h2(v.z, v.w);
    ((uint2*)s.dst)[i] = o;
}

// =================================================================================
// compact: per-batch exclusive offsets of unmasked positions (both masks)
// =================================================================================
__global__ void compact_kernel(const int* __restrict__ mE, const int* __restrict__ mS,
                               int* __restrict__ offE, int* __restrict__ offS,
                               int* __restrict__ mtot)
{
    __shared__ int sE[256], sS[256];
    const int b = threadIdx.x;
    int cE = 0, cS = 0;
    for (int n = 0; n < NN; n++) {
        cE += (mE[b * NN + n] == 0);
        cS += (mS[b * NN + n] == 0);
    }
    sE[b] = cE; sS[b] = cS;
    __syncthreads();
    for (int d = 1; d < 256; d <<= 1) {
        int vE = 0, vS = 0;
        if (b >= d) { vE = sE[b - d]; vS = sS[b - d]; }
        __syncthreads();
        sE[b] += vE; sS[b] += vS;
        __syncthreads();
    }
    offE[b] = sE[b] - cE;
    offS[b] = sS[b] - cS;
    if (b == 255) { mtot[0] = sE[255]; mtot[1] = sS[255]; }
}

// =================================================================================
// merged gather (grid.y = side): compact unmasked enc rows -> fp16
// =================================================================================
__global__ void gather2(const float* __restrict__ encE, const float* __restrict__ encS,
                        const int* __restrict__ mE, const int* __restrict__ mS,
                        const int* __restrict__ offE, const int* __restrict__ offS,
                        __half* __restrict__ geh, __half* __restrict__ gsh,
                        int* __restrict__ rowE, int* __restrict__ rowS,
                        float* __restrict__ uE, float* __restrict__ uS)
{
    const int side = blockIdx.y;
    const float* enc = side ? encS : encE;
    const int* mask  = side ? mS : mE;
    const int* off   = side ? offS : offE;
    __half* gh = side ? gsh : geh;
    int* rowinfo = side ? rowS : rowE;
    float* u     = side ? uS : uE;

    __shared__ int s_list[NN];
    __shared__ int s_wtot[8];
    const int b = blockIdx.x;
    const int t = threadIdx.x;
    const int base = off[b];
    const bool in = t < NN;
    const bool valid = in && (mask[b * NN + t] == 0);
    const unsigned wm = __ballot_sync(0xffffffffu, valid);
    const int lane = t & 31, w = t >> 5;
    if (lane == 0) s_wtot[w] = __popc(wm);
    __syncthreads();
    int wbase = 0;
#pragma unroll
    for (int i = 0; i < 4; i++) if (i < w) wbase += s_wtot[i];
    const int rank = wbase + __popc(wm & ((1u << lane) - 1));
    if (valid) {
        s_list[rank] = t;
        rowinfo[base + rank] = b * NN + t;
    } else if (in) {
        u[b * NN + t] = -INFINITY;
    }
    __syncthreads();
    const int cnt = s_wtot[0] + s_wtot[1] + s_wtot[2] + s_wtot[3];

    for (int i = 0; i < cnt; i++) {
        const int n = s_list[i];
        const float2 v = *(const float2*)(enc + ((size_t)b * NN + n) * HH + t * 2);
        *(uint32_t*)&gh[((size_t)base + i) * HH + t * 2] = pack_h2(v.x, v.y);
    }
}

// =================================================================================
// merged attention, fp16 single-pass (grid = (256, 2)); compacted rows.
// =================================================================================
__global__ void __launch_bounds__(256, 2) attn2h(
    const __half* __restrict__ geh, const __half* __restrict__ gsh,
    const __half* __restrict__ w1eh, const __half* __restrict__ w1sh,
    const float* __restrict__ dtg,
    const float* __restrict__ vte, const float* __restrict__ vts,
    const int* __restrict__ rowE, const int* __restrict__ rowS,
    const int* __restrict__ mtotp,
    float* __restrict__ uE, float* __restrict__ uS)
{
    extern __shared__ __half smh[];
    __shared__ float s_vt[512];
    __shared__ float s_u[128];

    const int side = blockIdx.y;
    const int mtot = mtotp[side];
    const int m0 = blockIdx.x * 128;
    if (m0 >= mtot) return;

    const __half* ge  = side ? gsh : geh;
    const __half* w1h = side ? w1sh : w1eh;
    const float* vt = side ? vts : vte;
    const int* rowinfo = side ? rowS : rowE;
    float* u = side ? uS : uE;

    const int t    = threadIdx.x;
    const int lane = t & 31;
    const int wid  = t >> 5;
    const int g    = lane >> 2;
    const int tg   = lane & 3;
    const int wr   = wid & 1;
    const int wc   = wid >> 1;

    const uint32_t smb  = (uint32_t)__cvta_generic_to_shared(smh);
    const uint32_t aoff = ldsm_aoff(lane);
    const uint32_t boff = ldsm_boff(lane);

    for (int i = t; i < 512; i += 256) s_vt[i] = vt[i];
    if (t < 128) s_u[t] = 0.f;

    int rb4[4][2];
#pragma unroll
    for (int mi = 0; mi < 4; mi++)
#pragma unroll
        for (int rr = 0; rr < 2; rr++)
            rb4[mi][rr] = rowinfo[m0 + wr * 64 + mi * 16 + g + rr * 8] >> 7;

    const int r  = t >> 1;
    const int hh = (t & 1) * 16;
    const uint32_t toff = (uint32_t)(r * SMS + hh) * 2;
    const __half* Ap = ge + (size_t)(m0 + r) * 512 + hh;

    float up[8];
#pragma unroll
    for (int i = 0; i < 8; i++) up[i] = 0.f;

    for (int nc = 0; nc < 4; nc++) {
        const __half* Bp = w1h + (size_t)(nc * 128 + r) * 512 + hh;

        float acc[4][4][4];
#pragma unroll
        for (int mi = 0; mi < 4; mi++)
#pragma unroll
            for (int ni = 0; ni < 4; ni++)
#pragma unroll
                for (int q = 0; q < 4; q++) acc[mi][ni][q] = 0.f;

        CP16(smb + toff,               Ap);
        CP16(smb + toff + 16,          Ap + 8);
        CP16(smb + STGB_H + toff,      Bp);
        CP16(smb + STGB_H + toff + 16, Bp + 8);
        CP_COMMIT();

        for (int k0 = 0; k0 < 512; k0 += 32) {
            const int s = (k0 >> 5) & 1;
            const bool more = (k0 + 32 < 512);
            CP_WAIT0();
            __syncthreads();
            if (more) {
                const uint32_t d = smb + (uint32_t)(s ^ 1) * STAGE_H;
                CP16(d + toff,               Ap + k0 + 32);
                CP16(d + toff + 16,          Ap + k0 + 40);
                CP16(d + STGB_H + toff,      Bp + k0 + 32);
                CP16(d + STGB_H + toff + 16, Bp + k0 + 40);
                CP_COMMIT();
            }
            const uint32_t stb = smb + (uint32_t)s * STAGE_H;
#pragma unroll
            for (int ks = 0; ks < 2; ks++) {
                const uint32_t kb2 = ks * 32;
                uint32_t bf[4][2];
#pragma unroll
                for (int ni = 0; ni < 4; ni++) {
                    const uint32_t rbo = (uint32_t)(wc * 32 + ni * 8) * (SMS * 2) + kb2 + boff;
                    ldsm_x2(bf[ni][0], bf[ni][1], stb + STGB_H + rbo);
                }
#pragma unroll
                for (int mi = 0; mi < 4; mi++) {
                    const uint32_t ra = (uint32_t)(wr * 64 + mi * 16) * (SMS * 2) + kb2 + aoff;
                    uint32_t a0, a1, a2, a3;
                    ldsm_x4(a0, a1, a2, a3, stb + ra);
#pragma unroll
                    for (int ni = 0; ni < 4; ni++)
                        mma16816h(acc[mi][ni], a0, a1, a2, a3, bf[ni][0], bf[ni][1]);
                }
            }
        }

#pragma unroll
        for (int mi = 0; mi < 4; mi++) {
            const float* dt0 = dtg + (size_t)rb4[mi][0] * NCAT + (side ? HH : 0);
            const float* dt1 = dtg + (size_t)rb4[mi][1] * NCAT + (side ? HH : 0);
#pragma unroll
            for (int ni = 0; ni < 4; ni++) {
                const int col = nc * 128 + wc * 32 + ni * 8 + tg * 2;
                const float v0 = s_vt[col], v1 = s_vt[col + 1];
                up[mi * 2 + 0] += v0 * tanhf(acc[mi][ni][0] + dt0[col])
                                + v1 * tanhf(acc[mi][ni][1] + dt0[col + 1]);
                up[mi * 2 + 1] += v0 * tanhf(acc[mi][ni][2] + dt1[col])
                                + v1 * tanhf(acc[mi][ni][3] + dt1[col + 1]);
            }
        }
    }

#pragma unroll
    for (int mi = 0; mi < 4; mi++)
#pragma unroll
        for (int rr = 0; rr < 2; rr++) {
            float v = up[mi * 2 + rr];
            v += __shfl_down_sync(0xffffffffu, v, 1);
            v += __shfl_down_sync(0xffffffffu, v, 2);
            if (tg == 0)
                atomicAdd(&s_u[wr * 64 + mi * 16 + g + rr * 8], v);
        }
    __syncthreads();

    if (t < 128 && m0 + t < mtot)
        u[rowinfo[m0 + t]] = s_u[t];
}

// =================================================================================
// plan = softmax(prev_h @ plan_W^T + plan_b)
// =================================================================================
__global__ void plan_kernel(const float* __restrict__ prev_h,
                            const float* __restrict__ plan_W,
                            const float* __restrict__ plan_b,
                            float* __restrict__ plan,
                            float* __restrict__ out_plan)
{
    const int b = blockIdx.x;
    const int t = threadIdx.x;
    __shared__ float s0[128], s1[128];
    float a0 = 0.f, a1 = 0.f;
    const float* hb = prev_h + (size_t)b * DD;
    for (int k = t; k < DD; k += 128) {
        const float h = hb[k];
        a0 += h * plan_W[k];
        a1 += h * plan_W[DD + k];
    }
    s0[t] = a0; s1[t] = a1;
    __syncthreads();
    for (int s = 64; s > 0; s >>= 1) {
        if (t < s) { s0[t] += s0[t + s]; s1[t] += s1[t + s]; }
        __syncthreads();
    }
    if (t == 0) {
        const float l0 = s0[0] + plan_b[0];
        const float l1 = s1[0] + plan_b[1];
        const float mx = fmaxf(l0, l1);
        const float e0 = expf(l0 - mx), e1 = expf(l1 - mx);
        const float inv = 1.f / (e0 + e1);
        plan[2 * b] = e0 * inv;       plan[2 * b + 1] = e1 * inv;
        out_plan[2 * b] = e0 * inv;   out_plan[2 * b + 1] = e1 * inv;
    }
}

// =================================================================================
// merged softmax+context (grid = (BSZ, 2)) — skips masked rows (aw == 0 exactly)
// =================================================================================
__global__ void softmax_ctx2(const float* __restrict__ uE, const float* __restrict__ uS,
                             const float* __restrict__ encE, const float* __restrict__ encS,
                             float* __restrict__ ctxE, float* __restrict__ ctxS)
{
    const int side = blockIdx.y;
    const float* u   = side ? uS : uE;
    const float* enc = side ? encS : encE;
    float* ctx       = side ? ctxS : ctxE;

    const int b = blockIdx.x;
    const int t = threadIdx.x;
    __shared__ float red[256];
    __shared__ float s_aw[NN];
    __shared__ int   s_list[NN];
    __shared__ int   s_wtot[4];

    const float uv = (t < NN) ? u[(size_t)b * NN + t] : -INFINITY;
    red[t] = uv;
    __syncthreads();
    for (int s = 128; s > 0; s >>= 1) {
        if (t < s) red[t] = fmaxf(red[t], red[t + s]);
        __syncthreads();
    }
    const float mx = red[0];
    __syncthreads();
    const float e = (t < NN) ? expf(uv - mx) : 0.f;
    red[t] = e;
    __syncthreads();
    for (int s = 128; s > 0; s >>= 1) {
        if (t < s) red[t] += red[t + s];
        __syncthreads();
    }
    const float inv = 1.f / red[0];

    const bool valid = (t < NN) && (uv != -INFINITY);
    const unsigned wm = __ballot_sync(0xffffffffu, valid);
    const int lane = t & 31, w = t >> 5;
    if (lane == 0 && w < 4) s_wtot[w] = __popc(wm);
    __syncthreads();
    int wbase = 0;
#pragma unroll
    for (int i = 0; i < 4; i++) if (i < w) wbase += s_wtot[i];
    if (valid) {
        const int rank = wbase + __popc(wm & ((1u << lane) - 1));
        s_list[rank] = t;
        s_aw[rank] = e * inv;
    }
    __syncthreads();
    const int cnt = s_wtot[0] + s_wtot[1] + s_wtot[2] + s_wtot[3];

    const float* eb = enc + (size_t)b * NN * HH;
    for (int h = t; h < HH; h += 256) {
        float s = 0.f;
        for (int i = 0; i < cnt; i++)
            s += s_aw[i] * eb[(size_t)s_list[i] * HH + h];
        ctx[(size_t)b * HH + h] = s;
    }
}

// =================================================================================
// y_ctx = [prev_y | plan0*ctx_e + plan1*ctx_s], written fp16
// =================================================================================
__global__ void combine_kernel(const float* __restrict__ prev_y,
                               const float* __restrict__ plan,
                               const float* __restrict__ ctx_e,
                               const float* __restrict__ ctx_s,
                               __half* __restrict__ ych)
{
    const int idx = blockIdx.x * blockDim.x + threadIdx.x;
    if (idx >= BSZ * YC) return;
    const int b = idx >> 10;
    const int c = idx & 1023;
    float v;
    if (c < EE) {
        v = prev_y[(size_t)b * EE + c];
    } else {
        const float p0 = plan[2 * b], p1 = plan[2 * b + 1];
        const int h = c - EE;
        v = p0 * ctx_e[(size_t)b * HH + h] + p1 * ctx_s[(size_t)b * HH + h];
    }
    ych[idx] = __float2half_rn(v);
}

// =================================================================================
// GRU cell elementwise; outputs out_hid (fp32) + hn fp16 (Wout A operand)
// =================================================================================
__global__ void gru_kernel(const float* __restrict__ gx,
                           const float* __restrict__ ghbase,
                           const float* __restrict__ b_hh,
                           const float* __restrict__ prev_h,
                           float* __restrict__ out_hid,
                           __half* __restrict__ hnh)
{
    const int idx = blockIdx.x * blockDim.x + threadIdx.x;
    if (idx >= BSZ * DD) return;
    const int b = idx / DD;
    const int d = idx - b * DD;
    const float* gxb = gx + (size_t)b * G3D;
    const float* ghb = ghbase + (size_t)b * NCAT;
    const float ghr = ghb[d]          + b_hh[d];
    const float ghz = ghb[DD + d]     + b_hh[DD + d];
    const float ghn = ghb[2 * DD + d] + b_hh[2 * DD + d];
    const float r = 1.f / (1.f + expf(-(gxb[d] + ghr)));
    const float z = 1.f / (1.f + expf(-(gxb[DD + d] + ghz)));
    const float n = tanhf(gxb[2 * DD + d] + r * ghn);
    const float h = (1.f - z) * n + z * prev_h[idx];
    out_hid[idx] = h;
    hnh[idx] = __float2half_rn(h);
}

// =================================================================================
// host launcher — graph-capturable
// =================================================================================
extern "C" void kernel_launch(void* const* d_in, const int* in_sizes, int n_in,
                              void* d_out, int out_size)
{
    const float* prev_y  = (const float*)d_in[0];
    const float* prev_h  = (const float*)d_in[1];
    const float* equ_enc = (const float*)d_in[2];
    const float* sns_enc = (const float*)d_in[3];
    const int* equ_mask = (const int*)d_in[5];
    const int* sns_mask = (const int*)d_in[6];
    const float* W1e    = (const float*)d_in[7];
    const float* W2e    = (const float*)d_in[8];
    const float* vte    = (const float*)d_in[9];
    const float* W1s    = (const float*)d_in[10];
    const float* W2s    = (const float*)d_in[11];
    const float* vts    = (const float*)d_in[12];
    const float* plan_W = (const float*)d_in[13];
    const float* plan_b = (const float*)d_in[14];
    const float* Wc     = (const float*)d_in[15];
    const float* bc     = (const float*)d_in[16];
    const float* w_ih   = (const float*)d_in[17];
    const float* w_hh   = (const float*)d_in[18];
    const float* b_ih   = (const float*)d_in[19];
    const float* b_hh   = (const float*)d_in[20];
    const float* Wout   = (const float*)d_in[21];
    const float* bout   = (const float*)d_in[22];

    float* out      = (float*)d_out;
    float* out_dec  = out;
    float* out_hid  = out + (size_t)BSZ * VV;
    float* out_plan = out + (size_t)BSZ * VV + (size_t)BSZ * DD;

    float *u_e, *u_s, *ctx_e, *ctx_s, *plan, *gx, *dtgh;
    int *offE, *offS, *rowE, *rowS, *mtot;
    __half *ph_h, *ee_h, *es_h, *w1e_h, *w1s_h;
    __half *wcat_h, *wc_h, *wih_h, *yc_h, *x_h, *hn_h;
    cudaGetSymbolAddress((void**)&u_e,   g_u_e);
    cudaGetSymbolAddress((void**)&u_s,   g_u_s);
    cudaGetSymbolAddress((void**)&ctx_e, g_ctx_e);
    cudaGetSymbolAddress((void**)&ctx_s, g_ctx_s);
    cudaGetSymbolAddress((void**)&plan,  g_plan);
    cudaGetSymbolAddress((void**)&gx,    g_gx);
    cudaGetSymbolAddress((void**)&dtgh,  g_dtgh);
    cudaGetSymbolAddress((void**)&offE,  g_offE);
    cudaGetSymbolAddress((void**)&offS,  g_offS);
    cudaGetSymbolAddress((void**)&rowE,  g_rowE);
    cudaGetSymbolAddress((void**)&rowS,  g_rowS);
    cudaGetSymbolAddress((void**)&mtot,  g_mtot);
    cudaGetSymbolAddress((void**)&ph_h,  g_ph_h);
    cudaGetSymbolAddress((void**)&ee_h,  g_ee_h);   cudaGetSymbolAddress((void**)&es_h,  g_es_h);
    cudaGetSymbolAddress((void**)&w1e_h, g_w1e_h);  cudaGetSymbolAddress((void**)&w1s_h, g_w1s_h);
    cudaGetSymbolAddress((void**)&wcat_h, g_wcat_h);
    cudaGetSymbolAddress((void**)&wc_h,  g_wc_h);   cudaGetSymbolAddress((void**)&wih_h, g_wih_h);
    cudaGetSymbolAddress((void**)&yc_h,  g_yc_h);   cudaGetSymbolAddress((void**)&x_h,   g_x_h);
    cudaGetSymbolAddress((void**)&hn_h,  g_hn_h);

    cudaFuncSetAttribute(gemm_h64,  cudaFuncAttributeMaxDynamicSharedMemorySize, SMEM64H);
    cudaFuncSetAttribute(gemm_fp16, cudaFuncAttributeMaxDynamicSharedMemorySize, SMEM_H);
    cudaFuncSetAttribute(attn2h,    cudaFuncAttributeMaxDynamicSharedMemorySize, SMEM_H);

    const dim3 blk(256);

    // compaction + merged fp16 gathers
    compact_kernel<<<1, 256>>>(equ_mask, sns_mask, offE, offS, mtot);
    gather2<<<dim3(BSZ, 2), 256>>>(equ_enc, sns_enc, equ_mask, sns_mask, offE, offS,
                                   ee_h, es_h, rowE, rowS, u_e, u_s);

    // one batched fp32 -> fp16 conversion for all operands
    {
        CvtArgs ca;
        ca.seg[0] = { prev_h, ph_h, BSZ * DD / 4 };
        ca.seg[1] = { W2e,  wcat_h,                       HH * DD / 4 };
        ca.seg[2] = { W2s,  wcat_h + (size_t)HH * DD,     HH * DD / 4 };
        ca.seg[3] = { w_hh, wcat_h + (size_t)2 * HH * DD, G3D * DD / 4 };
        ca.seg[4] = { Wc,   wc_h,  HH * YC / 4 };
        ca.seg[5] = { w_ih, wih_h, G3D * HH / 4 };
        ca.seg[6] = { W1e,  w1e_h, HH * HH / 4 };
        ca.seg[7] = { W1s,  w1s_h, HH * HH / 4 };
        const int maxb = (G3D * DD / 4 + 255) / 256;
        cvt_all<<<dim3(maxb, 8), blk>>>(ca);
    }

    // fused [dt_e | dt_s | gh] = prev_h @ Wcat^T   (fp16 single-pass)
    gemm_h64<<<dim3(NCAT / 128, BSZ / 64), blk, SMEM64H>>>(
        ph_h, wcat_h, nullptr, dtgh, nullptr, BSZ, NCAT, DD);

    plan_kernel<<<BSZ, 128>>>(prev_h, plan_W, plan_b, plan, out_plan);

    // merged attention, fp16 single-pass
    attn2h<<<dim3(BSZ, 2), blk, SMEM_H>>>(
        ee_h, es_h, w1e_h, w1s_h, dtgh, vte, vts, rowE, rowS, mtot, u_e, u_s);

    // merged softmax + context (masked rows skipped)
    softmax_ctx2<<<dim3(BSZ, 2), blk>>>(u_e, u_s, equ_enc, sns_enc, ctx_e, ctx_s);

    combine_kernel<<<(BSZ * YC) / 256, blk>>>(prev_y, plan, ctx_e, ctx_s, yc_h);

    // x = y_ctx @ Wc^T + bc (fp16 out) ; gx = x @ w_ih^T + b_ih
    gemm_h64<<<dim3(HH / 128, BSZ / 64), blk, SMEM64H>>>(
        yc_h, wc_h, bc, nullptr, x_h, BSZ, HH, YC);
    gemm_h64<<<dim3(G3D / 128, BSZ / 64), blk, SMEM64H>>>(
        x_h, wih_h, b_ih, gx, nullptr, BSZ, G3D, HH);

    gru_kernel<<<(BSZ * DD) / 256, blk>>>(gx, dtgh + 2 * HH, b_hh, prev_h, out_hid, hn_h);

    // dec_output = h_new @ Wout^T + bout — fp16 single-pass
    gemm_fp16<<<dim3(VV / 128, BSZ / 128), blk, SMEM_H>>>(
        hn_h, Wout, bout, out_dec, BSZ, VV, DD);
}